// round 1
// baseline (speedup 1.0000x reference)
#include <cuda_runtime.h>
#include <cuda_bf16.h>
#include <math.h>

#define Bq 64
#define Lq 512
#define Dq 512
#define Hq 8
#define Eq 64
#define DFF 2048
#define MODES 32
#define VOCAB 10000
#define NUM_APP 10000
#define CATD 536
#define BLq (Bq*Lq)

// ---------------- scratch (device globals; no allocs allowed) ----------------
__device__ float g_x[BLq*Dq];      // activations
__device__ float g_q[BLq*Dq];      // q / fourier output (reused)
__device__ float g_t[BLq*Dq];      // temp (pre-decomp)
__device__ float g_y[BLq*DFF];     // FFN intermediate
__device__ float g_xsr[Bq*Hq*Eq*MODES];
__device__ float g_xsi[Bq*Hq*Eq*MODES];
__device__ float g_osr[Bq*Hq*Eq*MODES];
__device__ float g_osi[Bq*Hq*Eq*MODES];
__device__ float g_ct[Lq*MODES];
__device__ float g_st[Lq*MODES];
__device__ float g_mu[BLq];
__device__ float g_rs[BLq];
__device__ float g_cat[Bq*CATD];

// ---------------- DFT tables: cos/sin(2*pi*m*l/512) ----------------
__global__ void init_tables() {
    int idx = blockIdx.x*blockDim.x + threadIdx.x;
    if (idx < Lq*MODES) {
        int l = idx >> 5, m = idx & 31;
        double a = (double)(m*l) / 256.0;   // 2*m*l/512
        double s, c;
        sincospi(a, &s, &c);
        g_ct[idx] = (float)c;
        g_st[idx] = (float)s;
    }
}

// ---------------- embedding ----------------
__global__ void embed_kernel(const int* __restrict__ app, const float* __restrict__ xt,
                             const float* __restrict__ emb, const float* __restrict__ tw,
                             const float* __restrict__ tb) {
    size_t idx = (size_t)blockIdx.x*256 + threadIdx.x;
    int d = (int)(idx & 511);
    size_t bl = idx >> 9;
    int a = app[bl];
    g_x[idx] = emb[(size_t)a*Dq + d] + xt[bl]*tw[d] + tb[d];
}

// ---------------- generic NT SGEMM: C = A(MxK) * B(NxK)^T [+bias][epi] --------
#define EPI_BIAS 0
#define EPI_RELU 1
#define EPI_RES  2

template<int EPI>
__global__ void __launch_bounds__(256) gemm_nt(
    const float* __restrict__ A, const float* __restrict__ Bw,
    const float* __restrict__ bias, const float* __restrict__ res,
    float* __restrict__ C, int M, int N, int K)
{
    const int BM=128, BN=128, BK=16;
    __shared__ float As[BK][BM+4];
    __shared__ float Bs[BK][BN+4];
    int bm = blockIdx.y * BM;
    int bn = blockIdx.x * BN;
    int t  = threadIdx.x;
    int tx = t & 15, ty = t >> 4;
    float acc[8][8] = {};

    for (int k0 = 0; k0 < K; k0 += BK) {
        #pragma unroll
        for (int j = 0; j < 2; j++) {
            int v   = t + j*256;          // 512 float4 per tile
            int row = v >> 2;
            int c4  = (v & 3) * 4;
            float4 va = *(const float4*)&A[(size_t)(bm+row)*K + k0 + c4];
            As[c4+0][row]=va.x; As[c4+1][row]=va.y; As[c4+2][row]=va.z; As[c4+3][row]=va.w;
            float4 vb = *(const float4*)&Bw[(size_t)(bn+row)*K + k0 + c4];
            Bs[c4+0][row]=vb.x; Bs[c4+1][row]=vb.y; Bs[c4+2][row]=vb.z; Bs[c4+3][row]=vb.w;
        }
        __syncthreads();
        #pragma unroll
        for (int k = 0; k < BK; k++) {
            float a[8], b[8];
            *(float4*)&a[0] = *(float4*)&As[k][ty*8];
            *(float4*)&a[4] = *(float4*)&As[k][ty*8+4];
            *(float4*)&b[0] = *(float4*)&Bs[k][tx*8];
            *(float4*)&b[4] = *(float4*)&Bs[k][tx*8+4];
            #pragma unroll
            for (int i = 0; i < 8; i++)
                #pragma unroll
                for (int j = 0; j < 8; j++)
                    acc[i][j] = fmaf(a[i], b[j], acc[i][j]);
        }
        __syncthreads();
    }

    int crow0 = bm + ty*8, ccol0 = bn + tx*8;
    float bv[8];
    #pragma unroll
    for (int j = 0; j < 8; j++) bv[j] = bias ? bias[ccol0+j] : 0.0f;
    #pragma unroll
    for (int i = 0; i < 8; i++) {
        size_t roff = (size_t)(crow0+i)*N + ccol0;
        #pragma unroll
        for (int j = 0; j < 8; j += 4) {
            float4 v;
            v.x = acc[i][j+0]+bv[j+0]; v.y = acc[i][j+1]+bv[j+1];
            v.z = acc[i][j+2]+bv[j+2]; v.w = acc[i][j+3]+bv[j+3];
            if (EPI == EPI_RELU) {
                v.x = fmaxf(v.x,0.f); v.y = fmaxf(v.y,0.f);
                v.z = fmaxf(v.z,0.f); v.w = fmaxf(v.w,0.f);
            }
            if (EPI == EPI_RES) {
                float4 r = *(const float4*)&res[roff + j];
                v.x += r.x; v.y += r.y; v.z += r.z; v.w += r.w;
            }
            *(float4*)&C[roff + j] = v;
        }
    }
}

// ---------------- forward DFT (32 modes) per (b,h): xs[i,m] ----------------
__global__ void __launch_bounds__(256) dft_kernel(const float* __restrict__ q) {
    int bh = blockIdx.x;
    int b = bh >> 3, h = bh & 7;
    __shared__ float sq[64][65];
    __shared__ float sct[64][32];
    __shared__ float sst[64][32];
    int t  = threadIdx.x;
    int i  = t >> 2;
    int mb = (t & 3) * 8;
    float ar[8] = {}, ai[8] = {};
    const float* qbase = q + (size_t)b*Lq*Dq + h*64;

    for (int l0 = 0; l0 < Lq; l0 += 64) {
        #pragma unroll
        for (int j = 0; j < 4; j++) {
            int v  = t + j*256;            // 1024 float4
            int ll = v >> 4;
            int c4 = (v & 15) * 4;
            float4 va = *(const float4*)&qbase[(size_t)(l0+ll)*Dq + c4];
            sq[ll][c4]=va.x; sq[ll][c4+1]=va.y; sq[ll][c4+2]=va.z; sq[ll][c4+3]=va.w;
        }
        #pragma unroll
        for (int j = 0; j < 2; j++) {
            int v  = t + j*256;            // 512 float4
            int ll = v >> 3;
            int c4 = (v & 7) * 4;
            *(float4*)&sct[ll][c4] = *(const float4*)&g_ct[(l0+ll)*32 + c4];
            *(float4*)&sst[ll][c4] = *(const float4*)&g_st[(l0+ll)*32 + c4];
        }
        __syncthreads();
        #pragma unroll 4
        for (int ll = 0; ll < 64; ll++) {
            float qv = sq[ll][i];
            float c[8], s[8];
            *(float4*)&c[0] = *(float4*)&sct[ll][mb];
            *(float4*)&c[4] = *(float4*)&sct[ll][mb+4];
            *(float4*)&s[0] = *(float4*)&sst[ll][mb];
            *(float4*)&s[4] = *(float4*)&sst[ll][mb+4];
            #pragma unroll
            for (int mm = 0; mm < 8; mm++) {
                ar[mm] = fmaf(qv,  c[mm], ar[mm]);
                ai[mm] = fmaf(-qv, s[mm], ai[mm]);
            }
        }
        __syncthreads();
    }
    size_t off = ((size_t)bh*64 + i)*32 + mb;
    #pragma unroll
    for (int mm = 0; mm < 8; mm += 4) {
        *(float4*)&g_xsr[off+mm] = *(float4*)&ar[mm];
        *(float4*)&g_xsi[off+mm] = *(float4*)&ai[mm];
    }
}

// ---------------- complex mode mix: os[o,m] = sum_i xs[i,m]*w[h,i,o,m] -------
__global__ void __launch_bounds__(256) mix_kernel(const float* __restrict__ wr,
                                                  const float* __restrict__ wi) {
    int bh = blockIdx.x;
    int h = bh & 7;
    __shared__ float sxr[64][32];
    __shared__ float sxi[64][32];
    int t = threadIdx.x;
    #pragma unroll
    for (int j = 0; j < 2; j++) {
        int v  = t + j*256;
        int ii = v >> 3;
        int c4 = (v & 7) * 4;
        size_t off = ((size_t)bh*64 + ii)*32 + c4;
        *(float4*)&sxr[ii][c4] = *(const float4*)&g_xsr[off];
        *(float4*)&sxi[ii][c4] = *(const float4*)&g_xsi[off];
    }
    __syncthreads();
    int o  = t >> 2;
    int mb = (t & 3) * 8;
    float orr[8] = {}, oii[8] = {};
    for (int i = 0; i < 64; i++) {
        float xr[8], xi[8], w0[8], w1[8];
        *(float4*)&xr[0] = *(float4*)&sxr[i][mb];
        *(float4*)&xr[4] = *(float4*)&sxr[i][mb+4];
        *(float4*)&xi[0] = *(float4*)&sxi[i][mb];
        *(float4*)&xi[4] = *(float4*)&sxi[i][mb+4];
        size_t woff = (((size_t)h*64 + i)*64 + o)*32 + mb;
        *(float4*)&w0[0] = *(const float4*)&wr[woff];
        *(float4*)&w0[4] = *(const float4*)&wr[woff+4];
        *(float4*)&w1[0] = *(const float4*)&wi[woff];
        *(float4*)&w1[4] = *(const float4*)&wi[woff+4];
        #pragma unroll
        for (int mm = 0; mm < 8; mm++) {
            orr[mm] = fmaf(xr[mm], w0[mm], orr[mm]);
            orr[mm] = fmaf(-xi[mm], w1[mm], orr[mm]);
            oii[mm] = fmaf(xr[mm], w1[mm], oii[mm]);
            oii[mm] = fmaf(xi[mm], w0[mm], oii[mm]);
        }
    }
    size_t off = ((size_t)bh*64 + o)*32 + mb;
    #pragma unroll
    for (int mm = 0; mm < 8; mm += 4) {
        *(float4*)&g_osr[off+mm] = *(float4*)&orr[mm];
        *(float4*)&g_osi[off+mm] = *(float4*)&oii[mm];
    }
}

// ---------------- 32-mode irfft; writes permuted layout directly -------------
// fout[b, h*64+o, lp] = (1/512)*Re(os[o,0]) + (2/512)*sum_{m>=1}(osr*cos - osi*sin)
__global__ void __launch_bounds__(256) irfft_kernel(float* __restrict__ fout) {
    int bh = blockIdx.x;
    int b = bh >> 3, h = bh & 7;
    __shared__ float sor[64][32];
    __shared__ float soi[64][32];
    int t = threadIdx.x;
    #pragma unroll
    for (int j = 0; j < 2; j++) {
        int v  = t + j*256;
        int oo = v >> 3;
        int c4 = (v & 7) * 4;
        size_t off = ((size_t)bh*64 + oo)*32 + c4;
        float4 r = *(const float4*)&g_osr[off];
        float4 im = *(const float4*)&g_osi[off];
        if (c4 == 0) { r.x *= 0.5f; im.x *= 0.5f; }   // mode-0 gets 1/512, not 2/512
        *(float4*)&sor[oo][c4] = r;
        *(float4*)&soi[oo][c4] = im;
    }
    __syncthreads();

    #pragma unroll
    for (int half = 0; half < 2; half++) {
        int lp = t + half*256;
        float c[32], s[32];
        #pragma unroll
        for (int j = 0; j < 32; j += 4) {
            *(float4*)&c[j] = *(const float4*)&g_ct[lp*32 + j];
            *(float4*)&s[j] = *(const float4*)&g_st[lp*32 + j];
        }
        float* orow = fout + ((size_t)b*Lq + h*64)*Dq + lp;
        for (int o = 0; o < 64; o++) {
            float acc = 0.f;
            #pragma unroll
            for (int m4 = 0; m4 < 32; m4 += 4) {
                float4 r = *(float4*)&sor[o][m4];
                float4 im = *(float4*)&soi[o][m4];
                acc = fmaf(r.x, c[m4+0], acc);  acc = fmaf(-im.x, s[m4+0], acc);
                acc = fmaf(r.y, c[m4+1], acc);  acc = fmaf(-im.y, s[m4+1], acc);
                acc = fmaf(r.z, c[m4+2], acc);  acc = fmaf(-im.z, s[m4+2], acc);
                acc = fmaf(r.w, c[m4+3], acc);  acc = fmaf(-im.w, s[m4+3], acc);
            }
            orow[(size_t)o*Dq] = acc * (1.0f/256.0f);
        }
    }
}

// ---------------- series_decomp: out = in - movavg25(in) ----------------
__global__ void decomp_kernel(const float* __restrict__ in, float* __restrict__ out) {
    int gid = blockIdx.x*blockDim.x + threadIdx.x;   // b*D + d
    int b = gid >> 9, d = gid & 511;
    const float* p = in + (size_t)b*Lq*Dq + d;
    float* po = out + (size_t)b*Lq*Dq + d;
    float wsum = 13.0f * p[0];
    #pragma unroll
    for (int j = 1; j <= 12; j++) wsum += p[(size_t)j*Dq];
    for (int l = 0; l < Lq; l++) {
        float xl = p[(size_t)l*Dq];
        po[(size_t)l*Dq] = xl - wsum*(1.0f/25.0f);
        int jn = l+13 > Lq-1 ? Lq-1 : l+13;
        int jo = l-12 < 0 ? 0 : l-12;
        wsum += p[(size_t)jn*Dq] - p[(size_t)jo*Dq];
    }
}

// ---------------- layernorm pass 1: row mean / rstd ----------------
__global__ void ln_rows(const float* __restrict__ x) {
    int row = blockIdx.x;
    int t = threadIdx.x;                 // 256
    const float* p = x + (size_t)row*Dq;
    float v0 = p[t], v1 = p[t+256];
    __shared__ float sh[8];
    float s = v0 + v1;
    int lane = t & 31, w = t >> 5;
    #pragma unroll
    for (int o = 16; o > 0; o >>= 1) s += __shfl_down_sync(~0u, s, o);
    if (lane == 0) sh[w] = s;
    __syncthreads();
    if (t < 32) {
        float v = (t < 8) ? sh[t] : 0.f;
        #pragma unroll
        for (int o = 4; o > 0; o >>= 1) v += __shfl_down_sync(~0u, v, o);
        if (t == 0) sh[0] = v;
    }
    __syncthreads();
    float mu = sh[0] * (1.0f/512.0f);
    __syncthreads();
    float d0 = v0 - mu, d1 = v1 - mu;
    s = d0*d0 + d1*d1;
    #pragma unroll
    for (int o = 16; o > 0; o >>= 1) s += __shfl_down_sync(~0u, s, o);
    if (lane == 0) sh[w] = s;
    __syncthreads();
    if (t < 32) {
        float v = (t < 8) ? sh[t] : 0.f;
        #pragma unroll
        for (int o = 4; o > 0; o >>= 1) v += __shfl_down_sync(~0u, v, o);
        if (t == 0) {
            float var = v * (1.0f/512.0f);
            g_mu[row] = mu;
            g_rs[row] = rsqrtf(var + 1e-5f);
        }
    }
}

// ---------------- layernorm pass 2 + build concat vector ----------------
__global__ void ln_cols(const float* __restrict__ x, const float* __restrict__ nw,
                        const float* __restrict__ nb, const float* __restrict__ tv) {
    int b = blockIdx.x;
    int d = threadIdx.x;                 // 512
    float w = nw[d], bb = nb[d];
    float sum = 0.f, lastv = 0.f;
    for (int l = 0; l < Lq; l++) {
        int row = b*Lq + l;
        float v = (x[(size_t)row*Dq + d] - g_mu[row]) * g_rs[row] * w + bb;
        sum += v;
        if (l == Lq-1) lastv = v;
    }
    g_cat[b*CATD + d] = lastv - sum*(1.0f/512.0f);
    if (d < 24) g_cat[b*CATD + 512 + d] = tv[((size_t)b*Lq + (Lq-1))*24 + d];
}

// ---------------- final projection: score = cat(64x536) @ pw(10000x536)^T ----
__global__ void __launch_bounds__(256) proj_kernel(const float* __restrict__ pw,
                                                   const float* __restrict__ pb,
                                                   float* __restrict__ out) {
    __shared__ float As[8][65];
    __shared__ float Bs[8][65];
    int n0 = blockIdx.x * 64;
    int t = threadIdx.x;
    int tx = t & 15, ty = t >> 4;
    float acc[4][4] = {};
    for (int k0 = 0; k0 < CATD; k0 += 8) {
        int v = t*2;
        int r = v >> 3, c = v & 7;
        As[c][r]   = g_cat[r*CATD + k0 + c];
        As[c+1][r] = g_cat[r*CATD + k0 + c + 1];
        int n = n0 + r;
        float f0 = 0.f, f1 = 0.f;
        if (n < NUM_APP) {
            f0 = pw[(size_t)n*CATD + k0 + c];
            f1 = pw[(size_t)n*CATD + k0 + c + 1];
        }
        Bs[c][r] = f0; Bs[c+1][r] = f1;
        __syncthreads();
        #pragma unroll
        for (int k = 0; k < 8; k++) {
            float a[4], bv[4];
            #pragma unroll
            for (int i = 0; i < 4; i++) { a[i] = As[k][ty*4+i]; bv[i] = Bs[k][tx*4+i]; }
            #pragma unroll
            for (int i = 0; i < 4; i++)
                #pragma unroll
                for (int j = 0; j < 4; j++)
                    acc[i][j] = fmaf(a[i], bv[j], acc[i][j]);
        }
        __syncthreads();
    }
    #pragma unroll
    for (int i = 0; i < 4; i++) {
        int bi = ty*4 + i;
        #pragma unroll
        for (int j = 0; j < 4; j++) {
            int n = n0 + tx*4 + j;
            if (n < NUM_APP) out[(size_t)bi*NUM_APP + n] = acc[i][j] + pb[n];
        }
    }
}

// ---------------- host orchestration ----------------
extern "C" void kernel_launch(void* const* d_in, const int* in_sizes, int n_in,
                              void* d_out, int out_size) {
    const int*   x_app     = (const int*)  d_in[0];
    const float* x_time    = (const float*)d_in[1];
    const float* time_vecs = (const float*)d_in[2];
    /* d_in[3] = targets (unused by reference output) */
    const float* app_emb_w = (const float*)d_in[4];
    const float* time_w    = (const float*)d_in[5];
    const float* time_b    = (const float*)d_in[6];
    const float* Wq        = (const float*)d_in[7];
    const float* bq        = (const float*)d_in[8];
    const float* Wo        = (const float*)d_in[9];
    const float* bo        = (const float*)d_in[10];
    const float* four_wr   = (const float*)d_in[11];
    const float* four_wi   = (const float*)d_in[12];
    const float* conv1_w   = (const float*)d_in[13];
    const float* conv2_w   = (const float*)d_in[14];
    const float* norm_w    = (const float*)d_in[15];
    const float* norm_b    = (const float*)d_in[16];
    const float* proj_w    = (const float*)d_in[17];
    const float* proj_b    = (const float*)d_in[18];
    float* out = (float*)d_out;

    void *px, *pq, *pt, *py;
    cudaGetSymbolAddress(&px, g_x);
    cudaGetSymbolAddress(&pq, g_q);
    cudaGetSymbolAddress(&pt, g_t);
    cudaGetSymbolAddress(&py, g_y);
    float* fx = (float*)px;
    float* fq = (float*)pq;
    float* ft = (float*)pt;
    float* fy = (float*)py;

    init_tables<<<64, 256>>>();
    embed_kernel<<<BLq*Dq/256, 256>>>(x_app, x_time, app_emb_w, time_w, time_b);

    const int M = BLq;
    for (int l = 0; l < 2; l++) {
        const float* wq = Wq + (size_t)l*Dq*Dq;
        const float* wo = Wo + (size_t)l*Dq*Dq;
        const float* c1 = conv1_w + (size_t)l*DFF*Dq;
        const float* c2 = conv2_w + (size_t)l*Dq*DFF;
        const float* fr = four_wr + (size_t)l*Hq*Eq*Eq*MODES;
        const float* fi = four_wi + (size_t)l*Hq*Eq*Eq*MODES;

        // q = x @ Wq^T + bq
        gemm_nt<EPI_BIAS><<<dim3(Dq/128, M/128), 256>>>(fx, wq, bq + l*Dq, nullptr, fq, M, Dq, Dq);
        // fourier block (32-mode DFT -> complex mix -> irfft, permuted write)
        dft_kernel<<<Bq*Hq, 256>>>(fq);
        mix_kernel<<<Bq*Hq, 256>>>(fr, fi);
        irfft_kernel<<<Bq*Hq, 256>>>(fq);
        // x2 = fourier_out @ Wo^T + bo + x ; then x = x2 - movavg(x2)
        gemm_nt<EPI_RES><<<dim3(Dq/128, M/128), 256>>>(fq, wo, bo + l*Dq, fx, ft, M, Dq, Dq);
        decomp_kernel<<<Bq*Dq/256, 256>>>(ft, fx);
        // FFN
        gemm_nt<EPI_RELU><<<dim3(DFF/128, M/128), 256>>>(fx, c1, nullptr, nullptr, fy, M, DFF, Dq);
        gemm_nt<EPI_RES><<<dim3(Dq/128, M/128), 256>>>(fy, c2, nullptr, fx, ft, M, Dq, DFF);
        decomp_kernel<<<Bq*Dq/256, 256>>>(ft, fx);
    }

    ln_rows<<<BLq, 256>>>(fx);
    ln_cols<<<Bq, 512>>>(fx, norm_w, norm_b, time_vecs);
    proj_kernel<<<(NUM_APP + 63)/64, 256>>>(proj_w, proj_b, out);
}

// round 3
// speedup vs baseline: 1.7751x; 1.7751x over previous
#include <cuda_runtime.h>
#include <cuda_bf16.h>
#include <math.h>
#include <stdint.h>

#define Bq 64
#define Lq 512
#define Dq 512
#define Hq 8
#define Eq 64
#define DFF 2048
#define MODES 32
#define VOCAB 10000
#define NUM_APP 10000
#define CATD 536
#define BLq (Bq*Lq)

// ================= helpers =================
__device__ __forceinline__ uint32_t smem_u32(const void* p) {
    uint32_t a;
    asm("{ .reg .u64 t; cvta.to.shared.u64 t, %1; cvt.u32.u64 %0, t; }" : "=r"(a) : "l"(p));
    return a;
}
__device__ __forceinline__ void cp16(uint32_t dst, const void* src) {
    asm volatile("cp.async.cg.shared.global [%0], [%1], 16;" :: "r"(dst), "l"(src) : "memory");
}
#define CP_COMMIT() asm volatile("cp.async.commit_group;" ::: "memory")

#define LDSM_X4(r0,r1,r2,r3, addr) \
    asm volatile("ldmatrix.sync.aligned.m8n8.x4.shared.b16 {%0,%1,%2,%3}, [%4];" \
        : "=r"(r0), "=r"(r1), "=r"(r2), "=r"(r3) : "r"(addr))

#define MMA16816(d, a, b0, b1) \
    asm volatile("mma.sync.aligned.m16n8k16.row.col.f32.bf16.bf16.f32 " \
        "{%0,%1,%2,%3},{%4,%5,%6,%7},{%8,%9},{%0,%1,%2,%3};" \
        : "+f"((d)[0]), "+f"((d)[1]), "+f"((d)[2]), "+f"((d)[3]) \
        : "r"((a)[0]), "r"((a)[1]), "r"((a)[2]), "r"((a)[3]), "r"(b0), "r"(b1))

// ================= scratch (device globals) =================
__device__ float g_x[BLq*Dq];
__device__ float g_q[BLq*Dq];
__device__ float g_t[BLq*Dq];
__device__ __align__(256) __nv_bfloat16 g_xh[BLq*Dq],  g_xl[BLq*Dq];
__device__ __align__(256) __nv_bfloat16 g_fh[BLq*Dq],  g_fl[BLq*Dq];
__device__ __align__(256) __nv_bfloat16 g_yh[BLq*DFF], g_yl[BLq*DFF];
__device__ __align__(256) __nv_bfloat16 g_wqh[2*Dq*Dq], g_wql[2*Dq*Dq];
__device__ __align__(256) __nv_bfloat16 g_woh[2*Dq*Dq], g_wol[2*Dq*Dq];
__device__ __align__(256) __nv_bfloat16 g_c1h[2*DFF*Dq], g_c1l[2*DFF*Dq];
__device__ __align__(256) __nv_bfloat16 g_c2h[2*Dq*DFF], g_c2l[2*Dq*DFF];
__device__ float g_xsr[Bq*Hq*Eq*MODES], g_xsi[Bq*Hq*Eq*MODES];
__device__ float g_osr[Bq*Hq*Eq*MODES], g_osi[Bq*Hq*Eq*MODES];
__device__ float g_ct[Lq*MODES], g_st[Lq*MODES];
__device__ float g_mu[BLq], g_rs[BLq];
__device__ float g_cat[Bq*CATD];

// ================= small kernels =================
__global__ void init_tables() {
    int idx = blockIdx.x*blockDim.x + threadIdx.x;
    if (idx < Lq*MODES) {
        int l = idx >> 5, m = idx & 31;
        double a = (double)(m*l) / 256.0;
        double s, c;
        sincospi(a, &s, &c);
        g_ct[idx] = (float)c;
        g_st[idx] = (float)s;
    }
}

__global__ void convert_hl(const float* __restrict__ src, __nv_bfloat16* __restrict__ h,
                           __nv_bfloat16* __restrict__ l, int n) {
    int i = blockIdx.x*256 + threadIdx.x;
    if (i < n) {
        float v = src[i];
        __nv_bfloat16 hv = __float2bfloat16(v);
        h[i] = hv;
        l[i] = __float2bfloat16(v - __bfloat162float(hv));
    }
}

__global__ void embed_kernel(const int* __restrict__ app, const float* __restrict__ xt,
                             const float* __restrict__ emb, const float* __restrict__ tw,
                             const float* __restrict__ tb) {
    size_t idx = (size_t)blockIdx.x*256 + threadIdx.x;
    int d = (int)(idx & 511);
    size_t bl = idx >> 9;
    int a = app[bl];
    float v = emb[(size_t)a*Dq + d] + xt[bl]*tw[d] + tb[d];
    g_x[idx] = v;
    __nv_bfloat16 hv = __float2bfloat16(v);
    g_xh[idx] = hv;
    g_xl[idx] = __float2bfloat16(v - __bfloat162float(hv));
}

// ================= mma.sync bf16x3 GEMM: C = A(MxK) @ B(NxK)^T =================
// BM=128, BN=128, BK=32, 3-stage cp.async pipeline, 256 threads (8 warps, 2x4),
// warp tile 64x32 -> 4x4 m16n8 mma tiles, 3 products per tile (hi*hi+hi*lo+lo*hi).
#define GF_BIAS 1
#define GF_RES  2
#define GF_RELU 4
#define GF_OUTF32 8
#define GF_OUTBF16 16

#define STG 32768                 // Ah(8K)+Al(8K)+Bh(8K)+Bl(8K) per stage
#define SMEM_GEMM (3*STG + 256)

template<int FLAGS>
__global__ void __launch_bounds__(256, 1) gemm_mma(
    const __nv_bfloat16* __restrict__ Ah, const __nv_bfloat16* __restrict__ Al,
    const __nv_bfloat16* __restrict__ Bh, const __nv_bfloat16* __restrict__ Bl,
    const float* __restrict__ bias, const float* __restrict__ res,
    float* __restrict__ Cf, __nv_bfloat16* __restrict__ Ch, __nv_bfloat16* __restrict__ Cl,
    int M, int N, int K)
{
    extern __shared__ char dsm[];
    uint32_t sbase = (smem_u32(dsm) + 127) & ~127u;

    const int t = threadIdx.x;
    const int lane = t & 31;
    const int wid = t >> 5;
    const int wm = wid >> 2;          // 0..1
    const int wn = wid & 3;           // 0..3
    const int bm = blockIdx.y * 128, bn = blockIdx.x * 128;
    const int NC = K >> 5;

    float acc[4][4][4] = {};

    // ---- async tile loader: 128x32 bf16 tiles for Ah/Al/Bh/Bl ----
    const int lrow = t >> 2;          // 0..63
    const int lcell = t & 3;          // 16B cell in 64B row
    auto load_chunk = [&](int c, int stg) {
        uint32_t sb = sbase + stg*STG;
        size_t k0 = (size_t)c * 32 + lcell*8;
        #pragma unroll
        for (int j = 0; j < 2; j++) {
            int row = lrow + j*64;
            uint32_t soff = row*64 + (((uint32_t)(lcell ^ (row & 3))) << 4);
            size_t ga = (size_t)(bm + row)*K + k0;
            size_t gb = (size_t)(bn + row)*K + k0;
            cp16(sb +         soff, Ah + ga);
            cp16(sb +  8192 + soff, Al + ga);
            cp16(sb + 16384 + soff, Bh + gb);
            cp16(sb + 24576 + soff, Bl + gb);
        }
        CP_COMMIT();
    };

    load_chunk(0, 0);
    load_chunk(1, 1);

    // precomputed ldmatrix row indices
    const int arow_base = wm*64 + (lane & 15);
    const int brow_base = wn*32 + (lane & 15);
    const int kc_hi = lane >> 4;      // 0/1

    for (int c = 0; c < NC; c++) {
        if (c + 2 < NC) asm volatile("cp.async.wait_group 1;" ::: "memory");
        else            asm volatile("cp.async.wait_group 0;" ::: "memory");
        __syncthreads();
        if (c + 2 < NC) load_chunk(c + 2, (c + 2) % 3);

        uint32_t sb = sbase + (c % 3)*STG;
        #pragma unroll
        for (int s = 0; s < 2; s++) {
            uint32_t ah[4][4], al[4][4], bh[2][4], bl[2][4];
            int chunk = s*2 + kc_hi;
            #pragma unroll
            for (int mt = 0; mt < 4; mt++) {
                int row = arow_base + mt*16;
                uint32_t off = row*64 + (((uint32_t)(chunk ^ (row & 3))) << 4);
                LDSM_X4(ah[mt][0], ah[mt][1], ah[mt][2], ah[mt][3], sb + off);
                LDSM_X4(al[mt][0], al[mt][1], al[mt][2], al[mt][3], sb + 8192 + off);
            }
            #pragma unroll
            for (int g = 0; g < 2; g++) {
                int row = brow_base + g*16;
                uint32_t off = row*64 + (((uint32_t)(chunk ^ (row & 3))) << 4);
                LDSM_X4(bh[g][0], bh[g][1], bh[g][2], bh[g][3], sb + 16384 + off);
                LDSM_X4(bl[g][0], bl[g][1], bl[g][2], bl[g][3], sb + 24576 + off);
            }
            #pragma unroll
            for (int mt = 0; mt < 4; mt++) {
                #pragma unroll
                for (int nt = 0; nt < 4; nt++) {
                    int g = nt >> 1, o = nt & 1;
                    MMA16816(acc[mt][nt], ah[mt], bh[g][o], bh[g][o+2]);
                    MMA16816(acc[mt][nt], ah[mt], bl[g][o], bl[g][o+2]);
                    MMA16816(acc[mt][nt], al[mt], bh[g][o], bh[g][o+2]);
                }
            }
        }
    }

    // ---- epilogue ----
    int r0 = bm + wm*64 + (lane >> 2);
    int c0 = bn + wn*32 + (lane & 3)*2;
    #pragma unroll
    for (int mt = 0; mt < 4; mt++) {
        #pragma unroll
        for (int nt = 0; nt < 4; nt++) {
            int col = c0 + nt*8;
            float b0 = 0.f, b1 = 0.f;
            if (FLAGS & GF_BIAS) { b0 = bias[col]; b1 = bias[col+1]; }
            #pragma unroll
            for (int half = 0; half < 2; half++) {
                int row = r0 + mt*16 + half*8;
                float v0 = acc[mt][nt][half*2+0] + b0;
                float v1 = acc[mt][nt][half*2+1] + b1;
                size_t ro = (size_t)row * N + col;
                if (FLAGS & GF_RES) {
                    float2 r2 = *(const float2*)&res[ro];
                    v0 += r2.x; v1 += r2.y;
                }
                if (FLAGS & GF_RELU) { v0 = fmaxf(v0, 0.f); v1 = fmaxf(v1, 0.f); }
                if (FLAGS & GF_OUTF32) {
                    float2 o2; o2.x = v0; o2.y = v1;
                    *(float2*)&Cf[ro] = o2;
                }
                if (FLAGS & GF_OUTBF16) {
                    __nv_bfloat16 h0 = __float2bfloat16(v0);
                    __nv_bfloat16 h1 = __float2bfloat16(v1);
                    __nv_bfloat162 hp; hp.x = h0; hp.y = h1;
                    *(__nv_bfloat162*)&Ch[ro] = hp;
                    __nv_bfloat162 lp;
                    lp.x = __float2bfloat16(v0 - __bfloat162float(h0));
                    lp.y = __float2bfloat16(v1 - __bfloat162float(h1));
                    *(__nv_bfloat162*)&Cl[ro] = lp;
                }
            }
        }
    }
}

// ================= fourier path =================
__global__ void __launch_bounds__(256) dft_kernel(const float* __restrict__ q) {
    int bh = blockIdx.x;
    int b = bh >> 3, h = bh & 7;
    __shared__ float sq[64][65];
    __shared__ float sct[64][32];
    __shared__ float sst[64][32];
    int t  = threadIdx.x;
    int i  = t >> 2;
    int mb = (t & 3) * 8;
    float ar[8] = {}, ai[8] = {};
    const float* qbase = q + (size_t)b*Lq*Dq + h*64;

    for (int l0 = 0; l0 < Lq; l0 += 64) {
        #pragma unroll
        for (int j = 0; j < 4; j++) {
            int v  = t + j*256;
            int ll = v >> 4;
            int c4 = (v & 15) * 4;
            float4 va = *(const float4*)&qbase[(size_t)(l0+ll)*Dq + c4];
            sq[ll][c4]=va.x; sq[ll][c4+1]=va.y; sq[ll][c4+2]=va.z; sq[ll][c4+3]=va.w;
        }
        #pragma unroll
        for (int j = 0; j < 2; j++) {
            int v  = t + j*256;
            int ll = v >> 3;
            int c4 = (v & 7) * 4;
            *(float4*)&sct[ll][c4] = *(const float4*)&g_ct[(l0+ll)*32 + c4];
            *(float4*)&sst[ll][c4] = *(const float4*)&g_st[(l0+ll)*32 + c4];
        }
        __syncthreads();
        #pragma unroll 4
        for (int ll = 0; ll < 64; ll++) {
            float qv = sq[ll][i];
            float c[8], s[8];
            *(float4*)&c[0] = *(float4*)&sct[ll][mb];
            *(float4*)&c[4] = *(float4*)&sct[ll][mb+4];
            *(float4*)&s[0] = *(float4*)&sst[ll][mb];
            *(float4*)&s[4] = *(float4*)&sst[ll][mb+4];
            #pragma unroll
            for (int mm = 0; mm < 8; mm++) {
                ar[mm] = fmaf(qv,  c[mm], ar[mm]);
                ai[mm] = fmaf(-qv, s[mm], ai[mm]);
            }
        }
        __syncthreads();
    }
    size_t off = ((size_t)bh*64 + i)*32 + mb;
    #pragma unroll
    for (int mm = 0; mm < 8; mm += 4) {
        *(float4*)&g_xsr[off+mm] = *(float4*)&ar[mm];
        *(float4*)&g_xsi[off+mm] = *(float4*)&ai[mm];
    }
}

__global__ void __launch_bounds__(256) mix_kernel(const float* __restrict__ wr,
                                                  const float* __restrict__ wi) {
    int bh = blockIdx.x;
    int h = bh & 7;
    __shared__ float sxr[64][32];
    __shared__ float sxi[64][32];
    int t = threadIdx.x;
    #pragma unroll
    for (int j = 0; j < 2; j++) {
        int v  = t + j*256;
        int ii = v >> 3;
        int c4 = (v & 7) * 4;
        size_t off = ((size_t)bh*64 + ii)*32 + c4;
        *(float4*)&sxr[ii][c4] = *(const float4*)&g_xsr[off];
        *(float4*)&sxi[ii][c4] = *(const float4*)&g_xsi[off];
    }
    __syncthreads();
    int o  = t >> 2;
    int mb = (t & 3) * 8;
    float orr[8] = {}, oii[8] = {};
    for (int i = 0; i < 64; i++) {
        float xr[8], xi[8], w0[8], w1[8];
        *(float4*)&xr[0] = *(float4*)&sxr[i][mb];
        *(float4*)&xr[4] = *(float4*)&sxr[i][mb+4];
        *(float4*)&xi[0] = *(float4*)&sxi[i][mb];
        *(float4*)&xi[4] = *(float4*)&sxi[i][mb+4];
        size_t woff = (((size_t)h*64 + i)*64 + o)*32 + mb;
        *(float4*)&w0[0] = *(const float4*)&wr[woff];
        *(float4*)&w0[4] = *(const float4*)&wr[woff+4];
        *(float4*)&w1[0] = *(const float4*)&wi[woff];
        *(float4*)&w1[4] = *(const float4*)&wi[woff+4];
        #pragma unroll
        for (int mm = 0; mm < 8; mm++) {
            orr[mm] = fmaf(xr[mm], w0[mm], orr[mm]);
            orr[mm] = fmaf(-xi[mm], w1[mm], orr[mm]);
            oii[mm] = fmaf(xr[mm], w1[mm], oii[mm]);
            oii[mm] = fmaf(xi[mm], w0[mm], oii[mm]);
        }
    }
    size_t off = ((size_t)bh*64 + o)*32 + mb;
    #pragma unroll
    for (int mm = 0; mm < 8; mm += 4) {
        *(float4*)&g_osr[off+mm] = *(float4*)&orr[mm];
        *(float4*)&g_osi[off+mm] = *(float4*)&oii[mm];
    }
}

__global__ void __launch_bounds__(256) irfft_kernel(__nv_bfloat16* __restrict__ fh,
                                                    __nv_bfloat16* __restrict__ fl) {
    int bh = blockIdx.x;
    int b = bh >> 3, h = bh & 7;
    __shared__ float sor[64][32];
    __shared__ float soi[64][32];
    int t = threadIdx.x;
    #pragma unroll
    for (int j = 0; j < 2; j++) {
        int v  = t + j*256;
        int oo = v >> 3;
        int c4 = (v & 7) * 4;
        size_t off = ((size_t)bh*64 + oo)*32 + c4;
        float4 r = *(const float4*)&g_osr[off];
        float4 im = *(const float4*)&g_osi[off];
        if (c4 == 0) { r.x *= 0.5f; im.x *= 0.5f; }
        *(float4*)&sor[oo][c4] = r;
        *(float4*)&soi[oo][c4] = im;
    }
    __syncthreads();

    #pragma unroll
    for (int half = 0; half < 2; half++) {
        int lp = t + half*256;
        float c[32], s[32];
        #pragma unroll
        for (int j = 0; j < 32; j += 4) {
            *(float4*)&c[j] = *(const float4*)&g_ct[lp*32 + j];
            *(float4*)&s[j] = *(const float4*)&g_st[lp*32 + j];
        }
        size_t base = ((size_t)b*Lq + h*64)*Dq + lp;
        for (int o = 0; o < 64; o++) {
            float acc = 0.f;
            #pragma unroll
            for (int m4 = 0; m4 < 32; m4 += 4) {
                float4 r = *(float4*)&sor[o][m4];
                float4 im = *(float4*)&soi[o][m4];
                acc = fmaf(r.x, c[m4+0], acc);  acc = fmaf(-im.x, s[m4+0], acc);
                acc = fmaf(r.y, c[m4+1], acc);  acc = fmaf(-im.y, s[m4+1], acc);
                acc = fmaf(r.z, c[m4+2], acc);  acc = fmaf(-im.z, s[m4+2], acc);
                acc = fmaf(r.w, c[m4+3], acc);  acc = fmaf(-im.w, s[m4+3], acc);
            }
            acc *= (1.0f/256.0f);
            __nv_bfloat16 hv = __float2bfloat16(acc);
            fh[base + (size_t)o*Dq] = hv;
            fl[base + (size_t)o*Dq] = __float2bfloat16(acc - __bfloat162float(hv));
        }
    }
}

// ================= series_decomp: out = in - movavg25(in), + bf16 hi/lo =======
__global__ void decomp_kernel(const float* __restrict__ in, float* __restrict__ out,
                              __nv_bfloat16* __restrict__ oh, __nv_bfloat16* __restrict__ ol) {
    int gid = blockIdx.x*blockDim.x + threadIdx.x;
    int b = gid >> 9, d = gid & 511;
    const float* p = in + (size_t)b*Lq*Dq + d;
    size_t obase = (size_t)b*Lq*Dq + d;
    float wsum = 13.0f * p[0];
    #pragma unroll
    for (int j = 1; j <= 12; j++) wsum += p[(size_t)j*Dq];
    for (int l = 0; l < Lq; l++) {
        float xl = p[(size_t)l*Dq];
        float v = xl - wsum*(1.0f/25.0f);
        out[obase + (size_t)l*Dq] = v;
        __nv_bfloat16 hv = __float2bfloat16(v);
        oh[obase + (size_t)l*Dq] = hv;
        ol[obase + (size_t)l*Dq] = __float2bfloat16(v - __bfloat162float(hv));
        int jn = l+13 > Lq-1 ? Lq-1 : l+13;
        int jo = l-12 < 0 ? 0 : l-12;
        wsum += p[(size_t)jn*Dq] - p[(size_t)jo*Dq];
    }
}

// ================= final layernorm / projection =================
__global__ void ln_rows(const float* __restrict__ x) {
    int row = blockIdx.x;
    int t = threadIdx.x;
    const float* p = x + (size_t)row*Dq;
    float v0 = p[t], v1 = p[t+256];
    __shared__ float sh[8];
    float s = v0 + v1;
    int lane = t & 31, w = t >> 5;
    #pragma unroll
    for (int o = 16; o > 0; o >>= 1) s += __shfl_down_sync(~0u, s, o);
    if (lane == 0) sh[w] = s;
    __syncthreads();
    if (t < 32) {
        float v = (t < 8) ? sh[t] : 0.f;
        #pragma unroll
        for (int o = 4; o > 0; o >>= 1) v += __shfl_down_sync(~0u, v, o);
        if (t == 0) sh[0] = v;
    }
    __syncthreads();
    float mu = sh[0] * (1.0f/512.0f);
    __syncthreads();
    float d0 = v0 - mu, d1 = v1 - mu;
    s = d0*d0 + d1*d1;
    #pragma unroll
    for (int o = 16; o > 0; o >>= 1) s += __shfl_down_sync(~0u, s, o);
    if (lane == 0) sh[w] = s;
    __syncthreads();
    if (t < 32) {
        float v = (t < 8) ? sh[t] : 0.f;
        #pragma unroll
        for (int o = 4; o > 0; o >>= 1) v += __shfl_down_sync(~0u, v, o);
        if (t == 0) {
            float var = v * (1.0f/512.0f);
            g_mu[row] = mu;
            g_rs[row] = rsqrtf(var + 1e-5f);
        }
    }
}

__global__ void ln_cols(const float* __restrict__ x, const float* __restrict__ nw,
                        const float* __restrict__ nb, const float* __restrict__ tv) {
    int b = blockIdx.x;
    int d = threadIdx.x;
    float w = nw[d], bb = nb[d];
    float sum = 0.f, lastv = 0.f;
    for (int l = 0; l < Lq; l++) {
        int row = b*Lq + l;
        float v = (x[(size_t)row*Dq + d] - g_mu[row]) * g_rs[row] * w + bb;
        sum += v;
        if (l == Lq-1) lastv = v;
    }
    g_cat[b*CATD + d] = lastv - sum*(1.0f/512.0f);
    if (d < 24) g_cat[b*CATD + 512 + d] = tv[((size_t)b*Lq + (Lq-1))*24 + d];
}

__global__ void __launch_bounds__(256) proj_kernel(const float* __restrict__ pw,
                                                   const float* __restrict__ pb,
                                                   float* __restrict__ out) {
    __shared__ float As[8][65];
    __shared__ float Bs[8][65];
    int n0 = blockIdx.x * 64;
    int t = threadIdx.x;
    int tx = t & 15, ty = t >> 4;
    float acc[4][4] = {};
    for (int k0 = 0; k0 < CATD; k0 += 8) {
        int v = t*2;
        int r = v >> 3, c = v & 7;
        As[c][r]   = g_cat[r*CATD + k0 + c];
        As[c+1][r] = g_cat[r*CATD + k0 + c + 1];
        int n = n0 + r;
        float f0 = 0.f, f1 = 0.f;
        if (n < NUM_APP) {
            f0 = pw[(size_t)n*CATD + k0 + c];
            f1 = pw[(size_t)n*CATD + k0 + c + 1];
        }
        Bs[c][r] = f0; Bs[c+1][r] = f1;
        __syncthreads();
        #pragma unroll
        for (int k = 0; k < 8; k++) {
            float a[4], bv[4];
            #pragma unroll
            for (int i = 0; i < 4; i++) { a[i] = As[k][ty*4+i]; bv[i] = Bs[k][tx*4+i]; }
            #pragma unroll
            for (int i = 0; i < 4; i++)
                #pragma unroll
                for (int j = 0; j < 4; j++)
                    acc[i][j] = fmaf(a[i], bv[j], acc[i][j]);
        }
        __syncthreads();
    }
    #pragma unroll
    for (int i = 0; i < 4; i++) {
        int bi = ty*4 + i;
        #pragma unroll
        for (int j = 0; j < 4; j++) {
            int n = n0 + tx*4 + j;
            if (n < NUM_APP) out[(size_t)bi*NUM_APP + n] = acc[i][j] + pb[n];
        }
    }
}

// ================= host orchestration =================
extern "C" void kernel_launch(void* const* d_in, const int* in_sizes, int n_in,
                              void* d_out, int out_size) {
    const int*   x_app     = (const int*)  d_in[0];
    const float* x_time    = (const float*)d_in[1];
    const float* time_vecs = (const float*)d_in[2];
    const float* app_emb_w = (const float*)d_in[4];
    const float* time_w    = (const float*)d_in[5];
    const float* time_b    = (const float*)d_in[6];
    const float* Wq        = (const float*)d_in[7];
    const float* bq        = (const float*)d_in[8];
    const float* Wo        = (const float*)d_in[9];
    const float* bo        = (const float*)d_in[10];
    const float* four_wr   = (const float*)d_in[11];
    const float* four_wi   = (const float*)d_in[12];
    const float* conv1_w   = (const float*)d_in[13];
    const float* conv2_w   = (const float*)d_in[14];
    const float* norm_w    = (const float*)d_in[15];
    const float* norm_b    = (const float*)d_in[16];
    const float* proj_w    = (const float*)d_in[17];
    const float* proj_b    = (const float*)d_in[18];
    float* out = (float*)d_out;

    cudaFuncSetAttribute(gemm_mma<GF_BIAS|GF_OUTF32>,        cudaFuncAttributeMaxDynamicSharedMemorySize, SMEM_GEMM);
    cudaFuncSetAttribute(gemm_mma<GF_BIAS|GF_RES|GF_OUTF32>, cudaFuncAttributeMaxDynamicSharedMemorySize, SMEM_GEMM);
    cudaFuncSetAttribute(gemm_mma<GF_RELU|GF_OUTBF16>,       cudaFuncAttributeMaxDynamicSharedMemorySize, SMEM_GEMM);
    cudaFuncSetAttribute(gemm_mma<GF_RES|GF_OUTF32>,         cudaFuncAttributeMaxDynamicSharedMemorySize, SMEM_GEMM);

    void *px, *pq, *pt;
    void *pxh, *pxl, *pfh, *pfl, *pyh, *pyl;
    void *pwqh, *pwql, *pwoh, *pwol, *pc1h, *pc1l, *pc2h, *pc2l;
    cudaGetSymbolAddress(&px, g_x);
    cudaGetSymbolAddress(&pq, g_q);
    cudaGetSymbolAddress(&pt, g_t);
    cudaGetSymbolAddress(&pxh, g_xh); cudaGetSymbolAddress(&pxl, g_xl);
    cudaGetSymbolAddress(&pfh, g_fh); cudaGetSymbolAddress(&pfl, g_fl);
    cudaGetSymbolAddress(&pyh, g_yh); cudaGetSymbolAddress(&pyl, g_yl);
    cudaGetSymbolAddress(&pwqh, g_wqh); cudaGetSymbolAddress(&pwql, g_wql);
    cudaGetSymbolAddress(&pwoh, g_woh); cudaGetSymbolAddress(&pwol, g_wol);
    cudaGetSymbolAddress(&pc1h, g_c1h); cudaGetSymbolAddress(&pc1l, g_c1l);
    cudaGetSymbolAddress(&pc2h, g_c2h); cudaGetSymbolAddress(&pc2l, g_c2l);
    float* fx = (float*)px;
    float* fq = (float*)pq;
    float* ft = (float*)pt;
    __nv_bfloat16 *xh=(__nv_bfloat16*)pxh, *xl=(__nv_bfloat16*)pxl;
    __nv_bfloat16 *fh=(__nv_bfloat16*)pfh, *fl=(__nv_bfloat16*)pfl;
    __nv_bfloat16 *yh=(__nv_bfloat16*)pyh, *yl=(__nv_bfloat16*)pyl;
    __nv_bfloat16 *wqh=(__nv_bfloat16*)pwqh, *wql=(__nv_bfloat16*)pwql;
    __nv_bfloat16 *woh=(__nv_bfloat16*)pwoh, *wol=(__nv_bfloat16*)pwol;
    __nv_bfloat16 *c1h=(__nv_bfloat16*)pc1h, *c1l=(__nv_bfloat16*)pc1l;
    __nv_bfloat16 *c2h=(__nv_bfloat16*)pc2h, *c2l=(__nv_bfloat16*)pc2l;

    init_tables<<<64, 256>>>();
    convert_hl<<<(2*Dq*Dq + 255)/256, 256>>>(Wq, wqh, wql, 2*Dq*Dq);
    convert_hl<<<(2*Dq*Dq + 255)/256, 256>>>(Wo, woh, wol, 2*Dq*Dq);
    convert_hl<<<(2*DFF*Dq + 255)/256, 256>>>(conv1_w, c1h, c1l, 2*DFF*Dq);
    convert_hl<<<(2*Dq*DFF + 255)/256, 256>>>(conv2_w, c2h, c2l, 2*Dq*DFF);
    embed_kernel<<<BLq*Dq/256, 256>>>(x_app, x_time, app_emb_w, time_w, time_b);

    const int M = BLq;
    for (int l = 0; l < 2; l++) {
        size_t woff = (size_t)l*Dq*Dq;
        size_t coff1 = (size_t)l*DFF*Dq;

        // q = x @ Wq^T + bq (fp32 out -> dft)
        gemm_mma<GF_BIAS|GF_OUTF32><<<dim3(Dq/128, M/128), 256, SMEM_GEMM>>>(
            xh, xl, wqh + woff, wql + woff, bq + l*Dq, nullptr,
            fq, nullptr, nullptr, M, Dq, Dq);
        dft_kernel<<<Bq*Hq, 256>>>(fq);
        mix_kernel<<<Bq*Hq, 256>>>(four_wr + (size_t)l*Hq*Eq*Eq*MODES,
                                   four_wi + (size_t)l*Hq*Eq*Eq*MODES);
        irfft_kernel<<<Bq*Hq, 256>>>(fh, fl);
        // t = four @ Wo^T + bo + x
        gemm_mma<GF_BIAS|GF_RES|GF_OUTF32><<<dim3(Dq/128, M/128), 256, SMEM_GEMM>>>(
            fh, fl, woh + woff, wol + woff, bo + l*Dq, fx,
            ft, nullptr, nullptr, M, Dq, Dq);
        decomp_kernel<<<Bq*Dq/256, 256>>>(ft, fx, xh, xl);
        // y = relu(x @ c1^T)  (bf16 pair out)
        gemm_mma<GF_RELU|GF_OUTBF16><<<dim3(DFF/128, M/128), 256, SMEM_GEMM>>>(
            xh, xl, c1h + coff1, c1l + coff1, nullptr, nullptr,
            nullptr, yh, yl, M, DFF, Dq);
        // t = y @ c2^T + x
        gemm_mma<GF_RES|GF_OUTF32><<<dim3(Dq/128, M/128), 256, SMEM_GEMM>>>(
            yh, yl, c2h + coff1, c2l + coff1, nullptr, fx,
            ft, nullptr, nullptr, M, Dq, DFF);
        decomp_kernel<<<Bq*Dq/256, 256>>>(ft, fx, xh, xl);
    }

    ln_rows<<<BLq, 256>>>(fx);
    ln_cols<<<Bq, 512>>>(fx, norm_w, norm_b, time_vecs);
    proj_kernel<<<(NUM_APP + 63)/64, 256>>>(proj_w, proj_b, out);
}

// round 4
// speedup vs baseline: 1.8604x; 1.0481x over previous
#include <cuda_runtime.h>
#include <cuda_fp16.h>
#include <math.h>
#include <stdint.h>

#define Bq 64
#define Lq 512
#define Dq 512
#define Hq 8
#define Eq 64
#define DFF 2048
#define MODES 32
#define VOCAB 10000
#define NUM_APP 10000
#define CATD 536
#define BLq (Bq*Lq)

// ================= helpers =================
__device__ __forceinline__ uint32_t smem_u32(const void* p) {
    uint32_t a;
    asm("{ .reg .u64 t; cvta.to.shared.u64 t, %1; cvt.u32.u64 %0, t; }" : "=r"(a) : "l"(p));
    return a;
}
__device__ __forceinline__ void cp16(uint32_t dst, const void* src) {
    asm volatile("cp.async.cg.shared.global [%0], [%1], 16;" :: "r"(dst), "l"(src) : "memory");
}
#define CP_COMMIT() asm volatile("cp.async.commit_group;" ::: "memory")

#define LDSM_X4(r0,r1,r2,r3, addr) \
    asm volatile("ldmatrix.sync.aligned.m8n8.x4.shared.b16 {%0,%1,%2,%3}, [%4];" \
        : "=r"(r0), "=r"(r1), "=r"(r2), "=r"(r3) : "r"(addr))

// fp16 operands, fp32 accumulate (main term)
#define MMA_F32(d, a, b0, b1) \
    asm volatile("mma.sync.aligned.m16n8k16.row.col.f32.f16.f16.f32 " \
        "{%0,%1,%2,%3},{%4,%5,%6,%7},{%8,%9},{%0,%1,%2,%3};" \
        : "+f"((d)[0]), "+f"((d)[1]), "+f"((d)[2]), "+f"((d)[3]) \
        : "r"((a)[0]), "r"((a)[1]), "r"((a)[2]), "r"((a)[3]), "r"(b0), "r"(b1))

// fp16 operands, fp16 accumulate (correction terms)
#define MMA_F16(d, a, b0, b1) \
    asm volatile("mma.sync.aligned.m16n8k16.row.col.f16.f16.f16.f16 " \
        "{%0,%1},{%2,%3,%4,%5},{%6,%7},{%0,%1};" \
        : "+r"((d)[0]), "+r"((d)[1]) \
        : "r"((a)[0]), "r"((a)[1]), "r"((a)[2]), "r"((a)[3]), "r"(b0), "r"(b1))

// ================= scratch (device globals) =================
__device__ float g_x[BLq*Dq];
__device__ float g_q[BLq*Dq];
__device__ float g_t[BLq*Dq];
__device__ __align__(256) __half g_xh[BLq*Dq],  g_xl[BLq*Dq];
__device__ __align__(256) __half g_fh[BLq*Dq],  g_fl[BLq*Dq];
__device__ __align__(256) __half g_yh[BLq*DFF], g_yl[BLq*DFF];
__device__ __align__(256) __half g_wqh[2*Dq*Dq], g_wql[2*Dq*Dq];
__device__ __align__(256) __half g_woh[2*Dq*Dq], g_wol[2*Dq*Dq];
__device__ __align__(256) __half g_c1h[2*DFF*Dq], g_c1l[2*DFF*Dq];
__device__ __align__(256) __half g_c2h[2*Dq*DFF], g_c2l[2*Dq*DFF];
__device__ float g_xsr[Bq*Hq*Eq*MODES], g_xsi[Bq*Hq*Eq*MODES];
__device__ float g_osr[Bq*Hq*Eq*MODES], g_osi[Bq*Hq*Eq*MODES];
__device__ float g_ct[Lq*MODES], g_st[Lq*MODES];
__device__ float g_mu[BLq], g_rs[BLq];
__device__ float g_cat[Bq*CATD];

// ================= small kernels =================
__global__ void init_tables() {
    int idx = blockIdx.x*blockDim.x + threadIdx.x;
    if (idx < Lq*MODES) {
        int l = idx >> 5, m = idx & 31;
        double a = (double)(m*l) / 256.0;
        double s, c;
        sincospi(a, &s, &c);
        g_ct[idx] = (float)c;
        g_st[idx] = (float)s;
    }
}

__global__ void convert_hl(const float* __restrict__ src, __half* __restrict__ h,
                           __half* __restrict__ l, int n) {
    int i = blockIdx.x*256 + threadIdx.x;
    if (i < n) {
        float v = src[i];
        __half hv = __float2half_rn(v);
        h[i] = hv;
        l[i] = __float2half_rn(v - __half2float(hv));
    }
}

__global__ void embed_kernel(const int* __restrict__ app, const float* __restrict__ xt,
                             const float* __restrict__ emb, const float* __restrict__ tw,
                             const float* __restrict__ tb) {
    size_t idx = (size_t)blockIdx.x*256 + threadIdx.x;
    int d = (int)(idx & 511);
    size_t bl = idx >> 9;
    int a = app[bl];
    float v = emb[(size_t)a*Dq + d] + xt[bl]*tw[d] + tb[d];
    g_x[idx] = v;
    __half hv = __float2half_rn(v);
    g_xh[idx] = hv;
    g_xl[idx] = __float2half_rn(v - __half2float(hv));
}

// ================= mma.sync fp16 split GEMM: C = A(MxK) @ B(NxK)^T =============
// Main term Ah*Bh in f32 accumulate; corrections Ah*Bl + Al*Bh in f16 accumulate.
#define GF_BIAS 1
#define GF_RES  2
#define GF_RELU 4
#define GF_OUTF32 8
#define GF_OUTH16 16

#define STG 32768                 // Ah(8K)+Al(8K)+Bh(8K)+Bl(8K) per stage
#define SMEM_GEMM (3*STG + 256)

template<int FLAGS>
__global__ void __launch_bounds__(256, 1) gemm_mma(
    const __half* __restrict__ Ah, const __half* __restrict__ Al,
    const __half* __restrict__ Bh, const __half* __restrict__ Bl,
    const float* __restrict__ bias, const float* __restrict__ res,
    float* __restrict__ Cf, __half* __restrict__ Ch, __half* __restrict__ Cl,
    int M, int N, int K)
{
    extern __shared__ char dsm[];
    uint32_t sbase = (smem_u32(dsm) + 127) & ~127u;

    const int t = threadIdx.x;
    const int lane = t & 31;
    const int wid = t >> 5;
    const int wm = wid >> 2;          // 0..1
    const int wn = wid & 3;           // 0..3
    const int bm = blockIdx.y * 128, bn = blockIdx.x * 128;
    const int NC = K >> 5;

    float acc[4][4][4] = {};
    uint32_t cor[4][4][2];
    #pragma unroll
    for (int i = 0; i < 4; i++)
        #pragma unroll
        for (int j = 0; j < 4; j++) { cor[i][j][0] = 0u; cor[i][j][1] = 0u; }

    // ---- async tile loader: 128x32 half tiles for Ah/Al/Bh/Bl ----
    const int lrow = t >> 2;          // 0..63
    const int lcell = t & 3;          // 16B cell in 64B row
    auto load_chunk = [&](int c, int stg) {
        uint32_t sb = sbase + stg*STG;
        size_t k0 = (size_t)c * 32 + lcell*8;
        #pragma unroll
        for (int j = 0; j < 2; j++) {
            int row = lrow + j*64;
            uint32_t soff = row*64 + (((uint32_t)(lcell ^ (row & 3))) << 4);
            size_t ga = (size_t)(bm + row)*K + k0;
            size_t gb = (size_t)(bn + row)*K + k0;
            cp16(sb +         soff, Ah + ga);
            cp16(sb +  8192 + soff, Al + ga);
            cp16(sb + 16384 + soff, Bh + gb);
            cp16(sb + 24576 + soff, Bl + gb);
        }
        CP_COMMIT();
    };

    load_chunk(0, 0);
    load_chunk(1, 1);

    const int arow_base = wm*64 + (lane & 15);
    const int brow_base = wn*32 + (lane & 15);
    const int kc_hi = lane >> 4;      // 0/1

    for (int c = 0; c < NC; c++) {
        if (c + 2 < NC) asm volatile("cp.async.wait_group 1;" ::: "memory");
        else            asm volatile("cp.async.wait_group 0;" ::: "memory");
        __syncthreads();
        if (c + 2 < NC) load_chunk(c + 2, (c + 2) % 3);

        uint32_t sb = sbase + (c % 3)*STG;
        #pragma unroll
        for (int s = 0; s < 2; s++) {
            uint32_t ah[4][4], al[4][4], bh[2][4], bl[2][4];
            int chunk = s*2 + kc_hi;
            #pragma unroll
            for (int mt = 0; mt < 4; mt++) {
                int row = arow_base + mt*16;
                uint32_t off = row*64 + (((uint32_t)(chunk ^ (row & 3))) << 4);
                LDSM_X4(ah[mt][0], ah[mt][1], ah[mt][2], ah[mt][3], sb + off);
                LDSM_X4(al[mt][0], al[mt][1], al[mt][2], al[mt][3], sb + 8192 + off);
            }
            #pragma unroll
            for (int g = 0; g < 2; g++) {
                int row = brow_base + g*16;
                uint32_t off = row*64 + (((uint32_t)(chunk ^ (row & 3))) << 4);
                LDSM_X4(bh[g][0], bh[g][1], bh[g][2], bh[g][3], sb + 16384 + off);
                LDSM_X4(bl[g][0], bl[g][1], bl[g][2], bl[g][3], sb + 24576 + off);
            }
            #pragma unroll
            for (int mt = 0; mt < 4; mt++) {
                #pragma unroll
                for (int nt = 0; nt < 4; nt++) {
                    int g = nt >> 1, o = nt & 1;
                    MMA_F32(acc[mt][nt], ah[mt], bh[g][o], bh[g][o+2]);
                    MMA_F16(cor[mt][nt], ah[mt], bl[g][o], bl[g][o+2]);
                    MMA_F16(cor[mt][nt], al[mt], bh[g][o], bh[g][o+2]);
                }
            }
        }
    }

    // ---- epilogue ----
    int r0 = bm + wm*64 + (lane >> 2);
    int c0 = bn + wn*32 + (lane & 3)*2;
    #pragma unroll
    for (int mt = 0; mt < 4; mt++) {
        #pragma unroll
        for (int nt = 0; nt < 4; nt++) {
            int col = c0 + nt*8;
            float b0 = 0.f, b1 = 0.f;
            if (FLAGS & GF_BIAS) { b0 = bias[col]; b1 = bias[col+1]; }
            #pragma unroll
            for (int half = 0; half < 2; half++) {
                int row = r0 + mt*16 + half*8;
                float2 cf = __half22float2(*reinterpret_cast<__half2*>(&cor[mt][nt][half]));
                float v0 = acc[mt][nt][half*2+0] + cf.x + b0;
                float v1 = acc[mt][nt][half*2+1] + cf.y + b1;
                size_t ro = (size_t)row * N + col;
                if (FLAGS & GF_RES) {
                    float2 r2 = *(const float2*)&res[ro];
                    v0 += r2.x; v1 += r2.y;
                }
                if (FLAGS & GF_RELU) { v0 = fmaxf(v0, 0.f); v1 = fmaxf(v1, 0.f); }
                if (FLAGS & GF_OUTF32) {
                    float2 o2; o2.x = v0; o2.y = v1;
                    *(float2*)&Cf[ro] = o2;
                }
                if (FLAGS & GF_OUTH16) {
                    __half h0 = __float2half_rn(v0);
                    __half h1 = __float2half_rn(v1);
                    __half2 hp; hp.x = h0; hp.y = h1;
                    *(__half2*)&Ch[ro] = hp;
                    __half2 lp;
                    lp.x = __float2half_rn(v0 - __half2float(h0));
                    lp.y = __float2half_rn(v1 - __half2float(h1));
                    *(__half2*)&Cl[ro] = lp;
                }
            }
        }
    }
}

// ================= fourier path =================
// dft: register-blocked. Block = 128 threads handles 2 (b,h) pairs.
// Thread: 4 i-rows x 8 modes. grid = 256.
__global__ void __launch_bounds__(128) dft_kernel(const float* __restrict__ q) {
    int bh0 = blockIdx.x * 2;
    int b = bh0 >> 3;
    int h0 = bh0 & 7;                 // even
    __shared__ float sq[32][132];     // 32 l x 128 cols (2 heads)
    __shared__ float sct[32][32];
    __shared__ float sst[32][32];
    int t = threadIdx.x;
    int sub = t >> 6;                 // head within block (0/1)
    int tl = t & 63;
    int i0 = (tl >> 2) * 4;
    int mb = (tl & 3) * 8;

    float ar[4][8] = {}, ai[4][8] = {};
    const float* qbase = q + (size_t)b*Lq*Dq + h0*64;

    for (int l0 = 0; l0 < Lq; l0 += 32) {
        #pragma unroll
        for (int j = 0; j < 8; j++) {
            int v = t + j*128;        // 1024 float4 total
            int ll = v >> 5;
            int c4 = (v & 31) * 4;
            float4 va = *(const float4*)&qbase[(size_t)(l0+ll)*Dq + c4];
            *(float4*)&sq[ll][c4] = va;
        }
        #pragma unroll
        for (int j = 0; j < 2; j++) {
            int v = t + j*128;        // 256 float4 per table
            int ll = v >> 3;
            int c4 = (v & 7) * 4;
            *(float4*)&sct[ll][c4] = *(const float4*)&g_ct[(l0+ll)*32 + c4];
            *(float4*)&sst[ll][c4] = *(const float4*)&g_st[(l0+ll)*32 + c4];
        }
        __syncthreads();
        #pragma unroll 2
        for (int ll = 0; ll < 32; ll++) {
            float c[8], s[8];
            *(float4*)&c[0] = *(float4*)&sct[ll][mb];
            *(float4*)&c[4] = *(float4*)&sct[ll][mb+4];
            *(float4*)&s[0] = *(float4*)&sst[ll][mb];
            *(float4*)&s[4] = *(float4*)&sst[ll][mb+4];
            float qv[4];
            #pragma unroll
            for (int j = 0; j < 4; j++) qv[j] = sq[ll][sub*64 + i0 + j];
            #pragma unroll
            for (int j = 0; j < 4; j++)
                #pragma unroll
                for (int mm = 0; mm < 8; mm++) {
                    ar[j][mm] = fmaf(qv[j],  c[mm], ar[j][mm]);
                    ai[j][mm] = fmaf(-qv[j], s[mm], ai[j][mm]);
                }
        }
        __syncthreads();
    }
    int bh = bh0 + sub;
    #pragma unroll
    for (int j = 0; j < 4; j++) {
        size_t off = ((size_t)bh*64 + i0 + j)*32 + mb;
        *(float4*)&g_xsr[off]   = *(float4*)&ar[j][0];
        *(float4*)&g_xsr[off+4] = *(float4*)&ar[j][4];
        *(float4*)&g_xsi[off]   = *(float4*)&ai[j][0];
        *(float4*)&g_xsi[off+4] = *(float4*)&ai[j][4];
    }
}

__global__ void __launch_bounds__(256) mix_kernel(const float* __restrict__ wr,
                                                  const float* __restrict__ wi) {
    int bh = blockIdx.x;
    int h = bh & 7;
    __shared__ float sxr[64][32];
    __shared__ float sxi[64][32];
    int t = threadIdx.x;
    #pragma unroll
    for (int j = 0; j < 2; j++) {
        int v  = t + j*256;
        int ii = v >> 3;
        int c4 = (v & 7) * 4;
        size_t off = ((size_t)bh*64 + ii)*32 + c4;
        *(float4*)&sxr[ii][c4] = *(const float4*)&g_xsr[off];
        *(float4*)&sxi[ii][c4] = *(const float4*)&g_xsi[off];
    }
    __syncthreads();
    int o  = t >> 2;
    int mb = (t & 3) * 8;
    float orr[8] = {}, oii[8] = {};
    for (int i = 0; i < 64; i++) {
        float xr[8], xi[8], w0[8], w1[8];
        *(float4*)&xr[0] = *(float4*)&sxr[i][mb];
        *(float4*)&xr[4] = *(float4*)&sxr[i][mb+4];
        *(float4*)&xi[0] = *(float4*)&sxi[i][mb];
        *(float4*)&xi[4] = *(float4*)&sxi[i][mb+4];
        size_t woff = (((size_t)h*64 + i)*64 + o)*32 + mb;
        *(float4*)&w0[0] = *(const float4*)&wr[woff];
        *(float4*)&w0[4] = *(const float4*)&wr[woff+4];
        *(float4*)&w1[0] = *(const float4*)&wi[woff];
        *(float4*)&w1[4] = *(const float4*)&wi[woff+4];
        #pragma unroll
        for (int mm = 0; mm < 8; mm++) {
            orr[mm] = fmaf(xr[mm], w0[mm], orr[mm]);
            orr[mm] = fmaf(-xi[mm], w1[mm], orr[mm]);
            oii[mm] = fmaf(xr[mm], w1[mm], oii[mm]);
            oii[mm] = fmaf(xi[mm], w0[mm], oii[mm]);
        }
    }
    size_t off = ((size_t)bh*64 + o)*32 + mb;
    #pragma unroll
    for (int mm = 0; mm < 8; mm += 4) {
        *(float4*)&g_osr[off+mm] = *(float4*)&orr[mm];
        *(float4*)&g_osi[off+mm] = *(float4*)&oii[mm];
    }
}

__global__ void __launch_bounds__(256) irfft_kernel(__half* __restrict__ fh,
                                                    __half* __restrict__ fl) {
    int bh = blockIdx.x;
    int b = bh >> 3, h = bh & 7;
    __shared__ float sor[64][32];
    __shared__ float soi[64][32];
    int t = threadIdx.x;
    #pragma unroll
    for (int j = 0; j < 2; j++) {
        int v  = t + j*256;
        int oo = v >> 3;
        int c4 = (v & 7) * 4;
        size_t off = ((size_t)bh*64 + oo)*32 + c4;
        float4 r = *(const float4*)&g_osr[off];
        float4 im = *(const float4*)&g_osi[off];
        if (c4 == 0) { r.x *= 0.5f; im.x *= 0.5f; }
        *(float4*)&sor[oo][c4] = r;
        *(float4*)&soi[oo][c4] = im;
    }
    __syncthreads();

    #pragma unroll
    for (int half = 0; half < 2; half++) {
        int lp = t + half*256;
        float c[32], s[32];
        #pragma unroll
        for (int j = 0; j < 32; j += 4) {
            *(float4*)&c[j] = *(const float4*)&g_ct[lp*32 + j];
            *(float4*)&s[j] = *(const float4*)&g_st[lp*32 + j];
        }
        size_t base = ((size_t)b*Lq + h*64)*Dq + lp;
        for (int o = 0; o < 64; o++) {
            float acc = 0.f;
            #pragma unroll
            for (int m4 = 0; m4 < 32; m4 += 4) {
                float4 r = *(float4*)&sor[o][m4];
                float4 im = *(float4*)&soi[o][m4];
                acc = fmaf(r.x, c[m4+0], acc);  acc = fmaf(-im.x, s[m4+0], acc);
                acc = fmaf(r.y, c[m4+1], acc);  acc = fmaf(-im.y, s[m4+1], acc);
                acc = fmaf(r.z, c[m4+2], acc);  acc = fmaf(-im.z, s[m4+2], acc);
                acc = fmaf(r.w, c[m4+3], acc);  acc = fmaf(-im.w, s[m4+3], acc);
            }
            acc *= (1.0f/256.0f);
            __half hv = __float2half_rn(acc);
            fh[base + (size_t)o*Dq] = hv;
            fl[base + (size_t)o*Dq] = __float2half_rn(acc - __half2float(hv));
        }
    }
}

// ================= series_decomp =================
__global__ void decomp_kernel(const float* __restrict__ in, float* __restrict__ out,
                              __half* __restrict__ oh, __half* __restrict__ ol) {
    int gid = blockIdx.x*blockDim.x + threadIdx.x;
    int b = gid >> 9, d = gid & 511;
    const float* p = in + (size_t)b*Lq*Dq + d;
    size_t obase = (size_t)b*Lq*Dq + d;
    float wsum = 13.0f * p[0];
    #pragma unroll
    for (int j = 1; j <= 12; j++) wsum += p[(size_t)j*Dq];
    for (int l = 0; l < Lq; l++) {
        float xl = p[(size_t)l*Dq];
        float v = xl - wsum*(1.0f/25.0f);
        out[obase + (size_t)l*Dq] = v;
        __half hv = __float2half_rn(v);
        oh[obase + (size_t)l*Dq] = hv;
        ol[obase + (size_t)l*Dq] = __float2half_rn(v - __half2float(hv));
        int jn = l+13 > Lq-1 ? Lq-1 : l+13;
        int jo = l-12 < 0 ? 0 : l-12;
        wsum += p[(size_t)jn*Dq] - p[(size_t)jo*Dq];
    }
}

// ================= final layernorm / projection =================
__global__ void ln_rows(const float* __restrict__ x) {
    int row = blockIdx.x;
    int t = threadIdx.x;
    const float* p = x + (size_t)row*Dq;
    float v0 = p[t], v1 = p[t+256];
    __shared__ float sh[8];
    float s = v0 + v1;
    int lane = t & 31, w = t >> 5;
    #pragma unroll
    for (int o = 16; o > 0; o >>= 1) s += __shfl_down_sync(~0u, s, o);
    if (lane == 0) sh[w] = s;
    __syncthreads();
    if (t < 32) {
        float v = (t < 8) ? sh[t] : 0.f;
        #pragma unroll
        for (int o = 4; o > 0; o >>= 1) v += __shfl_down_sync(~0u, v, o);
        if (t == 0) sh[0] = v;
    }
    __syncthreads();
    float mu = sh[0] * (1.0f/512.0f);
    __syncthreads();
    float d0 = v0 - mu, d1 = v1 - mu;
    s = d0*d0 + d1*d1;
    #pragma unroll
    for (int o = 16; o > 0; o >>= 1) s += __shfl_down_sync(~0u, s, o);
    if (lane == 0) sh[w] = s;
    __syncthreads();
    if (t < 32) {
        float v = (t < 8) ? sh[t] : 0.f;
        #pragma unroll
        for (int o = 4; o > 0; o >>= 1) v += __shfl_down_sync(~0u, v, o);
        if (t == 0) {
            float var = v * (1.0f/512.0f);
            g_mu[row] = mu;
            g_rs[row] = rsqrtf(var + 1e-5f);
        }
    }
}

__global__ void ln_cols(const float* __restrict__ x, const float* __restrict__ nw,
                        const float* __restrict__ nb, const float* __restrict__ tv) {
    int b = blockIdx.x;
    int d = threadIdx.x;
    float w = nw[d], bb = nb[d];
    float sum = 0.f, lastv = 0.f;
    for (int l = 0; l < Lq; l++) {
        int row = b*Lq + l;
        float v = (x[(size_t)row*Dq + d] - g_mu[row]) * g_rs[row] * w + bb;
        sum += v;
        if (l == Lq-1) lastv = v;
    }
    g_cat[b*CATD + d] = lastv - sum*(1.0f/512.0f);
    if (d < 24) g_cat[b*CATD + 512 + d] = tv[((size_t)b*Lq + (Lq-1))*24 + d];
}

__global__ void __launch_bounds__(256) proj_kernel(const float* __restrict__ pw,
                                                   const float* __restrict__ pb,
                                                   float* __restrict__ out) {
    __shared__ float As[8][65];
    __shared__ float Bs[8][65];
    int n0 = blockIdx.x * 64;
    int t = threadIdx.x;
    int tx = t & 15, ty = t >> 4;
    float acc[4][4] = {};
    for (int k0 = 0; k0 < CATD; k0 += 8) {
        int v = t*2;
        int r = v >> 3, c = v & 7;
        As[c][r]   = g_cat[r*CATD + k0 + c];
        As[c+1][r] = g_cat[r*CATD + k0 + c + 1];
        int n = n0 + r;
        float f0 = 0.f, f1 = 0.f;
        if (n < NUM_APP) {
            f0 = pw[(size_t)n*CATD + k0 + c];
            f1 = pw[(size_t)n*CATD + k0 + c + 1];
        }
        Bs[c][r] = f0; Bs[c+1][r] = f1;
        __syncthreads();
        #pragma unroll
        for (int k = 0; k < 8; k++) {
            float a[4], bv[4];
            #pragma unroll
            for (int i = 0; i < 4; i++) { a[i] = As[k][ty*4+i]; bv[i] = Bs[k][tx*4+i]; }
            #pragma unroll
            for (int i = 0; i < 4; i++)
                #pragma unroll
                for (int j = 0; j < 4; j++)
                    acc[i][j] = fmaf(a[i], bv[j], acc[i][j]);
        }
        __syncthreads();
    }
    #pragma unroll
    for (int i = 0; i < 4; i++) {
        int bi = ty*4 + i;
        #pragma unroll
        for (int j = 0; j < 4; j++) {
            int n = n0 + tx*4 + j;
            if (n < NUM_APP) out[(size_t)bi*NUM_APP + n] = acc[i][j] + pb[n];
        }
    }
}

// ================= host orchestration =================
extern "C" void kernel_launch(void* const* d_in, const int* in_sizes, int n_in,
                              void* d_out, int out_size) {
    const int*   x_app     = (const int*)  d_in[0];
    const float* x_time    = (const float*)d_in[1];
    const float* time_vecs = (const float*)d_in[2];
    const float* app_emb_w = (const float*)d_in[4];
    const float* time_w    = (const float*)d_in[5];
    const float* time_b    = (const float*)d_in[6];
    const float* Wq        = (const float*)d_in[7];
    const float* bq        = (const float*)d_in[8];
    const float* Wo        = (const float*)d_in[9];
    const float* bo        = (const float*)d_in[10];
    const float* four_wr   = (const float*)d_in[11];
    const float* four_wi   = (const float*)d_in[12];
    const float* conv1_w   = (const float*)d_in[13];
    const float* conv2_w   = (const float*)d_in[14];
    const float* norm_w    = (const float*)d_in[15];
    const float* norm_b    = (const float*)d_in[16];
    const float* proj_w    = (const float*)d_in[17];
    const float* proj_b    = (const float*)d_in[18];
    float* out = (float*)d_out;

    cudaFuncSetAttribute(gemm_mma<GF_BIAS|GF_OUTF32>,        cudaFuncAttributeMaxDynamicSharedMemorySize, SMEM_GEMM);
    cudaFuncSetAttribute(gemm_mma<GF_BIAS|GF_RES|GF_OUTF32>, cudaFuncAttributeMaxDynamicSharedMemorySize, SMEM_GEMM);
    cudaFuncSetAttribute(gemm_mma<GF_RELU|GF_OUTH16>,        cudaFuncAttributeMaxDynamicSharedMemorySize, SMEM_GEMM);
    cudaFuncSetAttribute(gemm_mma<GF_RES|GF_OUTF32>,         cudaFuncAttributeMaxDynamicSharedMemorySize, SMEM_GEMM);

    void *px, *pq, *pt;
    void *pxh, *pxl, *pfh, *pfl, *pyh, *pyl;
    void *pwqh, *pwql, *pwoh, *pwol, *pc1h, *pc1l, *pc2h, *pc2l;
    cudaGetSymbolAddress(&px, g_x);
    cudaGetSymbolAddress(&pq, g_q);
    cudaGetSymbolAddress(&pt, g_t);
    cudaGetSymbolAddress(&pxh, g_xh); cudaGetSymbolAddress(&pxl, g_xl);
    cudaGetSymbolAddress(&pfh, g_fh); cudaGetSymbolAddress(&pfl, g_fl);
    cudaGetSymbolAddress(&pyh, g_yh); cudaGetSymbolAddress(&pyl, g_yl);
    cudaGetSymbolAddress(&pwqh, g_wqh); cudaGetSymbolAddress(&pwql, g_wql);
    cudaGetSymbolAddress(&pwoh, g_woh); cudaGetSymbolAddress(&pwol, g_wol);
    cudaGetSymbolAddress(&pc1h, g_c1h); cudaGetSymbolAddress(&pc1l, g_c1l);
    cudaGetSymbolAddress(&pc2h, g_c2h); cudaGetSymbolAddress(&pc2l, g_c2l);
    float* fx = (float*)px;
    float* fq = (float*)pq;
    float* ft = (float*)pt;
    __half *xh=(__half*)pxh, *xl=(__half*)pxl;
    __half *fh=(__half*)pfh, *fl=(__half*)pfl;
    __half *yh=(__half*)pyh, *yl=(__half*)pyl;
    __half *wqh=(__half*)pwqh, *wql=(__half*)pwql;
    __half *woh=(__half*)pwoh, *wol=(__half*)pwol;
    __half *c1h=(__half*)pc1h, *c1l=(__half*)pc1l;
    __half *c2h=(__half*)pc2h, *c2l=(__half*)pc2l;

    init_tables<<<64, 256>>>();
    convert_hl<<<(2*Dq*Dq + 255)/256, 256>>>(Wq, wqh, wql, 2*Dq*Dq);
    convert_hl<<<(2*Dq*Dq + 255)/256, 256>>>(Wo, woh, wol, 2*Dq*Dq);
    convert_hl<<<(2*DFF*Dq + 255)/256, 256>>>(conv1_w, c1h, c1l, 2*DFF*Dq);
    convert_hl<<<(2*Dq*DFF + 255)/256, 256>>>(conv2_w, c2h, c2l, 2*Dq*DFF);
    embed_kernel<<<BLq*Dq/256, 256>>>(x_app, x_time, app_emb_w, time_w, time_b);

    const int M = BLq;
    for (int l = 0; l < 2; l++) {
        size_t woff = (size_t)l*Dq*Dq;
        size_t coff1 = (size_t)l*DFF*Dq;

        // q = x @ Wq^T + bq (fp32 out -> dft)
        gemm_mma<GF_BIAS|GF_OUTF32><<<dim3(Dq/128, M/128), 256, SMEM_GEMM>>>(
            xh, xl, wqh + woff, wql + woff, bq + l*Dq, nullptr,
            fq, nullptr, nullptr, M, Dq, Dq);
        dft_kernel<<<Bq*Hq/2, 128>>>(fq);
        mix_kernel<<<Bq*Hq, 256>>>(four_wr + (size_t)l*Hq*Eq*Eq*MODES,
                                   four_wi + (size_t)l*Hq*Eq*Eq*MODES);
        irfft_kernel<<<Bq*Hq, 256>>>(fh, fl);
        // t = four @ Wo^T + bo + x
        gemm_mma<GF_BIAS|GF_RES|GF_OUTF32><<<dim3(Dq/128, M/128), 256, SMEM_GEMM>>>(
            fh, fl, woh + woff, wol + woff, bo + l*Dq, fx,
            ft, nullptr, nullptr, M, Dq, Dq);
        decomp_kernel<<<Bq*Dq/256, 256>>>(ft, fx, xh, xl);
        // y = relu(x @ c1^T)  (half pair out)
        gemm_mma<GF_RELU|GF_OUTH16><<<dim3(DFF/128, M/128), 256, SMEM_GEMM>>>(
            xh, xl, c1h + coff1, c1l + coff1, nullptr, nullptr,
            nullptr, yh, yl, M, DFF, Dq);
        // t = y @ c2^T + x
        gemm_mma<GF_RES|GF_OUTF32><<<dim3(Dq/128, M/128), 256, SMEM_GEMM>>>(
            yh, yl, c2h + coff1, c2l + coff1, nullptr, fx,
            ft, nullptr, nullptr, M, Dq, DFF);
        decomp_kernel<<<Bq*Dq/256, 256>>>(ft, fx, xh, xl);
    }

    ln_rows<<<BLq, 256>>>(fx);
    ln_cols<<<Bq, 512>>>(fx, norm_w, norm_b, time_vecs);
    proj_kernel<<<(NUM_APP + 63)/64, 256>>>(proj_w, proj_b, out);
}

// round 5
// speedup vs baseline: 2.2085x; 1.1871x over previous
#include <cuda_runtime.h>
#include <cuda_fp16.h>
#include <math.h>
#include <stdint.h>

#define Bq 64
#define Lq 512
#define Dq 512
#define Hq 8
#define Eq 64
#define DFF 2048
#define MODES 32
#define VOCAB 10000
#define NUM_APP 10000
#define CATD 536
#define BLq (Bq*Lq)

// ================= helpers =================
__device__ __forceinline__ uint32_t smem_u32(const void* p) {
    uint32_t a;
    asm("{ .reg .u64 t; cvta.to.shared.u64 t, %1; cvt.u32.u64 %0, t; }" : "=r"(a) : "l"(p));
    return a;
}
__device__ __forceinline__ void cp16(uint32_t dst, const void* src) {
    asm volatile("cp.async.cg.shared.global [%0], [%1], 16;" :: "r"(dst), "l"(src) : "memory");
}
#define CP_COMMIT() asm volatile("cp.async.commit_group;" ::: "memory")

#define LDSM_X4(r0,r1,r2,r3, addr) \
    asm volatile("ldmatrix.sync.aligned.m8n8.x4.shared.b16 {%0,%1,%2,%3}, [%4];" \
        : "=r"(r0), "=r"(r1), "=r"(r2), "=r"(r3) : "r"(addr))

#define MMA_F32(d, a, b0, b1) \
    asm volatile("mma.sync.aligned.m16n8k16.row.col.f32.f16.f16.f32 " \
        "{%0,%1,%2,%3},{%4,%5,%6,%7},{%8,%9},{%0,%1,%2,%3};" \
        : "+f"((d)[0]), "+f"((d)[1]), "+f"((d)[2]), "+f"((d)[3]) \
        : "r"((a)[0]), "r"((a)[1]), "r"((a)[2]), "r"((a)[3]), "r"(b0), "r"(b1))

#define MMA_F16(d, a, b0, b1) \
    asm volatile("mma.sync.aligned.m16n8k16.row.col.f16.f16.f16.f16 " \
        "{%0,%1},{%2,%3,%4,%5},{%6,%7},{%0,%1};" \
        : "+r"((d)[0]), "+r"((d)[1]) \
        : "r"((a)[0]), "r"((a)[1]), "r"((a)[2]), "r"((a)[3]), "r"(b0), "r"(b1))

// ================= scratch (device globals) =================
__device__ float g_x[BLq*Dq];
__device__ float g_q[BLq*Dq];          // mode-GEMM output (4096x512 used)
__device__ float g_t[BLq*Dq];
__device__ __align__(256) __half g_xh[BLq*Dq],  g_xl[BLq*Dq];
__device__ __align__(256) __half g_Xh[4096*Dq], g_Xl[4096*Dq];     // DFT(x) rows (m,ri,b)
__device__ __align__(256) __half g_yh[BLq*DFF], g_yl[BLq*DFF];
__device__ __align__(256) __half g_osh[BLq*64], g_osl[BLq*64];      // os rows (b,he) x k64
__device__ __align__(256) __half g_wth[2*Dq*64], g_wtl[2*Dq*64];    // Wo tables
__device__ __align__(256) __half g_wqh[2*Dq*Dq], g_wql[2*Dq*Dq];
__device__ __align__(256) __half g_c1h[2*DFF*Dq], g_c1l[2*DFF*Dq];
__device__ __align__(256) __half g_c2h[2*Dq*DFF], g_c2l[2*Dq*DFF];
__device__ float g_ct[Lq*MODES], g_st[Lq*MODES];
__device__ float g_mu[BLq], g_rs[BLq];
__device__ float g_cat[Bq*CATD];

// ================= small kernels =================
__global__ void init_tables() {
    int idx = blockIdx.x*blockDim.x + threadIdx.x;
    if (idx < Lq*MODES) {
        int l = idx >> 5, m = idx & 31;
        double a = (double)(m*l) / 256.0;
        double s, c;
        sincospi(a, &s, &c);
        g_ct[idx] = (float)c;
        g_st[idx] = (float)s;
    }
}

__global__ void convert_hl(const float* __restrict__ src, __half* __restrict__ h,
                           __half* __restrict__ l, int n) {
    int i = blockIdx.x*256 + threadIdx.x;
    if (i < n) {
        float v = src[i];
        __half hv = __float2half_rn(v);
        h[i] = hv;
        l[i] = __float2half_rn(v - __half2float(hv));
    }
}

__global__ void embed_kernel(const int* __restrict__ app, const float* __restrict__ xt,
                             const float* __restrict__ emb, const float* __restrict__ tw,
                             const float* __restrict__ tb) {
    size_t idx = (size_t)blockIdx.x*256 + threadIdx.x;
    int d = (int)(idx & 511);
    size_t bl = idx >> 9;
    int a = app[bl];
    float v = emb[(size_t)a*Dq + d] + xt[bl]*tw[d] + tb[d];
    g_x[idx] = v;
    __half hv = __float2half_rn(v);
    g_xh[idx] = hv;
    g_xl[idx] = __float2half_rn(v - __half2float(hv));
}

// ========== Wo frequency table: wt[layer][j][2m+ri] ==========
// WoC[j,m]= cm*sum_l Wo[j,l]cos(wml); WoS[j,m]= -cm*sum_l Wo[j,l]sin(wml)
// cm = (m==0?1:2)/512 * 256 (256 = operand prescale, undone in GEMM epilogue)
__global__ void __launch_bounds__(128) wotab_kernel(const float* __restrict__ Wo,
                                                    __half* __restrict__ wth,
                                                    __half* __restrict__ wtl) {
    int layer = blockIdx.y;
    int j0 = blockIdx.x * 4;
    __shared__ float sw[4][512];
    int t = threadIdx.x;
    const float* wo = Wo + (size_t)layer*Dq*Dq + (size_t)j0*Dq;
    #pragma unroll
    for (int j = 0; j < 4; j++) {
        int v = t + j*128;
        int r = v >> 7, c4 = (v & 127) * 4;
        *(float4*)&sw[r][c4] = *(const float4*)&wo[(size_t)r*Dq + c4];
    }
    __syncthreads();
    int tj = t >> 5, tm = t & 31;
    float ac = 0.f, as = 0.f;
    for (int l = 0; l < Lq; l++) {
        float w = sw[tj][l];
        ac = fmaf(w, g_ct[l*32 + tm], ac);
        as = fmaf(w, g_st[l*32 + tm], as);
    }
    float cm = (tm == 0 ? 1.0f : 2.0f) * (256.0f/512.0f);
    float vc = ac*cm, vs = -as*cm;
    size_t base = ((size_t)layer*Dq + j0 + tj)*64 + tm*2;
    __half hc = __float2half_rn(vc);
    __half hs = __float2half_rn(vs);
    wth[base]   = hc;  wtl[base]   = __float2half_rn(vc - __half2float(hc));
    wth[base+1] = hs;  wtl[base+1] = __float2half_rn(vs - __half2float(hs));
}

// ================= mma.sync fp16 split GEMM: C = A(MxK) @ B(NxK)^T =============
#define GF_BIAS 1
#define GF_RES  2
#define GF_RELU 4
#define GF_OUTF32 8
#define GF_OUTH16 16

#define STG 32768
#define SMEM_GEMM (3*STG + 256)

template<int FLAGS>
__global__ void __launch_bounds__(256, 1) gemm_mma(
    const __half* __restrict__ Ah, const __half* __restrict__ Al,
    const __half* __restrict__ Bh, const __half* __restrict__ Bl,
    const float* __restrict__ bias, const float* __restrict__ res,
    float* __restrict__ Cf, __half* __restrict__ Ch, __half* __restrict__ Cl,
    int M, int N, int K, float scal)
{
    extern __shared__ char dsm[];
    uint32_t sbase = (smem_u32(dsm) + 127) & ~127u;

    const int t = threadIdx.x;
    const int lane = t & 31;
    const int wid = t >> 5;
    const int wm = wid >> 2;
    const int wn = wid & 3;
    const int bm = blockIdx.y * 128, bn = blockIdx.x * 128;
    const int NC = K >> 5;

    float acc[4][4][4] = {};
    uint32_t cor[4][4][2];
    #pragma unroll
    for (int i = 0; i < 4; i++)
        #pragma unroll
        for (int j = 0; j < 4; j++) { cor[i][j][0] = 0u; cor[i][j][1] = 0u; }

    const int lrow = t >> 2;
    const int lcell = t & 3;
    auto load_chunk = [&](int c, int stg) {
        uint32_t sb = sbase + stg*STG;
        size_t k0 = (size_t)c * 32 + lcell*8;
        #pragma unroll
        for (int j = 0; j < 2; j++) {
            int row = lrow + j*64;
            uint32_t soff = row*64 + (((uint32_t)(lcell ^ (row & 3))) << 4);
            size_t ga = (size_t)(bm + row)*K + k0;
            size_t gb = (size_t)(bn + row)*K + k0;
            cp16(sb +         soff, Ah + ga);
            cp16(sb +  8192 + soff, Al + ga);
            cp16(sb + 16384 + soff, Bh + gb);
            cp16(sb + 24576 + soff, Bl + gb);
        }
        CP_COMMIT();
    };

    load_chunk(0, 0);
    if (NC > 1) load_chunk(1, 1);

    const int arow_base = wm*64 + (lane & 15);
    const int brow_base = wn*32 + (lane & 15);
    const int kc_hi = lane >> 4;

    for (int c = 0; c < NC; c++) {
        if (c + 2 < NC) asm volatile("cp.async.wait_group 1;" ::: "memory");
        else            asm volatile("cp.async.wait_group 0;" ::: "memory");
        __syncthreads();
        if (c + 2 < NC) load_chunk(c + 2, (c + 2) % 3);

        uint32_t sb = sbase + (c % 3)*STG;
        #pragma unroll
        for (int s = 0; s < 2; s++) {
            uint32_t ah[4][4], al[4][4], bh[2][4], bl[2][4];
            int chunk = s*2 + kc_hi;
            #pragma unroll
            for (int mt = 0; mt < 4; mt++) {
                int row = arow_base + mt*16;
                uint32_t off = row*64 + (((uint32_t)(chunk ^ (row & 3))) << 4);
                LDSM_X4(ah[mt][0], ah[mt][1], ah[mt][2], ah[mt][3], sb + off);
                LDSM_X4(al[mt][0], al[mt][1], al[mt][2], al[mt][3], sb + 8192 + off);
            }
            #pragma unroll
            for (int g = 0; g < 2; g++) {
                int row = brow_base + g*16;
                uint32_t off = row*64 + (((uint32_t)(chunk ^ (row & 3))) << 4);
                LDSM_X4(bh[g][0], bh[g][1], bh[g][2], bh[g][3], sb + 16384 + off);
                LDSM_X4(bl[g][0], bl[g][1], bl[g][2], bl[g][3], sb + 24576 + off);
            }
            #pragma unroll
            for (int mt = 0; mt < 4; mt++) {
                #pragma unroll
                for (int nt = 0; nt < 4; nt++) {
                    int g = nt >> 1, o = nt & 1;
                    MMA_F32(acc[mt][nt], ah[mt], bh[g][o], bh[g][o+2]);
                    MMA_F16(cor[mt][nt], ah[mt], bl[g][o], bl[g][o+2]);
                    MMA_F16(cor[mt][nt], al[mt], bh[g][o], bh[g][o+2]);
                }
            }
        }
    }

    int r0 = bm + wm*64 + (lane >> 2);
    int c0 = bn + wn*32 + (lane & 3)*2;
    #pragma unroll
    for (int mt = 0; mt < 4; mt++) {
        #pragma unroll
        for (int nt = 0; nt < 4; nt++) {
            int col = c0 + nt*8;
            float b0 = 0.f, b1 = 0.f;
            if (FLAGS & GF_BIAS) { b0 = bias[col]; b1 = bias[col+1]; }
            #pragma unroll
            for (int half = 0; half < 2; half++) {
                int row = r0 + mt*16 + half*8;
                float2 cf = __half22float2(*reinterpret_cast<__half2*>(&cor[mt][nt][half]));
                float v0 = (acc[mt][nt][half*2+0] + cf.x) * scal + b0;
                float v1 = (acc[mt][nt][half*2+1] + cf.y) * scal + b1;
                size_t ro = (size_t)row * N + col;
                if (FLAGS & GF_RES) {
                    float2 r2 = *(const float2*)&res[ro];
                    v0 += r2.x; v1 += r2.y;
                }
                if (FLAGS & GF_RELU) { v0 = fmaxf(v0, 0.f); v1 = fmaxf(v1, 0.f); }
                if (FLAGS & GF_OUTF32) {
                    float2 o2; o2.x = v0; o2.y = v1;
                    *(float2*)&Cf[ro] = o2;
                }
                if (FLAGS & GF_OUTH16) {
                    __half h0 = __float2half_rn(v0);
                    __half h1 = __float2half_rn(v1);
                    __half2 hp; hp.x = h0; hp.y = h1;
                    *(__half2*)&Ch[ro] = hp;
                    __half2 lp;
                    lp.x = __float2half_rn(v0 - __half2float(h0));
                    lp.y = __float2half_rn(v1 - __half2float(h1));
                    *(__half2*)&Cl[ro] = lp;
                }
            }
        }
    }
}

// ========== DFT of x: X[(2m+ri)*64+b][d], half hi/lo ==========
// block = (b, 128-d-chunk); 128 threads; thread: 4 d-cols x 8 modes
__global__ void __launch_bounds__(128) dftx_kernel(const float* __restrict__ x,
                                                   __half* __restrict__ Xh,
                                                   __half* __restrict__ Xl) {
    int blk = blockIdx.x;
    int b = blk >> 2;
    int dchunk = (blk & 3) * 128;
    __shared__ float sq[32][132];
    __shared__ float sct[32][32];
    __shared__ float sst[32][32];
    int t = threadIdx.x;
    int sub = t >> 6;
    int tl = t & 63;
    int i0 = (tl >> 2) * 4;
    int mb = (tl & 3) * 8;

    float ar[4][8] = {}, ai[4][8] = {};
    const float* qbase = x + (size_t)b*Lq*Dq + dchunk;

    for (int l0 = 0; l0 < Lq; l0 += 32) {
        #pragma unroll
        for (int j = 0; j < 8; j++) {
            int v = t + j*128;
            int ll = v >> 5;
            int c4 = (v & 31) * 4;
            *(float4*)&sq[ll][c4] = *(const float4*)&qbase[(size_t)(l0+ll)*Dq + c4];
        }
        #pragma unroll
        for (int j = 0; j < 2; j++) {
            int v = t + j*128;
            int ll = v >> 3;
            int c4 = (v & 7) * 4;
            *(float4*)&sct[ll][c4] = *(const float4*)&g_ct[(l0+ll)*32 + c4];
            *(float4*)&sst[ll][c4] = *(const float4*)&g_st[(l0+ll)*32 + c4];
        }
        __syncthreads();
        #pragma unroll 2
        for (int ll = 0; ll < 32; ll++) {
            float c[8], s[8];
            *(float4*)&c[0] = *(float4*)&sct[ll][mb];
            *(float4*)&c[4] = *(float4*)&sct[ll][mb+4];
            *(float4*)&s[0] = *(float4*)&sst[ll][mb];
            *(float4*)&s[4] = *(float4*)&sst[ll][mb+4];
            float qv[4];
            #pragma unroll
            for (int j = 0; j < 4; j++) qv[j] = sq[ll][sub*64 + i0 + j];
            #pragma unroll
            for (int j = 0; j < 4; j++)
                #pragma unroll
                for (int mm = 0; mm < 8; mm++) {
                    ar[j][mm] = fmaf(qv[j],  c[mm], ar[j][mm]);
                    ai[j][mm] = fmaf(-qv[j], s[mm], ai[j][mm]);
                }
        }
        __syncthreads();
    }
    int d0 = dchunk + sub*64 + i0;
    #pragma unroll
    for (int mm = 0; mm < 8; mm++) {
        int m = mb + mm;
        size_t rowr = ((size_t)(m*2+0)*64 + b)*Dq + d0;
        size_t rowi = ((size_t)(m*2+1)*64 + b)*Dq + d0;
        __half hr[4], lr[4], hi_[4], li[4];
        #pragma unroll
        for (int j = 0; j < 4; j++) {
            float vr = ar[j][mm], vi = ai[j][mm];
            hr[j] = __float2half_rn(vr);  lr[j] = __float2half_rn(vr - __half2float(hr[j]));
            hi_[j] = __float2half_rn(vi); li[j] = __float2half_rn(vi - __half2float(hi_[j]));
        }
        __half2 p;
        p.x = hr[0]; p.y = hr[1];  *(__half2*)&Xh[rowr]   = p;
        p.x = hr[2]; p.y = hr[3];  *(__half2*)&Xh[rowr+2] = p;
        p.x = lr[0]; p.y = lr[1];  *(__half2*)&Xl[rowr]   = p;
        p.x = lr[2]; p.y = lr[3];  *(__half2*)&Xl[rowr+2] = p;
        p.x = hi_[0]; p.y = hi_[1]; *(__half2*)&Xh[rowi]   = p;
        p.x = hi_[2]; p.y = hi_[3]; *(__half2*)&Xh[rowi+2] = p;
        p.x = li[0]; p.y = li[1];  *(__half2*)&Xl[rowi]   = p;
        p.x = li[2]; p.y = li[3];  *(__half2*)&Xl[rowi+2] = p;
    }
}

// ========== complex mode mix; reads xs from mode-GEMM output ==========
// xs[(2m+ri)*64+b][he] fp32 -> os[(b*512+he)][2m+ri] half hi/lo, scaled x256
__global__ void __launch_bounds__(256) mix2_kernel(const float* __restrict__ xs,
                                                   const float* __restrict__ wr,
                                                   const float* __restrict__ wi,
                                                   const float* __restrict__ bq,
                                                   __half* __restrict__ osh,
                                                   __half* __restrict__ osl) {
    int bh = blockIdx.x;
    int b = bh >> 3, h = bh & 7;
    __shared__ float sxr[64][36];
    __shared__ float sxi[64][36];
    int t = threadIdx.x;
    #pragma unroll
    for (int j = 0; j < 8; j++) {
        int v = t + j*256;
        int ii = v & 63;
        int mm = v >> 6;
        float vr = xs[((size_t)(mm*2+0)*64 + b)*Dq + h*64 + ii];
        float vi = xs[((size_t)(mm*2+1)*64 + b)*Dq + h*64 + ii];
        if (mm == 0) vr += 512.0f * bq[h*64 + ii];
        sxr[ii][mm] = vr;
        sxi[ii][mm] = vi;
    }
    __syncthreads();
    int o  = t >> 2;
    int mb = (t & 3) * 8;
    float orr[8] = {}, oii[8] = {};
    for (int i = 0; i < 64; i++) {
        float xr[8], xi[8], w0[8], w1[8];
        *(float4*)&xr[0] = *(float4*)&sxr[i][mb];
        *(float4*)&xr[4] = *(float4*)&sxr[i][mb+4];
        *(float4*)&xi[0] = *(float4*)&sxi[i][mb];
        *(float4*)&xi[4] = *(float4*)&sxi[i][mb+4];
        size_t woff = (((size_t)h*64 + i)*64 + o)*32 + mb;
        *(float4*)&w0[0] = *(const float4*)&wr[woff];
        *(float4*)&w0[4] = *(const float4*)&wr[woff+4];
        *(float4*)&w1[0] = *(const float4*)&wi[woff];
        *(float4*)&w1[4] = *(const float4*)&wi[woff+4];
        #pragma unroll
        for (int mm = 0; mm < 8; mm++) {
            orr[mm] = fmaf(xr[mm], w0[mm], orr[mm]);
            orr[mm] = fmaf(-xi[mm], w1[mm], orr[mm]);
            oii[mm] = fmaf(xr[mm], w1[mm], oii[mm]);
            oii[mm] = fmaf(xi[mm], w0[mm], oii[mm]);
        }
    }
    size_t rbase = ((size_t)b*512 + h*64 + o)*64 + mb*2;
    #pragma unroll
    for (int mm = 0; mm < 8; mm++) {
        float vr = orr[mm] * 256.0f;
        float vi = oii[mm] * 256.0f;
        __half hr = __float2half_rn(vr);
        __half hi_ = __float2half_rn(vi);
        __half2 hp; hp.x = hr; hp.y = hi_;
        *(__half2*)&osh[rbase + mm*2] = hp;
        __half2 lp;
        lp.x = __float2half_rn(vr - __half2float(hr));
        lp.y = __float2half_rn(vi - __half2float(hi_));
        *(__half2*)&osl[rbase + mm*2] = lp;
    }
}

// ================= series_decomp =================
__global__ void decomp_kernel(const float* __restrict__ in, float* __restrict__ out,
                              __half* __restrict__ oh, __half* __restrict__ ol) {
    int gid = blockIdx.x*blockDim.x + threadIdx.x;
    int b = gid >> 9, d = gid & 511;
    const float* p = in + (size_t)b*Lq*Dq + d;
    size_t obase = (size_t)b*Lq*Dq + d;
    float wsum = 13.0f * p[0];
    #pragma unroll
    for (int j = 1; j <= 12; j++) wsum += p[(size_t)j*Dq];
    for (int l = 0; l < Lq; l++) {
        float xl = p[(size_t)l*Dq];
        float v = xl - wsum*(1.0f/25.0f);
        out[obase + (size_t)l*Dq] = v;
        __half hv = __float2half_rn(v);
        oh[obase + (size_t)l*Dq] = hv;
        ol[obase + (size_t)l*Dq] = __float2half_rn(v - __half2float(hv));
        int jn = l+13 > Lq-1 ? Lq-1 : l+13;
        int jo = l-12 < 0 ? 0 : l-12;
        wsum += p[(size_t)jn*Dq] - p[(size_t)jo*Dq];
    }
}

// ================= final layernorm / projection =================
__global__ void ln_rows(const float* __restrict__ x) {
    int row = blockIdx.x;
    int t = threadIdx.x;
    const float* p = x + (size_t)row*Dq;
    float v0 = p[t], v1 = p[t+256];
    __shared__ float sh[8];
    float s = v0 + v1;
    int lane = t & 31, w = t >> 5;
    #pragma unroll
    for (int o = 16; o > 0; o >>= 1) s += __shfl_down_sync(~0u, s, o);
    if (lane == 0) sh[w] = s;
    __syncthreads();
    if (t < 32) {
        float v = (t < 8) ? sh[t] : 0.f;
        #pragma unroll
        for (int o = 4; o > 0; o >>= 1) v += __shfl_down_sync(~0u, v, o);
        if (t == 0) sh[0] = v;
    }
    __syncthreads();
    float mu = sh[0] * (1.0f/512.0f);
    __syncthreads();
    float d0 = v0 - mu, d1 = v1 - mu;
    s = d0*d0 + d1*d1;
    #pragma unroll
    for (int o = 16; o > 0; o >>= 1) s += __shfl_down_sync(~0u, s, o);
    if (lane == 0) sh[w] = s;
    __syncthreads();
    if (t < 32) {
        float v = (t < 8) ? sh[t] : 0.f;
        #pragma unroll
        for (int o = 4; o > 0; o >>= 1) v += __shfl_down_sync(~0u, v, o);
        if (t == 0) {
            float var = v * (1.0f/512.0f);
            g_mu[row] = mu;
            g_rs[row] = rsqrtf(var + 1e-5f);
        }
    }
}

__global__ void ln_cols(const float* __restrict__ x, const float* __restrict__ nw,
                        const float* __restrict__ nb, const float* __restrict__ tv) {
    int b = blockIdx.x;
    int d = threadIdx.x;
    float w = nw[d], bb = nb[d];
    float sum = 0.f, lastv = 0.f;
    for (int l = 0; l < Lq; l++) {
        int row = b*Lq + l;
        float v = (x[(size_t)row*Dq + d] - g_mu[row]) * g_rs[row] * w + bb;
        sum += v;
        if (l == Lq-1) lastv = v;
    }
    g_cat[b*CATD + d] = lastv - sum*(1.0f/512.0f);
    if (d < 24) g_cat[b*CATD + 512 + d] = tv[((size_t)b*Lq + (Lq-1))*24 + d];
}

__global__ void __launch_bounds__(256) proj_kernel(const float* __restrict__ pw,
                                                   const float* __restrict__ pb,
                                                   float* __restrict__ out) {
    __shared__ float As[8][65];
    __shared__ float Bs[8][65];
    int n0 = blockIdx.x * 64;
    int t = threadIdx.x;
    int tx = t & 15, ty = t >> 4;
    float acc[4][4] = {};
    for (int k0 = 0; k0 < CATD; k0 += 8) {
        int v = t*2;
        int r = v >> 3, c = v & 7;
        As[c][r]   = g_cat[r*CATD + k0 + c];
        As[c+1][r] = g_cat[r*CATD + k0 + c + 1];
        int n = n0 + r;
        float f0 = 0.f, f1 = 0.f;
        if (n < NUM_APP) {
            f0 = pw[(size_t)n*CATD + k0 + c];
            f1 = pw[(size_t)n*CATD + k0 + c + 1];
        }
        Bs[c][r] = f0; Bs[c+1][r] = f1;
        __syncthreads();
        #pragma unroll
        for (int k = 0; k < 8; k++) {
            float a[4], bv[4];
            #pragma unroll
            for (int i = 0; i < 4; i++) { a[i] = As[k][ty*4+i]; bv[i] = Bs[k][tx*4+i]; }
            #pragma unroll
            for (int i = 0; i < 4; i++)
                #pragma unroll
                for (int j = 0; j < 4; j++)
                    acc[i][j] = fmaf(a[i], bv[j], acc[i][j]);
        }
        __syncthreads();
    }
    #pragma unroll
    for (int i = 0; i < 4; i++) {
        int bi = ty*4 + i;
        #pragma unroll
        for (int j = 0; j < 4; j++) {
            int n = n0 + tx*4 + j;
            if (n < NUM_APP) out[(size_t)bi*NUM_APP + n] = acc[i][j] + pb[n];
        }
    }
}

// ================= host orchestration =================
extern "C" void kernel_launch(void* const* d_in, const int* in_sizes, int n_in,
                              void* d_out, int out_size) {
    const int*   x_app     = (const int*)  d_in[0];
    const float* x_time    = (const float*)d_in[1];
    const float* time_vecs = (const float*)d_in[2];
    const float* app_emb_w = (const float*)d_in[4];
    const float* time_w    = (const float*)d_in[5];
    const float* time_b    = (const float*)d_in[6];
    const float* Wq        = (const float*)d_in[7];
    const float* bq        = (const float*)d_in[8];
    const float* Wo        = (const float*)d_in[9];
    const float* bo        = (const float*)d_in[10];
    const float* four_wr   = (const float*)d_in[11];
    const float* four_wi   = (const float*)d_in[12];
    const float* conv1_w   = (const float*)d_in[13];
    const float* conv2_w   = (const float*)d_in[14];
    const float* norm_w    = (const float*)d_in[15];
    const float* norm_b    = (const float*)d_in[16];
    const float* proj_w    = (const float*)d_in[17];
    const float* proj_b    = (const float*)d_in[18];
    float* out = (float*)d_out;

    cudaFuncSetAttribute(gemm_mma<GF_OUTF32>,                cudaFuncAttributeMaxDynamicSharedMemorySize, SMEM_GEMM);
    cudaFuncSetAttribute(gemm_mma<GF_BIAS|GF_RES|GF_OUTF32>, cudaFuncAttributeMaxDynamicSharedMemorySize, SMEM_GEMM);
    cudaFuncSetAttribute(gemm_mma<GF_RELU|GF_OUTH16>,        cudaFuncAttributeMaxDynamicSharedMemorySize, SMEM_GEMM);
    cudaFuncSetAttribute(gemm_mma<GF_RES|GF_OUTF32>,         cudaFuncAttributeMaxDynamicSharedMemorySize, SMEM_GEMM);

    void *px, *pq, *pt;
    void *pxh, *pxl, *pXh, *pXl, *pyh, *pyl, *posh, *posl, *pwth, *pwtl;
    void *pwqh, *pwql, *pc1h, *pc1l, *pc2h, *pc2l;
    cudaGetSymbolAddress(&px, g_x);
    cudaGetSymbolAddress(&pq, g_q);
    cudaGetSymbolAddress(&pt, g_t);
    cudaGetSymbolAddress(&pxh, g_xh); cudaGetSymbolAddress(&pxl, g_xl);
    cudaGetSymbolAddress(&pXh, g_Xh); cudaGetSymbolAddress(&pXl, g_Xl);
    cudaGetSymbolAddress(&pyh, g_yh); cudaGetSymbolAddress(&pyl, g_yl);
    cudaGetSymbolAddress(&posh, g_osh); cudaGetSymbolAddress(&posl, g_osl);
    cudaGetSymbolAddress(&pwth, g_wth); cudaGetSymbolAddress(&pwtl, g_wtl);
    cudaGetSymbolAddress(&pwqh, g_wqh); cudaGetSymbolAddress(&pwql, g_wql);
    cudaGetSymbolAddress(&pc1h, g_c1h); cudaGetSymbolAddress(&pc1l, g_c1l);
    cudaGetSymbolAddress(&pc2h, g_c2h); cudaGetSymbolAddress(&pc2l, g_c2l);
    float* fx = (float*)px;
    float* fq = (float*)pq;
    float* ft = (float*)pt;
    __half *xh=(__half*)pxh, *xl=(__half*)pxl;
    __half *Xh=(__half*)pXh, *Xl=(__half*)pXl;
    __half *yh=(__half*)pyh, *yl=(__half*)pyl;
    __half *osh=(__half*)posh, *osl=(__half*)posl;
    __half *wth=(__half*)pwth, *wtl=(__half*)pwtl;
    __half *wqh=(__half*)pwqh, *wql=(__half*)pwql;
    __half *c1h=(__half*)pc1h, *c1l=(__half*)pc1l;
    __half *c2h=(__half*)pc2h, *c2l=(__half*)pc2l;

    init_tables<<<64, 256>>>();
    convert_hl<<<(2*Dq*Dq + 255)/256, 256>>>(Wq, wqh, wql, 2*Dq*Dq);
    convert_hl<<<(2*DFF*Dq + 255)/256, 256>>>(conv1_w, c1h, c1l, 2*DFF*Dq);
    convert_hl<<<(2*Dq*DFF + 255)/256, 256>>>(conv2_w, c2h, c2l, 2*Dq*DFF);
    wotab_kernel<<<dim3(128, 2), 128>>>(Wo, wth, wtl);
    embed_kernel<<<BLq*Dq/256, 256>>>(x_app, x_time, app_emb_w, time_w, time_b);

    const int M = BLq;
    for (int l = 0; l < 2; l++) {
        size_t woff = (size_t)l*Dq*Dq;
        size_t coff1 = (size_t)l*DFF*Dq;

        // X = DFT_l(x)   (rows (m,ri,b) x d, half split)
        dftx_kernel<<<256, 128>>>(fx, Xh, Xl);
        // xs = X @ Wq^T  (4096 x 512 x 512)
        gemm_mma<GF_OUTF32><<<dim3(4, 32), 256, SMEM_GEMM>>>(
            Xh, Xl, wqh + woff, wql + woff, nullptr, nullptr,
            fq, nullptr, nullptr, 4096, Dq, Dq, 1.0f);
        // os = mode mix (+ bq into mode 0); writes x256-scaled half pairs
        mix2_kernel<<<Bq*Hq, 256>>>(fq, four_wr + (size_t)l*Hq*Eq*Eq*MODES,
                                    four_wi + (size_t)l*Hq*Eq*Eq*MODES,
                                    bq + l*Dq, osh, osl);
        // new_x = os @ WoT^T * (1/65536) + bo + x   (32768 x 512 x 64)
        gemm_mma<GF_BIAS|GF_RES|GF_OUTF32><<<dim3(4, 256), 256, SMEM_GEMM>>>(
            osh, osl, wth + (size_t)l*Dq*64, wtl + (size_t)l*Dq*64, bo + l*Dq, fx,
            ft, nullptr, nullptr, M, Dq, 64, 1.0f/65536.0f);
        decomp_kernel<<<Bq*Dq/256, 256>>>(ft, fx, xh, xl);
        // FFN
        gemm_mma<GF_RELU|GF_OUTH16><<<dim3(DFF/128, M/128), 256, SMEM_GEMM>>>(
            xh, xl, c1h + coff1, c1l + coff1, nullptr, nullptr,
            nullptr, yh, yl, M, DFF, Dq, 1.0f);
        gemm_mma<GF_RES|GF_OUTF32><<<dim3(Dq/128, M/128), 256, SMEM_GEMM>>>(
            yh, yl, c2h + coff1, c2l + coff1, nullptr, fx,
            ft, nullptr, nullptr, M, Dq, DFF, 1.0f);
        decomp_kernel<<<Bq*Dq/256, 256>>>(ft, fx, xh, xl);
    }

    ln_rows<<<BLq, 256>>>(fx);
    ln_cols<<<Bq, 512>>>(fx, norm_w, norm_b, time_vecs);
    proj_kernel<<<(NUM_APP + 63)/64, 256>>>(proj_w, proj_b, out);
}

// round 6
// speedup vs baseline: 2.7280x; 1.2353x over previous
#include <cuda_runtime.h>
#include <cuda_fp16.h>
#include <math.h>
#include <stdint.h>

#define Bq 64
#define Lq 512
#define Dq 512
#define Hq 8
#define Eq 64
#define DFF 2048
#define MODES 32
#define VOCAB 10000
#define NUM_APP 10000
#define CATD 536
#define BLq (Bq*Lq)

// ================= helpers =================
__device__ __forceinline__ uint32_t smem_u32(const void* p) {
    uint32_t a;
    asm("{ .reg .u64 t; cvta.to.shared.u64 t, %1; cvt.u32.u64 %0, t; }" : "=r"(a) : "l"(p));
    return a;
}
__device__ __forceinline__ void cp16(uint32_t dst, const void* src) {
    asm volatile("cp.async.cg.shared.global [%0], [%1], 16;" :: "r"(dst), "l"(src) : "memory");
}
#define CP_COMMIT() asm volatile("cp.async.commit_group;" ::: "memory")

#define LDSM_X4(r0,r1,r2,r3, addr) \
    asm volatile("ldmatrix.sync.aligned.m8n8.x4.shared.b16 {%0,%1,%2,%3}, [%4];" \
        : "=r"(r0), "=r"(r1), "=r"(r2), "=r"(r3) : "r"(addr))

#define MMA_F32(d, a, b0, b1) \
    asm volatile("mma.sync.aligned.m16n8k16.row.col.f32.f16.f16.f32 " \
        "{%0,%1,%2,%3},{%4,%5,%6,%7},{%8,%9},{%0,%1,%2,%3};" \
        : "+f"((d)[0]), "+f"((d)[1]), "+f"((d)[2]), "+f"((d)[3]) \
        : "r"((a)[0]), "r"((a)[1]), "r"((a)[2]), "r"((a)[3]), "r"(b0), "r"(b1))

// ================= scratch (device globals) =================
__device__ float g_x[BLq*Dq];
__device__ float g_q[BLq*Dq];          // mode-GEMM output
__device__ float g_t[BLq*Dq];
__device__ __align__(256) __half g_xh[BLq*Dq];
__device__ __align__(256) __half g_Xh[4096*Dq], g_Xl[4096*Dq];     // DFT(x)
__device__ __align__(256) __half g_yh[BLq*DFF];
__device__ __align__(256) __half g_osh[BLq*64], g_osl[BLq*64];
__device__ __align__(256) __half g_wth[2*Dq*64], g_wtl[2*Dq*64];
__device__ __align__(256) __half g_wqh[2*Dq*Dq], g_wql[2*Dq*Dq];
__device__ __align__(256) __half g_c1h[2*DFF*Dq], g_c1l[2*DFF*Dq];
__device__ __align__(256) __half g_c2h[2*Dq*DFF], g_c2l[2*Dq*DFF];
__device__ float g_ct[Lq*MODES], g_st[Lq*MODES];
__device__ float g_mu[BLq], g_rs[BLq];
__device__ float g_cat[Bq*CATD];

// ================= small kernels =================
__global__ void init_tables() {
    int idx = blockIdx.x*blockDim.x + threadIdx.x;
    if (idx < Lq*MODES) {
        int l = idx >> 5, m = idx & 31;
        double a = (double)(m*l) / 256.0;
        double s, c;
        sincospi(a, &s, &c);
        g_ct[idx] = (float)c;
        g_st[idx] = (float)s;
    }
}

__global__ void convert_hl(const float* __restrict__ src, __half* __restrict__ h,
                           __half* __restrict__ l, int n) {
    int i = blockIdx.x*256 + threadIdx.x;
    if (i < n) {
        float v = src[i];
        __half hv = __float2half_rn(v);
        h[i] = hv;
        l[i] = __float2half_rn(v - __half2float(hv));
    }
}

__global__ void embed_kernel(const int* __restrict__ app, const float* __restrict__ xt,
                             const float* __restrict__ emb, const float* __restrict__ tw,
                             const float* __restrict__ tb) {
    size_t idx = (size_t)blockIdx.x*256 + threadIdx.x;
    int d = (int)(idx & 511);
    size_t bl = idx >> 9;
    int a = app[bl];
    g_x[idx] = emb[(size_t)a*Dq + d] + xt[bl]*tw[d] + tb[d];
}

// ========== Wo frequency table ==========
__global__ void __launch_bounds__(128) wotab_kernel(const float* __restrict__ Wo,
                                                    __half* __restrict__ wth,
                                                    __half* __restrict__ wtl) {
    int layer = blockIdx.y;
    int j0 = blockIdx.x * 4;
    __shared__ float sw[4][512];
    int t = threadIdx.x;
    const float* wo = Wo + (size_t)layer*Dq*Dq + (size_t)j0*Dq;
    #pragma unroll
    for (int j = 0; j < 4; j++) {
        int v = t + j*128;
        int r = v >> 7, c4 = (v & 127) * 4;
        *(float4*)&sw[r][c4] = *(const float4*)&wo[(size_t)r*Dq + c4];
    }
    __syncthreads();
    int tj = t >> 5, tm = t & 31;
    float ac = 0.f, as = 0.f;
    for (int l = 0; l < Lq; l++) {
        float w = sw[tj][l];
        ac = fmaf(w, g_ct[l*32 + tm], ac);
        as = fmaf(w, g_st[l*32 + tm], as);
    }
    float cm = (tm == 0 ? 1.0f : 2.0f) * (256.0f/512.0f);
    float vc = ac*cm, vs = -as*cm;
    size_t base = ((size_t)layer*Dq + j0 + tj)*64 + tm*2;
    __half hc = __float2half_rn(vc);
    __half hs = __float2half_rn(vs);
    wth[base]   = hc;  wtl[base]   = __float2half_rn(vc - __half2float(hc));
    wth[base+1] = hs;  wtl[base+1] = __float2half_rn(vs - __half2float(hs));
}

// ================= mma.sync fp16 split GEMM: C = A(MxK) @ B(NxK)^T =============
// TERMS==3: Ah*Bh + Ah*Bl + Al*Bh.  TERMS==2: Ah*Bh + Ah*Bl (A single fp16).
// All f32 accumulate into one accumulator.
#define GF_BIAS 1
#define GF_RES  2
#define GF_RELU 4
#define GF_OUTF32 8
#define GF_OUTH16 16

#define STG 32768
#define SMEM_GEMM (3*STG + 256)

template<int FLAGS, int TERMS>
__global__ void __launch_bounds__(256, 1) gemm_mma(
    const __half* __restrict__ Ah, const __half* __restrict__ Al,
    const __half* __restrict__ Bh, const __half* __restrict__ Bl,
    const float* __restrict__ bias, const float* __restrict__ res,
    float* __restrict__ Cf, __half* __restrict__ Ch,
    int M, int N, int K, float scal)
{
    extern __shared__ char dsm[];
    uint32_t sbase = (smem_u32(dsm) + 127) & ~127u;

    const int t = threadIdx.x;
    const int lane = t & 31;
    const int wid = t >> 5;
    const int wm = wid >> 2;
    const int wn = wid & 3;
    const int bm = blockIdx.y * 128, bn = blockIdx.x * 128;
    const int NC = K >> 5;

    float acc[4][4][4] = {};

    const int lrow = t >> 2;
    const int lcell = t & 3;
    auto load_chunk = [&](int c, int stg) {
        uint32_t sb = sbase + stg*STG;
        size_t k0 = (size_t)c * 32 + lcell*8;
        #pragma unroll
        for (int j = 0; j < 2; j++) {
            int row = lrow + j*64;
            uint32_t soff = row*64 + (((uint32_t)(lcell ^ (row & 3))) << 4);
            size_t ga = (size_t)(bm + row)*K + k0;
            size_t gb = (size_t)(bn + row)*K + k0;
            cp16(sb +         soff, Ah + ga);
            if (TERMS == 3) cp16(sb + 8192 + soff, Al + ga);
            cp16(sb + 16384 + soff, Bh + gb);
            cp16(sb + 24576 + soff, Bl + gb);
        }
        CP_COMMIT();
    };

    load_chunk(0, 0);
    if (NC > 1) load_chunk(1, 1);

    const int arow_base = wm*64 + (lane & 15);
    const int brow_base = wn*32 + (lane & 15);
    const int kc_hi = lane >> 4;

    for (int c = 0; c < NC; c++) {
        if (c + 2 < NC) asm volatile("cp.async.wait_group 1;" ::: "memory");
        else            asm volatile("cp.async.wait_group 0;" ::: "memory");
        __syncthreads();
        if (c + 2 < NC) load_chunk(c + 2, (c + 2) % 3);

        uint32_t sb = sbase + (c % 3)*STG;
        #pragma unroll
        for (int s = 0; s < 2; s++) {
            uint32_t ah[4][4], al[4][4], bh[2][4], bl[2][4];
            int chunk = s*2 + kc_hi;
            #pragma unroll
            for (int mt = 0; mt < 4; mt++) {
                int row = arow_base + mt*16;
                uint32_t off = row*64 + (((uint32_t)(chunk ^ (row & 3))) << 4);
                LDSM_X4(ah[mt][0], ah[mt][1], ah[mt][2], ah[mt][3], sb + off);
                if (TERMS == 3)
                    LDSM_X4(al[mt][0], al[mt][1], al[mt][2], al[mt][3], sb + 8192 + off);
            }
            #pragma unroll
            for (int g = 0; g < 2; g++) {
                int row = brow_base + g*16;
                uint32_t off = row*64 + (((uint32_t)(chunk ^ (row & 3))) << 4);
                LDSM_X4(bh[g][0], bh[g][1], bh[g][2], bh[g][3], sb + 16384 + off);
                LDSM_X4(bl[g][0], bl[g][1], bl[g][2], bl[g][3], sb + 24576 + off);
            }
            #pragma unroll
            for (int mt = 0; mt < 4; mt++) {
                #pragma unroll
                for (int nt = 0; nt < 4; nt++) {
                    int g = nt >> 1, o = nt & 1;
                    MMA_F32(acc[mt][nt], ah[mt], bh[g][o], bh[g][o+2]);
                    MMA_F32(acc[mt][nt], ah[mt], bl[g][o], bl[g][o+2]);
                    if (TERMS == 3)
                        MMA_F32(acc[mt][nt], al[mt], bh[g][o], bh[g][o+2]);
                }
            }
        }
    }

    int r0 = bm + wm*64 + (lane >> 2);
    int c0 = bn + wn*32 + (lane & 3)*2;
    #pragma unroll
    for (int mt = 0; mt < 4; mt++) {
        #pragma unroll
        for (int nt = 0; nt < 4; nt++) {
            int col = c0 + nt*8;
            float b0 = 0.f, b1 = 0.f;
            if (FLAGS & GF_BIAS) { b0 = bias[col]; b1 = bias[col+1]; }
            #pragma unroll
            for (int half = 0; half < 2; half++) {
                int row = r0 + mt*16 + half*8;
                float v0 = acc[mt][nt][half*2+0] * scal + b0;
                float v1 = acc[mt][nt][half*2+1] * scal + b1;
                size_t ro = (size_t)row * N + col;
                if (FLAGS & GF_RES) {
                    float2 r2 = *(const float2*)&res[ro];
                    v0 += r2.x; v1 += r2.y;
                }
                if (FLAGS & GF_RELU) { v0 = fmaxf(v0, 0.f); v1 = fmaxf(v1, 0.f); }
                if (FLAGS & GF_OUTF32) {
                    float2 o2; o2.x = v0; o2.y = v1;
                    *(float2*)&Cf[ro] = o2;
                }
                if (FLAGS & GF_OUTH16) {
                    __half2 hp; hp.x = __float2half_rn(v0); hp.y = __float2half_rn(v1);
                    *(__half2*)&Ch[ro] = hp;
                }
            }
        }
    }
}

// ========== DFT of x ==========
__global__ void __launch_bounds__(128) dftx_kernel(const float* __restrict__ x,
                                                   __half* __restrict__ Xh,
                                                   __half* __restrict__ Xl) {
    int blk = blockIdx.x;
    int b = blk >> 2;
    int dchunk = (blk & 3) * 128;
    __shared__ float sq[32][132];
    __shared__ float sct[32][32];
    __shared__ float sst[32][32];
    int t = threadIdx.x;
    int sub = t >> 6;
    int tl = t & 63;
    int i0 = (tl >> 2) * 4;
    int mb = (tl & 3) * 8;

    float ar[4][8] = {}, ai[4][8] = {};
    const float* qbase = x + (size_t)b*Lq*Dq + dchunk;

    for (int l0 = 0; l0 < Lq; l0 += 32) {
        #pragma unroll
        for (int j = 0; j < 8; j++) {
            int v = t + j*128;
            int ll = v >> 5;
            int c4 = (v & 31) * 4;
            *(float4*)&sq[ll][c4] = *(const float4*)&qbase[(size_t)(l0+ll)*Dq + c4];
        }
        #pragma unroll
        for (int j = 0; j < 2; j++) {
            int v = t + j*128;
            int ll = v >> 3;
            int c4 = (v & 7) * 4;
            *(float4*)&sct[ll][c4] = *(const float4*)&g_ct[(l0+ll)*32 + c4];
            *(float4*)&sst[ll][c4] = *(const float4*)&g_st[(l0+ll)*32 + c4];
        }
        __syncthreads();
        #pragma unroll 2
        for (int ll = 0; ll < 32; ll++) {
            float c[8], s[8];
            *(float4*)&c[0] = *(float4*)&sct[ll][mb];
            *(float4*)&c[4] = *(float4*)&sct[ll][mb+4];
            *(float4*)&s[0] = *(float4*)&sst[ll][mb];
            *(float4*)&s[4] = *(float4*)&sst[ll][mb+4];
            float qv[4];
            #pragma unroll
            for (int j = 0; j < 4; j++) qv[j] = sq[ll][sub*64 + i0 + j];
            #pragma unroll
            for (int j = 0; j < 4; j++)
                #pragma unroll
                for (int mm = 0; mm < 8; mm++) {
                    ar[j][mm] = fmaf(qv[j],  c[mm], ar[j][mm]);
                    ai[j][mm] = fmaf(-qv[j], s[mm], ai[j][mm]);
                }
        }
        __syncthreads();
    }
    int d0 = dchunk + sub*64 + i0;
    #pragma unroll
    for (int mm = 0; mm < 8; mm++) {
        int m = mb + mm;
        size_t rowr = ((size_t)(m*2+0)*64 + b)*Dq + d0;
        size_t rowi = ((size_t)(m*2+1)*64 + b)*Dq + d0;
        __half hr[4], lr[4], hi_[4], li[4];
        #pragma unroll
        for (int j = 0; j < 4; j++) {
            float vr = ar[j][mm], vi = ai[j][mm];
            hr[j] = __float2half_rn(vr);  lr[j] = __float2half_rn(vr - __half2float(hr[j]));
            hi_[j] = __float2half_rn(vi); li[j] = __float2half_rn(vi - __half2float(hi_[j]));
        }
        __half2 p;
        p.x = hr[0]; p.y = hr[1];  *(__half2*)&Xh[rowr]   = p;
        p.x = hr[2]; p.y = hr[3];  *(__half2*)&Xh[rowr+2] = p;
        p.x = lr[0]; p.y = lr[1];  *(__half2*)&Xl[rowr]   = p;
        p.x = lr[2]; p.y = lr[3];  *(__half2*)&Xl[rowr+2] = p;
        p.x = hi_[0]; p.y = hi_[1]; *(__half2*)&Xh[rowi]   = p;
        p.x = hi_[2]; p.y = hi_[3]; *(__half2*)&Xh[rowi+2] = p;
        p.x = li[0]; p.y = li[1];  *(__half2*)&Xl[rowi]   = p;
        p.x = li[2]; p.y = li[3];  *(__half2*)&Xl[rowi+2] = p;
    }
}

// ========== complex mode mix ==========
__global__ void __launch_bounds__(256) mix2_kernel(const float* __restrict__ xs,
                                                   const float* __restrict__ wr,
                                                   const float* __restrict__ wi,
                                                   const float* __restrict__ bq,
                                                   __half* __restrict__ osh,
                                                   __half* __restrict__ osl) {
    int bh = blockIdx.x;
    int b = bh >> 3, h = bh & 7;
    __shared__ float sxr[64][36];
    __shared__ float sxi[64][36];
    int t = threadIdx.x;
    #pragma unroll
    for (int j = 0; j < 8; j++) {
        int v = t + j*256;
        int ii = v & 63;
        int mm = v >> 6;
        float vr = xs[((size_t)(mm*2+0)*64 + b)*Dq + h*64 + ii];
        float vi = xs[((size_t)(mm*2+1)*64 + b)*Dq + h*64 + ii];
        if (mm == 0) vr += 512.0f * bq[h*64 + ii];
        sxr[ii][mm] = vr;
        sxi[ii][mm] = vi;
    }
    __syncthreads();
    int o  = t >> 2;
    int mb = (t & 3) * 8;
    float orr[8] = {}, oii[8] = {};
    for (int i = 0; i < 64; i++) {
        float xr[8], xi[8], w0[8], w1[8];
        *(float4*)&xr[0] = *(float4*)&sxr[i][mb];
        *(float4*)&xr[4] = *(float4*)&sxr[i][mb+4];
        *(float4*)&xi[0] = *(float4*)&sxi[i][mb];
        *(float4*)&xi[4] = *(float4*)&sxi[i][mb+4];
        size_t woff = (((size_t)h*64 + i)*64 + o)*32 + mb;
        *(float4*)&w0[0] = *(const float4*)&wr[woff];
        *(float4*)&w0[4] = *(const float4*)&wr[woff+4];
        *(float4*)&w1[0] = *(const float4*)&wi[woff];
        *(float4*)&w1[4] = *(const float4*)&wi[woff+4];
        #pragma unroll
        for (int mm = 0; mm < 8; mm++) {
            orr[mm] = fmaf(xr[mm], w0[mm], orr[mm]);
            orr[mm] = fmaf(-xi[mm], w1[mm], orr[mm]);
            oii[mm] = fmaf(xr[mm], w1[mm], oii[mm]);
            oii[mm] = fmaf(xi[mm], w0[mm], oii[mm]);
        }
    }
    size_t rbase = ((size_t)b*512 + h*64 + o)*64 + mb*2;
    #pragma unroll
    for (int mm = 0; mm < 8; mm++) {
        float vr = orr[mm] * 256.0f;
        float vi = oii[mm] * 256.0f;
        __half hr = __float2half_rn(vr);
        __half hi_ = __float2half_rn(vi);
        __half2 hp; hp.x = hr; hp.y = hi_;
        *(__half2*)&osh[rbase + mm*2] = hp;
        __half2 lp;
        lp.x = __float2half_rn(vr - __half2float(hr));
        lp.y = __float2half_rn(vi - __half2float(hi_));
        *(__half2*)&osl[rbase + mm*2] = lp;
    }
}

// ================= series_decomp =================
__global__ void decomp_kernel(const float* __restrict__ in, float* __restrict__ out,
                              __half* __restrict__ oh) {
    int gid = blockIdx.x*blockDim.x + threadIdx.x;
    int b = gid >> 9, d = gid & 511;
    const float* p = in + (size_t)b*Lq*Dq + d;
    size_t obase = (size_t)b*Lq*Dq + d;
    float wsum = 13.0f * p[0];
    #pragma unroll
    for (int j = 1; j <= 12; j++) wsum += p[(size_t)j*Dq];
    for (int l = 0; l < Lq; l++) {
        float xl = p[(size_t)l*Dq];
        float v = xl - wsum*(1.0f/25.0f);
        out[obase + (size_t)l*Dq] = v;
        oh[obase + (size_t)l*Dq] = __float2half_rn(v);
        int jn = l+13 > Lq-1 ? Lq-1 : l+13;
        int jo = l-12 < 0 ? 0 : l-12;
        wsum += p[(size_t)jn*Dq] - p[(size_t)jo*Dq];
    }
}

// ================= final layernorm / projection =================
__global__ void ln_rows(const float* __restrict__ x) {
    int row = blockIdx.x;
    int t = threadIdx.x;
    const float* p = x + (size_t)row*Dq;
    float v0 = p[t], v1 = p[t+256];
    __shared__ float sh[8];
    float s = v0 + v1;
    int lane = t & 31, w = t >> 5;
    #pragma unroll
    for (int o = 16; o > 0; o >>= 1) s += __shfl_down_sync(~0u, s, o);
    if (lane == 0) sh[w] = s;
    __syncthreads();
    if (t < 32) {
        float v = (t < 8) ? sh[t] : 0.f;
        #pragma unroll
        for (int o = 4; o > 0; o >>= 1) v += __shfl_down_sync(~0u, v, o);
        if (t == 0) sh[0] = v;
    }
    __syncthreads();
    float mu = sh[0] * (1.0f/512.0f);
    __syncthreads();
    float d0 = v0 - mu, d1 = v1 - mu;
    s = d0*d0 + d1*d1;
    #pragma unroll
    for (int o = 16; o > 0; o >>= 1) s += __shfl_down_sync(~0u, s, o);
    if (lane == 0) sh[w] = s;
    __syncthreads();
    if (t < 32) {
        float v = (t < 8) ? sh[t] : 0.f;
        #pragma unroll
        for (int o = 4; o > 0; o >>= 1) v += __shfl_down_sync(~0u, v, o);
        if (t == 0) {
            float var = v * (1.0f/512.0f);
            g_mu[row] = mu;
            g_rs[row] = rsqrtf(var + 1e-5f);
        }
    }
}

__global__ void ln_cols(const float* __restrict__ x, const float* __restrict__ nw,
                        const float* __restrict__ nb, const float* __restrict__ tv) {
    int b = blockIdx.x;
    int d = threadIdx.x;
    float w = nw[d], bb = nb[d];
    float sum = 0.f, lastv = 0.f;
    for (int l = 0; l < Lq; l++) {
        int row = b*Lq + l;
        float v = (x[(size_t)row*Dq + d] - g_mu[row]) * g_rs[row] * w + bb;
        sum += v;
        if (l == Lq-1) lastv = v;
    }
    g_cat[b*CATD + d] = lastv - sum*(1.0f/512.0f);
    if (d < 24) g_cat[b*CATD + 512 + d] = tv[((size_t)b*Lq + (Lq-1))*24 + d];
}

__global__ void __launch_bounds__(256) proj_kernel(const float* __restrict__ pw,
                                                   const float* __restrict__ pb,
                                                   float* __restrict__ out) {
    __shared__ float As[8][65];
    __shared__ float Bs[8][65];
    int n0 = blockIdx.x * 64;
    int t = threadIdx.x;
    int tx = t & 15, ty = t >> 4;
    float acc[4][4] = {};
    for (int k0 = 0; k0 < CATD; k0 += 8) {
        int v = t*2;
        int r = v >> 3, c = v & 7;
        As[c][r]   = g_cat[r*CATD + k0 + c];
        As[c+1][r] = g_cat[r*CATD + k0 + c + 1];
        int n = n0 + r;
        float f0 = 0.f, f1 = 0.f;
        if (n < NUM_APP) {
            f0 = pw[(size_t)n*CATD + k0 + c];
            f1 = pw[(size_t)n*CATD + k0 + c + 1];
        }
        Bs[c][r] = f0; Bs[c+1][r] = f1;
        __syncthreads();
        #pragma unroll
        for (int k = 0; k < 8; k++) {
            float a[4], bv[4];
            #pragma unroll
            for (int i = 0; i < 4; i++) { a[i] = As[k][ty*4+i]; bv[i] = Bs[k][tx*4+i]; }
            #pragma unroll
            for (int i = 0; i < 4; i++)
                #pragma unroll
                for (int j = 0; j < 4; j++)
                    acc[i][j] = fmaf(a[i], bv[j], acc[i][j]);
        }
        __syncthreads();
    }
    #pragma unroll
    for (int i = 0; i < 4; i++) {
        int bi = ty*4 + i;
        #pragma unroll
        for (int j = 0; j < 4; j++) {
            int n = n0 + tx*4 + j;
            if (n < NUM_APP) out[(size_t)bi*NUM_APP + n] = acc[i][j] + pb[n];
        }
    }
}

// ================= host orchestration =================
extern "C" void kernel_launch(void* const* d_in, const int* in_sizes, int n_in,
                              void* d_out, int out_size) {
    const int*   x_app     = (const int*)  d_in[0];
    const float* x_time    = (const float*)d_in[1];
    const float* time_vecs = (const float*)d_in[2];
    const float* app_emb_w = (const float*)d_in[4];
    const float* time_w    = (const float*)d_in[5];
    const float* time_b    = (const float*)d_in[6];
    const float* Wq        = (const float*)d_in[7];
    const float* bq        = (const float*)d_in[8];
    const float* Wo        = (const float*)d_in[9];
    const float* bo        = (const float*)d_in[10];
    const float* four_wr   = (const float*)d_in[11];
    const float* four_wi   = (const float*)d_in[12];
    const float* conv1_w   = (const float*)d_in[13];
    const float* conv2_w   = (const float*)d_in[14];
    const float* norm_w    = (const float*)d_in[15];
    const float* norm_b    = (const float*)d_in[16];
    const float* proj_w    = (const float*)d_in[17];
    const float* proj_b    = (const float*)d_in[18];
    float* out = (float*)d_out;

    cudaFuncSetAttribute((const void*)gemm_mma<GF_OUTF32, 3>,                cudaFuncAttributeMaxDynamicSharedMemorySize, SMEM_GEMM);
    cudaFuncSetAttribute((const void*)gemm_mma<GF_BIAS|GF_RES|GF_OUTF32, 3>, cudaFuncAttributeMaxDynamicSharedMemorySize, SMEM_GEMM);
    cudaFuncSetAttribute((const void*)gemm_mma<GF_RELU|GF_OUTH16, 2>,        cudaFuncAttributeMaxDynamicSharedMemorySize, SMEM_GEMM);
    cudaFuncSetAttribute((const void*)gemm_mma<GF_RES|GF_OUTF32, 2>,         cudaFuncAttributeMaxDynamicSharedMemorySize, SMEM_GEMM);

    void *px, *pq, *pt;
    void *pxh, *pXh, *pXl, *pyh, *posh, *posl, *pwth, *pwtl;
    void *pwqh, *pwql, *pc1h, *pc1l, *pc2h, *pc2l;
    cudaGetSymbolAddress(&px, g_x);
    cudaGetSymbolAddress(&pq, g_q);
    cudaGetSymbolAddress(&pt, g_t);
    cudaGetSymbolAddress(&pxh, g_xh);
    cudaGetSymbolAddress(&pXh, g_Xh); cudaGetSymbolAddress(&pXl, g_Xl);
    cudaGetSymbolAddress(&pyh, g_yh);
    cudaGetSymbolAddress(&posh, g_osh); cudaGetSymbolAddress(&posl, g_osl);
    cudaGetSymbolAddress(&pwth, g_wth); cudaGetSymbolAddress(&pwtl, g_wtl);
    cudaGetSymbolAddress(&pwqh, g_wqh); cudaGetSymbolAddress(&pwql, g_wql);
    cudaGetSymbolAddress(&pc1h, g_c1h); cudaGetSymbolAddress(&pc1l, g_c1l);
    cudaGetSymbolAddress(&pc2h, g_c2h); cudaGetSymbolAddress(&pc2l, g_c2l);
    float* fx = (float*)px;
    float* fq = (float*)pq;
    float* ft = (float*)pt;
    __half *xh=(__half*)pxh;
    __half *Xh=(__half*)pXh, *Xl=(__half*)pXl;
    __half *yh=(__half*)pyh;
    __half *osh=(__half*)posh, *osl=(__half*)posl;
    __half *wth=(__half*)pwth, *wtl=(__half*)pwtl;
    __half *wqh=(__half*)pwqh, *wql=(__half*)pwql;
    __half *c1h=(__half*)pc1h, *c1l=(__half*)pc1l;
    __half *c2h=(__half*)pc2h, *c2l=(__half*)pc2l;

    init_tables<<<64, 256>>>();
    convert_hl<<<(2*Dq*Dq + 255)/256, 256>>>(Wq, wqh, wql, 2*Dq*Dq);
    convert_hl<<<(2*DFF*Dq + 255)/256, 256>>>(conv1_w, c1h, c1l, 2*DFF*Dq);
    convert_hl<<<(2*Dq*DFF + 255)/256, 256>>>(conv2_w, c2h, c2l, 2*Dq*DFF);
    wotab_kernel<<<dim3(128, 2), 128>>>(Wo, wth, wtl);
    embed_kernel<<<BLq*Dq/256, 256>>>(x_app, x_time, app_emb_w, time_w, time_b);

    const int M = BLq;
    for (int l = 0; l < 2; l++) {
        size_t woff = (size_t)l*Dq*Dq;
        size_t coff1 = (size_t)l*DFF*Dq;

        // X = DFT_l(x)
        dftx_kernel<<<256, 128>>>(fx, Xh, Xl);
        // xs = X @ Wq^T  (4096 x 512 x 512), 3-term
        gemm_mma<GF_OUTF32, 3><<<dim3(4, 32), 256, SMEM_GEMM>>>(
            Xh, Xl, wqh + woff, wql + woff, nullptr, nullptr,
            fq, nullptr, 4096, Dq, Dq, 1.0f);
        // os = mode mix (+ bq into mode 0)
        mix2_kernel<<<Bq*Hq, 256>>>(fq, four_wr + (size_t)l*Hq*Eq*Eq*MODES,
                                    four_wi + (size_t)l*Hq*Eq*Eq*MODES,
                                    bq + l*Dq, osh, osl);
        // new_x = os @ WoT^T * (1/65536) + bo + x, 3-term
        gemm_mma<GF_BIAS|GF_RES|GF_OUTF32, 3><<<dim3(4, 256), 256, SMEM_GEMM>>>(
            osh, osl, wth + (size_t)l*Dq*64, wtl + (size_t)l*Dq*64, bo + l*Dq, fx,
            ft, nullptr, M, Dq, 64, 1.0f/65536.0f);
        decomp_kernel<<<Bq*Dq/256, 256>>>(ft, fx, xh);
        // y = relu(x @ c1^T), 2-term (A = xh only)
        gemm_mma<GF_RELU|GF_OUTH16, 2><<<dim3(DFF/128, M/128), 256, SMEM_GEMM>>>(
            xh, nullptr, c1h + coff1, c1l + coff1, nullptr, nullptr,
            nullptr, yh, M, DFF, Dq, 1.0f);
        // t = y @ c2^T + x, 2-term (A = yh only)
        gemm_mma<GF_RES|GF_OUTF32, 2><<<dim3(Dq/128, M/128), 256, SMEM_GEMM>>>(
            yh, nullptr, c2h + coff1, c2l + coff1, nullptr, fx,
            ft, nullptr, M, Dq, DFF, 1.0f);
        decomp_kernel<<<Bq*Dq/256, 256>>>(ft, fx, xh);
    }

    ln_rows<<<BLq, 256>>>(fx);
    ln_cols<<<Bq, 512>>>(fx, norm_w, norm_b, time_vecs);
    proj_kernel<<<(NUM_APP + 63)/64, 256>>>(proj_w, proj_b, out);
}

// round 7
// speedup vs baseline: 3.7604x; 1.3784x over previous
#include <cuda_runtime.h>
#include <cuda_fp16.h>
#include <math.h>
#include <stdint.h>

#define Bq 64
#define Lq 512
#define Dq 512
#define Hq 8
#define Eq 64
#define DFF 2048
#define MODES 32
#define VOCAB 10000
#define NUM_APP 10000
#define CATD 536
#define BLq (Bq*Lq)

// ================= helpers =================
__device__ __forceinline__ uint32_t smem_u32(const void* p) {
    uint32_t a;
    asm("{ .reg .u64 t; cvta.to.shared.u64 t, %1; cvt.u32.u64 %0, t; }" : "=r"(a) : "l"(p));
    return a;
}
__device__ __forceinline__ void cp16(uint32_t dst, const void* src) {
    asm volatile("cp.async.cg.shared.global [%0], [%1], 16;" :: "r"(dst), "l"(src) : "memory");
}
#define CP_COMMIT() asm volatile("cp.async.commit_group;" ::: "memory")

#define LDSM_X4(r0,r1,r2,r3, addr) \
    asm volatile("ldmatrix.sync.aligned.m8n8.x4.shared.b16 {%0,%1,%2,%3}, [%4];" \
        : "=r"(r0), "=r"(r1), "=r"(r2), "=r"(r3) : "r"(addr))

#define MMA_F32(d, a, b0, b1) \
    asm volatile("mma.sync.aligned.m16n8k16.row.col.f32.f16.f16.f32 " \
        "{%0,%1,%2,%3},{%4,%5,%6,%7},{%8,%9},{%0,%1,%2,%3};" \
        : "+f"((d)[0]), "+f"((d)[1]), "+f"((d)[2]), "+f"((d)[3]) \
        : "r"((a)[0]), "r"((a)[1]), "r"((a)[2]), "r"((a)[3]), "r"(b0), "r"(b1))

// ================= scratch (device globals) =================
__device__ float g_x[BLq*Dq];
__device__ float g_q[BLq*Dq];
__device__ float g_t[BLq*Dq];
__device__ __align__(256) __half g_xh[BLq*Dq];
__device__ __align__(256) __half g_Xh[4096*Dq], g_Xl[4096*Dq];
__device__ __align__(256) __half g_yh[BLq*DFF];
__device__ __align__(256) __half g_osh[BLq*64], g_osl[BLq*64];
__device__ __align__(256) __half g_wth[2*Dq*64], g_wtl[2*Dq*64];
__device__ __align__(256) __half g_wqh[2*Dq*Dq], g_wql[2*Dq*Dq];
__device__ __align__(256) __half g_c1h[2*DFF*Dq];
__device__ __align__(256) __half g_c2h[2*Dq*DFF];
__device__ float g_ct[Lq*MODES], g_st[Lq*MODES];
__device__ float g_mu[BLq], g_rs[BLq];
__device__ float g_cat[Bq*CATD];

// ================= small kernels =================
__global__ void init_tables() {
    int idx = blockIdx.x*blockDim.x + threadIdx.x;
    if (idx < Lq*MODES) {
        int l = idx >> 5, m = idx & 31;
        double a = (double)(m*l) / 256.0;
        double s, c;
        sincospi(a, &s, &c);
        g_ct[idx] = (float)c;
        g_st[idx] = (float)s;
    }
}

__global__ void convert_hl(const float* __restrict__ src, __half* __restrict__ h,
                           __half* __restrict__ l, int n) {
    int i = blockIdx.x*256 + threadIdx.x;
    if (i < n) {
        float v = src[i];
        __half hv = __float2half_rn(v);
        h[i] = hv;
        if (l) l[i] = __float2half_rn(v - __half2float(hv));
    }
}

__global__ void embed_kernel(const int* __restrict__ app, const float* __restrict__ xt,
                             const float* __restrict__ emb, const float* __restrict__ tw,
                             const float* __restrict__ tb) {
    size_t idx = (size_t)blockIdx.x*256 + threadIdx.x;
    int d = (int)(idx & 511);
    size_t bl = idx >> 9;
    int a = app[bl];
    g_x[idx] = emb[(size_t)a*Dq + d] + xt[bl]*tw[d] + tb[d];
}

// ========== Wo frequency table ==========
__global__ void __launch_bounds__(128) wotab_kernel(const float* __restrict__ Wo,
                                                    __half* __restrict__ wth,
                                                    __half* __restrict__ wtl) {
    int layer = blockIdx.y;
    int j0 = blockIdx.x * 4;
    __shared__ float sw[4][512];
    int t = threadIdx.x;
    const float* wo = Wo + (size_t)layer*Dq*Dq + (size_t)j0*Dq;
    #pragma unroll
    for (int j = 0; j < 4; j++) {
        int v = t + j*128;
        int r = v >> 7, c4 = (v & 127) * 4;
        *(float4*)&sw[r][c4] = *(const float4*)&wo[(size_t)r*Dq + c4];
    }
    __syncthreads();
    int tj = t >> 5, tm = t & 31;
    float ac = 0.f, as = 0.f;
    for (int l = 0; l < Lq; l++) {
        float w = sw[tj][l];
        ac = fmaf(w, g_ct[l*32 + tm], ac);
        as = fmaf(w, g_st[l*32 + tm], as);
    }
    float cm = (tm == 0 ? 1.0f : 2.0f) * (256.0f/512.0f);
    float vc = ac*cm, vs = -as*cm;
    size_t base = ((size_t)layer*Dq + j0 + tj)*64 + tm*2;
    __half hc = __float2half_rn(vc);
    __half hs = __float2half_rn(vs);
    wth[base]   = hc;  wtl[base]   = __float2half_rn(vc - __half2float(hc));
    wth[base+1] = hs;  wtl[base+1] = __float2half_rn(vs - __half2float(hs));
}

// ================= mma.sync fp16 GEMM: C = A(MxK) @ B(NxK)^T =============
// TERMS==3: Ah*Bh + Ah*Bl + Al*Bh.  TERMS==2: Ah*(Bh+Bl).  TERMS==1: Ah*Bh.
#define GF_BIAS 1
#define GF_RES  2
#define GF_RELU 4
#define GF_OUTF32 8
#define GF_OUTH16 16

#define STG 32768
#define SMEM_GEMM (3*STG + 256)

template<int FLAGS, int TERMS>
__global__ void __launch_bounds__(256, 1) gemm_mma(
    const __half* __restrict__ Ah, const __half* __restrict__ Al,
    const __half* __restrict__ Bh, const __half* __restrict__ Bl,
    const float* __restrict__ bias, const float* __restrict__ res,
    float* __restrict__ Cf, __half* __restrict__ Ch,
    int M, int N, int K, float scal)
{
    extern __shared__ char dsm[];
    uint32_t sbase = (smem_u32(dsm) + 127) & ~127u;

    const int t = threadIdx.x;
    const int lane = t & 31;
    const int wid = t >> 5;
    const int wm = wid >> 2;
    const int wn = wid & 3;
    const int bm = blockIdx.y * 128, bn = blockIdx.x * 128;
    const int NC = K >> 5;

    float acc[4][4][4] = {};

    const int lrow = t >> 2;
    const int lcell = t & 3;
    auto load_chunk = [&](int c, int stg) {
        uint32_t sb = sbase + stg*STG;
        size_t k0 = (size_t)c * 32 + lcell*8;
        #pragma unroll
        for (int j = 0; j < 2; j++) {
            int row = lrow + j*64;
            uint32_t soff = row*64 + (((uint32_t)(lcell ^ (row & 3))) << 4);
            size_t ga = (size_t)(bm + row)*K + k0;
            size_t gb = (size_t)(bn + row)*K + k0;
            cp16(sb +         soff, Ah + ga);
            if (TERMS == 3) cp16(sb + 8192 + soff, Al + ga);
            cp16(sb + 16384 + soff, Bh + gb);
            if (TERMS >= 2) cp16(sb + 24576 + soff, Bl + gb);
        }
        CP_COMMIT();
    };

    load_chunk(0, 0);
    if (NC > 1) load_chunk(1, 1);

    const int arow_base = wm*64 + (lane & 15);
    const int brow_base = wn*32 + (lane & 15);
    const int kc_hi = lane >> 4;

    for (int c = 0; c < NC; c++) {
        if (c + 2 < NC) asm volatile("cp.async.wait_group 1;" ::: "memory");
        else            asm volatile("cp.async.wait_group 0;" ::: "memory");
        __syncthreads();
        if (c + 2 < NC) load_chunk(c + 2, (c + 2) % 3);

        uint32_t sb = sbase + (c % 3)*STG;
        #pragma unroll
        for (int s = 0; s < 2; s++) {
            uint32_t ah[4][4], al[4][4], bh[2][4], bl[2][4];
            int chunk = s*2 + kc_hi;
            #pragma unroll
            for (int mt = 0; mt < 4; mt++) {
                int row = arow_base + mt*16;
                uint32_t off = row*64 + (((uint32_t)(chunk ^ (row & 3))) << 4);
                LDSM_X4(ah[mt][0], ah[mt][1], ah[mt][2], ah[mt][3], sb + off);
                if (TERMS == 3)
                    LDSM_X4(al[mt][0], al[mt][1], al[mt][2], al[mt][3], sb + 8192 + off);
            }
            #pragma unroll
            for (int g = 0; g < 2; g++) {
                int row = brow_base + g*16;
                uint32_t off = row*64 + (((uint32_t)(chunk ^ (row & 3))) << 4);
                LDSM_X4(bh[g][0], bh[g][1], bh[g][2], bh[g][3], sb + 16384 + off);
                if (TERMS >= 2)
                    LDSM_X4(bl[g][0], bl[g][1], bl[g][2], bl[g][3], sb + 24576 + off);
            }
            #pragma unroll
            for (int mt = 0; mt < 4; mt++) {
                #pragma unroll
                for (int nt = 0; nt < 4; nt++) {
                    int g = nt >> 1, o = nt & 1;
                    MMA_F32(acc[mt][nt], ah[mt], bh[g][o], bh[g][o+2]);
                    if (TERMS >= 2)
                        MMA_F32(acc[mt][nt], ah[mt], bl[g][o], bl[g][o+2]);
                    if (TERMS == 3)
                        MMA_F32(acc[mt][nt], al[mt], bh[g][o], bh[g][o+2]);
                }
            }
        }
    }

    int r0 = bm + wm*64 + (lane >> 2);
    int c0 = bn + wn*32 + (lane & 3)*2;
    #pragma unroll
    for (int mt = 0; mt < 4; mt++) {
        #pragma unroll
        for (int nt = 0; nt < 4; nt++) {
            int col = c0 + nt*8;
            float b0 = 0.f, b1 = 0.f;
            if (FLAGS & GF_BIAS) { b0 = bias[col]; b1 = bias[col+1]; }
            #pragma unroll
            for (int half = 0; half < 2; half++) {
                int row = r0 + mt*16 + half*8;
                float v0 = acc[mt][nt][half*2+0] * scal + b0;
                float v1 = acc[mt][nt][half*2+1] * scal + b1;
                size_t ro = (size_t)row * N + col;
                if (FLAGS & GF_RES) {
                    float2 r2 = *(const float2*)&res[ro];
                    v0 += r2.x; v1 += r2.y;
                }
                if (FLAGS & GF_RELU) { v0 = fmaxf(v0, 0.f); v1 = fmaxf(v1, 0.f); }
                if (FLAGS & GF_OUTF32) {
                    float2 o2; o2.x = v0; o2.y = v1;
                    *(float2*)&Cf[ro] = o2;
                }
                if (FLAGS & GF_OUTH16) {
                    __half2 hp; hp.x = __float2half_rn(v0); hp.y = __float2half_rn(v1);
                    *(__half2*)&Ch[ro] = hp;
                }
            }
        }
    }
}

// ========== DFT of x ==========
__global__ void __launch_bounds__(128) dftx_kernel(const float* __restrict__ x,
                                                   __half* __restrict__ Xh,
                                                   __half* __restrict__ Xl) {
    int blk = blockIdx.x;
    int b = blk >> 2;
    int dchunk = (blk & 3) * 128;
    __shared__ float sq[32][132];
    __shared__ float sct[32][32];
    __shared__ float sst[32][32];
    int t = threadIdx.x;
    int sub = t >> 6;
    int tl = t & 63;
    int i0 = (tl >> 2) * 4;
    int mb = (tl & 3) * 8;

    float ar[4][8] = {}, ai[4][8] = {};
    const float* qbase = x + (size_t)b*Lq*Dq + dchunk;

    for (int l0 = 0; l0 < Lq; l0 += 32) {
        #pragma unroll
        for (int j = 0; j < 8; j++) {
            int v = t + j*128;
            int ll = v >> 5;
            int c4 = (v & 31) * 4;
            *(float4*)&sq[ll][c4] = *(const float4*)&qbase[(size_t)(l0+ll)*Dq + c4];
        }
        #pragma unroll
        for (int j = 0; j < 2; j++) {
            int v = t + j*128;
            int ll = v >> 3;
            int c4 = (v & 7) * 4;
            *(float4*)&sct[ll][c4] = *(const float4*)&g_ct[(l0+ll)*32 + c4];
            *(float4*)&sst[ll][c4] = *(const float4*)&g_st[(l0+ll)*32 + c4];
        }
        __syncthreads();
        #pragma unroll 2
        for (int ll = 0; ll < 32; ll++) {
            float c[8], s[8];
            *(float4*)&c[0] = *(float4*)&sct[ll][mb];
            *(float4*)&c[4] = *(float4*)&sct[ll][mb+4];
            *(float4*)&s[0] = *(float4*)&sst[ll][mb];
            *(float4*)&s[4] = *(float4*)&sst[ll][mb+4];
            float qv[4];
            #pragma unroll
            for (int j = 0; j < 4; j++) qv[j] = sq[ll][sub*64 + i0 + j];
            #pragma unroll
            for (int j = 0; j < 4; j++)
                #pragma unroll
                for (int mm = 0; mm < 8; mm++) {
                    ar[j][mm] = fmaf(qv[j],  c[mm], ar[j][mm]);
                    ai[j][mm] = fmaf(-qv[j], s[mm], ai[j][mm]);
                }
        }
        __syncthreads();
    }
    int d0 = dchunk + sub*64 + i0;
    #pragma unroll
    for (int mm = 0; mm < 8; mm++) {
        int m = mb + mm;
        size_t rowr = ((size_t)(m*2+0)*64 + b)*Dq + d0;
        size_t rowi = ((size_t)(m*2+1)*64 + b)*Dq + d0;
        __half hr[4], lr[4], hi_[4], li[4];
        #pragma unroll
        for (int j = 0; j < 4; j++) {
            float vr = ar[j][mm], vi = ai[j][mm];
            hr[j] = __float2half_rn(vr);  lr[j] = __float2half_rn(vr - __half2float(hr[j]));
            hi_[j] = __float2half_rn(vi); li[j] = __float2half_rn(vi - __half2float(hi_[j]));
        }
        __half2 p;
        p.x = hr[0]; p.y = hr[1];  *(__half2*)&Xh[rowr]   = p;
        p.x = hr[2]; p.y = hr[3];  *(__half2*)&Xh[rowr+2] = p;
        p.x = lr[0]; p.y = lr[1];  *(__half2*)&Xl[rowr]   = p;
        p.x = lr[2]; p.y = lr[3];  *(__half2*)&Xl[rowr+2] = p;
        p.x = hi_[0]; p.y = hi_[1]; *(__half2*)&Xh[rowi]   = p;
        p.x = hi_[2]; p.y = hi_[3]; *(__half2*)&Xh[rowi+2] = p;
        p.x = li[0]; p.y = li[1];  *(__half2*)&Xl[rowi]   = p;
        p.x = li[2]; p.y = li[3];  *(__half2*)&Xl[rowi+2] = p;
    }
}

// ========== complex mode mix ==========
__global__ void __launch_bounds__(256) mix2_kernel(const float* __restrict__ xs,
                                                   const float* __restrict__ wr,
                                                   const float* __restrict__ wi,
                                                   const float* __restrict__ bq,
                                                   __half* __restrict__ osh,
                                                   __half* __restrict__ osl) {
    int bh = blockIdx.x;
    int b = bh >> 3, h = bh & 7;
    __shared__ float sxr[64][36];
    __shared__ float sxi[64][36];
    int t = threadIdx.x;
    #pragma unroll
    for (int j = 0; j < 8; j++) {
        int v = t + j*256;
        int ii = v & 63;
        int mm = v >> 6;
        float vr = xs[((size_t)(mm*2+0)*64 + b)*Dq + h*64 + ii];
        float vi = xs[((size_t)(mm*2+1)*64 + b)*Dq + h*64 + ii];
        if (mm == 0) vr += 512.0f * bq[h*64 + ii];
        sxr[ii][mm] = vr;
        sxi[ii][mm] = vi;
    }
    __syncthreads();
    int o  = t >> 2;
    int mb = (t & 3) * 8;
    float orr[8] = {}, oii[8] = {};
    for (int i = 0; i < 64; i++) {
        float xr[8], xi[8], w0[8], w1[8];
        *(float4*)&xr[0] = *(float4*)&sxr[i][mb];
        *(float4*)&xr[4] = *(float4*)&sxr[i][mb+4];
        *(float4*)&xi[0] = *(float4*)&sxi[i][mb];
        *(float4*)&xi[4] = *(float4*)&sxi[i][mb+4];
        size_t woff = (((size_t)h*64 + i)*64 + o)*32 + mb;
        *(float4*)&w0[0] = *(const float4*)&wr[woff];
        *(float4*)&w0[4] = *(const float4*)&wr[woff+4];
        *(float4*)&w1[0] = *(const float4*)&wi[woff];
        *(float4*)&w1[4] = *(const float4*)&wi[woff+4];
        #pragma unroll
        for (int mm = 0; mm < 8; mm++) {
            orr[mm] = fmaf(xr[mm], w0[mm], orr[mm]);
            orr[mm] = fmaf(-xi[mm], w1[mm], orr[mm]);
            oii[mm] = fmaf(xr[mm], w1[mm], oii[mm]);
            oii[mm] = fmaf(xi[mm], w0[mm], oii[mm]);
        }
    }
    size_t rbase = ((size_t)b*512 + h*64 + o)*64 + mb*2;
    #pragma unroll
    for (int mm = 0; mm < 8; mm++) {
        float vr = orr[mm] * 256.0f;
        float vi = oii[mm] * 256.0f;
        __half hr = __float2half_rn(vr);
        __half hi_ = __float2half_rn(vi);
        __half2 hp; hp.x = hr; hp.y = hi_;
        *(__half2*)&osh[rbase + mm*2] = hp;
        __half2 lp;
        lp.x = __float2half_rn(vr - __half2float(hr));
        lp.y = __float2half_rn(vi - __half2float(hi_));
        *(__half2*)&osl[rbase + mm*2] = lp;
    }
}

// ================= series_decomp =================
__global__ void decomp_kernel(const float* __restrict__ in, float* __restrict__ out,
                              __half* __restrict__ oh) {
    int gid = blockIdx.x*blockDim.x + threadIdx.x;
    int b = gid >> 9, d = gid & 511;
    const float* p = in + (size_t)b*Lq*Dq + d;
    size_t obase = (size_t)b*Lq*Dq + d;
    float wsum = 13.0f * p[0];
    #pragma unroll
    for (int j = 1; j <= 12; j++) wsum += p[(size_t)j*Dq];
    for (int l = 0; l < Lq; l++) {
        float xl = p[(size_t)l*Dq];
        float v = xl - wsum*(1.0f/25.0f);
        out[obase + (size_t)l*Dq] = v;
        oh[obase + (size_t)l*Dq] = __float2half_rn(v);
        int jn = l+13 > Lq-1 ? Lq-1 : l+13;
        int jo = l-12 < 0 ? 0 : l-12;
        wsum += p[(size_t)jn*Dq] - p[(size_t)jo*Dq];
    }
}

// ================= final layernorm / projection =================
__global__ void ln_rows(const float* __restrict__ x) {
    int row = blockIdx.x;
    int t = threadIdx.x;
    const float* p = x + (size_t)row*Dq;
    float v0 = p[t], v1 = p[t+256];
    __shared__ float sh[8];
    float s = v0 + v1;
    int lane = t & 31, w = t >> 5;
    #pragma unroll
    for (int o = 16; o > 0; o >>= 1) s += __shfl_down_sync(~0u, s, o);
    if (lane == 0) sh[w] = s;
    __syncthreads();
    if (t < 32) {
        float v = (t < 8) ? sh[t] : 0.f;
        #pragma unroll
        for (int o = 4; o > 0; o >>= 1) v += __shfl_down_sync(~0u, v, o);
        if (t == 0) sh[0] = v;
    }
    __syncthreads();
    float mu = sh[0] * (1.0f/512.0f);
    __syncthreads();
    float d0 = v0 - mu, d1 = v1 - mu;
    s = d0*d0 + d1*d1;
    #pragma unroll
    for (int o = 16; o > 0; o >>= 1) s += __shfl_down_sync(~0u, s, o);
    if (lane == 0) sh[w] = s;
    __syncthreads();
    if (t < 32) {
        float v = (t < 8) ? sh[t] : 0.f;
        #pragma unroll
        for (int o = 4; o > 0; o >>= 1) v += __shfl_down_sync(~0u, v, o);
        if (t == 0) {
            float var = v * (1.0f/512.0f);
            g_mu[row] = mu;
            g_rs[row] = rsqrtf(var + 1e-5f);
        }
    }
}

__global__ void ln_cols(const float* __restrict__ x, const float* __restrict__ nw,
                        const float* __restrict__ nb, const float* __restrict__ tv) {
    int b = blockIdx.x;
    int d = threadIdx.x;
    float w = nw[d], bb = nb[d];
    float sum = 0.f, lastv = 0.f;
    for (int l = 0; l < Lq; l++) {
        int row = b*Lq + l;
        float v = (x[(size_t)row*Dq + d] - g_mu[row]) * g_rs[row] * w + bb;
        sum += v;
        if (l == Lq-1) lastv = v;
    }
    g_cat[b*CATD + d] = lastv - sum*(1.0f/512.0f);
    if (d < 24) g_cat[b*CATD + 512 + d] = tv[((size_t)b*Lq + (Lq-1))*24 + d];
}

__global__ void __launch_bounds__(256) proj_kernel(const float* __restrict__ pw,
                                                   const float* __restrict__ pb,
                                                   float* __restrict__ out) {
    __shared__ float As[8][65];
    __shared__ float Bs[8][65];
    int n0 = blockIdx.x * 64;
    int t = threadIdx.x;
    int tx = t & 15, ty = t >> 4;
    float acc[4][4] = {};
    for (int k0 = 0; k0 < CATD; k0 += 8) {
        int v = t*2;
        int r = v >> 3, c = v & 7;
        As[c][r]   = g_cat[r*CATD + k0 + c];
        As[c+1][r] = g_cat[r*CATD + k0 + c + 1];
        int n = n0 + r;
        float f0 = 0.f, f1 = 0.f;
        if (n < NUM_APP) {
            f0 = pw[(size_t)n*CATD + k0 + c];
            f1 = pw[(size_t)n*CATD + k0 + c + 1];
        }
        Bs[c][r] = f0; Bs[c+1][r] = f1;
        __syncthreads();
        #pragma unroll
        for (int k = 0; k < 8; k++) {
            float a[4], bv[4];
            #pragma unroll
            for (int i = 0; i < 4; i++) { a[i] = As[k][ty*4+i]; bv[i] = Bs[k][tx*4+i]; }
            #pragma unroll
            for (int i = 0; i < 4; i++)
                #pragma unroll
                for (int j = 0; j < 4; j++)
                    acc[i][j] = fmaf(a[i], bv[j], acc[i][j]);
        }
        __syncthreads();
    }
    #pragma unroll
    for (int i = 0; i < 4; i++) {
        int bi = ty*4 + i;
        #pragma unroll
        for (int j = 0; j < 4; j++) {
            int n = n0 + tx*4 + j;
            if (n < NUM_APP) out[(size_t)bi*NUM_APP + n] = acc[i][j] + pb[n];
        }
    }
}

// ================= host orchestration =================
extern "C" void kernel_launch(void* const* d_in, const int* in_sizes, int n_in,
                              void* d_out, int out_size) {
    const int*   x_app     = (const int*)  d_in[0];
    const float* x_time    = (const float*)d_in[1];
    const float* time_vecs = (const float*)d_in[2];
    const float* app_emb_w = (const float*)d_in[4];
    const float* time_w    = (const float*)d_in[5];
    const float* time_b    = (const float*)d_in[6];
    const float* Wq        = (const float*)d_in[7];
    const float* bq        = (const float*)d_in[8];
    const float* Wo        = (const float*)d_in[9];
    const float* bo        = (const float*)d_in[10];
    const float* four_wr   = (const float*)d_in[11];
    const float* four_wi   = (const float*)d_in[12];
    const float* conv1_w   = (const float*)d_in[13];
    const float* conv2_w   = (const float*)d_in[14];
    const float* norm_w    = (const float*)d_in[15];
    const float* norm_b    = (const float*)d_in[16];
    const float* proj_w    = (const float*)d_in[17];
    const float* proj_b    = (const float*)d_in[18];
    float* out = (float*)d_out;

    cudaFuncSetAttribute((const void*)gemm_mma<GF_OUTF32, 3>,                cudaFuncAttributeMaxDynamicSharedMemorySize, SMEM_GEMM);
    cudaFuncSetAttribute((const void*)gemm_mma<GF_BIAS|GF_RES|GF_OUTF32, 3>, cudaFuncAttributeMaxDynamicSharedMemorySize, SMEM_GEMM);
    cudaFuncSetAttribute((const void*)gemm_mma<GF_RELU|GF_OUTH16, 1>,        cudaFuncAttributeMaxDynamicSharedMemorySize, SMEM_GEMM);
    cudaFuncSetAttribute((const void*)gemm_mma<GF_RES|GF_OUTF32, 1>,         cudaFuncAttributeMaxDynamicSharedMemorySize, SMEM_GEMM);

    void *px, *pq, *pt;
    void *pxh, *pXh, *pXl, *pyh, *posh, *posl, *pwth, *pwtl;
    void *pwqh, *pwql, *pc1h, *pc2h;
    cudaGetSymbolAddress(&px, g_x);
    cudaGetSymbolAddress(&pq, g_q);
    cudaGetSymbolAddress(&pt, g_t);
    cudaGetSymbolAddress(&pxh, g_xh);
    cudaGetSymbolAddress(&pXh, g_Xh); cudaGetSymbolAddress(&pXl, g_Xl);
    cudaGetSymbolAddress(&pyh, g_yh);
    cudaGetSymbolAddress(&posh, g_osh); cudaGetSymbolAddress(&posl, g_osl);
    cudaGetSymbolAddress(&pwth, g_wth); cudaGetSymbolAddress(&pwtl, g_wtl);
    cudaGetSymbolAddress(&pwqh, g_wqh); cudaGetSymbolAddress(&pwql, g_wql);
    cudaGetSymbolAddress(&pc1h, g_c1h);
    cudaGetSymbolAddress(&pc2h, g_c2h);
    float* fx = (float*)px;
    float* fq = (float*)pq;
    float* ft = (float*)pt;
    __half *xh=(__half*)pxh;
    __half *Xh=(__half*)pXh, *Xl=(__half*)pXl;
    __half *yh=(__half*)pyh;
    __half *osh=(__half*)posh, *osl=(__half*)posl;
    __half *wth=(__half*)pwth, *wtl=(__half*)pwtl;
    __half *wqh=(__half*)pwqh, *wql=(__half*)pwql;
    __half *c1h=(__half*)pc1h;
    __half *c2h=(__half*)pc2h;

    init_tables<<<64, 256>>>();
    convert_hl<<<(2*Dq*Dq + 255)/256, 256>>>(Wq, wqh, wql, 2*Dq*Dq);
    convert_hl<<<(2*DFF*Dq + 255)/256, 256>>>(conv1_w, c1h, nullptr, 2*DFF*Dq);
    convert_hl<<<(2*Dq*DFF + 255)/256, 256>>>(conv2_w, c2h, nullptr, 2*Dq*DFF);
    wotab_kernel<<<dim3(128, 2), 128>>>(Wo, wth, wtl);
    embed_kernel<<<BLq*Dq/256, 256>>>(x_app, x_time, app_emb_w, time_w, time_b);

    const int M = BLq;
    for (int l = 0; l < 2; l++) {
        size_t woff = (size_t)l*Dq*Dq;
        size_t coff1 = (size_t)l*DFF*Dq;

        // X = DFT_l(x)
        dftx_kernel<<<256, 128>>>(fx, Xh, Xl);
        // xs = X @ Wq^T  (4096 x 512 x 512), 3-term
        gemm_mma<GF_OUTF32, 3><<<dim3(4, 32), 256, SMEM_GEMM>>>(
            Xh, Xl, wqh + woff, wql + woff, nullptr, nullptr,
            fq, nullptr, 4096, Dq, Dq, 1.0f);
        // os = mode mix (+ bq into mode 0)
        mix2_kernel<<<Bq*Hq, 256>>>(fq, four_wr + (size_t)l*Hq*Eq*Eq*MODES,
                                    four_wi + (size_t)l*Hq*Eq*Eq*MODES,
                                    bq + l*Dq, osh, osl);
        // new_x = os @ WoT^T * (1/65536) + bo + x, 3-term
        gemm_mma<GF_BIAS|GF_RES|GF_OUTF32, 3><<<dim3(4, 256), 256, SMEM_GEMM>>>(
            osh, osl, wth + (size_t)l*Dq*64, wtl + (size_t)l*Dq*64, bo + l*Dq, fx,
            ft, nullptr, M, Dq, 64, 1.0f/65536.0f);
        decomp_kernel<<<Bq*Dq/256, 256>>>(ft, fx, xh);
        // y = relu(x @ c1^T), 1-term pure fp16
        gemm_mma<GF_RELU|GF_OUTH16, 1><<<dim3(DFF/128, M/128), 256, SMEM_GEMM>>>(
            xh, nullptr, c1h + coff1, nullptr, nullptr, nullptr,
            nullptr, yh, M, DFF, Dq, 1.0f);
        // t = y @ c2^T + x, 1-term pure fp16
        gemm_mma<GF_RES|GF_OUTF32, 1><<<dim3(Dq/128, M/128), 256, SMEM_GEMM>>>(
            yh, nullptr, c2h + coff1, nullptr, nullptr, fx,
            ft, nullptr, M, Dq, DFF, 1.0f);
        decomp_kernel<<<Bq*Dq/256, 256>>>(ft, fx, xh);
    }

    ln_rows<<<BLq, 256>>>(fx);
    ln_cols<<<Bq, 512>>>(fx, norm_w, norm_b, time_vecs);
    proj_kernel<<<(NUM_APP + 63)/64, 256>>>(proj_w, proj_b, out);
}

// round 8
// speedup vs baseline: 3.7828x; 1.0060x over previous
#include <cuda_runtime.h>
#include <cuda_fp16.h>
#include <math.h>
#include <stdint.h>

#define Bq 64
#define Lq 512
#define Dq 512
#define Hq 8
#define Eq 64
#define DFF 2048
#define MODES 32
#define VOCAB 10000
#define NUM_APP 10000
#define CATD 536
#define BLq (Bq*Lq)

// ================= helpers =================
__device__ __forceinline__ uint32_t smem_u32(const void* p) {
    uint32_t a;
    asm("{ .reg .u64 t; cvta.to.shared.u64 t, %1; cvt.u32.u64 %0, t; }" : "=r"(a) : "l"(p));
    return a;
}
__device__ __forceinline__ void cp16(uint32_t dst, const void* src) {
    asm volatile("cp.async.cg.shared.global [%0], [%1], 16;" :: "r"(dst), "l"(src) : "memory");
}
#define CP_COMMIT() asm volatile("cp.async.commit_group;" ::: "memory")

#define LDSM_X4(r0,r1,r2,r3, addr) \
    asm volatile("ldmatrix.sync.aligned.m8n8.x4.shared.b16 {%0,%1,%2,%3}, [%4];" \
        : "=r"(r0), "=r"(r1), "=r"(r2), "=r"(r3) : "r"(addr))

#define MMA_F32(d, a, b0, b1) \
    asm volatile("mma.sync.aligned.m16n8k16.row.col.f32.f16.f16.f32 " \
        "{%0,%1,%2,%3},{%4,%5,%6,%7},{%8,%9},{%0,%1,%2,%3};" \
        : "+f"((d)[0]), "+f"((d)[1]), "+f"((d)[2]), "+f"((d)[3]) \
        : "r"((a)[0]), "r"((a)[1]), "r"((a)[2]), "r"((a)[3]), "r"(b0), "r"(b1))

// ================= scratch (device globals) =================
__device__ float g_x[BLq*Dq];
__device__ float g_q[BLq*Dq];
__device__ float g_t[BLq*Dq];
__device__ __align__(256) __half g_xh[BLq*Dq];
__device__ __align__(256) __half g_Xh[4096*Dq], g_Xl[4096*Dq];
__device__ __align__(256) __half g_yh[BLq*DFF];
__device__ __align__(256) __half g_osh[BLq*64], g_osl[BLq*64];
__device__ __align__(256) __half g_wth[2*Dq*64], g_wtl[2*Dq*64];
__device__ __align__(256) __half g_wqh[2*Dq*Dq], g_wql[2*Dq*Dq];
__device__ __align__(256) __half g_c1h[2*DFF*Dq];
__device__ __align__(256) __half g_c2h[2*Dq*DFF];
__device__ float g_wtr[2*Hq*MODES*Eq*Eq];   // transposed four_wr: [l][h][m][i][o]
__device__ float g_wti[2*Hq*MODES*Eq*Eq];
__device__ float g_ct[Lq*MODES], g_st[Lq*MODES];
__device__ float g_mu[BLq], g_rs[BLq];
__device__ float g_cat[Bq*CATD];

// ================= small kernels =================
__global__ void init_tables() {
    int idx = blockIdx.x*blockDim.x + threadIdx.x;
    if (idx < Lq*MODES) {
        int l = idx >> 5, m = idx & 31;
        double a = (double)(m*l) / 256.0;
        double s, c;
        sincospi(a, &s, &c);
        g_ct[idx] = (float)c;
        g_st[idx] = (float)s;
    }
}

__global__ void convert_hl(const float* __restrict__ src, __half* __restrict__ h,
                           __half* __restrict__ l, int n) {
    int i = blockIdx.x*256 + threadIdx.x;
    if (i < n) {
        float v = src[i];
        __half hv = __float2half_rn(v);
        h[i] = hv;
        if (l) l[i] = __float2half_rn(v - __half2float(hv));
    }
}

__global__ void embed_kernel(const int* __restrict__ app, const float* __restrict__ xt,
                             const float* __restrict__ emb, const float* __restrict__ tw,
                             const float* __restrict__ tb) {
    size_t idx = (size_t)blockIdx.x*256 + threadIdx.x;
    int d = (int)(idx & 511);
    size_t bl = idx >> 9;
    int a = app[bl];
    g_x[idx] = emb[(size_t)a*Dq + d] + xt[bl]*tw[d] + tb[d];
}

// ========== transpose four_wr/wi: [l][h][i][o][m] -> [l][h][m][i][o] ==========
__global__ void __launch_bounds__(256) wtrans_kernel(const float* __restrict__ wr,
                                                     const float* __restrict__ wi) {
    int blk = blockIdx.x;          // (l*8+h)*64 + i
    int i  = blk & 63;
    int lh = blk >> 6;
    __shared__ float tr[64][33], ti_[64][33];   // [o][m]
    int t = threadIdx.x;
    const float* pr = wr + ((size_t)lh*64 + i)*64*32;
    const float* pi = wi + ((size_t)lh*64 + i)*64*32;
    #pragma unroll
    for (int j = 0; j < 8; j++) {
        int v = t + j*256;
        int o = v >> 5, m = v & 31;
        tr[o][m]  = pr[v];
        ti_[o][m] = pi[v];
    }
    __syncthreads();
    #pragma unroll
    for (int j = 0; j < 8; j++) {
        int v = t + j*256;
        int m = v >> 6, o = v & 63;
        size_t dst = ((size_t)(lh*32 + m)*64 + i)*64 + o;
        g_wtr[dst] = tr[o][m];
        g_wti[dst] = ti_[o][m];
    }
}

// ========== Wo frequency table ==========
__global__ void __launch_bounds__(128) wotab_kernel(const float* __restrict__ Wo,
                                                    __half* __restrict__ wth,
                                                    __half* __restrict__ wtl) {
    int layer = blockIdx.y;
    int j0 = blockIdx.x * 4;
    __shared__ float sw[4][512];
    int t = threadIdx.x;
    const float* wo = Wo + (size_t)layer*Dq*Dq + (size_t)j0*Dq;
    #pragma unroll
    for (int j = 0; j < 4; j++) {
        int v = t + j*128;
        int r = v >> 7, c4 = (v & 127) * 4;
        *(float4*)&sw[r][c4] = *(const float4*)&wo[(size_t)r*Dq + c4];
    }
    __syncthreads();
    int tj = t >> 5, tm = t & 31;
    float ac = 0.f, as = 0.f;
    for (int l = 0; l < Lq; l++) {
        float w = sw[tj][l];
        ac = fmaf(w, g_ct[l*32 + tm], ac);
        as = fmaf(w, g_st[l*32 + tm], as);
    }
    float cm = (tm == 0 ? 1.0f : 2.0f) * (256.0f/512.0f);
    float vc = ac*cm, vs = -as*cm;
    size_t base = ((size_t)layer*Dq + j0 + tj)*64 + tm*2;
    __half hc = __float2half_rn(vc);
    __half hs = __float2half_rn(vs);
    wth[base]   = hc;  wtl[base]   = __float2half_rn(vc - __half2float(hc));
    wth[base+1] = hs;  wtl[base+1] = __float2half_rn(vs - __half2float(hs));
}

// ================= mma.sync fp16 GEMM: C = A(MxK) @ B(NxK)^T =============
#define GF_BIAS 1
#define GF_RES  2
#define GF_RELU 4
#define GF_OUTF32 8
#define GF_OUTH16 16

#define STG 32768
#define SMEM_GEMM (3*STG + 256)

template<int FLAGS, int TERMS>
__global__ void __launch_bounds__(256, 1) gemm_mma(
    const __half* __restrict__ Ah, const __half* __restrict__ Al,
    const __half* __restrict__ Bh, const __half* __restrict__ Bl,
    const float* __restrict__ bias, const float* __restrict__ res,
    float* __restrict__ Cf, __half* __restrict__ Ch,
    int M, int N, int K, float scal)
{
    extern __shared__ char dsm[];
    uint32_t sbase = (smem_u32(dsm) + 127) & ~127u;

    const int t = threadIdx.x;
    const int lane = t & 31;
    const int wid = t >> 5;
    const int wm = wid >> 2;
    const int wn = wid & 3;
    const int bm = blockIdx.y * 128, bn = blockIdx.x * 128;
    const int NC = K >> 5;

    float acc[4][4][4] = {};

    const int lrow = t >> 2;
    const int lcell = t & 3;
    auto load_chunk = [&](int c, int stg) {
        uint32_t sb = sbase + stg*STG;
        size_t k0 = (size_t)c * 32 + lcell*8;
        #pragma unroll
        for (int j = 0; j < 2; j++) {
            int row = lrow + j*64;
            uint32_t soff = row*64 + (((uint32_t)(lcell ^ (row & 3))) << 4);
            size_t ga = (size_t)(bm + row)*K + k0;
            size_t gb = (size_t)(bn + row)*K + k0;
            cp16(sb +         soff, Ah + ga);
            if (TERMS == 3) cp16(sb + 8192 + soff, Al + ga);
            cp16(sb + 16384 + soff, Bh + gb);
            if (TERMS >= 2) cp16(sb + 24576 + soff, Bl + gb);
        }
        CP_COMMIT();
    };

    load_chunk(0, 0);
    if (NC > 1) load_chunk(1, 1);

    const int arow_base = wm*64 + (lane & 15);
    const int brow_base = wn*32 + (lane & 15);
    const int kc_hi = lane >> 4;

    for (int c = 0; c < NC; c++) {
        if (c + 2 < NC) asm volatile("cp.async.wait_group 1;" ::: "memory");
        else            asm volatile("cp.async.wait_group 0;" ::: "memory");
        __syncthreads();
        if (c + 2 < NC) load_chunk(c + 2, (c + 2) % 3);

        uint32_t sb = sbase + (c % 3)*STG;
        #pragma unroll
        for (int s = 0; s < 2; s++) {
            uint32_t ah[4][4], al[4][4], bh[2][4], bl[2][4];
            int chunk = s*2 + kc_hi;
            #pragma unroll
            for (int mt = 0; mt < 4; mt++) {
                int row = arow_base + mt*16;
                uint32_t off = row*64 + (((uint32_t)(chunk ^ (row & 3))) << 4);
                LDSM_X4(ah[mt][0], ah[mt][1], ah[mt][2], ah[mt][3], sb + off);
                if (TERMS == 3)
                    LDSM_X4(al[mt][0], al[mt][1], al[mt][2], al[mt][3], sb + 8192 + off);
            }
            #pragma unroll
            for (int g = 0; g < 2; g++) {
                int row = brow_base + g*16;
                uint32_t off = row*64 + (((uint32_t)(chunk ^ (row & 3))) << 4);
                LDSM_X4(bh[g][0], bh[g][1], bh[g][2], bh[g][3], sb + 16384 + off);
                if (TERMS >= 2)
                    LDSM_X4(bl[g][0], bl[g][1], bl[g][2], bl[g][3], sb + 24576 + off);
            }
            #pragma unroll
            for (int mt = 0; mt < 4; mt++) {
                #pragma unroll
                for (int nt = 0; nt < 4; nt++) {
                    int g = nt >> 1, o = nt & 1;
                    MMA_F32(acc[mt][nt], ah[mt], bh[g][o], bh[g][o+2]);
                    if (TERMS >= 2)
                        MMA_F32(acc[mt][nt], ah[mt], bl[g][o], bl[g][o+2]);
                    if (TERMS == 3)
                        MMA_F32(acc[mt][nt], al[mt], bh[g][o], bh[g][o+2]);
                }
            }
        }
    }

    int r0 = bm + wm*64 + (lane >> 2);
    int c0 = bn + wn*32 + (lane & 3)*2;
    #pragma unroll
    for (int mt = 0; mt < 4; mt++) {
        #pragma unroll
        for (int nt = 0; nt < 4; nt++) {
            int col = c0 + nt*8;
            float b0 = 0.f, b1 = 0.f;
            if (FLAGS & GF_BIAS) { b0 = bias[col]; b1 = bias[col+1]; }
            #pragma unroll
            for (int half = 0; half < 2; half++) {
                int row = r0 + mt*16 + half*8;
                float v0 = acc[mt][nt][half*2+0] * scal + b0;
                float v1 = acc[mt][nt][half*2+1] * scal + b1;
                size_t ro = (size_t)row * N + col;
                if (FLAGS & GF_RES) {
                    float2 r2 = *(const float2*)&res[ro];
                    v0 += r2.x; v1 += r2.y;
                }
                if (FLAGS & GF_RELU) { v0 = fmaxf(v0, 0.f); v1 = fmaxf(v1, 0.f); }
                if (FLAGS & GF_OUTF32) {
                    float2 o2; o2.x = v0; o2.y = v1;
                    *(float2*)&Cf[ro] = o2;
                }
                if (FLAGS & GF_OUTH16) {
                    __half2 hp; hp.x = __float2half_rn(v0); hp.y = __float2half_rn(v1);
                    *(__half2*)&Ch[ro] = hp;
                }
            }
        }
    }
}

// ========== DFT of x: X[(2m+ri)*64+b][d], half hi/lo ==========
// grid 512 = b(64) x dchunk(8 of 64); block 128; thread = 1 d x 16 modes
__global__ void __launch_bounds__(128) dftx_kernel(const float* __restrict__ x,
                                                   __half* __restrict__ Xh,
                                                   __half* __restrict__ Xl) {
    int blk = blockIdx.x;
    int b = blk >> 3;
    int dchunk = (blk & 7) * 64;
    __shared__ float sq[32][68];
    __shared__ float sct[32][32];
    __shared__ float sst[32][32];
    int t = threadIdx.x;
    int td = t & 63;
    int tm = (t >> 6) * 16;

    float ar[16] = {}, ai[16] = {};
    const float* qbase = x + (size_t)b*Lq*Dq + dchunk;

    for (int l0 = 0; l0 < Lq; l0 += 32) {
        #pragma unroll
        for (int j = 0; j < 4; j++) {
            int v = t + j*128;              // 512 float4
            int ll = v >> 4;
            int c4 = (v & 15) * 4;
            *(float4*)&sq[ll][c4] = *(const float4*)&qbase[(size_t)(l0+ll)*Dq + c4];
        }
        #pragma unroll
        for (int j = 0; j < 2; j++) {
            int v = t + j*128;              // 256 float4 per table
            int ll = v >> 3;
            int c4 = (v & 7) * 4;
            *(float4*)&sct[ll][c4] = *(const float4*)&g_ct[(l0+ll)*32 + c4];
            *(float4*)&sst[ll][c4] = *(const float4*)&g_st[(l0+ll)*32 + c4];
        }
        __syncthreads();
        #pragma unroll 2
        for (int ll = 0; ll < 32; ll++) {
            float qv = sq[ll][td];
            float c[16], s[16];
            #pragma unroll
            for (int j = 0; j < 16; j += 4) {
                *(float4*)&c[j] = *(float4*)&sct[ll][tm+j];
                *(float4*)&s[j] = *(float4*)&sst[ll][tm+j];
            }
            #pragma unroll
            for (int mm = 0; mm < 16; mm++) {
                ar[mm] = fmaf(qv,  c[mm], ar[mm]);
                ai[mm] = fmaf(-qv, s[mm], ai[mm]);
            }
        }
        __syncthreads();
    }
    int d0 = dchunk + td;
    #pragma unroll
    for (int mm = 0; mm < 16; mm++) {
        int m = tm + mm;
        float vr = ar[mm], vi = ai[mm];
        __half hr = __float2half_rn(vr);
        __half hi_ = __float2half_rn(vi);
        size_t rowr = ((size_t)(m*2+0)*64 + b)*Dq + d0;
        size_t rowi = ((size_t)(m*2+1)*64 + b)*Dq + d0;
        Xh[rowr] = hr;   Xl[rowr] = __float2half_rn(vr - __half2float(hr));
        Xh[rowi] = hi_;  Xl[rowi] = __float2half_rn(vi - __half2float(hi_));
    }
}

// ========== complex mode mix, block = (h,m) ==========
__global__ void __launch_bounds__(256) mix2_kernel(const float* __restrict__ xs,
                                                   const float* __restrict__ wtr,
                                                   const float* __restrict__ wti,
                                                   const float* __restrict__ bq,
                                                   __half* __restrict__ osh,
                                                   __half* __restrict__ osl) {
    int h = blockIdx.x >> 5, m = blockIdx.x & 31;
    __shared__ float swr[64][64];     // [i][o]
    __shared__ float swi[64][64];
    __shared__ float sxr[64][65];     // [b][i]
    __shared__ float sxi[64][65];
    int t = threadIdx.x;
    const float* pr = wtr + ((size_t)(h*32 + m))*4096;
    const float* pi = wti + ((size_t)(h*32 + m))*4096;
    #pragma unroll
    for (int j = 0; j < 16; j++) {
        int v = t + j*256;
        int r = v >> 6, c = v & 63;
        swr[r][c] = pr[v];
        swi[r][c] = pi[v];
    }
    #pragma unroll
    for (int j = 0; j < 16; j++) {
        int v = t + j*256;
        int b = v >> 6, i = v & 63;
        if (j < 8) {
            float vr = xs[((size_t)(2*m)*64 + b)*Dq + h*64 + i];
            if (m == 0) vr += 512.0f * bq[h*64 + i];
            sxr[b][i] = vr;
        } else {
            sxi[b][i] = xs[((size_t)(2*m+1)*64 + b)*Dq + h*64 + i];
        }
    }
    __syncthreads();

    int b = t >> 2;
    int o0 = (t & 3) * 16;
    float orr[16] = {}, oii[16] = {};
    for (int i = 0; i < 64; i++) {
        float xr = sxr[b][i], xi = sxi[b][i];
        float wr4[16], wi4[16];
        #pragma unroll
        for (int j = 0; j < 16; j += 4) {
            *(float4*)&wr4[j] = *(float4*)&swr[i][o0+j];
            *(float4*)&wi4[j] = *(float4*)&swi[i][o0+j];
        }
        #pragma unroll
        for (int j = 0; j < 16; j++) {
            orr[j] = fmaf(xr, wr4[j], orr[j]);
            orr[j] = fmaf(-xi, wi4[j], orr[j]);
            oii[j] = fmaf(xr, wi4[j], oii[j]);
            oii[j] = fmaf(xi, wr4[j], oii[j]);
        }
    }
    #pragma unroll
    for (int j = 0; j < 16; j++) {
        int o = o0 + j;
        float vr = orr[j] * 256.0f;
        float vi = oii[j] * 256.0f;
        __half hr = __float2half_rn(vr);
        __half hi_ = __float2half_rn(vi);
        size_t base = ((size_t)b*512 + h*64 + o)*64 + 2*m;
        __half2 hp; hp.x = hr; hp.y = hi_;
        *(__half2*)&osh[base] = hp;
        __half2 lp;
        lp.x = __float2half_rn(vr - __half2float(hr));
        lp.y = __float2half_rn(vi - __half2float(hi_));
        *(__half2*)&osl[base] = lp;
    }
}

// ================= series_decomp =================
__global__ void decomp_kernel(const float* __restrict__ in, float* __restrict__ out,
                              __half* __restrict__ oh) {
    int gid = blockIdx.x*blockDim.x + threadIdx.x;
    int b = gid >> 9, d = gid & 511;
    const float* p = in + (size_t)b*Lq*Dq + d;
    size_t obase = (size_t)b*Lq*Dq + d;
    float wsum = 13.0f * p[0];
    #pragma unroll
    for (int j = 1; j <= 12; j++) wsum += p[(size_t)j*Dq];
    for (int l = 0; l < Lq; l++) {
        float xl = p[(size_t)l*Dq];
        float v = xl - wsum*(1.0f/25.0f);
        out[obase + (size_t)l*Dq] = v;
        oh[obase + (size_t)l*Dq] = __float2half_rn(v);
        int jn = l+13 > Lq-1 ? Lq-1 : l+13;
        int jo = l-12 < 0 ? 0 : l-12;
        wsum += p[(size_t)jn*Dq] - p[(size_t)jo*Dq];
    }
}

// ================= final layernorm / projection =================
__global__ void ln_rows(const float* __restrict__ x) {
    int row = blockIdx.x;
    int t = threadIdx.x;
    const float* p = x + (size_t)row*Dq;
    float v0 = p[t], v1 = p[t+256];
    __shared__ float sh[8];
    float s = v0 + v1;
    int lane = t & 31, w = t >> 5;
    #pragma unroll
    for (int o = 16; o > 0; o >>= 1) s += __shfl_down_sync(~0u, s, o);
    if (lane == 0) sh[w] = s;
    __syncthreads();
    if (t < 32) {
        float v = (t < 8) ? sh[t] : 0.f;
        #pragma unroll
        for (int o = 4; o > 0; o >>= 1) v += __shfl_down_sync(~0u, v, o);
        if (t == 0) sh[0] = v;
    }
    __syncthreads();
    float mu = sh[0] * (1.0f/512.0f);
    __syncthreads();
    float d0 = v0 - mu, d1 = v1 - mu;
    s = d0*d0 + d1*d1;
    #pragma unroll
    for (int o = 16; o > 0; o >>= 1) s += __shfl_down_sync(~0u, s, o);
    if (lane == 0) sh[w] = s;
    __syncthreads();
    if (t < 32) {
        float v = (t < 8) ? sh[t] : 0.f;
        #pragma unroll
        for (int o = 4; o > 0; o >>= 1) v += __shfl_down_sync(~0u, v, o);
        if (t == 0) {
            float var = v * (1.0f/512.0f);
            g_mu[row] = mu;
            g_rs[row] = rsqrtf(var + 1e-5f);
        }
    }
}

__global__ void ln_cols(const float* __restrict__ x, const float* __restrict__ nw,
                        const float* __restrict__ nb, const float* __restrict__ tv) {
    int b = blockIdx.x;
    int d = threadIdx.x;
    float w = nw[d], bb = nb[d];
    float sum = 0.f, lastv = 0.f;
    for (int l = 0; l < Lq; l++) {
        int row = b*Lq + l;
        float v = (x[(size_t)row*Dq + d] - g_mu[row]) * g_rs[row] * w + bb;
        sum += v;
        if (l == Lq-1) lastv = v;
    }
    g_cat[b*CATD + d] = lastv - sum*(1.0f/512.0f);
    if (d < 24) g_cat[b*CATD + 512 + d] = tv[((size_t)b*Lq + (Lq-1))*24 + d];
}

__global__ void __launch_bounds__(256) proj_kernel(const float* __restrict__ pw,
                                                   const float* __restrict__ pb,
                                                   float* __restrict__ out) {
    __shared__ float As[8][65];
    __shared__ float Bs[8][65];
    int n0 = blockIdx.x * 64;
    int t = threadIdx.x;
    int tx = t & 15, ty = t >> 4;
    float acc[4][4] = {};
    for (int k0 = 0; k0 < CATD; k0 += 8) {
        int v = t*2;
        int r = v >> 3, c = v & 7;
        As[c][r]   = g_cat[r*CATD + k0 + c];
        As[c+1][r] = g_cat[r*CATD + k0 + c + 1];
        int n = n0 + r;
        float f0 = 0.f, f1 = 0.f;
        if (n < NUM_APP) {
            f0 = pw[(size_t)n*CATD + k0 + c];
            f1 = pw[(size_t)n*CATD + k0 + c + 1];
        }
        Bs[c][r] = f0; Bs[c+1][r] = f1;
        __syncthreads();
        #pragma unroll
        for (int k = 0; k < 8; k++) {
            float a[4], bv[4];
            #pragma unroll
            for (int i = 0; i < 4; i++) { a[i] = As[k][ty*4+i]; bv[i] = Bs[k][tx*4+i]; }
            #pragma unroll
            for (int i = 0; i < 4; i++)
                #pragma unroll
                for (int j = 0; j < 4; j++)
                    acc[i][j] = fmaf(a[i], bv[j], acc[i][j]);
        }
        __syncthreads();
    }
    #pragma unroll
    for (int i = 0; i < 4; i++) {
        int bi = ty*4 + i;
        #pragma unroll
        for (int j = 0; j < 4; j++) {
            int n = n0 + tx*4 + j;
            if (n < NUM_APP) out[(size_t)bi*NUM_APP + n] = acc[i][j] + pb[n];
        }
    }
}

// ================= host orchestration =================
extern "C" void kernel_launch(void* const* d_in, const int* in_sizes, int n_in,
                              void* d_out, int out_size) {
    const int*   x_app     = (const int*)  d_in[0];
    const float* x_time    = (const float*)d_in[1];
    const float* time_vecs = (const float*)d_in[2];
    const float* app_emb_w = (const float*)d_in[4];
    const float* time_w    = (const float*)d_in[5];
    const float* time_b    = (const float*)d_in[6];
    const float* Wq        = (const float*)d_in[7];
    const float* bq        = (const float*)d_in[8];
    const float* Wo        = (const float*)d_in[9];
    const float* bo        = (const float*)d_in[10];
    const float* four_wr   = (const float*)d_in[11];
    const float* four_wi   = (const float*)d_in[12];
    const float* conv1_w   = (const float*)d_in[13];
    const float* conv2_w   = (const float*)d_in[14];
    const float* norm_w    = (const float*)d_in[15];
    const float* norm_b    = (const float*)d_in[16];
    const float* proj_w    = (const float*)d_in[17];
    const float* proj_b    = (const float*)d_in[18];
    float* out = (float*)d_out;

    cudaFuncSetAttribute((const void*)gemm_mma<GF_OUTF32, 3>,                cudaFuncAttributeMaxDynamicSharedMemorySize, SMEM_GEMM);
    cudaFuncSetAttribute((const void*)gemm_mma<GF_BIAS|GF_RES|GF_OUTF32, 3>, cudaFuncAttributeMaxDynamicSharedMemorySize, SMEM_GEMM);
    cudaFuncSetAttribute((const void*)gemm_mma<GF_RELU|GF_OUTH16, 1>,        cudaFuncAttributeMaxDynamicSharedMemorySize, SMEM_GEMM);
    cudaFuncSetAttribute((const void*)gemm_mma<GF_RES|GF_OUTF32, 1>,         cudaFuncAttributeMaxDynamicSharedMemorySize, SMEM_GEMM);

    void *px, *pq, *pt;
    void *pxh, *pXh, *pXl, *pyh, *posh, *posl, *pwth, *pwtl;
    void *pwqh, *pwql, *pc1h, *pc2h, *pwtr, *pwti;
    cudaGetSymbolAddress(&px, g_x);
    cudaGetSymbolAddress(&pq, g_q);
    cudaGetSymbolAddress(&pt, g_t);
    cudaGetSymbolAddress(&pxh, g_xh);
    cudaGetSymbolAddress(&pXh, g_Xh); cudaGetSymbolAddress(&pXl, g_Xl);
    cudaGetSymbolAddress(&pyh, g_yh);
    cudaGetSymbolAddress(&posh, g_osh); cudaGetSymbolAddress(&posl, g_osl);
    cudaGetSymbolAddress(&pwth, g_wth); cudaGetSymbolAddress(&pwtl, g_wtl);
    cudaGetSymbolAddress(&pwqh, g_wqh); cudaGetSymbolAddress(&pwql, g_wql);
    cudaGetSymbolAddress(&pc1h, g_c1h);
    cudaGetSymbolAddress(&pc2h, g_c2h);
    cudaGetSymbolAddress(&pwtr, g_wtr); cudaGetSymbolAddress(&pwti, g_wti);
    float* fx = (float*)px;
    float* fq = (float*)pq;
    float* ft = (float*)pt;
    __half *xh=(__half*)pxh;
    __half *Xh=(__half*)pXh, *Xl=(__half*)pXl;
    __half *yh=(__half*)pyh;
    __half *osh=(__half*)posh, *osl=(__half*)posl;
    __half *wth=(__half*)pwth, *wtl=(__half*)pwtl;
    __half *wqh=(__half*)pwqh, *wql=(__half*)pwql;
    __half *c1h=(__half*)pc1h;
    __half *c2h=(__half*)pc2h;
    float *wtr=(float*)pwtr, *wti=(float*)pwti;

    init_tables<<<64, 256>>>();
    convert_hl<<<(2*Dq*Dq + 255)/256, 256>>>(Wq, wqh, wql, 2*Dq*Dq);
    convert_hl<<<(2*DFF*Dq + 255)/256, 256>>>(conv1_w, c1h, nullptr, 2*DFF*Dq);
    convert_hl<<<(2*Dq*DFF + 255)/256, 256>>>(conv2_w, c2h, nullptr, 2*Dq*DFF);
    wotab_kernel<<<dim3(128, 2), 128>>>(Wo, wth, wtl);
    wtrans_kernel<<<1024, 256>>>(four_wr, four_wi);
    embed_kernel<<<BLq*Dq/256, 256>>>(x_app, x_time, app_emb_w, time_w, time_b);

    const int M = BLq;
    for (int l = 0; l < 2; l++) {
        size_t woff = (size_t)l*Dq*Dq;
        size_t coff1 = (size_t)l*DFF*Dq;
        size_t mixoff = (size_t)l*Hq*MODES*Eq*Eq;

        // X = DFT_l(x)
        dftx_kernel<<<512, 128>>>(fx, Xh, Xl);
        // xs = X @ Wq^T  (4096 x 512 x 512), 3-term
        gemm_mma<GF_OUTF32, 3><<<dim3(4, 32), 256, SMEM_GEMM>>>(
            Xh, Xl, wqh + woff, wql + woff, nullptr, nullptr,
            fq, nullptr, 4096, Dq, Dq, 1.0f);
        // os = mode mix (+ bq into mode 0)
        mix2_kernel<<<Hq*MODES, 256>>>(fq, wtr + mixoff, wti + mixoff,
                                       bq + l*Dq, osh, osl);
        // new_x = os @ WoT^T * (1/65536) + bo + x, 3-term
        gemm_mma<GF_BIAS|GF_RES|GF_OUTF32, 3><<<dim3(4, 256), 256, SMEM_GEMM>>>(
            osh, osl, wth + (size_t)l*Dq*64, wtl + (size_t)l*Dq*64, bo + l*Dq, fx,
            ft, nullptr, M, Dq, 64, 1.0f/65536.0f);
        decomp_kernel<<<Bq*Dq/256, 256>>>(ft, fx, xh);
        // y = relu(x @ c1^T), 1-term pure fp16
        gemm_mma<GF_RELU|GF_OUTH16, 1><<<dim3(DFF/128, M/128), 256, SMEM_GEMM>>>(
            xh, nullptr, c1h + coff1, nullptr, nullptr, nullptr,
            nullptr, yh, M, DFF, Dq, 1.0f);
        // t = y @ c2^T + x, 1-term pure fp16
        gemm_mma<GF_RES|GF_OUTF32, 1><<<dim3(Dq/128, M/128), 256, SMEM_GEMM>>>(
            yh, nullptr, c2h + coff1, nullptr, nullptr, fx,
            ft, nullptr, M, Dq, DFF, 1.0f);
        decomp_kernel<<<Bq*Dq/256, 256>>>(ft, fx, xh);
    }

    ln_rows<<<BLq, 256>>>(fx);
    ln_cols<<<Bq, 512>>>(fx, norm_w, norm_b, time_vecs);
    proj_kernel<<<(NUM_APP + 63)/64, 256>>>(proj_w, proj_b, out);
}

// round 9
// speedup vs baseline: 4.3563x; 1.1516x over previous
#include <cuda_runtime.h>
#include <cuda_fp16.h>
#include <math.h>
#include <stdint.h>

#define Bq 64
#define Lq 512
#define Dq 512
#define Hq 8
#define Eq 64
#define DFF 2048
#define MODES 32
#define VOCAB 10000
#define NUM_APP 10000
#define CATD 536
#define BLq (Bq*Lq)

// ================= helpers =================
__device__ __forceinline__ uint32_t smem_u32(const void* p) {
    uint32_t a;
    asm("{ .reg .u64 t; cvta.to.shared.u64 t, %1; cvt.u32.u64 %0, t; }" : "=r"(a) : "l"(p));
    return a;
}
__device__ __forceinline__ void cp16(uint32_t dst, const void* src) {
    asm volatile("cp.async.cg.shared.global [%0], [%1], 16;" :: "r"(dst), "l"(src) : "memory");
}
#define CP_COMMIT() asm volatile("cp.async.commit_group;" ::: "memory")

#define LDSM_X4(r0,r1,r2,r3, addr) \
    asm volatile("ldmatrix.sync.aligned.m8n8.x4.shared.b16 {%0,%1,%2,%3}, [%4];" \
        : "=r"(r0), "=r"(r1), "=r"(r2), "=r"(r3) : "r"(addr))

#define MMA_F32(d, a, b0, b1) \
    asm volatile("mma.sync.aligned.m16n8k16.row.col.f32.f16.f16.f32 " \
        "{%0,%1,%2,%3},{%4,%5,%6,%7},{%8,%9},{%0,%1,%2,%3};" \
        : "+f"((d)[0]), "+f"((d)[1]), "+f"((d)[2]), "+f"((d)[3]) \
        : "r"((a)[0]), "r"((a)[1]), "r"((a)[2]), "r"((a)[3]), "r"(b0), "r"(b1))

// ================= scratch (device globals) =================
__device__ float g_x[BLq*Dq];
__device__ float g_q[BLq*Dq];
__device__ float g_t[BLq*Dq];
__device__ __align__(256) __half g_xh[BLq*Dq];
__device__ __align__(256) __half g_Xh[4096*Dq], g_Xl[4096*Dq];
__device__ __align__(256) __half g_yh[BLq*DFF];
__device__ __align__(256) __half g_osh[BLq*64], g_osl[BLq*64];
__device__ __align__(256) __half g_wth[2*Dq*64], g_wtl[2*Dq*64];
__device__ __align__(256) __half g_wqh[2*Dq*Dq], g_wql[2*Dq*Dq];
__device__ __align__(256) __half g_c1h[2*DFF*Dq];
__device__ __align__(256) __half g_c2h[2*Dq*DFF];
__device__ float g_wtr[2*Hq*MODES*Eq*Eq];   // transposed four_wr: [l][h][m][i][o]
__device__ float g_wti[2*Hq*MODES*Eq*Eq];
__device__ float g_ct[Lq*MODES], g_st[Lq*MODES];
__device__ float g_mu[BLq], g_rs[BLq];
__device__ float g_cat[Bq*CATD];

// ================= small kernels =================
__global__ void init_tables() {
    int idx = blockIdx.x*blockDim.x + threadIdx.x;
    if (idx < Lq*MODES) {
        int l = idx >> 5, m = idx & 31;
        double a = (double)(m*l) / 256.0;
        double s, c;
        sincospi(a, &s, &c);
        g_ct[idx] = (float)c;
        g_st[idx] = (float)s;
    }
}

__global__ void convert_hl(const float* __restrict__ src, __half* __restrict__ h,
                           __half* __restrict__ l, int n) {
    int i = blockIdx.x*256 + threadIdx.x;
    if (i < n) {
        float v = src[i];
        __half hv = __float2half_rn(v);
        h[i] = hv;
        if (l) l[i] = __float2half_rn(v - __half2float(hv));
    }
}

__global__ void embed_kernel(const int* __restrict__ app, const float* __restrict__ xt,
                             const float* __restrict__ emb, const float* __restrict__ tw,
                             const float* __restrict__ tb) {
    size_t idx = (size_t)blockIdx.x*256 + threadIdx.x;
    int d = (int)(idx & 511);
    size_t bl = idx >> 9;
    int a = app[bl];
    g_x[idx] = emb[(size_t)a*Dq + d] + xt[bl]*tw[d] + tb[d];
}

// ========== transpose four_wr/wi: [l][h][i][o][m] -> [l][h][m][i][o] ==========
__global__ void __launch_bounds__(256) wtrans_kernel(const float* __restrict__ wr,
                                                     const float* __restrict__ wi) {
    int blk = blockIdx.x;
    int i  = blk & 63;
    int lh = blk >> 6;
    __shared__ float tr[64][33], ti_[64][33];
    int t = threadIdx.x;
    const float* pr = wr + ((size_t)lh*64 + i)*64*32;
    const float* pi = wi + ((size_t)lh*64 + i)*64*32;
    #pragma unroll
    for (int j = 0; j < 8; j++) {
        int v = t + j*256;
        int o = v >> 5, m = v & 31;
        tr[o][m]  = pr[v];
        ti_[o][m] = pi[v];
    }
    __syncthreads();
    #pragma unroll
    for (int j = 0; j < 8; j++) {
        int v = t + j*256;
        int m = v >> 6, o = v & 63;
        size_t dst = ((size_t)(lh*32 + m)*64 + i)*64 + o;
        g_wtr[dst] = tr[o][m];
        g_wti[dst] = ti_[o][m];
    }
}

// ========== Wo frequency table ==========
__global__ void __launch_bounds__(128) wotab_kernel(const float* __restrict__ Wo,
                                                    __half* __restrict__ wth,
                                                    __half* __restrict__ wtl) {
    int layer = blockIdx.y;
    int j0 = blockIdx.x * 4;
    __shared__ float sw[4][512];
    int t = threadIdx.x;
    const float* wo = Wo + (size_t)layer*Dq*Dq + (size_t)j0*Dq;
    #pragma unroll
    for (int j = 0; j < 4; j++) {
        int v = t + j*128;
        int r = v >> 7, c4 = (v & 127) * 4;
        *(float4*)&sw[r][c4] = *(const float4*)&wo[(size_t)r*Dq + c4];
    }
    __syncthreads();
    int tj = t >> 5, tm = t & 31;
    float ac = 0.f, as = 0.f;
    for (int l = 0; l < Lq; l++) {
        float w = sw[tj][l];
        ac = fmaf(w, g_ct[l*32 + tm], ac);
        as = fmaf(w, g_st[l*32 + tm], as);
    }
    float cm = (tm == 0 ? 1.0f : 2.0f) * (256.0f/512.0f);
    float vc = ac*cm, vs = -as*cm;
    size_t base = ((size_t)layer*Dq + j0 + tj)*64 + tm*2;
    __half hc = __float2half_rn(vc);
    __half hs = __float2half_rn(vs);
    wth[base]   = hc;  wtl[base]   = __float2half_rn(vc - __half2float(hc));
    wth[base+1] = hs;  wtl[base+1] = __float2half_rn(vs - __half2float(hs));
}

// ================= mma.sync fp16 GEMM: C = A(MxK) @ B(NxK)^T =============
#define GF_BIAS 1
#define GF_RES  2
#define GF_RELU 4
#define GF_OUTF32 8
#define GF_OUTH16 16

#define STG 32768
#define SMEM_GEMM (3*STG + 256)

template<int FLAGS, int TERMS>
__global__ void __launch_bounds__(256, 1) gemm_mma(
    const __half* __restrict__ Ah, const __half* __restrict__ Al,
    const __half* __restrict__ Bh, const __half* __restrict__ Bl,
    const float* __restrict__ bias, const float* __restrict__ res,
    float* __restrict__ Cf, __half* __restrict__ Ch,
    int M, int N, int K, float scal)
{
    extern __shared__ char dsm[];
    uint32_t sbase = (smem_u32(dsm) + 127) & ~127u;

    const int t = threadIdx.x;
    const int lane = t & 31;
    const int wid = t >> 5;
    const int wm = wid >> 2;
    const int wn = wid & 3;
    const int bm = blockIdx.y * 128, bn = blockIdx.x * 128;
    const int NC = K >> 5;

    float acc[4][4][4] = {};

    const int lrow = t >> 2;
    const int lcell = t & 3;
    auto load_chunk = [&](int c, int stg) {
        uint32_t sb = sbase + stg*STG;
        size_t k0 = (size_t)c * 32 + lcell*8;
        #pragma unroll
        for (int j = 0; j < 2; j++) {
            int row = lrow + j*64;
            uint32_t soff = row*64 + (((uint32_t)(lcell ^ (row & 3))) << 4);
            size_t ga = (size_t)(bm + row)*K + k0;
            size_t gb = (size_t)(bn + row)*K + k0;
            cp16(sb +         soff, Ah + ga);
            if (TERMS == 3) cp16(sb + 8192 + soff, Al + ga);
            cp16(sb + 16384 + soff, Bh + gb);
            if (TERMS >= 2) cp16(sb + 24576 + soff, Bl + gb);
        }
        CP_COMMIT();
    };

    load_chunk(0, 0);
    if (NC > 1) load_chunk(1, 1);

    const int arow_base = wm*64 + (lane & 15);
    const int brow_base = wn*32 + (lane & 15);
    const int kc_hi = lane >> 4;

    for (int c = 0; c < NC; c++) {
        if (c + 2 < NC) asm volatile("cp.async.wait_group 1;" ::: "memory");
        else            asm volatile("cp.async.wait_group 0;" ::: "memory");
        __syncthreads();
        if (c + 2 < NC) load_chunk(c + 2, (c + 2) % 3);

        uint32_t sb = sbase + (c % 3)*STG;
        #pragma unroll
        for (int s = 0; s < 2; s++) {
            uint32_t ah[4][4], al[4][4], bh[2][4], bl[2][4];
            int chunk = s*2 + kc_hi;
            #pragma unroll
            for (int mt = 0; mt < 4; mt++) {
                int row = arow_base + mt*16;
                uint32_t off = row*64 + (((uint32_t)(chunk ^ (row & 3))) << 4);
                LDSM_X4(ah[mt][0], ah[mt][1], ah[mt][2], ah[mt][3], sb + off);
                if (TERMS == 3)
                    LDSM_X4(al[mt][0], al[mt][1], al[mt][2], al[mt][3], sb + 8192 + off);
            }
            #pragma unroll
            for (int g = 0; g < 2; g++) {
                int row = brow_base + g*16;
                uint32_t off = row*64 + (((uint32_t)(chunk ^ (row & 3))) << 4);
                LDSM_X4(bh[g][0], bh[g][1], bh[g][2], bh[g][3], sb + 16384 + off);
                if (TERMS >= 2)
                    LDSM_X4(bl[g][0], bl[g][1], bl[g][2], bl[g][3], sb + 24576 + off);
            }
            #pragma unroll
            for (int mt = 0; mt < 4; mt++) {
                #pragma unroll
                for (int nt = 0; nt < 4; nt++) {
                    int g = nt >> 1, o = nt & 1;
                    MMA_F32(acc[mt][nt], ah[mt], bh[g][o], bh[g][o+2]);
                    if (TERMS >= 2)
                        MMA_F32(acc[mt][nt], ah[mt], bl[g][o], bl[g][o+2]);
                    if (TERMS == 3)
                        MMA_F32(acc[mt][nt], al[mt], bh[g][o], bh[g][o+2]);
                }
            }
        }
    }

    int r0 = bm + wm*64 + (lane >> 2);
    int c0 = bn + wn*32 + (lane & 3)*2;
    #pragma unroll
    for (int mt = 0; mt < 4; mt++) {
        #pragma unroll
        for (int nt = 0; nt < 4; nt++) {
            int col = c0 + nt*8;
            float b0 = 0.f, b1 = 0.f;
            if (FLAGS & GF_BIAS) { b0 = bias[col]; b1 = bias[col+1]; }
            #pragma unroll
            for (int half = 0; half < 2; half++) {
                int row = r0 + mt*16 + half*8;
                float v0 = acc[mt][nt][half*2+0] * scal + b0;
                float v1 = acc[mt][nt][half*2+1] * scal + b1;
                size_t ro = (size_t)row * N + col;
                if (FLAGS & GF_RES) {
                    float2 r2 = *(const float2*)&res[ro];
                    v0 += r2.x; v1 += r2.y;
                }
                if (FLAGS & GF_RELU) { v0 = fmaxf(v0, 0.f); v1 = fmaxf(v1, 0.f); }
                if (FLAGS & GF_OUTF32) {
                    float2 o2; o2.x = v0; o2.y = v1;
                    *(float2*)&Cf[ro] = o2;
                }
                if (FLAGS & GF_OUTH16) {
                    __half2 hp; hp.x = __float2half_rn(v0); hp.y = __float2half_rn(v1);
                    *(__half2*)&Ch[ro] = hp;
                }
            }
        }
    }
}

// ========== DFT of x with l/l+256 symmetry: X[m] = sum_{l<256}(x[l] +/- x[l+256])e^{-iwml}
// grid 512 = b(64) x dchunk(8 of 64); block 128; thread = 1 d x 16 modes
__global__ void __launch_bounds__(128) dftx_kernel(const float* __restrict__ x,
                                                   __half* __restrict__ Xh,
                                                   __half* __restrict__ Xl) {
    int blk = blockIdx.x;
    int b = blk >> 3;
    int dchunk = (blk & 7) * 64;
    __shared__ float sqA[32][68];   // rows l0..l0+31
    __shared__ float sqB[32][68];   // rows l0+256..l0+287
    __shared__ float sct[32][32];
    __shared__ float sst[32][32];
    int t = threadIdx.x;
    int td = t & 63;
    int tm = (t >> 6) * 16;         // 0 or 16 (even)

    float ar[16] = {}, ai[16] = {};
    const float* qbase = x + (size_t)b*Lq*Dq + dchunk;

    for (int l0 = 0; l0 < 256; l0 += 32) {
        #pragma unroll
        for (int j = 0; j < 4; j++) {
            int v = t + j*128;              // 512 float4 per half
            int ll = v >> 4;
            int c4 = (v & 15) * 4;
            *(float4*)&sqA[ll][c4] = *(const float4*)&qbase[(size_t)(l0+ll)*Dq + c4];
            *(float4*)&sqB[ll][c4] = *(const float4*)&qbase[(size_t)(l0+256+ll)*Dq + c4];
        }
        #pragma unroll
        for (int j = 0; j < 2; j++) {
            int v = t + j*128;
            int ll = v >> 3;
            int c4 = (v & 7) * 4;
            *(float4*)&sct[ll][c4] = *(const float4*)&g_ct[(l0+ll)*32 + c4];
            *(float4*)&sst[ll][c4] = *(const float4*)&g_st[(l0+ll)*32 + c4];
        }
        __syncthreads();
        #pragma unroll 2
        for (int ll = 0; ll < 32; ll++) {
            float xa = sqA[ll][td], xb = sqB[ll][td];
            float u = xa + xb;              // even m
            float w = xa - xb;              // odd m
            float c[16], s[16];
            #pragma unroll
            for (int j = 0; j < 16; j += 4) {
                *(float4*)&c[j] = *(float4*)&sct[ll][tm+j];
                *(float4*)&s[j] = *(float4*)&sst[ll][tm+j];
            }
            #pragma unroll
            for (int mm = 0; mm < 16; mm++) {
                float v = (mm & 1) ? w : u;
                ar[mm] = fmaf(v,  c[mm], ar[mm]);
                ai[mm] = fmaf(-v, s[mm], ai[mm]);
            }
        }
        __syncthreads();
    }
    int d0 = dchunk + td;
    #pragma unroll
    for (int mm = 0; mm < 16; mm++) {
        int m = tm + mm;
        float vr = ar[mm], vi = ai[mm];
        __half hr = __float2half_rn(vr);
        __half hi_ = __float2half_rn(vi);
        size_t rowr = ((size_t)(m*2+0)*64 + b)*Dq + d0;
        size_t rowi = ((size_t)(m*2+1)*64 + b)*Dq + d0;
        Xh[rowr] = hr;   Xl[rowr] = __float2half_rn(vr - __half2float(hr));
        Xh[rowi] = hi_;  Xl[rowi] = __float2half_rn(vi - __half2float(hi_));
    }
}

// ========== complex mode mix, block = (h,m) ==========
__global__ void __launch_bounds__(256) mix2_kernel(const float* __restrict__ xs,
                                                   const float* __restrict__ wtr,
                                                   const float* __restrict__ wti,
                                                   const float* __restrict__ bq,
                                                   __half* __restrict__ osh,
                                                   __half* __restrict__ osl) {
    int h = blockIdx.x >> 5, m = blockIdx.x & 31;
    __shared__ float swr[64][64];
    __shared__ float swi[64][64];
    __shared__ float sxr[64][65];
    __shared__ float sxi[64][65];
    int t = threadIdx.x;
    const float* pr = wtr + ((size_t)(h*32 + m))*4096;
    const float* pi = wti + ((size_t)(h*32 + m))*4096;
    #pragma unroll
    for (int j = 0; j < 16; j++) {
        int v = t + j*256;
        int r = v >> 6, c = v & 63;
        swr[r][c] = pr[v];
        swi[r][c] = pi[v];
    }
    #pragma unroll
    for (int j = 0; j < 16; j++) {
        int v = t + j*256;
        int b = v >> 6, i = v & 63;
        if (j < 8) {
            float vr = xs[((size_t)(2*m)*64 + b)*Dq + h*64 + i];
            if (m == 0) vr += 512.0f * bq[h*64 + i];
            sxr[b][i] = vr;
        } else {
            sxi[b][i] = xs[((size_t)(2*m+1)*64 + b)*Dq + h*64 + i];
        }
    }
    __syncthreads();

    int b = t >> 2;
    int o0 = (t & 3) * 16;
    float orr[16] = {}, oii[16] = {};
    for (int i = 0; i < 64; i++) {
        float xr = sxr[b][i], xi = sxi[b][i];
        float wr4[16], wi4[16];
        #pragma unroll
        for (int j = 0; j < 16; j += 4) {
            *(float4*)&wr4[j] = *(float4*)&swr[i][o0+j];
            *(float4*)&wi4[j] = *(float4*)&swi[i][o0+j];
        }
        #pragma unroll
        for (int j = 0; j < 16; j++) {
            orr[j] = fmaf(xr, wr4[j], orr[j]);
            orr[j] = fmaf(-xi, wi4[j], orr[j]);
            oii[j] = fmaf(xr, wi4[j], oii[j]);
            oii[j] = fmaf(xi, wr4[j], oii[j]);
        }
    }
    #pragma unroll
    for (int j = 0; j < 16; j++) {
        int o = o0 + j;
        float vr = orr[j] * 256.0f;
        float vi = oii[j] * 256.0f;
        __half hr = __float2half_rn(vr);
        __half hi_ = __float2half_rn(vi);
        size_t base = ((size_t)b*512 + h*64 + o)*64 + 2*m;
        __half2 hp; hp.x = hr; hp.y = hi_;
        *(__half2*)&osh[base] = hp;
        __half2 lp;
        lp.x = __float2half_rn(vr - __half2float(hr));
        lp.y = __float2half_rn(vi - __half2float(hi_));
        *(__half2*)&osl[base] = lp;
    }
}

// ================= series_decomp, 4-way L-split =================
__global__ void decomp_kernel(const float* __restrict__ in, float* __restrict__ out,
                              __half* __restrict__ oh) {
    int gid = blockIdx.x*blockDim.x + threadIdx.x;   // 131072 total
    int seg = gid >> 15;            // 0..3
    int r = gid & 32767;
    int b = r >> 9, d = r & 511;
    const float* p = in + (size_t)b*Lq*Dq + d;
    size_t obase = (size_t)b*Lq*Dq + d;
    int lstart = seg * 128;
    // initial window sum for l = lstart over [lstart-12, lstart+12] (clamped low)
    float wsum = 0.f;
    #pragma unroll
    for (int j = -12; j <= 12; j++) {
        int jj = lstart + j;
        jj = jj < 0 ? 0 : jj;
        wsum += p[(size_t)jj*Dq];
    }
    int lend = lstart + 128;
    for (int l = lstart; l < lend; l++) {
        float xl = p[(size_t)l*Dq];
        float v = xl - wsum*(1.0f/25.0f);
        out[obase + (size_t)l*Dq] = v;
        oh[obase + (size_t)l*Dq] = __float2half_rn(v);
        int jn = l+13 > Lq-1 ? Lq-1 : l+13;
        int jo = l-12 < 0 ? 0 : l-12;
        wsum += p[(size_t)jn*Dq] - p[(size_t)jo*Dq];
    }
}

// ================= final layernorm / projection =================
__global__ void ln_rows(const float* __restrict__ x) {
    int row = blockIdx.x;
    int t = threadIdx.x;
    const float* p = x + (size_t)row*Dq;
    float v0 = p[t], v1 = p[t+256];
    __shared__ float sh[8];
    float s = v0 + v1;
    int lane = t & 31, w = t >> 5;
    #pragma unroll
    for (int o = 16; o > 0; o >>= 1) s += __shfl_down_sync(~0u, s, o);
    if (lane == 0) sh[w] = s;
    __syncthreads();
    if (t < 32) {
        float v = (t < 8) ? sh[t] : 0.f;
        #pragma unroll
        for (int o = 4; o > 0; o >>= 1) v += __shfl_down_sync(~0u, v, o);
        if (t == 0) sh[0] = v;
    }
    __syncthreads();
    float mu = sh[0] * (1.0f/512.0f);
    __syncthreads();
    float d0 = v0 - mu, d1 = v1 - mu;
    s = d0*d0 + d1*d1;
    #pragma unroll
    for (int o = 16; o > 0; o >>= 1) s += __shfl_down_sync(~0u, s, o);
    if (lane == 0) sh[w] = s;
    __syncthreads();
    if (t < 32) {
        float v = (t < 8) ? sh[t] : 0.f;
        #pragma unroll
        for (int o = 4; o > 0; o >>= 1) v += __shfl_down_sync(~0u, v, o);
        if (t == 0) {
            float var = v * (1.0f/512.0f);
            g_mu[row] = mu;
            g_rs[row] = rsqrtf(var + 1e-5f);
        }
    }
}

__global__ void ln_cols(const float* __restrict__ x, const float* __restrict__ nw,
                        const float* __restrict__ nb, const float* __restrict__ tv) {
    int b = blockIdx.x;
    int d = threadIdx.x;
    float w = nw[d], bb = nb[d];
    float sum = 0.f, lastv = 0.f;
    for (int l = 0; l < Lq; l++) {
        int row = b*Lq + l;
        float v = (x[(size_t)row*Dq + d] - g_mu[row]) * g_rs[row] * w + bb;
        sum += v;
        if (l == Lq-1) lastv = v;
    }
    g_cat[b*CATD + d] = lastv - sum*(1.0f/512.0f);
    if (d < 24) g_cat[b*CATD + 512 + d] = tv[((size_t)b*Lq + (Lq-1))*24 + d];
}

__global__ void __launch_bounds__(256) proj_kernel(const float* __restrict__ pw,
                                                   const float* __restrict__ pb,
                                                   float* __restrict__ out) {
    __shared__ float As[8][65];
    __shared__ float Bs[8][65];
    int n0 = blockIdx.x * 64;
    int t = threadIdx.x;
    int tx = t & 15, ty = t >> 4;
    float acc[4][4] = {};
    for (int k0 = 0; k0 < CATD; k0 += 8) {
        int v = t*2;
        int r = v >> 3, c = v & 7;
        As[c][r]   = g_cat[r*CATD + k0 + c];
        As[c+1][r] = g_cat[r*CATD + k0 + c + 1];
        int n = n0 + r;
        float f0 = 0.f, f1 = 0.f;
        if (n < NUM_APP) {
            f0 = pw[(size_t)n*CATD + k0 + c];
            f1 = pw[(size_t)n*CATD + k0 + c + 1];
        }
        Bs[c][r] = f0; Bs[c+1][r] = f1;
        __syncthreads();
        #pragma unroll
        for (int k = 0; k < 8; k++) {
            float a[4], bv[4];
            #pragma unroll
            for (int i = 0; i < 4; i++) { a[i] = As[k][ty*4+i]; bv[i] = Bs[k][tx*4+i]; }
            #pragma unroll
            for (int i = 0; i < 4; i++)
                #pragma unroll
                for (int j = 0; j < 4; j++)
                    acc[i][j] = fmaf(a[i], bv[j], acc[i][j]);
        }
        __syncthreads();
    }
    #pragma unroll
    for (int i = 0; i < 4; i++) {
        int bi = ty*4 + i;
        #pragma unroll
        for (int j = 0; j < 4; j++) {
            int n = n0 + tx*4 + j;
            if (n < NUM_APP) out[(size_t)bi*NUM_APP + n] = acc[i][j] + pb[n];
        }
    }
}

// ================= host orchestration =================
extern "C" void kernel_launch(void* const* d_in, const int* in_sizes, int n_in,
                              void* d_out, int out_size) {
    const int*   x_app     = (const int*)  d_in[0];
    const float* x_time    = (const float*)d_in[1];
    const float* time_vecs = (const float*)d_in[2];
    const float* app_emb_w = (const float*)d_in[4];
    const float* time_w    = (const float*)d_in[5];
    const float* time_b    = (const float*)d_in[6];
    const float* Wq        = (const float*)d_in[7];
    const float* bq        = (const float*)d_in[8];
    const float* Wo        = (const float*)d_in[9];
    const float* bo        = (const float*)d_in[10];
    const float* four_wr   = (const float*)d_in[11];
    const float* four_wi   = (const float*)d_in[12];
    const float* conv1_w   = (const float*)d_in[13];
    const float* conv2_w   = (const float*)d_in[14];
    const float* norm_w    = (const float*)d_in[15];
    const float* norm_b    = (const float*)d_in[16];
    const float* proj_w    = (const float*)d_in[17];
    const float* proj_b    = (const float*)d_in[18];
    float* out = (float*)d_out;

    cudaFuncSetAttribute((const void*)gemm_mma<GF_OUTF32, 3>,                cudaFuncAttributeMaxDynamicSharedMemorySize, SMEM_GEMM);
    cudaFuncSetAttribute((const void*)gemm_mma<GF_BIAS|GF_RES|GF_OUTF32, 3>, cudaFuncAttributeMaxDynamicSharedMemorySize, SMEM_GEMM);
    cudaFuncSetAttribute((const void*)gemm_mma<GF_RELU|GF_OUTH16, 1>,        cudaFuncAttributeMaxDynamicSharedMemorySize, SMEM_GEMM);
    cudaFuncSetAttribute((const void*)gemm_mma<GF_RES|GF_OUTF32, 1>,         cudaFuncAttributeMaxDynamicSharedMemorySize, SMEM_GEMM);

    void *px, *pq, *pt;
    void *pxh, *pXh, *pXl, *pyh, *posh, *posl, *pwth, *pwtl;
    void *pwqh, *pwql, *pc1h, *pc2h, *pwtr, *pwti;
    cudaGetSymbolAddress(&px, g_x);
    cudaGetSymbolAddress(&pq, g_q);
    cudaGetSymbolAddress(&pt, g_t);
    cudaGetSymbolAddress(&pxh, g_xh);
    cudaGetSymbolAddress(&pXh, g_Xh); cudaGetSymbolAddress(&pXl, g_Xl);
    cudaGetSymbolAddress(&pyh, g_yh);
    cudaGetSymbolAddress(&posh, g_osh); cudaGetSymbolAddress(&posl, g_osl);
    cudaGetSymbolAddress(&pwth, g_wth); cudaGetSymbolAddress(&pwtl, g_wtl);
    cudaGetSymbolAddress(&pwqh, g_wqh); cudaGetSymbolAddress(&pwql, g_wql);
    cudaGetSymbolAddress(&pc1h, g_c1h);
    cudaGetSymbolAddress(&pc2h, g_c2h);
    cudaGetSymbolAddress(&pwtr, g_wtr); cudaGetSymbolAddress(&pwti, g_wti);
    float* fx = (float*)px;
    float* fq = (float*)pq;
    float* ft = (float*)pt;
    __half *xh=(__half*)pxh;
    __half *Xh=(__half*)pXh, *Xl=(__half*)pXl;
    __half *yh=(__half*)pyh;
    __half *osh=(__half*)posh, *osl=(__half*)posl;
    __half *wth=(__half*)pwth, *wtl=(__half*)pwtl;
    __half *wqh=(__half*)pwqh, *wql=(__half*)pwql;
    __half *c1h=(__half*)pc1h;
    __half *c2h=(__half*)pc2h;
    float *wtr=(float*)pwtr, *wti=(float*)pwti;

    init_tables<<<64, 256>>>();
    convert_hl<<<(2*Dq*Dq + 255)/256, 256>>>(Wq, wqh, wql, 2*Dq*Dq);
    convert_hl<<<(2*DFF*Dq + 255)/256, 256>>>(conv1_w, c1h, nullptr, 2*DFF*Dq);
    convert_hl<<<(2*Dq*DFF + 255)/256, 256>>>(conv2_w, c2h, nullptr, 2*Dq*DFF);
    wotab_kernel<<<dim3(128, 2), 128>>>(Wo, wth, wtl);
    wtrans_kernel<<<1024, 256>>>(four_wr, four_wi);
    embed_kernel<<<BLq*Dq/256, 256>>>(x_app, x_time, app_emb_w, time_w, time_b);

    const int M = BLq;
    for (int l = 0; l < 2; l++) {
        size_t woff = (size_t)l*Dq*Dq;
        size_t coff1 = (size_t)l*DFF*Dq;
        size_t mixoff = (size_t)l*Hq*MODES*Eq*Eq;

        // X = DFT_l(x)  (symmetry-halved)
        dftx_kernel<<<512, 128>>>(fx, Xh, Xl);
        // xs = X @ Wq^T  (4096 x 512 x 512), 3-term
        gemm_mma<GF_OUTF32, 3><<<dim3(4, 32), 256, SMEM_GEMM>>>(
            Xh, Xl, wqh + woff, wql + woff, nullptr, nullptr,
            fq, nullptr, 4096, Dq, Dq, 1.0f);
        // os = mode mix (+ bq into mode 0)
        mix2_kernel<<<Hq*MODES, 256>>>(fq, wtr + mixoff, wti + mixoff,
                                       bq + l*Dq, osh, osl);
        // new_x = os @ WoT^T * (1/65536) + bo + x, 3-term
        gemm_mma<GF_BIAS|GF_RES|GF_OUTF32, 3><<<dim3(4, 256), 256, SMEM_GEMM>>>(
            osh, osl, wth + (size_t)l*Dq*64, wtl + (size_t)l*Dq*64, bo + l*Dq, fx,
            ft, nullptr, M, Dq, 64, 1.0f/65536.0f);
        decomp_kernel<<<512, 256>>>(ft, fx, xh);
        // y = relu(x @ c1^T), 1-term pure fp16
        gemm_mma<GF_RELU|GF_OUTH16, 1><<<dim3(DFF/128, M/128), 256, SMEM_GEMM>>>(
            xh, nullptr, c1h + coff1, nullptr, nullptr, nullptr,
            nullptr, yh, M, DFF, Dq, 1.0f);
        // t = y @ c2^T + x, 1-term pure fp16
        gemm_mma<GF_RES|GF_OUTF32, 1><<<dim3(Dq/128, M/128), 256, SMEM_GEMM>>>(
            yh, nullptr, c2h + coff1, nullptr, nullptr, fx,
            ft, nullptr, M, Dq, DFF, 1.0f);
        decomp_kernel<<<512, 256>>>(ft, fx, xh);
    }

    ln_rows<<<BLq, 256>>>(fx);
    ln_cols<<<Bq, 512>>>(fx, norm_w, norm_b, time_vecs);
    proj_kernel<<<(NUM_APP + 63)/64, 256>>>(proj_w, proj_b, out);
}

// round 10
// speedup vs baseline: 4.4473x; 1.0209x over previous
#include <cuda_runtime.h>
#include <cuda_fp16.h>
#include <math.h>
#include <stdint.h>

#define Bq 64
#define Lq 512
#define Dq 512
#define Hq 8
#define Eq 64
#define DFF 2048
#define MODES 32
#define VOCAB 10000
#define NUM_APP 10000
#define CATD 536
#define BLq (Bq*Lq)

// ================= helpers =================
__device__ __forceinline__ uint32_t smem_u32(const void* p) {
    uint32_t a;
    asm("{ .reg .u64 t; cvta.to.shared.u64 t, %1; cvt.u32.u64 %0, t; }" : "=r"(a) : "l"(p));
    return a;
}
__device__ __forceinline__ void cp16(uint32_t dst, const void* src) {
    asm volatile("cp.async.cg.shared.global [%0], [%1], 16;" :: "r"(dst), "l"(src) : "memory");
}
#define CP_COMMIT() asm volatile("cp.async.commit_group;" ::: "memory")

#define LDSM_X4(r0,r1,r2,r3, addr) \
    asm volatile("ldmatrix.sync.aligned.m8n8.x4.shared.b16 {%0,%1,%2,%3}, [%4];" \
        : "=r"(r0), "=r"(r1), "=r"(r2), "=r"(r3) : "r"(addr))

#define MMA_F32(d, a, b0, b1) \
    asm volatile("mma.sync.aligned.m16n8k16.row.col.f32.f16.f16.f32 " \
        "{%0,%1,%2,%3},{%4,%5,%6,%7},{%8,%9},{%0,%1,%2,%3};" \
        : "+f"((d)[0]), "+f"((d)[1]), "+f"((d)[2]), "+f"((d)[3]) \
        : "r"((a)[0]), "r"((a)[1]), "r"((a)[2]), "r"((a)[3]), "r"(b0), "r"(b1))

// ================= scratch (device globals) =================
__device__ float g_x[BLq*Dq];
__device__ float g_q[BLq*Dq];
__device__ float g_t[BLq*Dq];
__device__ __align__(256) __half g_xh[BLq*Dq];
__device__ __align__(256) __half g_Xh[4096*Dq], g_Xl[4096*Dq];
__device__ __align__(256) __half g_yh[BLq*DFF];
__device__ __align__(256) __half g_osh[BLq*64], g_osl[BLq*64];
__device__ __align__(256) __half g_wth[2*Dq*64], g_wtl[2*Dq*64];
__device__ __align__(256) __half g_wqh[2*Dq*Dq], g_wql[2*Dq*Dq];
__device__ __align__(256) __half g_c1h[2*DFF*Dq];
__device__ __align__(256) __half g_c2h[2*Dq*DFF];
__device__ float g_wtr[2*Hq*MODES*Eq*Eq];
__device__ float g_wti[2*Hq*MODES*Eq*Eq];
__device__ float g_ct[Lq*MODES], g_st[Lq*MODES];
__device__ float g_mu[BLq], g_rs[BLq];
__device__ float g_part[8*Bq*Dq];           // ln_cols partial sums
__device__ float g_cat[Bq*CATD];

// ================= small kernels =================
__global__ void init_tables() {
    int idx = blockIdx.x*blockDim.x + threadIdx.x;
    if (idx < Lq*MODES) {
        int l = idx >> 5, m = idx & 31;
        double a = (double)(m*l) / 256.0;
        double s, c;
        sincospi(a, &s, &c);
        g_ct[idx] = (float)c;
        g_st[idx] = (float)s;
    }
}

__global__ void convert_hl(const float* __restrict__ src, __half* __restrict__ h,
                           __half* __restrict__ l, int n) {
    int i = blockIdx.x*256 + threadIdx.x;
    if (i < n) {
        float v = src[i];
        __half hv = __float2half_rn(v);
        h[i] = hv;
        if (l) l[i] = __float2half_rn(v - __half2float(hv));
    }
}

__global__ void embed_kernel(const int* __restrict__ app, const float* __restrict__ xt,
                             const float* __restrict__ emb, const float* __restrict__ tw,
                             const float* __restrict__ tb) {
    size_t idx = (size_t)blockIdx.x*256 + threadIdx.x;
    int d = (int)(idx & 511);
    size_t bl = idx >> 9;
    int a = app[bl];
    g_x[idx] = emb[(size_t)a*Dq + d] + xt[bl]*tw[d] + tb[d];
}

// ========== transpose four_wr/wi ==========
__global__ void __launch_bounds__(256) wtrans_kernel(const float* __restrict__ wr,
                                                     const float* __restrict__ wi) {
    int blk = blockIdx.x;
    int i  = blk & 63;
    int lh = blk >> 6;
    __shared__ float tr[64][33], ti_[64][33];
    int t = threadIdx.x;
    const float* pr = wr + ((size_t)lh*64 + i)*64*32;
    const float* pi = wi + ((size_t)lh*64 + i)*64*32;
    #pragma unroll
    for (int j = 0; j < 8; j++) {
        int v = t + j*256;
        int o = v >> 5, m = v & 31;
        tr[o][m]  = pr[v];
        ti_[o][m] = pi[v];
    }
    __syncthreads();
    #pragma unroll
    for (int j = 0; j < 8; j++) {
        int v = t + j*256;
        int m = v >> 6, o = v & 63;
        size_t dst = ((size_t)(lh*32 + m)*64 + i)*64 + o;
        g_wtr[dst] = tr[o][m];
        g_wti[dst] = ti_[o][m];
    }
}

// ========== Wo frequency table ==========
__global__ void __launch_bounds__(128) wotab_kernel(const float* __restrict__ Wo,
                                                    __half* __restrict__ wth,
                                                    __half* __restrict__ wtl) {
    int layer = blockIdx.y;
    int j0 = blockIdx.x * 4;
    __shared__ float sw[4][512];
    int t = threadIdx.x;
    const float* wo = Wo + (size_t)layer*Dq*Dq + (size_t)j0*Dq;
    #pragma unroll
    for (int j = 0; j < 4; j++) {
        int v = t + j*128;
        int r = v >> 7, c4 = (v & 127) * 4;
        *(float4*)&sw[r][c4] = *(const float4*)&wo[(size_t)r*Dq + c4];
    }
    __syncthreads();
    int tj = t >> 5, tm = t & 31;
    float ac = 0.f, as = 0.f;
    for (int l = 0; l < Lq; l++) {
        float w = sw[tj][l];
        ac = fmaf(w, g_ct[l*32 + tm], ac);
        as = fmaf(w, g_st[l*32 + tm], as);
    }
    float cm = (tm == 0 ? 1.0f : 2.0f) * (256.0f/512.0f);
    float vc = ac*cm, vs = -as*cm;
    size_t base = ((size_t)layer*Dq + j0 + tj)*64 + tm*2;
    __half hc = __float2half_rn(vc);
    __half hs = __float2half_rn(vs);
    wth[base]   = hc;  wtl[base]   = __float2half_rn(vc - __half2float(hc));
    wth[base+1] = hs;  wtl[base+1] = __float2half_rn(vs - __half2float(hs));
}

// ================= mma.sync fp16 GEMM: C = A(MxK) @ B(NxK)^T =============
#define GF_BIAS 1
#define GF_RES  2
#define GF_RELU 4
#define GF_OUTF32 8
#define GF_OUTH16 16

#define STG 32768
#define SMEM_GEMM (3*STG + 256)

template<int FLAGS, int TERMS>
__global__ void __launch_bounds__(256, 1) gemm_mma(
    const __half* __restrict__ Ah, const __half* __restrict__ Al,
    const __half* __restrict__ Bh, const __half* __restrict__ Bl,
    const float* __restrict__ bias, const float* __restrict__ res,
    float* __restrict__ Cf, __half* __restrict__ Ch,
    int M, int N, int K, float scal)
{
    extern __shared__ char dsm[];
    uint32_t sbase = (smem_u32(dsm) + 127) & ~127u;

    const int t = threadIdx.x;
    const int lane = t & 31;
    const int wid = t >> 5;
    const int wm = wid >> 2;
    const int wn = wid & 3;
    const int bm = blockIdx.y * 128, bn = blockIdx.x * 128;
    const int NC = K >> 5;

    float acc[4][4][4] = {};

    const int lrow = t >> 2;
    const int lcell = t & 3;
    auto load_chunk = [&](int c, int stg) {
        uint32_t sb = sbase + stg*STG;
        size_t k0 = (size_t)c * 32 + lcell*8;
        #pragma unroll
        for (int j = 0; j < 2; j++) {
            int row = lrow + j*64;
            uint32_t soff = row*64 + (((uint32_t)(lcell ^ (row & 3))) << 4);
            size_t ga = (size_t)(bm + row)*K + k0;
            size_t gb = (size_t)(bn + row)*K + k0;
            cp16(sb +         soff, Ah + ga);
            if (TERMS == 3) cp16(sb + 8192 + soff, Al + ga);
            cp16(sb + 16384 + soff, Bh + gb);
            if (TERMS >= 2) cp16(sb + 24576 + soff, Bl + gb);
        }
        CP_COMMIT();
    };

    load_chunk(0, 0);
    if (NC > 1) load_chunk(1, 1);

    const int arow_base = wm*64 + (lane & 15);
    const int brow_base = wn*32 + (lane & 15);
    const int kc_hi = lane >> 4;

    for (int c = 0; c < NC; c++) {
        if (c + 2 < NC) asm volatile("cp.async.wait_group 1;" ::: "memory");
        else            asm volatile("cp.async.wait_group 0;" ::: "memory");
        __syncthreads();
        if (c + 2 < NC) load_chunk(c + 2, (c + 2) % 3);

        uint32_t sb = sbase + (c % 3)*STG;
        #pragma unroll
        for (int s = 0; s < 2; s++) {
            uint32_t ah[4][4], al[4][4], bh[2][4], bl[2][4];
            int chunk = s*2 + kc_hi;
            #pragma unroll
            for (int mt = 0; mt < 4; mt++) {
                int row = arow_base + mt*16;
                uint32_t off = row*64 + (((uint32_t)(chunk ^ (row & 3))) << 4);
                LDSM_X4(ah[mt][0], ah[mt][1], ah[mt][2], ah[mt][3], sb + off);
                if (TERMS == 3)
                    LDSM_X4(al[mt][0], al[mt][1], al[mt][2], al[mt][3], sb + 8192 + off);
            }
            #pragma unroll
            for (int g = 0; g < 2; g++) {
                int row = brow_base + g*16;
                uint32_t off = row*64 + (((uint32_t)(chunk ^ (row & 3))) << 4);
                LDSM_X4(bh[g][0], bh[g][1], bh[g][2], bh[g][3], sb + 16384 + off);
                if (TERMS >= 2)
                    LDSM_X4(bl[g][0], bl[g][1], bl[g][2], bl[g][3], sb + 24576 + off);
            }
            #pragma unroll
            for (int mt = 0; mt < 4; mt++) {
                #pragma unroll
                for (int nt = 0; nt < 4; nt++) {
                    int g = nt >> 1, o = nt & 1;
                    MMA_F32(acc[mt][nt], ah[mt], bh[g][o], bh[g][o+2]);
                    if (TERMS >= 2)
                        MMA_F32(acc[mt][nt], ah[mt], bl[g][o], bl[g][o+2]);
                    if (TERMS == 3)
                        MMA_F32(acc[mt][nt], al[mt], bh[g][o], bh[g][o+2]);
                }
            }
        }
    }

    int r0 = bm + wm*64 + (lane >> 2);
    int c0 = bn + wn*32 + (lane & 3)*2;
    #pragma unroll
    for (int mt = 0; mt < 4; mt++) {
        #pragma unroll
        for (int nt = 0; nt < 4; nt++) {
            int col = c0 + nt*8;
            float b0 = 0.f, b1 = 0.f;
            if (FLAGS & GF_BIAS) { b0 = bias[col]; b1 = bias[col+1]; }
            #pragma unroll
            for (int half = 0; half < 2; half++) {
                int row = r0 + mt*16 + half*8;
                float v0 = acc[mt][nt][half*2+0] * scal + b0;
                float v1 = acc[mt][nt][half*2+1] * scal + b1;
                size_t ro = (size_t)row * N + col;
                if (FLAGS & GF_RES) {
                    float2 r2 = *(const float2*)&res[ro];
                    v0 += r2.x; v1 += r2.y;
                }
                if (FLAGS & GF_RELU) { v0 = fmaxf(v0, 0.f); v1 = fmaxf(v1, 0.f); }
                if (FLAGS & GF_OUTF32) {
                    float2 o2; o2.x = v0; o2.y = v1;
                    *(float2*)&Cf[ro] = o2;
                }
                if (FLAGS & GF_OUTH16) {
                    __half2 hp; hp.x = __float2half_rn(v0); hp.y = __float2half_rn(v1);
                    *(__half2*)&Ch[ro] = hp;
                }
            }
        }
    }
}

// ========== DFT of x with l/l+256 symmetry ==========
__global__ void __launch_bounds__(128) dftx_kernel(const float* __restrict__ x,
                                                   __half* __restrict__ Xh,
                                                   __half* __restrict__ Xl) {
    int blk = blockIdx.x;
    int b = blk >> 3;
    int dchunk = (blk & 7) * 64;
    __shared__ float sqA[32][68];
    __shared__ float sqB[32][68];
    __shared__ float sct[32][32];
    __shared__ float sst[32][32];
    int t = threadIdx.x;
    int td = t & 63;
    int tm = (t >> 6) * 16;

    float ar[16] = {}, ai[16] = {};
    const float* qbase = x + (size_t)b*Lq*Dq + dchunk;

    for (int l0 = 0; l0 < 256; l0 += 32) {
        #pragma unroll
        for (int j = 0; j < 4; j++) {
            int v = t + j*128;
            int ll = v >> 4;
            int c4 = (v & 15) * 4;
            *(float4*)&sqA[ll][c4] = *(const float4*)&qbase[(size_t)(l0+ll)*Dq + c4];
            *(float4*)&sqB[ll][c4] = *(const float4*)&qbase[(size_t)(l0+256+ll)*Dq + c4];
        }
        #pragma unroll
        for (int j = 0; j < 2; j++) {
            int v = t + j*128;
            int ll = v >> 3;
            int c4 = (v & 7) * 4;
            *(float4*)&sct[ll][c4] = *(const float4*)&g_ct[(l0+ll)*32 + c4];
            *(float4*)&sst[ll][c4] = *(const float4*)&g_st[(l0+ll)*32 + c4];
        }
        __syncthreads();
        #pragma unroll 2
        for (int ll = 0; ll < 32; ll++) {
            float xa = sqA[ll][td], xb = sqB[ll][td];
            float u = xa + xb;
            float w = xa - xb;
            float c[16], s[16];
            #pragma unroll
            for (int j = 0; j < 16; j += 4) {
                *(float4*)&c[j] = *(float4*)&sct[ll][tm+j];
                *(float4*)&s[j] = *(float4*)&sst[ll][tm+j];
            }
            #pragma unroll
            for (int mm = 0; mm < 16; mm++) {
                float v = (mm & 1) ? w : u;
                ar[mm] = fmaf(v,  c[mm], ar[mm]);
                ai[mm] = fmaf(-v, s[mm], ai[mm]);
            }
        }
        __syncthreads();
    }
    int d0 = dchunk + td;
    #pragma unroll
    for (int mm = 0; mm < 16; mm++) {
        int m = tm + mm;
        float vr = ar[mm], vi = ai[mm];
        __half hr = __float2half_rn(vr);
        __half hi_ = __float2half_rn(vi);
        size_t rowr = ((size_t)(m*2+0)*64 + b)*Dq + d0;
        size_t rowi = ((size_t)(m*2+1)*64 + b)*Dq + d0;
        Xh[rowr] = hr;   Xl[rowr] = __float2half_rn(vr - __half2float(hr));
        Xh[rowi] = hi_;  Xl[rowi] = __float2half_rn(vi - __half2float(hi_));
    }
}

// ========== complex mode mix ==========
__global__ void __launch_bounds__(256) mix2_kernel(const float* __restrict__ xs,
                                                   const float* __restrict__ wtr,
                                                   const float* __restrict__ wti,
                                                   const float* __restrict__ bq,
                                                   __half* __restrict__ osh,
                                                   __half* __restrict__ osl) {
    int h = blockIdx.x >> 5, m = blockIdx.x & 31;
    __shared__ float swr[64][64];
    __shared__ float swi[64][64];
    __shared__ float sxr[64][65];
    __shared__ float sxi[64][65];
    int t = threadIdx.x;
    const float* pr = wtr + ((size_t)(h*32 + m))*4096;
    const float* pi = wti + ((size_t)(h*32 + m))*4096;
    #pragma unroll
    for (int j = 0; j < 16; j++) {
        int v = t + j*256;
        int r = v >> 6, c = v & 63;
        swr[r][c] = pr[v];
        swi[r][c] = pi[v];
    }
    #pragma unroll
    for (int j = 0; j < 16; j++) {
        int v = t + j*256;
        int b = v >> 6, i = v & 63;
        if (j < 8) {
            float vr = xs[((size_t)(2*m)*64 + b)*Dq + h*64 + i];
            if (m == 0) vr += 512.0f * bq[h*64 + i];
            sxr[b][i] = vr;
        } else {
            sxi[b][i] = xs[((size_t)(2*m+1)*64 + b)*Dq + h*64 + i];
        }
    }
    __syncthreads();

    int b = t >> 2;
    int o0 = (t & 3) * 16;
    float orr[16] = {}, oii[16] = {};
    for (int i = 0; i < 64; i++) {
        float xr = sxr[b][i], xi = sxi[b][i];
        float wr4[16], wi4[16];
        #pragma unroll
        for (int j = 0; j < 16; j += 4) {
            *(float4*)&wr4[j] = *(float4*)&swr[i][o0+j];
            *(float4*)&wi4[j] = *(float4*)&swi[i][o0+j];
        }
        #pragma unroll
        for (int j = 0; j < 16; j++) {
            orr[j] = fmaf(xr, wr4[j], orr[j]);
            orr[j] = fmaf(-xi, wi4[j], orr[j]);
            oii[j] = fmaf(xr, wi4[j], oii[j]);
            oii[j] = fmaf(xi, wr4[j], oii[j]);
        }
    }
    #pragma unroll
    for (int j = 0; j < 16; j++) {
        int o = o0 + j;
        float vr = orr[j] * 256.0f;
        float vi = oii[j] * 256.0f;
        __half hr = __float2half_rn(vr);
        __half hi_ = __float2half_rn(vi);
        size_t base = ((size_t)b*512 + h*64 + o)*64 + 2*m;
        __half2 hp; hp.x = hr; hp.y = hi_;
        *(__half2*)&osh[base] = hp;
        __half2 lp;
        lp.x = __float2half_rn(vr - __half2float(hr));
        lp.y = __float2half_rn(vi - __half2float(hi_));
        *(__half2*)&osl[base] = lp;
    }
}

// ================= series_decomp, 4-way L-split; oh nullable =================
__global__ void decomp_kernel(const float* __restrict__ in, float* __restrict__ out,
                              __half* __restrict__ oh) {
    int gid = blockIdx.x*blockDim.x + threadIdx.x;
    int seg = gid >> 15;
    int r = gid & 32767;
    int b = r >> 9, d = r & 511;
    const float* p = in + (size_t)b*Lq*Dq + d;
    size_t obase = (size_t)b*Lq*Dq + d;
    int lstart = seg * 128;
    float wsum = 0.f;
    #pragma unroll
    for (int j = -12; j <= 12; j++) {
        int jj = lstart + j;
        jj = jj < 0 ? 0 : jj;
        wsum += p[(size_t)jj*Dq];
    }
    int lend = lstart + 128;
    if (oh) {
        for (int l = lstart; l < lend; l++) {
            float xl = p[(size_t)l*Dq];
            float v = xl - wsum*(1.0f/25.0f);
            out[obase + (size_t)l*Dq] = v;
            oh[obase + (size_t)l*Dq] = __float2half_rn(v);
            int jn = l+13 > Lq-1 ? Lq-1 : l+13;
            int jo = l-12 < 0 ? 0 : l-12;
            wsum += p[(size_t)jn*Dq] - p[(size_t)jo*Dq];
        }
    } else {
        for (int l = lstart; l < lend; l++) {
            float xl = p[(size_t)l*Dq];
            float v = xl - wsum*(1.0f/25.0f);
            out[obase + (size_t)l*Dq] = v;
            int jn = l+13 > Lq-1 ? Lq-1 : l+13;
            int jo = l-12 < 0 ? 0 : l-12;
            wsum += p[(size_t)jn*Dq] - p[(size_t)jo*Dq];
        }
    }
}

// ================= final layernorm / projection =================
__global__ void ln_rows(const float* __restrict__ x) {
    int row = blockIdx.x;
    int t = threadIdx.x;
    const float* p = x + (size_t)row*Dq;
    float v0 = p[t], v1 = p[t+256];
    __shared__ float sh[8];
    float s = v0 + v1;
    int lane = t & 31, w = t >> 5;
    #pragma unroll
    for (int o = 16; o > 0; o >>= 1) s += __shfl_down_sync(~0u, s, o);
    if (lane == 0) sh[w] = s;
    __syncthreads();
    if (t < 32) {
        float v = (t < 8) ? sh[t] : 0.f;
        #pragma unroll
        for (int o = 4; o > 0; o >>= 1) v += __shfl_down_sync(~0u, v, o);
        if (t == 0) sh[0] = v;
    }
    __syncthreads();
    float mu = sh[0] * (1.0f/512.0f);
    __syncthreads();
    float d0 = v0 - mu, d1 = v1 - mu;
    s = d0*d0 + d1*d1;
    #pragma unroll
    for (int o = 16; o > 0; o >>= 1) s += __shfl_down_sync(~0u, s, o);
    if (lane == 0) sh[w] = s;
    __syncthreads();
    if (t < 32) {
        float v = (t < 8) ? sh[t] : 0.f;
        #pragma unroll
        for (int o = 4; o > 0; o >>= 1) v += __shfl_down_sync(~0u, v, o);
        if (t == 0) {
            float var = v * (1.0f/512.0f);
            g_mu[row] = mu;
            g_rs[row] = rsqrtf(var + 1e-5f);
        }
    }
}

// stage 1: partial column sums over 64-row segments (deterministic, no atomics)
__global__ void ln_cols_part(const float* __restrict__ x, const float* __restrict__ nw,
                             const float* __restrict__ nb) {
    int blk = blockIdx.x;          // b*8 + seg
    int b = blk >> 3, seg = blk & 7;
    int d = threadIdx.x;
    float w = nw[d], bb = nb[d];
    float sum = 0.f;
    int l0 = seg * 64;
    #pragma unroll 4
    for (int l = l0; l < l0 + 64; l++) {
        int row = b*Lq + l;
        sum += (x[(size_t)row*Dq + d] - g_mu[row]) * g_rs[row] * w + bb;
    }
    g_part[(size_t)seg*Bq*Dq + b*Dq + d] = sum;
}

// stage 2: finalize cat = last - colsum/512 (+ time vec tail)
__global__ void ln_cols_fin(const float* __restrict__ x, const float* __restrict__ nw,
                            const float* __restrict__ nb, const float* __restrict__ tv) {
    int b = blockIdx.x;
    int d = threadIdx.x;
    float sum = 0.f;
    #pragma unroll
    for (int seg = 0; seg < 8; seg++)
        sum += g_part[(size_t)seg*Bq*Dq + b*Dq + d];
    int row = b*Lq + (Lq-1);
    float lastv = (x[(size_t)row*Dq + d] - g_mu[row]) * g_rs[row] * nw[d] + nb[d];
    g_cat[b*CATD + d] = lastv - sum*(1.0f/512.0f);
    if (d < 24) g_cat[b*CATD + 512 + d] = tv[((size_t)b*Lq + (Lq-1))*24 + d];
}

__global__ void __launch_bounds__(256) proj_kernel(const float* __restrict__ pw,
                                                   const float* __restrict__ pb,
                                                   float* __restrict__ out) {
    __shared__ float As[8][65];
    __shared__ float Bs[8][65];
    int n0 = blockIdx.x * 64;
    int t = threadIdx.x;
    int tx = t & 15, ty = t >> 4;
    float acc[4][4] = {};
    for (int k0 = 0; k0 < CATD; k0 += 8) {
        int v = t*2;
        int r = v >> 3, c = v & 7;
        As[c][r]   = g_cat[r*CATD + k0 + c];
        As[c+1][r] = g_cat[r*CATD + k0 + c + 1];
        int n = n0 + r;
        float f0 = 0.f, f1 = 0.f;
        if (n < NUM_APP) {
            f0 = pw[(size_t)n*CATD + k0 + c];
            f1 = pw[(size_t)n*CATD + k0 + c + 1];
        }
        Bs[c][r] = f0; Bs[c+1][r] = f1;
        __syncthreads();
        #pragma unroll
        for (int k = 0; k < 8; k++) {
            float a[4], bv[4];
            #pragma unroll
            for (int i = 0; i < 4; i++) { a[i] = As[k][ty*4+i]; bv[i] = Bs[k][tx*4+i]; }
            #pragma unroll
            for (int i = 0; i < 4; i++)
                #pragma unroll
                for (int j = 0; j < 4; j++)
                    acc[i][j] = fmaf(a[i], bv[j], acc[i][j]);
        }
        __syncthreads();
    }
    #pragma unroll
    for (int i = 0; i < 4; i++) {
        int bi = ty*4 + i;
        #pragma unroll
        for (int j = 0; j < 4; j++) {
            int n = n0 + tx*4 + j;
            if (n < NUM_APP) out[(size_t)bi*NUM_APP + n] = acc[i][j] + pb[n];
        }
    }
}

// ================= host orchestration =================
extern "C" void kernel_launch(void* const* d_in, const int* in_sizes, int n_in,
                              void* d_out, int out_size) {
    const int*   x_app     = (const int*)  d_in[0];
    const float* x_time    = (const float*)d_in[1];
    const float* time_vecs = (const float*)d_in[2];
    const float* app_emb_w = (const float*)d_in[4];
    const float* time_w    = (const float*)d_in[5];
    const float* time_b    = (const float*)d_in[6];
    const float* Wq        = (const float*)d_in[7];
    const float* bq        = (const float*)d_in[8];
    const float* Wo        = (const float*)d_in[9];
    const float* bo        = (const float*)d_in[10];
    const float* four_wr   = (const float*)d_in[11];
    const float* four_wi   = (const float*)d_in[12];
    const float* conv1_w   = (const float*)d_in[13];
    const float* conv2_w   = (const float*)d_in[14];
    const float* norm_w    = (const float*)d_in[15];
    const float* norm_b    = (const float*)d_in[16];
    const float* proj_w    = (const float*)d_in[17];
    const float* proj_b    = (const float*)d_in[18];
    float* out = (float*)d_out;

    cudaFuncSetAttribute((const void*)gemm_mma<GF_OUTF32, 3>,                cudaFuncAttributeMaxDynamicSharedMemorySize, SMEM_GEMM);
    cudaFuncSetAttribute((const void*)gemm_mma<GF_BIAS|GF_RES|GF_OUTF32, 3>, cudaFuncAttributeMaxDynamicSharedMemorySize, SMEM_GEMM);
    cudaFuncSetAttribute((const void*)gemm_mma<GF_RELU|GF_OUTH16, 1>,        cudaFuncAttributeMaxDynamicSharedMemorySize, SMEM_GEMM);
    cudaFuncSetAttribute((const void*)gemm_mma<GF_RES|GF_OUTF32, 1>,         cudaFuncAttributeMaxDynamicSharedMemorySize, SMEM_GEMM);

    void *px, *pq, *pt;
    void *pxh, *pXh, *pXl, *pyh, *posh, *posl, *pwth, *pwtl;
    void *pwqh, *pwql, *pc1h, *pc2h, *pwtr, *pwti;
    cudaGetSymbolAddress(&px, g_x);
    cudaGetSymbolAddress(&pq, g_q);
    cudaGetSymbolAddress(&pt, g_t);
    cudaGetSymbolAddress(&pxh, g_xh);
    cudaGetSymbolAddress(&pXh, g_Xh); cudaGetSymbolAddress(&pXl, g_Xl);
    cudaGetSymbolAddress(&pyh, g_yh);
    cudaGetSymbolAddress(&posh, g_osh); cudaGetSymbolAddress(&posl, g_osl);
    cudaGetSymbolAddress(&pwth, g_wth); cudaGetSymbolAddress(&pwtl, g_wtl);
    cudaGetSymbolAddress(&pwqh, g_wqh); cudaGetSymbolAddress(&pwql, g_wql);
    cudaGetSymbolAddress(&pc1h, g_c1h);
    cudaGetSymbolAddress(&pc2h, g_c2h);
    cudaGetSymbolAddress(&pwtr, g_wtr); cudaGetSymbolAddress(&pwti, g_wti);
    float* fx = (float*)px;
    float* fq = (float*)pq;
    float* ft = (float*)pt;
    __half *xh=(__half*)pxh;
    __half *Xh=(__half*)pXh, *Xl=(__half*)pXl;
    __half *yh=(__half*)pyh;
    __half *osh=(__half*)posh, *osl=(__half*)posl;
    __half *wth=(__half*)pwth, *wtl=(__half*)pwtl;
    __half *wqh=(__half*)pwqh, *wql=(__half*)pwql;
    __half *c1h=(__half*)pc1h;
    __half *c2h=(__half*)pc2h;
    float *wtr=(float*)pwtr, *wti=(float*)pwti;

    init_tables<<<64, 256>>>();
    convert_hl<<<(2*Dq*Dq + 255)/256, 256>>>(Wq, wqh, wql, 2*Dq*Dq);
    convert_hl<<<(2*DFF*Dq + 255)/256, 256>>>(conv1_w, c1h, nullptr, 2*DFF*Dq);
    convert_hl<<<(2*Dq*DFF + 255)/256, 256>>>(conv2_w, c2h, nullptr, 2*Dq*DFF);
    wotab_kernel<<<dim3(128, 2), 128>>>(Wo, wth, wtl);
    wtrans_kernel<<<1024, 256>>>(four_wr, four_wi);
    embed_kernel<<<BLq*Dq/256, 256>>>(x_app, x_time, app_emb_w, time_w, time_b);

    const int M = BLq;
    for (int l = 0; l < 2; l++) {
        size_t woff = (size_t)l*Dq*Dq;
        size_t coff1 = (size_t)l*DFF*Dq;
        size_t mixoff = (size_t)l*Hq*MODES*Eq*Eq;

        dftx_kernel<<<512, 128>>>(fx, Xh, Xl);
        gemm_mma<GF_OUTF32, 3><<<dim3(4, 32), 256, SMEM_GEMM>>>(
            Xh, Xl, wqh + woff, wql + woff, nullptr, nullptr,
            fq, nullptr, 4096, Dq, Dq, 1.0f);
        mix2_kernel<<<Hq*MODES, 256>>>(fq, wtr + mixoff, wti + mixoff,
                                       bq + l*Dq, osh, osl);
        gemm_mma<GF_BIAS|GF_RES|GF_OUTF32, 3><<<dim3(4, 256), 256, SMEM_GEMM>>>(
            osh, osl, wth + (size_t)l*Dq*64, wtl + (size_t)l*Dq*64, bo + l*Dq, fx,
            ft, nullptr, M, Dq, 64, 1.0f/65536.0f);
        decomp_kernel<<<512, 256>>>(ft, fx, xh);
        gemm_mma<GF_RELU|GF_OUTH16, 1><<<dim3(DFF/128, M/128), 256, SMEM_GEMM>>>(
            xh, nullptr, c1h + coff1, nullptr, nullptr, nullptr,
            nullptr, yh, M, DFF, Dq, 1.0f);
        gemm_mma<GF_RES|GF_OUTF32, 1><<<dim3(Dq/128, M/128), 256, SMEM_GEMM>>>(
            yh, nullptr, c2h + coff1, nullptr, nullptr, fx,
            ft, nullptr, M, Dq, DFF, 1.0f);
        // last decomp of last layer: xh is dead afterwards
        decomp_kernel<<<512, 256>>>(ft, fx, (l == 1) ? nullptr : xh);
    }

    ln_rows<<<BLq, 256>>>(fx);
    ln_cols_part<<<Bq*8, 512>>>(fx, norm_w, norm_b);
    ln_cols_fin<<<Bq, 512>>>(fx, norm_w, norm_b, time_vecs);
    proj_kernel<<<(NUM_APP + 63)/64, 256>>>(proj_w, proj_b, out);
}

// round 11
// speedup vs baseline: 4.6403x; 1.0434x over previous
#include <cuda_runtime.h>
#include <cuda_fp16.h>
#include <math.h>
#include <stdint.h>

#define Bq 64
#define Lq 512
#define Dq 512
#define Hq 8
#define Eq 64
#define DFF 2048
#define MODES 32
#define VOCAB 10000
#define NUM_APP 10000
#define CATD 536
#define BLq (Bq*Lq)

// ================= helpers =================
__device__ __forceinline__ uint32_t smem_u32(const void* p) {
    uint32_t a;
    asm("{ .reg .u64 t; cvta.to.shared.u64 t, %1; cvt.u32.u64 %0, t; }" : "=r"(a) : "l"(p));
    return a;
}
__device__ __forceinline__ void cp16(uint32_t dst, const void* src) {
    asm volatile("cp.async.cg.shared.global [%0], [%1], 16;" :: "r"(dst), "l"(src) : "memory");
}
#define CP_COMMIT() asm volatile("cp.async.commit_group;" ::: "memory")

#define LDSM_X4(r0,r1,r2,r3, addr) \
    asm volatile("ldmatrix.sync.aligned.m8n8.x4.shared.b16 {%0,%1,%2,%3}, [%4];" \
        : "=r"(r0), "=r"(r1), "=r"(r2), "=r"(r3) : "r"(addr))

#define MMA_F32(d, a, b0, b1) \
    asm volatile("mma.sync.aligned.m16n8k16.row.col.f32.f16.f16.f32 " \
        "{%0,%1,%2,%3},{%4,%5,%6,%7},{%8,%9},{%0,%1,%2,%3};" \
        : "+f"((d)[0]), "+f"((d)[1]), "+f"((d)[2]), "+f"((d)[3]) \
        : "r"((a)[0]), "r"((a)[1]), "r"((a)[2]), "r"((a)[3]), "r"(b0), "r"(b1))

// ================= scratch (device globals) =================
__device__ float g_x[BLq*Dq];
__device__ float g_q[BLq*Dq];
__device__ __align__(256) __half g_th[BLq*Dq];      // pre-decomp tensor, fp16
__device__ __align__(256) __half g_xh[BLq*Dq];
__device__ __align__(256) __half g_Xh[4096*Dq], g_Xl[4096*Dq];
__device__ __align__(256) __half g_yh[BLq*DFF];
__device__ __align__(256) __half g_osh[BLq*64], g_osl[BLq*64];
__device__ __align__(256) __half g_wth[2*Dq*64], g_wtl[2*Dq*64];
__device__ __align__(256) __half g_wqh[2*Dq*Dq], g_wql[2*Dq*Dq];
__device__ __align__(256) __half g_c1h[2*DFF*Dq];
__device__ __align__(256) __half g_c2h[2*Dq*DFF];
__device__ float g_wtr[2*Hq*MODES*Eq*Eq];
__device__ float g_wti[2*Hq*MODES*Eq*Eq];
__device__ float g_ct[Lq*MODES], g_st[Lq*MODES];
__device__ float g_mu[BLq], g_rs[BLq];
__device__ float g_part[8*Bq*Dq];
__device__ float g_cat[Bq*CATD];

// ================= small kernels =================
__global__ void init_tables() {
    int idx = blockIdx.x*blockDim.x + threadIdx.x;
    if (idx < Lq*MODES) {
        int l = idx >> 5, m = idx & 31;
        double a = (double)(m*l) / 256.0;
        double s, c;
        sincospi(a, &s, &c);
        g_ct[idx] = (float)c;
        g_st[idx] = (float)s;
    }
}

// one kernel: Wq hi/lo + c1 hi + c2 hi
#define NWQ (2*Dq*Dq)
#define NC1 (2*DFF*Dq)
#define NC2 (2*Dq*DFF)
__global__ void convert_all(const float* __restrict__ Wq, const float* __restrict__ c1,
                            const float* __restrict__ c2) {
    int i = blockIdx.x*256 + threadIdx.x;
    if (i < NWQ) {
        float v = Wq[i];
        __half hv = __float2half_rn(v);
        g_wqh[i] = hv;
        g_wql[i] = __float2half_rn(v - __half2float(hv));
    } else if (i < NWQ + NC1) {
        int j = i - NWQ;
        g_c1h[j] = __float2half_rn(c1[j]);
    } else if (i < NWQ + NC1 + NC2) {
        int j = i - NWQ - NC1;
        g_c2h[j] = __float2half_rn(c2[j]);
    }
}

__global__ void embed_kernel(const int* __restrict__ app, const float* __restrict__ xt,
                             const float* __restrict__ emb, const float* __restrict__ tw,
                             const float* __restrict__ tb) {
    int idx = blockIdx.x*256 + threadIdx.x;      // BLq*Dq/4 elements
    int d4 = (idx & 127) * 4;
    size_t bl = (size_t)(idx >> 7);
    int a = app[bl];
    float xtv = xt[bl];
    float4 e = *(const float4*)&emb[(size_t)a*Dq + d4];
    float4 w = *(const float4*)&tw[d4];
    float4 bb = *(const float4*)&tb[d4];
    float4 v;
    v.x = fmaf(xtv, w.x, e.x) + bb.x;
    v.y = fmaf(xtv, w.y, e.y) + bb.y;
    v.z = fmaf(xtv, w.z, e.z) + bb.z;
    v.w = fmaf(xtv, w.w, e.w) + bb.w;
    *(float4*)&g_x[bl*Dq + d4] = v;
}

// ========== transpose four_wr/wi ==========
__global__ void __launch_bounds__(256) wtrans_kernel(const float* __restrict__ wr,
                                                     const float* __restrict__ wi) {
    int blk = blockIdx.x;
    int i  = blk & 63;
    int lh = blk >> 6;
    __shared__ float tr[64][33], ti_[64][33];
    int t = threadIdx.x;
    const float* pr = wr + ((size_t)lh*64 + i)*64*32;
    const float* pi = wi + ((size_t)lh*64 + i)*64*32;
    #pragma unroll
    for (int j = 0; j < 8; j++) {
        int v = t + j*256;
        int o = v >> 5, m = v & 31;
        tr[o][m]  = pr[v];
        ti_[o][m] = pi[v];
    }
    __syncthreads();
    #pragma unroll
    for (int j = 0; j < 8; j++) {
        int v = t + j*256;
        int m = v >> 6, o = v & 63;
        size_t dst = ((size_t)(lh*32 + m)*64 + i)*64 + o;
        g_wtr[dst] = tr[o][m];
        g_wti[dst] = ti_[o][m];
    }
}

// ========== Wo frequency table ==========
__global__ void __launch_bounds__(128) wotab_kernel(const float* __restrict__ Wo,
                                                    __half* __restrict__ wth,
                                                    __half* __restrict__ wtl) {
    int layer = blockIdx.y;
    int j0 = blockIdx.x * 4;
    __shared__ float sw[4][512];
    int t = threadIdx.x;
    const float* wo = Wo + (size_t)layer*Dq*Dq + (size_t)j0*Dq;
    #pragma unroll
    for (int j = 0; j < 4; j++) {
        int v = t + j*128;
        int r = v >> 7, c4 = (v & 127) * 4;
        *(float4*)&sw[r][c4] = *(const float4*)&wo[(size_t)r*Dq + c4];
    }
    __syncthreads();
    int tj = t >> 5, tm = t & 31;
    float ac = 0.f, as = 0.f;
    for (int l = 0; l < Lq; l++) {
        float w = sw[tj][l];
        ac = fmaf(w, g_ct[l*32 + tm], ac);
        as = fmaf(w, g_st[l*32 + tm], as);
    }
    float cm = (tm == 0 ? 1.0f : 2.0f) * (256.0f/512.0f);
    float vc = ac*cm, vs = -as*cm;
    size_t base = ((size_t)layer*Dq + j0 + tj)*64 + tm*2;
    __half hc = __float2half_rn(vc);
    __half hs = __float2half_rn(vs);
    wth[base]   = hc;  wtl[base]   = __float2half_rn(vc - __half2float(hc));
    wth[base+1] = hs;  wtl[base+1] = __float2half_rn(vs - __half2float(hs));
}

// ================= mma.sync fp16 GEMM: C = A(MxK) @ B(NxK)^T =============
#define GF_BIAS 1
#define GF_RES  2
#define GF_RELU 4
#define GF_OUTF32 8
#define GF_OUTH16 16

#define STG 32768
#define SMEM_GEMM (3*STG + 256)

template<int FLAGS, int TERMS>
__global__ void __launch_bounds__(256, 1) gemm_mma(
    const __half* __restrict__ Ah, const __half* __restrict__ Al,
    const __half* __restrict__ Bh, const __half* __restrict__ Bl,
    const float* __restrict__ bias, const float* __restrict__ res,
    float* __restrict__ Cf, __half* __restrict__ Ch,
    int M, int N, int K, float scal)
{
    extern __shared__ char dsm[];
    uint32_t sbase = (smem_u32(dsm) + 127) & ~127u;

    const int t = threadIdx.x;
    const int lane = t & 31;
    const int wid = t >> 5;
    const int wm = wid >> 2;
    const int wn = wid & 3;
    const int bm = blockIdx.y * 128, bn = blockIdx.x * 128;
    const int NC = K >> 5;

    float acc[4][4][4] = {};

    const int lrow = t >> 2;
    const int lcell = t & 3;
    auto load_chunk = [&](int c, int stg) {
        uint32_t sb = sbase + stg*STG;
        size_t k0 = (size_t)c * 32 + lcell*8;
        #pragma unroll
        for (int j = 0; j < 2; j++) {
            int row = lrow + j*64;
            uint32_t soff = row*64 + (((uint32_t)(lcell ^ (row & 3))) << 4);
            size_t ga = (size_t)(bm + row)*K + k0;
            size_t gb = (size_t)(bn + row)*K + k0;
            cp16(sb +         soff, Ah + ga);
            if (TERMS == 3) cp16(sb + 8192 + soff, Al + ga);
            cp16(sb + 16384 + soff, Bh + gb);
            if (TERMS >= 2) cp16(sb + 24576 + soff, Bl + gb);
        }
        CP_COMMIT();
    };

    load_chunk(0, 0);
    if (NC > 1) load_chunk(1, 1);

    const int arow_base = wm*64 + (lane & 15);
    const int brow_base = wn*32 + (lane & 15);
    const int kc_hi = lane >> 4;

    for (int c = 0; c < NC; c++) {
        if (c + 2 < NC) asm volatile("cp.async.wait_group 1;" ::: "memory");
        else            asm volatile("cp.async.wait_group 0;" ::: "memory");
        __syncthreads();
        if (c + 2 < NC) load_chunk(c + 2, (c + 2) % 3);

        uint32_t sb = sbase + (c % 3)*STG;
        #pragma unroll
        for (int s = 0; s < 2; s++) {
            uint32_t ah[4][4], al[4][4], bh[2][4], bl[2][4];
            int chunk = s*2 + kc_hi;
            #pragma unroll
            for (int mt = 0; mt < 4; mt++) {
                int row = arow_base + mt*16;
                uint32_t off = row*64 + (((uint32_t)(chunk ^ (row & 3))) << 4);
                LDSM_X4(ah[mt][0], ah[mt][1], ah[mt][2], ah[mt][3], sb + off);
                if (TERMS == 3)
                    LDSM_X4(al[mt][0], al[mt][1], al[mt][2], al[mt][3], sb + 8192 + off);
            }
            #pragma unroll
            for (int g = 0; g < 2; g++) {
                int row = brow_base + g*16;
                uint32_t off = row*64 + (((uint32_t)(chunk ^ (row & 3))) << 4);
                LDSM_X4(bh[g][0], bh[g][1], bh[g][2], bh[g][3], sb + 16384 + off);
                if (TERMS >= 2)
                    LDSM_X4(bl[g][0], bl[g][1], bl[g][2], bl[g][3], sb + 24576 + off);
            }
            #pragma unroll
            for (int mt = 0; mt < 4; mt++) {
                #pragma unroll
                for (int nt = 0; nt < 4; nt++) {
                    int g = nt >> 1, o = nt & 1;
                    MMA_F32(acc[mt][nt], ah[mt], bh[g][o], bh[g][o+2]);
                    if (TERMS >= 2)
                        MMA_F32(acc[mt][nt], ah[mt], bl[g][o], bl[g][o+2]);
                    if (TERMS == 3)
                        MMA_F32(acc[mt][nt], al[mt], bh[g][o], bh[g][o+2]);
                }
            }
        }
    }

    int r0 = bm + wm*64 + (lane >> 2);
    int c0 = bn + wn*32 + (lane & 3)*2;
    #pragma unroll
    for (int mt = 0; mt < 4; mt++) {
        #pragma unroll
        for (int nt = 0; nt < 4; nt++) {
            int col = c0 + nt*8;
            float b0 = 0.f, b1 = 0.f;
            if (FLAGS & GF_BIAS) { b0 = bias[col]; b1 = bias[col+1]; }
            #pragma unroll
            for (int half = 0; half < 2; half++) {
                int row = r0 + mt*16 + half*8;
                float v0 = acc[mt][nt][half*2+0] * scal + b0;
                float v1 = acc[mt][nt][half*2+1] * scal + b1;
                size_t ro = (size_t)row * N + col;
                if (FLAGS & GF_RES) {
                    float2 r2 = *(const float2*)&res[ro];
                    v0 += r2.x; v1 += r2.y;
                }
                if (FLAGS & GF_RELU) { v0 = fmaxf(v0, 0.f); v1 = fmaxf(v1, 0.f); }
                if (FLAGS & GF_OUTF32) {
                    float2 o2; o2.x = v0; o2.y = v1;
                    *(float2*)&Cf[ro] = o2;
                }
                if (FLAGS & GF_OUTH16) {
                    __half2 hp; hp.x = __float2half_rn(v0); hp.y = __float2half_rn(v1);
                    *(__half2*)&Ch[ro] = hp;
                }
            }
        }
    }
}

// ========== DFT of x with l/l+256 symmetry ==========
__global__ void __launch_bounds__(128) dftx_kernel(const float* __restrict__ x,
                                                   __half* __restrict__ Xh,
                                                   __half* __restrict__ Xl) {
    int blk = blockIdx.x;
    int b = blk >> 3;
    int dchunk = (blk & 7) * 64;
    __shared__ float sqA[32][68];
    __shared__ float sqB[32][68];
    __shared__ float sct[32][32];
    __shared__ float sst[32][32];
    int t = threadIdx.x;
    int td = t & 63;
    int tm = (t >> 6) * 16;

    float ar[16] = {}, ai[16] = {};
    const float* qbase = x + (size_t)b*Lq*Dq + dchunk;

    for (int l0 = 0; l0 < 256; l0 += 32) {
        #pragma unroll
        for (int j = 0; j < 4; j++) {
            int v = t + j*128;
            int ll = v >> 4;
            int c4 = (v & 15) * 4;
            *(float4*)&sqA[ll][c4] = *(const float4*)&qbase[(size_t)(l0+ll)*Dq + c4];
            *(float4*)&sqB[ll][c4] = *(const float4*)&qbase[(size_t)(l0+256+ll)*Dq + c4];
        }
        #pragma unroll
        for (int j = 0; j < 2; j++) {
            int v = t + j*128;
            int ll = v >> 3;
            int c4 = (v & 7) * 4;
            *(float4*)&sct[ll][c4] = *(const float4*)&g_ct[(l0+ll)*32 + c4];
            *(float4*)&sst[ll][c4] = *(const float4*)&g_st[(l0+ll)*32 + c4];
        }
        __syncthreads();
        #pragma unroll 2
        for (int ll = 0; ll < 32; ll++) {
            float xa = sqA[ll][td], xb = sqB[ll][td];
            float u = xa + xb;
            float w = xa - xb;
            float c[16], s[16];
            #pragma unroll
            for (int j = 0; j < 16; j += 4) {
                *(float4*)&c[j] = *(float4*)&sct[ll][tm+j];
                *(float4*)&s[j] = *(float4*)&sst[ll][tm+j];
            }
            #pragma unroll
            for (int mm = 0; mm < 16; mm++) {
                float v = (mm & 1) ? w : u;
                ar[mm] = fmaf(v,  c[mm], ar[mm]);
                ai[mm] = fmaf(-v, s[mm], ai[mm]);
            }
        }
        __syncthreads();
    }
    int d0 = dchunk + td;
    #pragma unroll
    for (int mm = 0; mm < 16; mm++) {
        int m = tm + mm;
        float vr = ar[mm], vi = ai[mm];
        __half hr = __float2half_rn(vr);
        __half hi_ = __float2half_rn(vi);
        size_t rowr = ((size_t)(m*2+0)*64 + b)*Dq + d0;
        size_t rowi = ((size_t)(m*2+1)*64 + b)*Dq + d0;
        Xh[rowr] = hr;   Xl[rowr] = __float2half_rn(vr - __half2float(hr));
        Xh[rowi] = hi_;  Xl[rowi] = __float2half_rn(vi - __half2float(hi_));
    }
}

// ========== complex mode mix ==========
__global__ void __launch_bounds__(256) mix2_kernel(const float* __restrict__ xs,
                                                   const float* __restrict__ wtr,
                                                   const float* __restrict__ wti,
                                                   const float* __restrict__ bq,
                                                   __half* __restrict__ osh,
                                                   __half* __restrict__ osl) {
    int h = blockIdx.x >> 5, m = blockIdx.x & 31;
    __shared__ float swr[64][64];
    __shared__ float swi[64][64];
    __shared__ float sxr[64][65];
    __shared__ float sxi[64][65];
    int t = threadIdx.x;
    const float* pr = wtr + ((size_t)(h*32 + m))*4096;
    const float* pi = wti + ((size_t)(h*32 + m))*4096;
    #pragma unroll
    for (int j = 0; j < 16; j++) {
        int v = t + j*256;
        int r = v >> 6, c = v & 63;
        swr[r][c] = pr[v];
        swi[r][c] = pi[v];
    }
    #pragma unroll
    for (int j = 0; j < 16; j++) {
        int v = t + j*256;
        int b = v >> 6, i = v & 63;
        if (j < 8) {
            float vr = xs[((size_t)(2*m)*64 + b)*Dq + h*64 + i];
            if (m == 0) vr += 512.0f * bq[h*64 + i];
            sxr[b][i] = vr;
        } else {
            sxi[b][i] = xs[((size_t)(2*m+1)*64 + b)*Dq + h*64 + i];
        }
    }
    __syncthreads();

    int b = t >> 2;
    int o0 = (t & 3) * 16;
    float orr[16] = {}, oii[16] = {};
    for (int i = 0; i < 64; i++) {
        float xr = sxr[b][i], xi = sxi[b][i];
        float wr4[16], wi4[16];
        #pragma unroll
        for (int j = 0; j < 16; j += 4) {
            *(float4*)&wr4[j] = *(float4*)&swr[i][o0+j];
            *(float4*)&wi4[j] = *(float4*)&swi[i][o0+j];
        }
        #pragma unroll
        for (int j = 0; j < 16; j++) {
            orr[j] = fmaf(xr, wr4[j], orr[j]);
            orr[j] = fmaf(-xi, wi4[j], orr[j]);
            oii[j] = fmaf(xr, wi4[j], oii[j]);
            oii[j] = fmaf(xi, wr4[j], oii[j]);
        }
    }
    #pragma unroll
    for (int j = 0; j < 16; j++) {
        int o = o0 + j;
        float vr = orr[j] * 256.0f;
        float vi = oii[j] * 256.0f;
        __half hr = __float2half_rn(vr);
        __half hi_ = __float2half_rn(vi);
        size_t base = ((size_t)b*512 + h*64 + o)*64 + 2*m;
        __half2 hp; hp.x = hr; hp.y = hi_;
        *(__half2*)&osh[base] = hp;
        __half2 lp;
        lp.x = __float2half_rn(vr - __half2float(hr));
        lp.y = __float2half_rn(vi - __half2float(hi_));
        *(__half2*)&osl[base] = lp;
    }
}

// ========== series_decomp: half in, fp32 + half out; 8-way L-split, float2 ====
__global__ void decomp_kernel(const __half* __restrict__ in, float* __restrict__ out,
                              __half* __restrict__ oh) {
    int gid = blockIdx.x*blockDim.x + threadIdx.x;   // 131072 threads
    int seg = gid >> 14;            // 0..7
    int r = gid & 16383;
    int b = r >> 8, d2 = (r & 255) * 2;
    const __half2* p = (const __half2*)(in + (size_t)b*Lq*Dq + d2);  // stride 256 half2
    size_t obase = (size_t)b*Lq*Dq + d2;
    int lstart = seg * 64;
    float2 ws; ws.x = 0.f; ws.y = 0.f;
    #pragma unroll
    for (int j = -12; j <= 12; j++) {
        int jj = lstart + j;
        jj = jj < 0 ? 0 : jj;
        float2 q = __half22float2(p[(size_t)jj*256]);
        ws.x += q.x; ws.y += q.y;
    }
    int lend = lstart + 64;
    if (oh) {
        for (int l = lstart; l < lend; l++) {
            float2 xl = __half22float2(p[(size_t)l*256]);
            float2 v;
            v.x = xl.x - ws.x*(1.0f/25.0f);
            v.y = xl.y - ws.y*(1.0f/25.0f);
            *(float2*)&out[obase + (size_t)l*Dq] = v;
            __half2 hv; hv.x = __float2half_rn(v.x); hv.y = __float2half_rn(v.y);
            *(__half2*)&oh[obase + (size_t)l*Dq] = hv;
            int jn = l+13 > Lq-1 ? Lq-1 : l+13;
            int jo = l-12 < 0 ? 0 : l-12;
            float2 a = __half22float2(p[(size_t)jn*256]);
            float2 bb = __half22float2(p[(size_t)jo*256]);
            ws.x += a.x - bb.x; ws.y += a.y - bb.y;
        }
    } else {
        for (int l = lstart; l < lend; l++) {
            float2 xl = __half22float2(p[(size_t)l*256]);
            float2 v;
            v.x = xl.x - ws.x*(1.0f/25.0f);
            v.y = xl.y - ws.y*(1.0f/25.0f);
            *(float2*)&out[obase + (size_t)l*Dq] = v;
            int jn = l+13 > Lq-1 ? Lq-1 : l+13;
            int jo = l-12 < 0 ? 0 : l-12;
            float2 a = __half22float2(p[(size_t)jn*256]);
            float2 bb = __half22float2(p[(size_t)jo*256]);
            ws.x += a.x - bb.x; ws.y += a.y - bb.y;
        }
    }
}

// ================= final layernorm / projection =================
__global__ void ln_rows(const float* __restrict__ x) {
    int row = blockIdx.x;
    int t = threadIdx.x;
    const float* p = x + (size_t)row*Dq;
    float v0 = p[t], v1 = p[t+256];
    __shared__ float sh[8];
    float s = v0 + v1;
    int lane = t & 31, w = t >> 5;
    #pragma unroll
    for (int o = 16; o > 0; o >>= 1) s += __shfl_down_sync(~0u, s, o);
    if (lane == 0) sh[w] = s;
    __syncthreads();
    if (t < 32) {
        float v = (t < 8) ? sh[t] : 0.f;
        #pragma unroll
        for (int o = 4; o > 0; o >>= 1) v += __shfl_down_sync(~0u, v, o);
        if (t == 0) sh[0] = v;
    }
    __syncthreads();
    float mu = sh[0] * (1.0f/512.0f);
    __syncthreads();
    float d0 = v0 - mu, d1 = v1 - mu;
    s = d0*d0 + d1*d1;
    #pragma unroll
    for (int o = 16; o > 0; o >>= 1) s += __shfl_down_sync(~0u, s, o);
    if (lane == 0) sh[w] = s;
    __syncthreads();
    if (t < 32) {
        float v = (t < 8) ? sh[t] : 0.f;
        #pragma unroll
        for (int o = 4; o > 0; o >>= 1) v += __shfl_down_sync(~0u, v, o);
        if (t == 0) {
            float var = v * (1.0f/512.0f);
            g_mu[row] = mu;
            g_rs[row] = rsqrtf(var + 1e-5f);
        }
    }
}

__global__ void ln_cols_part(const float* __restrict__ x, const float* __restrict__ nw,
                             const float* __restrict__ nb) {
    int blk = blockIdx.x;
    int b = blk >> 3, seg = blk & 7;
    int d = threadIdx.x;
    float w = nw[d], bb = nb[d];
    float sum = 0.f;
    int l0 = seg * 64;
    #pragma unroll 4
    for (int l = l0; l < l0 + 64; l++) {
        int row = b*Lq + l;
        sum += (x[(size_t)row*Dq + d] - g_mu[row]) * g_rs[row] * w + bb;
    }
    g_part[(size_t)seg*Bq*Dq + b*Dq + d] = sum;
}

__global__ void ln_cols_fin(const float* __restrict__ x, const float* __restrict__ nw,
                            const float* __restrict__ nb, const float* __restrict__ tv) {
    int b = blockIdx.x;
    int d = threadIdx.x;
    float sum = 0.f;
    #pragma unroll
    for (int seg = 0; seg < 8; seg++)
        sum += g_part[(size_t)seg*Bq*Dq + b*Dq + d];
    int row = b*Lq + (Lq-1);
    float lastv = (x[(size_t)row*Dq + d] - g_mu[row]) * g_rs[row] * nw[d] + nb[d];
    g_cat[b*CATD + d] = lastv - sum*(1.0f/512.0f);
    if (d < 24) g_cat[b*CATD + 512 + d] = tv[((size_t)b*Lq + (Lq-1))*24 + d];
}

__global__ void __launch_bounds__(256) proj_kernel(const float* __restrict__ pw,
                                                   const float* __restrict__ pb,
                                                   float* __restrict__ out) {
    __shared__ float As[8][65];
    __shared__ float Bs[8][65];
    int n0 = blockIdx.x * 64;
    int t = threadIdx.x;
    int tx = t & 15, ty = t >> 4;
    float acc[4][4] = {};
    for (int k0 = 0; k0 < CATD; k0 += 8) {
        int v = t*2;
        int r = v >> 3, c = v & 7;
        As[c][r]   = g_cat[r*CATD + k0 + c];
        As[c+1][r] = g_cat[r*CATD + k0 + c + 1];
        int n = n0 + r;
        float f0 = 0.f, f1 = 0.f;
        if (n < NUM_APP) {
            f0 = pw[(size_t)n*CATD + k0 + c];
            f1 = pw[(size_t)n*CATD + k0 + c + 1];
        }
        Bs[c][r] = f0; Bs[c+1][r] = f1;
        __syncthreads();
        #pragma unroll
        for (int k = 0; k < 8; k++) {
            float a[4], bv[4];
            #pragma unroll
            for (int i = 0; i < 4; i++) { a[i] = As[k][ty*4+i]; bv[i] = Bs[k][tx*4+i]; }
            #pragma unroll
            for (int i = 0; i < 4; i++)
                #pragma unroll
                for (int j = 0; j < 4; j++)
                    acc[i][j] = fmaf(a[i], bv[j], acc[i][j]);
        }
        __syncthreads();
    }
    #pragma unroll
    for (int i = 0; i < 4; i++) {
        int bi = ty*4 + i;
        #pragma unroll
        for (int j = 0; j < 4; j++) {
            int n = n0 + tx*4 + j;
            if (n < NUM_APP) out[(size_t)bi*NUM_APP + n] = acc[i][j] + pb[n];
        }
    }
}

// ================= host orchestration =================
extern "C" void kernel_launch(void* const* d_in, const int* in_sizes, int n_in,
                              void* d_out, int out_size) {
    const int*   x_app     = (const int*)  d_in[0];
    const float* x_time    = (const float*)d_in[1];
    const float* time_vecs = (const float*)d_in[2];
    const float* app_emb_w = (const float*)d_in[4];
    const float* time_w    = (const float*)d_in[5];
    const float* time_b    = (const float*)d_in[6];
    const float* Wq        = (const float*)d_in[7];
    const float* bq        = (const float*)d_in[8];
    const float* Wo        = (const float*)d_in[9];
    const float* bo        = (const float*)d_in[10];
    const float* four_wr   = (const float*)d_in[11];
    const float* four_wi   = (const float*)d_in[12];
    const float* conv1_w   = (const float*)d_in[13];
    const float* conv2_w   = (const float*)d_in[14];
    const float* norm_w    = (const float*)d_in[15];
    const float* norm_b    = (const float*)d_in[16];
    const float* proj_w    = (const float*)d_in[17];
    const float* proj_b    = (const float*)d_in[18];
    float* out = (float*)d_out;

    cudaFuncSetAttribute((const void*)gemm_mma<GF_OUTF32, 3>,                cudaFuncAttributeMaxDynamicSharedMemorySize, SMEM_GEMM);
    cudaFuncSetAttribute((const void*)gemm_mma<GF_BIAS|GF_RES|GF_OUTH16, 3>, cudaFuncAttributeMaxDynamicSharedMemorySize, SMEM_GEMM);
    cudaFuncSetAttribute((const void*)gemm_mma<GF_RELU|GF_OUTH16, 1>,        cudaFuncAttributeMaxDynamicSharedMemorySize, SMEM_GEMM);
    cudaFuncSetAttribute((const void*)gemm_mma<GF_RES|GF_OUTH16, 1>,         cudaFuncAttributeMaxDynamicSharedMemorySize, SMEM_GEMM);

    void *px, *pq, *pth;
    void *pxh, *pXh, *pXl, *pyh, *posh, *posl, *pwth, *pwtl;
    void *pwqh, *pwql, *pc1h, *pc2h, *pwtr, *pwti;
    cudaGetSymbolAddress(&px, g_x);
    cudaGetSymbolAddress(&pq, g_q);
    cudaGetSymbolAddress(&pth, g_th);
    cudaGetSymbolAddress(&pxh, g_xh);
    cudaGetSymbolAddress(&pXh, g_Xh); cudaGetSymbolAddress(&pXl, g_Xl);
    cudaGetSymbolAddress(&pyh, g_yh);
    cudaGetSymbolAddress(&posh, g_osh); cudaGetSymbolAddress(&posl, g_osl);
    cudaGetSymbolAddress(&pwth, g_wth); cudaGetSymbolAddress(&pwtl, g_wtl);
    cudaGetSymbolAddress(&pwqh, g_wqh); cudaGetSymbolAddress(&pwql, g_wql);
    cudaGetSymbolAddress(&pc1h, g_c1h);
    cudaGetSymbolAddress(&pc2h, g_c2h);
    cudaGetSymbolAddress(&pwtr, g_wtr); cudaGetSymbolAddress(&pwti, g_wti);
    float* fx = (float*)px;
    float* fq = (float*)pq;
    __half* th = (__half*)pth;
    __half *xh=(__half*)pxh;
    __half *Xh=(__half*)pXh, *Xl=(__half*)pXl;
    __half *yh=(__half*)pyh;
    __half *osh=(__half*)posh, *osl=(__half*)posl;
    __half *wth=(__half*)pwth, *wtl=(__half*)pwtl;
    __half *wqh=(__half*)pwqh, *wql=(__half*)pwql;
    __half *c1h=(__half*)pc1h;
    __half *c2h=(__half*)pc2h;
    float *wtr=(float*)pwtr, *wti=(float*)pwti;

    init_tables<<<64, 256>>>();
    convert_all<<<(NWQ + NC1 + NC2 + 255)/256, 256>>>(Wq, conv1_w, conv2_w);
    wotab_kernel<<<dim3(128, 2), 128>>>(Wo, wth, wtl);
    wtrans_kernel<<<1024, 256>>>(four_wr, four_wi);
    embed_kernel<<<BLq*Dq/4/256, 256>>>(x_app, x_time, app_emb_w, time_w, time_b);

    const int M = BLq;
    for (int l = 0; l < 2; l++) {
        size_t woff = (size_t)l*Dq*Dq;
        size_t coff1 = (size_t)l*DFF*Dq;
        size_t mixoff = (size_t)l*Hq*MODES*Eq*Eq;

        dftx_kernel<<<512, 128>>>(fx, Xh, Xl);
        gemm_mma<GF_OUTF32, 3><<<dim3(4, 32), 256, SMEM_GEMM>>>(
            Xh, Xl, wqh + woff, wql + woff, nullptr, nullptr,
            fq, nullptr, 4096, Dq, Dq, 1.0f);
        mix2_kernel<<<Hq*MODES, 256>>>(fq, wtr + mixoff, wti + mixoff,
                                       bq + l*Dq, osh, osl);
        // new_x = os @ WoT^T * (1/65536) + bo + x  -> half tensor th
        gemm_mma<GF_BIAS|GF_RES|GF_OUTH16, 3><<<dim3(4, 256), 256, SMEM_GEMM>>>(
            osh, osl, wth + (size_t)l*Dq*64, wtl + (size_t)l*Dq*64, bo + l*Dq, fx,
            nullptr, th, M, Dq, 64, 1.0f/65536.0f);
        decomp_kernel<<<512, 256>>>(th, fx, xh);
        gemm_mma<GF_RELU|GF_OUTH16, 1><<<dim3(DFF/128, M/128), 256, SMEM_GEMM>>>(
            xh, nullptr, c1h + coff1, nullptr, nullptr, nullptr,
            nullptr, yh, M, DFF, Dq, 1.0f);
        // t = y @ c2^T + x -> half tensor th
        gemm_mma<GF_RES|GF_OUTH16, 1><<<dim3(Dq/128, M/128), 256, SMEM_GEMM>>>(
            yh, nullptr, c2h + coff1, nullptr, nullptr, fx,
            nullptr, th, M, Dq, DFF, 1.0f);
        decomp_kernel<<<512, 256>>>(th, fx, (l == 1) ? nullptr : xh);
    }

    ln_rows<<<BLq, 256>>>(fx);
    ln_cols_part<<<Bq*8, 512>>>(fx, norm_w, norm_b);
    ln_cols_fin<<<Bq, 512>>>(fx, norm_w, norm_b, time_vecs);
    proj_kernel<<<(NUM_APP + 63)/64, 256>>>(proj_w, proj_b, out);
}

// round 12
// speedup vs baseline: 5.1542x; 1.1108x over previous
#include <cuda_runtime.h>
#include <cuda_fp16.h>
#include <math.h>
#include <stdint.h>

#define Bq 64
#define Lq 512
#define Dq 512
#define Hq 8
#define Eq 64
#define DFF 2048
#define MODES 32
#define VOCAB 10000
#define NUM_APP 10000
#define CATD 536
#define BLq (Bq*Lq)

// ================= helpers =================
__device__ __forceinline__ uint32_t smem_u32(const void* p) {
    uint32_t a;
    asm("{ .reg .u64 t; cvta.to.shared.u64 t, %1; cvt.u32.u64 %0, t; }" : "=r"(a) : "l"(p));
    return a;
}
__device__ __forceinline__ void cp16(uint32_t dst, const void* src) {
    asm volatile("cp.async.cg.shared.global [%0], [%1], 16;" :: "r"(dst), "l"(src) : "memory");
}
#define CP_COMMIT() asm volatile("cp.async.commit_group;" ::: "memory")

#define LDSM_X4(r0,r1,r2,r3, addr) \
    asm volatile("ldmatrix.sync.aligned.m8n8.x4.shared.b16 {%0,%1,%2,%3}, [%4];" \
        : "=r"(r0), "=r"(r1), "=r"(r2), "=r"(r3) : "r"(addr))

#define MMA_F32(d, a, b0, b1) \
    asm volatile("mma.sync.aligned.m16n8k16.row.col.f32.f16.f16.f32 " \
        "{%0,%1,%2,%3},{%4,%5,%6,%7},{%8,%9},{%0,%1,%2,%3};" \
        : "+f"((d)[0]), "+f"((d)[1]), "+f"((d)[2]), "+f"((d)[3]) \
        : "r"((a)[0]), "r"((a)[1]), "r"((a)[2]), "r"((a)[3]), "r"(b0), "r"(b1))

// ================= scratch (device globals) =================
__device__ float g_x[BLq*Dq];                        // only final-layer x (for ln)
__device__ float g_q[BLq*Dq];
__device__ __align__(256) __half g_th[BLq*Dq];       // pre-decomp tensor, fp16
__device__ __align__(256) __half g_xh[BLq*Dq];       // activation x, fp16
__device__ __align__(256) __half g_Xh[4096*Dq], g_Xl[4096*Dq];
__device__ __align__(256) __half g_yh[BLq*DFF];
__device__ __align__(256) __half g_osh[BLq*64], g_osl[BLq*64];
__device__ __align__(256) __half g_wth[2*Dq*64], g_wtl[2*Dq*64];
__device__ __align__(256) __half g_wqh[2*Dq*Dq], g_wql[2*Dq*Dq];
__device__ __align__(256) __half g_c1h[2*DFF*Dq];
__device__ __align__(256) __half g_c2h[2*Dq*DFF];
__device__ float g_wtr[2*Hq*MODES*Eq*Eq];
__device__ float g_wti[2*Hq*MODES*Eq*Eq];
__device__ float g_ct[Lq*MODES], g_st[Lq*MODES];
__device__ float g_mu[BLq], g_rs[BLq];
__device__ float g_part[8*Bq*Dq];
__device__ float g_cat[Bq*CATD];

// ================= small kernels =================
__global__ void init_tables() {
    int idx = blockIdx.x*blockDim.x + threadIdx.x;
    if (idx < Lq*MODES) {
        int l = idx >> 5, m = idx & 31;
        double a = (double)(m*l) / 256.0;
        double s, c;
        sincospi(a, &s, &c);
        g_ct[idx] = (float)c;
        g_st[idx] = (float)s;
    }
}

#define NWQ (2*Dq*Dq)
#define NC1 (2*DFF*Dq)
#define NC2 (2*Dq*DFF)
__global__ void convert_all(const float* __restrict__ Wq, const float* __restrict__ c1,
                            const float* __restrict__ c2) {
    int i = blockIdx.x*256 + threadIdx.x;
    if (i < NWQ) {
        float v = Wq[i];
        __half hv = __float2half_rn(v);
        g_wqh[i] = hv;
        g_wql[i] = __float2half_rn(v - __half2float(hv));
    } else if (i < NWQ + NC1) {
        int j = i - NWQ;
        g_c1h[j] = __float2half_rn(c1[j]);
    } else if (i < NWQ + NC1 + NC2) {
        int j = i - NWQ - NC1;
        g_c2h[j] = __float2half_rn(c2[j]);
    }
}

// embed -> xh (half only)
__global__ void embed_kernel(const int* __restrict__ app, const float* __restrict__ xt,
                             const float* __restrict__ emb, const float* __restrict__ tw,
                             const float* __restrict__ tb) {
    int idx = blockIdx.x*256 + threadIdx.x;      // BLq*Dq/4 elements
    int d4 = (idx & 127) * 4;
    size_t bl = (size_t)(idx >> 7);
    int a = app[bl];
    float xtv = xt[bl];
    float4 e = *(const float4*)&emb[(size_t)a*Dq + d4];
    float4 w = *(const float4*)&tw[d4];
    float4 bb = *(const float4*)&tb[d4];
    __half2 h0, h1;
    h0.x = __float2half_rn(fmaf(xtv, w.x, e.x) + bb.x);
    h0.y = __float2half_rn(fmaf(xtv, w.y, e.y) + bb.y);
    h1.x = __float2half_rn(fmaf(xtv, w.z, e.z) + bb.z);
    h1.y = __float2half_rn(fmaf(xtv, w.w, e.w) + bb.w);
    *(__half2*)&g_xh[bl*Dq + d4]     = h0;
    *(__half2*)&g_xh[bl*Dq + d4 + 2] = h1;
}

// ========== transpose four_wr/wi ==========
__global__ void __launch_bounds__(256) wtrans_kernel(const float* __restrict__ wr,
                                                     const float* __restrict__ wi) {
    int blk = blockIdx.x;
    int i  = blk & 63;
    int lh = blk >> 6;
    __shared__ float tr[64][33], ti_[64][33];
    int t = threadIdx.x;
    const float* pr = wr + ((size_t)lh*64 + i)*64*32;
    const float* pi = wi + ((size_t)lh*64 + i)*64*32;
    #pragma unroll
    for (int j = 0; j < 8; j++) {
        int v = t + j*256;
        int o = v >> 5, m = v & 31;
        tr[o][m]  = pr[v];
        ti_[o][m] = pi[v];
    }
    __syncthreads();
    #pragma unroll
    for (int j = 0; j < 8; j++) {
        int v = t + j*256;
        int m = v >> 6, o = v & 63;
        size_t dst = ((size_t)(lh*32 + m)*64 + i)*64 + o;
        g_wtr[dst] = tr[o][m];
        g_wti[dst] = ti_[o][m];
    }
}

// ========== Wo frequency table ==========
__global__ void __launch_bounds__(128) wotab_kernel(const float* __restrict__ Wo,
                                                    __half* __restrict__ wth,
                                                    __half* __restrict__ wtl) {
    int layer = blockIdx.y;
    int j0 = blockIdx.x * 4;
    __shared__ float sw[4][512];
    int t = threadIdx.x;
    const float* wo = Wo + (size_t)layer*Dq*Dq + (size_t)j0*Dq;
    #pragma unroll
    for (int j = 0; j < 4; j++) {
        int v = t + j*128;
        int r = v >> 7, c4 = (v & 127) * 4;
        *(float4*)&sw[r][c4] = *(const float4*)&wo[(size_t)r*Dq + c4];
    }
    __syncthreads();
    int tj = t >> 5, tm = t & 31;
    float ac = 0.f, as = 0.f;
    for (int l = 0; l < Lq; l++) {
        float w = sw[tj][l];
        ac = fmaf(w, g_ct[l*32 + tm], ac);
        as = fmaf(w, g_st[l*32 + tm], as);
    }
    float cm = (tm == 0 ? 1.0f : 2.0f) * (256.0f/512.0f);
    float vc = ac*cm, vs = -as*cm;
    size_t base = ((size_t)layer*Dq + j0 + tj)*64 + tm*2;
    __half hc = __float2half_rn(vc);
    __half hs = __float2half_rn(vs);
    wth[base]   = hc;  wtl[base]   = __float2half_rn(vc - __half2float(hc));
    wth[base+1] = hs;  wtl[base+1] = __float2half_rn(vs - __half2float(hs));
}

// ================= mma.sync fp16 GEMM: C = A(MxK) @ B(NxK)^T =============
// residual is fp16 now
#define GF_BIAS 1
#define GF_RES  2
#define GF_RELU 4
#define GF_OUTF32 8
#define GF_OUTH16 16

#define STG 32768
#define SMEM_GEMM (3*STG + 256)

template<int FLAGS, int TERMS>
__global__ void __launch_bounds__(256, 1) gemm_mma(
    const __half* __restrict__ Ah, const __half* __restrict__ Al,
    const __half* __restrict__ Bh, const __half* __restrict__ Bl,
    const float* __restrict__ bias, const __half* __restrict__ res,
    float* __restrict__ Cf, __half* __restrict__ Ch,
    int M, int N, int K, float scal)
{
    extern __shared__ char dsm[];
    uint32_t sbase = (smem_u32(dsm) + 127) & ~127u;

    const int t = threadIdx.x;
    const int lane = t & 31;
    const int wid = t >> 5;
    const int wm = wid >> 2;
    const int wn = wid & 3;
    const int bm = blockIdx.y * 128, bn = blockIdx.x * 128;
    const int NC = K >> 5;

    float acc[4][4][4] = {};

    const int lrow = t >> 2;
    const int lcell = t & 3;
    auto load_chunk = [&](int c, int stg) {
        uint32_t sb = sbase + stg*STG;
        size_t k0 = (size_t)c * 32 + lcell*8;
        #pragma unroll
        for (int j = 0; j < 2; j++) {
            int row = lrow + j*64;
            uint32_t soff = row*64 + (((uint32_t)(lcell ^ (row & 3))) << 4);
            size_t ga = (size_t)(bm + row)*K + k0;
            size_t gb = (size_t)(bn + row)*K + k0;
            cp16(sb +         soff, Ah + ga);
            if (TERMS == 3) cp16(sb + 8192 + soff, Al + ga);
            cp16(sb + 16384 + soff, Bh + gb);
            if (TERMS >= 2) cp16(sb + 24576 + soff, Bl + gb);
        }
        CP_COMMIT();
    };

    load_chunk(0, 0);
    if (NC > 1) load_chunk(1, 1);

    const int arow_base = wm*64 + (lane & 15);
    const int brow_base = wn*32 + (lane & 15);
    const int kc_hi = lane >> 4;

    for (int c = 0; c < NC; c++) {
        if (c + 2 < NC) asm volatile("cp.async.wait_group 1;" ::: "memory");
        else            asm volatile("cp.async.wait_group 0;" ::: "memory");
        __syncthreads();
        if (c + 2 < NC) load_chunk(c + 2, (c + 2) % 3);

        uint32_t sb = sbase + (c % 3)*STG;
        #pragma unroll
        for (int s = 0; s < 2; s++) {
            uint32_t ah[4][4], al[4][4], bh[2][4], bl[2][4];
            int chunk = s*2 + kc_hi;
            #pragma unroll
            for (int mt = 0; mt < 4; mt++) {
                int row = arow_base + mt*16;
                uint32_t off = row*64 + (((uint32_t)(chunk ^ (row & 3))) << 4);
                LDSM_X4(ah[mt][0], ah[mt][1], ah[mt][2], ah[mt][3], sb + off);
                if (TERMS == 3)
                    LDSM_X4(al[mt][0], al[mt][1], al[mt][2], al[mt][3], sb + 8192 + off);
            }
            #pragma unroll
            for (int g = 0; g < 2; g++) {
                int row = brow_base + g*16;
                uint32_t off = row*64 + (((uint32_t)(chunk ^ (row & 3))) << 4);
                LDSM_X4(bh[g][0], bh[g][1], bh[g][2], bh[g][3], sb + 16384 + off);
                if (TERMS >= 2)
                    LDSM_X4(bl[g][0], bl[g][1], bl[g][2], bl[g][3], sb + 24576 + off);
            }
            #pragma unroll
            for (int mt = 0; mt < 4; mt++) {
                #pragma unroll
                for (int nt = 0; nt < 4; nt++) {
                    int g = nt >> 1, o = nt & 1;
                    MMA_F32(acc[mt][nt], ah[mt], bh[g][o], bh[g][o+2]);
                    if (TERMS >= 2)
                        MMA_F32(acc[mt][nt], ah[mt], bl[g][o], bl[g][o+2]);
                    if (TERMS == 3)
                        MMA_F32(acc[mt][nt], al[mt], bh[g][o], bh[g][o+2]);
                }
            }
        }
    }

    int r0 = bm + wm*64 + (lane >> 2);
    int c0 = bn + wn*32 + (lane & 3)*2;
    #pragma unroll
    for (int mt = 0; mt < 4; mt++) {
        #pragma unroll
        for (int nt = 0; nt < 4; nt++) {
            int col = c0 + nt*8;
            float b0 = 0.f, b1 = 0.f;
            if (FLAGS & GF_BIAS) { b0 = bias[col]; b1 = bias[col+1]; }
            #pragma unroll
            for (int half = 0; half < 2; half++) {
                int row = r0 + mt*16 + half*8;
                float v0 = acc[mt][nt][half*2+0] * scal + b0;
                float v1 = acc[mt][nt][half*2+1] * scal + b1;
                size_t ro = (size_t)row * N + col;
                if (FLAGS & GF_RES) {
                    float2 r2 = __half22float2(*(const __half2*)&res[ro]);
                    v0 += r2.x; v1 += r2.y;
                }
                if (FLAGS & GF_RELU) { v0 = fmaxf(v0, 0.f); v1 = fmaxf(v1, 0.f); }
                if (FLAGS & GF_OUTF32) {
                    float2 o2; o2.x = v0; o2.y = v1;
                    *(float2*)&Cf[ro] = o2;
                }
                if (FLAGS & GF_OUTH16) {
                    __half2 hp; hp.x = __float2half_rn(v0); hp.y = __float2half_rn(v1);
                    *(__half2*)&Ch[ro] = hp;
                }
            }
        }
    }
}

// ========== DFT of x (half input) with l/l+256 symmetry ==========
__global__ void __launch_bounds__(128) dftx_kernel(const __half* __restrict__ x,
                                                   __half* __restrict__ Xh,
                                                   __half* __restrict__ Xl) {
    int blk = blockIdx.x;
    int b = blk >> 3;
    int dchunk = (blk & 7) * 64;
    __shared__ float sqA[32][68];
    __shared__ float sqB[32][68];
    __shared__ float sct[32][32];
    __shared__ float sst[32][32];
    int t = threadIdx.x;
    int td = t & 63;
    int tm = (t >> 6) * 16;

    float ar[16] = {}, ai[16] = {};
    const __half* qbase = x + (size_t)b*Lq*Dq + dchunk;

    for (int l0 = 0; l0 < 256; l0 += 32) {
        #pragma unroll
        for (int j = 0; j < 8; j++) {
            int v = t + j*128;              // 1024 half2 per tile
            int ll = v >> 5;
            int c2 = (v & 31) * 2;
            float2 fa = __half22float2(*(const __half2*)&qbase[(size_t)(l0+ll)*Dq + c2]);
            sqA[ll][c2] = fa.x; sqA[ll][c2+1] = fa.y;
            float2 fb = __half22float2(*(const __half2*)&qbase[(size_t)(l0+256+ll)*Dq + c2]);
            sqB[ll][c2] = fb.x; sqB[ll][c2+1] = fb.y;
        }
        #pragma unroll
        for (int j = 0; j < 2; j++) {
            int v = t + j*128;
            int ll = v >> 3;
            int c4 = (v & 7) * 4;
            *(float4*)&sct[ll][c4] = *(const float4*)&g_ct[(l0+ll)*32 + c4];
            *(float4*)&sst[ll][c4] = *(const float4*)&g_st[(l0+ll)*32 + c4];
        }
        __syncthreads();
        #pragma unroll 2
        for (int ll = 0; ll < 32; ll++) {
            float xa = sqA[ll][td], xb = sqB[ll][td];
            float u = xa + xb;
            float w = xa - xb;
            float c[16], s[16];
            #pragma unroll
            for (int j = 0; j < 16; j += 4) {
                *(float4*)&c[j] = *(float4*)&sct[ll][tm+j];
                *(float4*)&s[j] = *(float4*)&sst[ll][tm+j];
            }
            #pragma unroll
            for (int mm = 0; mm < 16; mm++) {
                float v = (mm & 1) ? w : u;
                ar[mm] = fmaf(v,  c[mm], ar[mm]);
                ai[mm] = fmaf(-v, s[mm], ai[mm]);
            }
        }
        __syncthreads();
    }
    int d0 = dchunk + td;
    #pragma unroll
    for (int mm = 0; mm < 16; mm++) {
        int m = tm + mm;
        float vr = ar[mm], vi = ai[mm];
        __half hr = __float2half_rn(vr);
        __half hi_ = __float2half_rn(vi);
        size_t rowr = ((size_t)(m*2+0)*64 + b)*Dq + d0;
        size_t rowi = ((size_t)(m*2+1)*64 + b)*Dq + d0;
        Xh[rowr] = hr;   Xl[rowr] = __float2half_rn(vr - __half2float(hr));
        Xh[rowi] = hi_;  Xl[rowi] = __float2half_rn(vi - __half2float(hi_));
    }
}

// ========== complex mode mix ==========
__global__ void __launch_bounds__(256) mix2_kernel(const float* __restrict__ xs,
                                                   const float* __restrict__ wtr,
                                                   const float* __restrict__ wti,
                                                   const float* __restrict__ bq,
                                                   __half* __restrict__ osh,
                                                   __half* __restrict__ osl) {
    int h = blockIdx.x >> 5, m = blockIdx.x & 31;
    __shared__ float swr[64][64];
    __shared__ float swi[64][64];
    __shared__ float sxr[64][65];
    __shared__ float sxi[64][65];
    int t = threadIdx.x;
    const float* pr = wtr + ((size_t)(h*32 + m))*4096;
    const float* pi = wti + ((size_t)(h*32 + m))*4096;
    #pragma unroll
    for (int j = 0; j < 16; j++) {
        int v = t + j*256;
        int r = v >> 6, c = v & 63;
        swr[r][c] = pr[v];
        swi[r][c] = pi[v];
    }
    #pragma unroll
    for (int j = 0; j < 16; j++) {
        int v = t + j*256;
        int b = v >> 6, i = v & 63;
        if (j < 8) {
            float vr = xs[((size_t)(2*m)*64 + b)*Dq + h*64 + i];
            if (m == 0) vr += 512.0f * bq[h*64 + i];
            sxr[b][i] = vr;
        } else {
            sxi[b][i] = xs[((size_t)(2*m+1)*64 + b)*Dq + h*64 + i];
        }
    }
    __syncthreads();

    int b = t >> 2;
    int o0 = (t & 3) * 16;
    float orr[16] = {}, oii[16] = {};
    for (int i = 0; i < 64; i++) {
        float xr = sxr[b][i], xi = sxi[b][i];
        float wr4[16], wi4[16];
        #pragma unroll
        for (int j = 0; j < 16; j += 4) {
            *(float4*)&wr4[j] = *(float4*)&swr[i][o0+j];
            *(float4*)&wi4[j] = *(float4*)&swi[i][o0+j];
        }
        #pragma unroll
        for (int j = 0; j < 16; j++) {
            orr[j] = fmaf(xr, wr4[j], orr[j]);
            orr[j] = fmaf(-xi, wi4[j], orr[j]);
            oii[j] = fmaf(xr, wi4[j], oii[j]);
            oii[j] = fmaf(xi, wr4[j], oii[j]);
        }
    }
    #pragma unroll
    for (int j = 0; j < 16; j++) {
        int o = o0 + j;
        float vr = orr[j] * 256.0f;
        float vi = oii[j] * 256.0f;
        __half hr = __float2half_rn(vr);
        __half hi_ = __float2half_rn(vi);
        size_t base = ((size_t)b*512 + h*64 + o)*64 + 2*m;
        __half2 hp; hp.x = hr; hp.y = hi_;
        *(__half2*)&osh[base] = hp;
        __half2 lp;
        lp.x = __float2half_rn(vr - __half2float(hr));
        lp.y = __float2half_rn(vi - __half2float(hi_));
        *(__half2*)&osl[base] = lp;
    }
}

// ========== series_decomp: half in; writes EITHER xh (half) OR fx (fp32) =====
__global__ void decomp_kernel(const __half* __restrict__ in, float* __restrict__ out_f,
                              __half* __restrict__ oh) {
    int gid = blockIdx.x*blockDim.x + threadIdx.x;
    int seg = gid >> 14;
    int r = gid & 16383;
    int b = r >> 8, d2 = (r & 255) * 2;
    const __half2* p = (const __half2*)(in + (size_t)b*Lq*Dq + d2);
    size_t obase = (size_t)b*Lq*Dq + d2;
    int lstart = seg * 64;
    float2 ws; ws.x = 0.f; ws.y = 0.f;
    #pragma unroll
    for (int j = -12; j <= 12; j++) {
        int jj = lstart + j;
        jj = jj < 0 ? 0 : jj;
        float2 q = __half22float2(p[(size_t)jj*256]);
        ws.x += q.x; ws.y += q.y;
    }
    int lend = lstart + 64;
    if (oh) {
        for (int l = lstart; l < lend; l++) {
            float2 xl = __half22float2(p[(size_t)l*256]);
            float2 v;
            v.x = xl.x - ws.x*(1.0f/25.0f);
            v.y = xl.y - ws.y*(1.0f/25.0f);
            __half2 hv; hv.x = __float2half_rn(v.x); hv.y = __float2half_rn(v.y);
            *(__half2*)&oh[obase + (size_t)l*Dq] = hv;
            int jn = l+13 > Lq-1 ? Lq-1 : l+13;
            int jo = l-12 < 0 ? 0 : l-12;
            float2 a = __half22float2(p[(size_t)jn*256]);
            float2 bb = __half22float2(p[(size_t)jo*256]);
            ws.x += a.x - bb.x; ws.y += a.y - bb.y;
        }
    } else {
        for (int l = lstart; l < lend; l++) {
            float2 xl = __half22float2(p[(size_t)l*256]);
            float2 v;
            v.x = xl.x - ws.x*(1.0f/25.0f);
            v.y = xl.y - ws.y*(1.0f/25.0f);
            *(float2*)&out_f[obase + (size_t)l*Dq] = v;
            int jn = l+13 > Lq-1 ? Lq-1 : l+13;
            int jo = l-12 < 0 ? 0 : l-12;
            float2 a = __half22float2(p[(size_t)jn*256]);
            float2 bb = __half22float2(p[(size_t)jo*256]);
            ws.x += a.x - bb.x; ws.y += a.y - bb.y;
        }
    }
}

// ================= final layernorm / projection =================
__global__ void ln_rows(const float* __restrict__ x) {
    int row = blockIdx.x;
    int t = threadIdx.x;
    const float* p = x + (size_t)row*Dq;
    float v0 = p[t], v1 = p[t+256];
    __shared__ float sh[8];
    float s = v0 + v1;
    int lane = t & 31, w = t >> 5;
    #pragma unroll
    for (int o = 16; o > 0; o >>= 1) s += __shfl_down_sync(~0u, s, o);
    if (lane == 0) sh[w] = s;
    __syncthreads();
    if (t < 32) {
        float v = (t < 8) ? sh[t] : 0.f;
        #pragma unroll
        for (int o = 4; o > 0; o >>= 1) v += __shfl_down_sync(~0u, v, o);
        if (t == 0) sh[0] = v;
    }
    __syncthreads();
    float mu = sh[0] * (1.0f/512.0f);
    __syncthreads();
    float d0 = v0 - mu, d1 = v1 - mu;
    s = d0*d0 + d1*d1;
    #pragma unroll
    for (int o = 16; o > 0; o >>= 1) s += __shfl_down_sync(~0u, s, o);
    if (lane == 0) sh[w] = s;
    __syncthreads();
    if (t < 32) {
        float v = (t < 8) ? sh[t] : 0.f;
        #pragma unroll
        for (int o = 4; o > 0; o >>= 1) v += __shfl_down_sync(~0u, v, o);
        if (t == 0) {
            float var = v * (1.0f/512.0f);
            g_mu[row] = mu;
            g_rs[row] = rsqrtf(var + 1e-5f);
        }
    }
}

__global__ void ln_cols_part(const float* __restrict__ x, const float* __restrict__ nw,
                             const float* __restrict__ nb) {
    int blk = blockIdx.x;
    int b = blk >> 3, seg = blk & 7;
    int d = threadIdx.x;
    float w = nw[d], bb = nb[d];
    float sum = 0.f;
    int l0 = seg * 64;
    #pragma unroll 4
    for (int l = l0; l < l0 + 64; l++) {
        int row = b*Lq + l;
        sum += (x[(size_t)row*Dq + d] - g_mu[row]) * g_rs[row] * w + bb;
    }
    g_part[(size_t)seg*Bq*Dq + b*Dq + d] = sum;
}

__global__ void ln_cols_fin(const float* __restrict__ x, const float* __restrict__ nw,
                            const float* __restrict__ nb, const float* __restrict__ tv) {
    int b = blockIdx.x;
    int d = threadIdx.x;
    float sum = 0.f;
    #pragma unroll
    for (int seg = 0; seg < 8; seg++)
        sum += g_part[(size_t)seg*Bq*Dq + b*Dq + d];
    int row = b*Lq + (Lq-1);
    float lastv = (x[(size_t)row*Dq + d] - g_mu[row]) * g_rs[row] * nw[d] + nb[d];
    g_cat[b*CATD + d] = lastv - sum*(1.0f/512.0f);
    if (d < 24) g_cat[b*CATD + 512 + d] = tv[((size_t)b*Lq + (Lq-1))*24 + d];
}

__global__ void __launch_bounds__(256) proj_kernel(const float* __restrict__ pw,
                                                   const float* __restrict__ pb,
                                                   float* __restrict__ out) {
    __shared__ float As[8][65];
    __shared__ float Bs[8][65];
    int n0 = blockIdx.x * 64;
    int t = threadIdx.x;
    int tx = t & 15, ty = t >> 4;
    float acc[4][4] = {};
    for (int k0 = 0; k0 < CATD; k0 += 8) {
        int v = t*2;
        int r = v >> 3, c = v & 7;
        As[c][r]   = g_cat[r*CATD + k0 + c];
        As[c+1][r] = g_cat[r*CATD + k0 + c + 1];
        int n = n0 + r;
        float f0 = 0.f, f1 = 0.f;
        if (n < NUM_APP) {
            f0 = pw[(size_t)n*CATD + k0 + c];
            f1 = pw[(size_t)n*CATD + k0 + c + 1];
        }
        Bs[c][r] = f0; Bs[c+1][r] = f1;
        __syncthreads();
        #pragma unroll
        for (int k = 0; k < 8; k++) {
            float a[4], bv[4];
            #pragma unroll
            for (int i = 0; i < 4; i++) { a[i] = As[k][ty*4+i]; bv[i] = Bs[k][tx*4+i]; }
            #pragma unroll
            for (int i = 0; i < 4; i++)
                #pragma unroll
                for (int j = 0; j < 4; j++)
                    acc[i][j] = fmaf(a[i], bv[j], acc[i][j]);
        }
        __syncthreads();
    }
    #pragma unroll
    for (int i = 0; i < 4; i++) {
        int bi = ty*4 + i;
        #pragma unroll
        for (int j = 0; j < 4; j++) {
            int n = n0 + tx*4 + j;
            if (n < NUM_APP) out[(size_t)bi*NUM_APP + n] = acc[i][j] + pb[n];
        }
    }
}

// ================= host orchestration =================
extern "C" void kernel_launch(void* const* d_in, const int* in_sizes, int n_in,
                              void* d_out, int out_size) {
    const int*   x_app     = (const int*)  d_in[0];
    const float* x_time    = (const float*)d_in[1];
    const float* time_vecs = (const float*)d_in[2];
    const float* app_emb_w = (const float*)d_in[4];
    const float* time_w    = (const float*)d_in[5];
    const float* time_b    = (const float*)d_in[6];
    const float* Wq        = (const float*)d_in[7];
    const float* bq        = (const float*)d_in[8];
    const float* Wo        = (const float*)d_in[9];
    const float* bo        = (const float*)d_in[10];
    const float* four_wr   = (const float*)d_in[11];
    const float* four_wi   = (const float*)d_in[12];
    const float* conv1_w   = (const float*)d_in[13];
    const float* conv2_w   = (const float*)d_in[14];
    const float* norm_w    = (const float*)d_in[15];
    const float* norm_b    = (const float*)d_in[16];
    const float* proj_w    = (const float*)d_in[17];
    const float* proj_b    = (const float*)d_in[18];
    float* out = (float*)d_out;

    cudaFuncSetAttribute((const void*)gemm_mma<GF_OUTF32, 3>,                cudaFuncAttributeMaxDynamicSharedMemorySize, SMEM_GEMM);
    cudaFuncSetAttribute((const void*)gemm_mma<GF_BIAS|GF_RES|GF_OUTH16, 3>, cudaFuncAttributeMaxDynamicSharedMemorySize, SMEM_GEMM);
    cudaFuncSetAttribute((const void*)gemm_mma<GF_RELU|GF_OUTH16, 1>,        cudaFuncAttributeMaxDynamicSharedMemorySize, SMEM_GEMM);
    cudaFuncSetAttribute((const void*)gemm_mma<GF_RES|GF_OUTH16, 1>,         cudaFuncAttributeMaxDynamicSharedMemorySize, SMEM_GEMM);

    void *px, *pq, *pth;
    void *pxh, *pXh, *pXl, *pyh, *posh, *posl, *pwth, *pwtl;
    void *pwqh, *pwql, *pc1h, *pc2h, *pwtr, *pwti;
    cudaGetSymbolAddress(&px, g_x);
    cudaGetSymbolAddress(&pq, g_q);
    cudaGetSymbolAddress(&pth, g_th);
    cudaGetSymbolAddress(&pxh, g_xh);
    cudaGetSymbolAddress(&pXh, g_Xh); cudaGetSymbolAddress(&pXl, g_Xl);
    cudaGetSymbolAddress(&pyh, g_yh);
    cudaGetSymbolAddress(&posh, g_osh); cudaGetSymbolAddress(&posl, g_osl);
    cudaGetSymbolAddress(&pwth, g_wth); cudaGetSymbolAddress(&pwtl, g_wtl);
    cudaGetSymbolAddress(&pwqh, g_wqh); cudaGetSymbolAddress(&pwql, g_wql);
    cudaGetSymbolAddress(&pc1h, g_c1h);
    cudaGetSymbolAddress(&pc2h, g_c2h);
    cudaGetSymbolAddress(&pwtr, g_wtr); cudaGetSymbolAddress(&pwti, g_wti);
    float* fx = (float*)px;
    float* fq = (float*)pq;
    __half* th = (__half*)pth;
    __half *xh=(__half*)pxh;
    __half *Xh=(__half*)pXh, *Xl=(__half*)pXl;
    __half *yh=(__half*)pyh;
    __half *osh=(__half*)posh, *osl=(__half*)posl;
    __half *wth=(__half*)pwth, *wtl=(__half*)pwtl;
    __half *wqh=(__half*)pwqh, *wql=(__half*)pwql;
    __half *c1h=(__half*)pc1h;
    __half *c2h=(__half*)pc2h;
    float *wtr=(float*)pwtr, *wti=(float*)pwti;

    init_tables<<<64, 256>>>();
    convert_all<<<(NWQ + NC1 + NC2 + 255)/256, 256>>>(Wq, conv1_w, conv2_w);
    wotab_kernel<<<dim3(128, 2), 128>>>(Wo, wth, wtl);
    wtrans_kernel<<<1024, 256>>>(four_wr, four_wi);
    embed_kernel<<<BLq*Dq/4/256, 256>>>(x_app, x_time, app_emb_w, time_w, time_b);

    const int M = BLq;
    for (int l = 0; l < 2; l++) {
        size_t woff = (size_t)l*Dq*Dq;
        size_t coff1 = (size_t)l*DFF*Dq;
        size_t mixoff = (size_t)l*Hq*MODES*Eq*Eq;

        dftx_kernel<<<512, 128>>>(xh, Xh, Xl);
        gemm_mma<GF_OUTF32, 3><<<dim3(4, 32), 256, SMEM_GEMM>>>(
            Xh, Xl, wqh + woff, wql + woff, nullptr, nullptr,
            fq, nullptr, 4096, Dq, Dq, 1.0f);
        mix2_kernel<<<Hq*MODES, 256>>>(fq, wtr + mixoff, wti + mixoff,
                                       bq + l*Dq, osh, osl);
        // new_x = os @ WoT^T * (1/65536) + bo + x(half) -> th (half)
        gemm_mma<GF_BIAS|GF_RES|GF_OUTH16, 3><<<dim3(4, 256), 256, SMEM_GEMM>>>(
            osh, osl, wth + (size_t)l*Dq*64, wtl + (size_t)l*Dq*64, bo + l*Dq, xh,
            nullptr, th, M, Dq, 64, 1.0f/65536.0f);
        decomp_kernel<<<512, 256>>>(th, nullptr, xh);
        gemm_mma<GF_RELU|GF_OUTH16, 1><<<dim3(DFF/128, M/128), 256, SMEM_GEMM>>>(
            xh, nullptr, c1h + coff1, nullptr, nullptr, nullptr,
            nullptr, yh, M, DFF, Dq, 1.0f);
        // t = y @ c2^T + x(half) -> th (half)
        gemm_mma<GF_RES|GF_OUTH16, 1><<<dim3(Dq/128, M/128), 256, SMEM_GEMM>>>(
            yh, nullptr, c2h + coff1, nullptr, nullptr, xh,
            nullptr, th, M, Dq, DFF, 1.0f);
        // final decomp writes fp32 fx (for exact ln); others write half xh
        if (l == 1) decomp_kernel<<<512, 256>>>(th, fx, nullptr);
        else        decomp_kernel<<<512, 256>>>(th, nullptr, xh);
    }

    ln_rows<<<BLq, 256>>>(fx);
    ln_cols_part<<<Bq*8, 512>>>(fx, norm_w, norm_b);
    ln_cols_fin<<<Bq, 512>>>(fx, norm_w, norm_b, time_vecs);
    proj_kernel<<<(NUM_APP + 63)/64, 256>>>(proj_w, proj_b, out);
}

// round 13
// speedup vs baseline: 5.2545x; 1.0195x over previous
#include <cuda_runtime.h>
#include <cuda_fp16.h>
#include <math.h>
#include <stdint.h>

#define Bq 64
#define Lq 512
#define Dq 512
#define Hq 8
#define Eq 64
#define DFF 2048
#define MODES 32
#define VOCAB 10000
#define NUM_APP 10000
#define CATD 536
#define BLq (Bq*Lq)

// ================= helpers =================
__device__ __forceinline__ uint32_t smem_u32(const void* p) {
    uint32_t a;
    asm("{ .reg .u64 t; cvta.to.shared.u64 t, %1; cvt.u32.u64 %0, t; }" : "=r"(a) : "l"(p));
    return a;
}
__device__ __forceinline__ void cp16(uint32_t dst, const void* src) {
    asm volatile("cp.async.cg.shared.global [%0], [%1], 16;" :: "r"(dst), "l"(src) : "memory");
}
#define CP_COMMIT() asm volatile("cp.async.commit_group;" ::: "memory")

#define LDSM_X4(r0,r1,r2,r3, addr) \
    asm volatile("ldmatrix.sync.aligned.m8n8.x4.shared.b16 {%0,%1,%2,%3}, [%4];" \
        : "=r"(r0), "=r"(r1), "=r"(r2), "=r"(r3) : "r"(addr))

#define MMA_F32(d, a, b0, b1) \
    asm volatile("mma.sync.aligned.m16n8k16.row.col.f32.f16.f16.f32 " \
        "{%0,%1,%2,%3},{%4,%5,%6,%7},{%8,%9},{%0,%1,%2,%3};" \
        : "+f"((d)[0]), "+f"((d)[1]), "+f"((d)[2]), "+f"((d)[3]) \
        : "r"((a)[0]), "r"((a)[1]), "r"((a)[2]), "r"((a)[3]), "r"(b0), "r"(b1))

// ================= scratch (device globals) =================
__device__ float g_x[BLq*Dq];                        // only final-layer x (for ln)
__device__ float g_q[BLq*Dq];
__device__ __align__(256) __half g_th[BLq*Dq];       // pre-decomp tensor, fp16
__device__ __align__(256) __half g_xh[BLq*Dq];       // activation x, fp16
__device__ __align__(256) __half g_Xh[4096*Dq];
__device__ __align__(256) __half g_yh[BLq*DFF];
__device__ __align__(256) __half g_osh[BLq*64];
__device__ __align__(256) __half g_wth[2*Dq*64], g_wtl[2*Dq*64];
__device__ __align__(256) __half g_wqh[2*Dq*Dq], g_wql[2*Dq*Dq];
__device__ __align__(256) __half g_c1h[2*DFF*Dq];
__device__ __align__(256) __half g_c2h[2*Dq*DFF];
__device__ float g_wtr[2*Hq*MODES*Eq*Eq];
__device__ float g_wti[2*Hq*MODES*Eq*Eq];
__device__ float g_ct[Lq*MODES], g_st[Lq*MODES];
__device__ float g_mu[BLq], g_rs[BLq];
__device__ float g_part[8*Bq*Dq];
__device__ float g_cat[Bq*CATD];

// ================= merged preamble kernel =================
#define NWQ (2*Dq*Dq)
#define NC1 (2*DFF*Dq)
#define NC2 (2*Dq*DFF)
#define PB_INIT 64
#define PB_CONV ((NWQ + NC1 + NC2 + 255)/256)
#define PB_WTRANS 1024
#define PB_EMBED (BLq*Dq/4/256)
#define PB_TOTAL (PB_INIT + PB_CONV + PB_WTRANS + PB_EMBED)

__global__ void __launch_bounds__(256) prep_kernel(
    const float* __restrict__ Wq, const float* __restrict__ c1, const float* __restrict__ c2,
    const float* __restrict__ wr, const float* __restrict__ wi,
    const int* __restrict__ app, const float* __restrict__ xt,
    const float* __restrict__ emb, const float* __restrict__ tw, const float* __restrict__ tb)
{
    __shared__ float tr[64][33], ti_[64][33];
    int blk = blockIdx.x;
    int t = threadIdx.x;

    if (blk < PB_INIT) {
        // trig tables
        int idx = blk*256 + t;
        int l = idx >> 5, m = idx & 31;
        double a = (double)(m*l) / 256.0;
        double s, c;
        sincospi(a, &s, &c);
        g_ct[idx] = (float)c;
        g_st[idx] = (float)s;
    } else if (blk < PB_INIT + PB_CONV) {
        // weight conversions
        int i = (blk - PB_INIT)*256 + t;
        if (i < NWQ) {
            float v = Wq[i];
            __half hv = __float2half_rn(v);
            g_wqh[i] = hv;
            g_wql[i] = __float2half_rn(v - __half2float(hv));
        } else if (i < NWQ + NC1) {
            int j = i - NWQ;
            g_c1h[j] = __float2half_rn(c1[j]);
        } else if (i < NWQ + NC1 + NC2) {
            int j = i - NWQ - NC1;
            g_c2h[j] = __float2half_rn(c2[j]);
        }
    } else if (blk < PB_INIT + PB_CONV + PB_WTRANS) {
        // transpose four_wr/wi: [l][h][i][o][m] -> [l][h][m][i][o]
        int b2 = blk - PB_INIT - PB_CONV;
        int i  = b2 & 63;
        int lh = b2 >> 6;
        const float* pr = wr + ((size_t)lh*64 + i)*64*32;
        const float* pi = wi + ((size_t)lh*64 + i)*64*32;
        #pragma unroll
        for (int j = 0; j < 8; j++) {
            int v = t + j*256;
            int o = v >> 5, m = v & 31;
            tr[o][m]  = pr[v];
            ti_[o][m] = pi[v];
        }
        __syncthreads();
        #pragma unroll
        for (int j = 0; j < 8; j++) {
            int v = t + j*256;
            int m = v >> 6, o = v & 63;
            size_t dst = ((size_t)(lh*32 + m)*64 + i)*64 + o;
            g_wtr[dst] = tr[o][m];
            g_wti[dst] = ti_[o][m];
        }
    } else {
        // embed -> xh (half)
        int idx = (blk - PB_INIT - PB_CONV - PB_WTRANS)*256 + t;
        int d4 = (idx & 127) * 4;
        size_t bl = (size_t)(idx >> 7);
        int a = app[bl];
        float xtv = xt[bl];
        float4 e = *(const float4*)&emb[(size_t)a*Dq + d4];
        float4 w = *(const float4*)&tw[d4];
        float4 bb = *(const float4*)&tb[d4];
        __half2 h0, h1;
        h0.x = __float2half_rn(fmaf(xtv, w.x, e.x) + bb.x);
        h0.y = __float2half_rn(fmaf(xtv, w.y, e.y) + bb.y);
        h1.x = __float2half_rn(fmaf(xtv, w.z, e.z) + bb.z);
        h1.y = __float2half_rn(fmaf(xtv, w.w, e.w) + bb.w);
        *(__half2*)&g_xh[bl*Dq + d4]     = h0;
        *(__half2*)&g_xh[bl*Dq + d4 + 2] = h1;
    }
}

// ========== Wo frequency table (needs g_ct/g_st) ==========
__global__ void __launch_bounds__(128) wotab_kernel(const float* __restrict__ Wo,
                                                    __half* __restrict__ wth,
                                                    __half* __restrict__ wtl) {
    int layer = blockIdx.y;
    int j0 = blockIdx.x * 4;
    __shared__ float sw[4][512];
    int t = threadIdx.x;
    const float* wo = Wo + (size_t)layer*Dq*Dq + (size_t)j0*Dq;
    #pragma unroll
    for (int j = 0; j < 4; j++) {
        int v = t + j*128;
        int r = v >> 7, c4 = (v & 127) * 4;
        *(float4*)&sw[r][c4] = *(const float4*)&wo[(size_t)r*Dq + c4];
    }
    __syncthreads();
    int tj = t >> 5, tm = t & 31;
    float ac = 0.f, as = 0.f;
    for (int l = 0; l < Lq; l++) {
        float w = sw[tj][l];
        ac = fmaf(w, g_ct[l*32 + tm], ac);
        as = fmaf(w, g_st[l*32 + tm], as);
    }
    float cm = (tm == 0 ? 1.0f : 2.0f) * (256.0f/512.0f);
    float vc = ac*cm, vs = -as*cm;
    size_t base = ((size_t)layer*Dq + j0 + tj)*64 + tm*2;
    __half hc = __float2half_rn(vc);
    __half hs = __float2half_rn(vs);
    wth[base]   = hc;  wtl[base]   = __float2half_rn(vc - __half2float(hc));
    wth[base+1] = hs;  wtl[base+1] = __float2half_rn(vs - __half2float(hs));
}

// ================= mma.sync fp16 GEMM: C = A(MxK) @ B(NxK)^T =============
// TERMS==2: Ah*(Bh+Bl).  TERMS==1: Ah*Bh.   (residual fp16)
#define GF_BIAS 1
#define GF_RES  2
#define GF_RELU 4
#define GF_OUTF32 8
#define GF_OUTH16 16

#define STG 32768
#define SMEM_GEMM (3*STG + 256)

template<int FLAGS, int TERMS>
__global__ void __launch_bounds__(256, 1) gemm_mma(
    const __half* __restrict__ Ah,
    const __half* __restrict__ Bh, const __half* __restrict__ Bl,
    const float* __restrict__ bias, const __half* __restrict__ res,
    float* __restrict__ Cf, __half* __restrict__ Ch,
    int M, int N, int K, float scal)
{
    extern __shared__ char dsm[];
    uint32_t sbase = (smem_u32(dsm) + 127) & ~127u;

    const int t = threadIdx.x;
    const int lane = t & 31;
    const int wid = t >> 5;
    const int wm = wid >> 2;
    const int wn = wid & 3;
    const int bm = blockIdx.y * 128, bn = blockIdx.x * 128;
    const int NC = K >> 5;

    float acc[4][4][4] = {};

    const int lrow = t >> 2;
    const int lcell = t & 3;
    auto load_chunk = [&](int c, int stg) {
        uint32_t sb = sbase + stg*STG;
        size_t k0 = (size_t)c * 32 + lcell*8;
        #pragma unroll
        for (int j = 0; j < 2; j++) {
            int row = lrow + j*64;
            uint32_t soff = row*64 + (((uint32_t)(lcell ^ (row & 3))) << 4);
            size_t ga = (size_t)(bm + row)*K + k0;
            size_t gb = (size_t)(bn + row)*K + k0;
            cp16(sb +         soff, Ah + ga);
            cp16(sb + 16384 + soff, Bh + gb);
            if (TERMS >= 2) cp16(sb + 24576 + soff, Bl + gb);
        }
        CP_COMMIT();
    };

    load_chunk(0, 0);
    if (NC > 1) load_chunk(1, 1);

    const int arow_base = wm*64 + (lane & 15);
    const int brow_base = wn*32 + (lane & 15);
    const int kc_hi = lane >> 4;

    for (int c = 0; c < NC; c++) {
        if (c + 2 < NC) asm volatile("cp.async.wait_group 1;" ::: "memory");
        else            asm volatile("cp.async.wait_group 0;" ::: "memory");
        __syncthreads();
        if (c + 2 < NC) load_chunk(c + 2, (c + 2) % 3);

        uint32_t sb = sbase + (c % 3)*STG;
        #pragma unroll
        for (int s = 0; s < 2; s++) {
            uint32_t ah[4][4], bh[2][4], bl[2][4];
            int chunk = s*2 + kc_hi;
            #pragma unroll
            for (int mt = 0; mt < 4; mt++) {
                int row = arow_base + mt*16;
                uint32_t off = row*64 + (((uint32_t)(chunk ^ (row & 3))) << 4);
                LDSM_X4(ah[mt][0], ah[mt][1], ah[mt][2], ah[mt][3], sb + off);
            }
            #pragma unroll
            for (int g = 0; g < 2; g++) {
                int row = brow_base + g*16;
                uint32_t off = row*64 + (((uint32_t)(chunk ^ (row & 3))) << 4);
                LDSM_X4(bh[g][0], bh[g][1], bh[g][2], bh[g][3], sb + 16384 + off);
                if (TERMS >= 2)
                    LDSM_X4(bl[g][0], bl[g][1], bl[g][2], bl[g][3], sb + 24576 + off);
            }
            #pragma unroll
            for (int mt = 0; mt < 4; mt++) {
                #pragma unroll
                for (int nt = 0; nt < 4; nt++) {
                    int g = nt >> 1, o = nt & 1;
                    MMA_F32(acc[mt][nt], ah[mt], bh[g][o], bh[g][o+2]);
                    if (TERMS >= 2)
                        MMA_F32(acc[mt][nt], ah[mt], bl[g][o], bl[g][o+2]);
                }
            }
        }
    }

    int r0 = bm + wm*64 + (lane >> 2);
    int c0 = bn + wn*32 + (lane & 3)*2;
    #pragma unroll
    for (int mt = 0; mt < 4; mt++) {
        #pragma unroll
        for (int nt = 0; nt < 4; nt++) {
            int col = c0 + nt*8;
            float b0 = 0.f, b1 = 0.f;
            if (FLAGS & GF_BIAS) { b0 = bias[col]; b1 = bias[col+1]; }
            #pragma unroll
            for (int half = 0; half < 2; half++) {
                int row = r0 + mt*16 + half*8;
                float v0 = acc[mt][nt][half*2+0] * scal + b0;
                float v1 = acc[mt][nt][half*2+1] * scal + b1;
                size_t ro = (size_t)row * N + col;
                if (FLAGS & GF_RES) {
                    float2 r2 = __half22float2(*(const __half2*)&res[ro]);
                    v0 += r2.x; v1 += r2.y;
                }
                if (FLAGS & GF_RELU) { v0 = fmaxf(v0, 0.f); v1 = fmaxf(v1, 0.f); }
                if (FLAGS & GF_OUTF32) {
                    float2 o2; o2.x = v0; o2.y = v1;
                    *(float2*)&Cf[ro] = o2;
                }
                if (FLAGS & GF_OUTH16) {
                    __half2 hp; hp.x = __float2half_rn(v0); hp.y = __float2half_rn(v1);
                    *(__half2*)&Ch[ro] = hp;
                }
            }
        }
    }
}

// ========== DFT of x (half input) with l/l+256 symmetry; half output ==========
__global__ void __launch_bounds__(128) dftx_kernel(const __half* __restrict__ x,
                                                   __half* __restrict__ Xh) {
    int blk = blockIdx.x;
    int b = blk >> 3;
    int dchunk = (blk & 7) * 64;
    __shared__ float sqA[32][68];
    __shared__ float sqB[32][68];
    __shared__ float sct[32][32];
    __shared__ float sst[32][32];
    int t = threadIdx.x;
    int td = t & 63;
    int tm = (t >> 6) * 16;

    float ar[16] = {}, ai[16] = {};
    const __half* qbase = x + (size_t)b*Lq*Dq + dchunk;

    for (int l0 = 0; l0 < 256; l0 += 32) {
        #pragma unroll
        for (int j = 0; j < 8; j++) {
            int v = t + j*128;
            int ll = v >> 5;
            int c2 = (v & 31) * 2;
            float2 fa = __half22float2(*(const __half2*)&qbase[(size_t)(l0+ll)*Dq + c2]);
            sqA[ll][c2] = fa.x; sqA[ll][c2+1] = fa.y;
            float2 fb = __half22float2(*(const __half2*)&qbase[(size_t)(l0+256+ll)*Dq + c2]);
            sqB[ll][c2] = fb.x; sqB[ll][c2+1] = fb.y;
        }
        #pragma unroll
        for (int j = 0; j < 2; j++) {
            int v = t + j*128;
            int ll = v >> 3;
            int c4 = (v & 7) * 4;
            *(float4*)&sct[ll][c4] = *(const float4*)&g_ct[(l0+ll)*32 + c4];
            *(float4*)&sst[ll][c4] = *(const float4*)&g_st[(l0+ll)*32 + c4];
        }
        __syncthreads();
        #pragma unroll 2
        for (int ll = 0; ll < 32; ll++) {
            float xa = sqA[ll][td], xb = sqB[ll][td];
            float u = xa + xb;
            float w = xa - xb;
            float c[16], s[16];
            #pragma unroll
            for (int j = 0; j < 16; j += 4) {
                *(float4*)&c[j] = *(float4*)&sct[ll][tm+j];
                *(float4*)&s[j] = *(float4*)&sst[ll][tm+j];
            }
            #pragma unroll
            for (int mm = 0; mm < 16; mm++) {
                float v = (mm & 1) ? w : u;
                ar[mm] = fmaf(v,  c[mm], ar[mm]);
                ai[mm] = fmaf(-v, s[mm], ai[mm]);
            }
        }
        __syncthreads();
    }
    int d0 = dchunk + td;
    #pragma unroll
    for (int mm = 0; mm < 16; mm++) {
        int m = tm + mm;
        size_t rowr = ((size_t)(m*2+0)*64 + b)*Dq + d0;
        size_t rowi = ((size_t)(m*2+1)*64 + b)*Dq + d0;
        Xh[rowr] = __float2half_rn(ar[mm]);
        Xh[rowi] = __float2half_rn(ai[mm]);
    }
}

// ========== complex mode mix (half output, single) ==========
__global__ void __launch_bounds__(256) mix2_kernel(const float* __restrict__ xs,
                                                   const float* __restrict__ wtr,
                                                   const float* __restrict__ wti,
                                                   const float* __restrict__ bq,
                                                   __half* __restrict__ osh) {
    int h = blockIdx.x >> 5, m = blockIdx.x & 31;
    __shared__ float swr[64][64];
    __shared__ float swi[64][64];
    __shared__ float sxr[64][65];
    __shared__ float sxi[64][65];
    int t = threadIdx.x;
    const float* pr = wtr + ((size_t)(h*32 + m))*4096;
    const float* pi = wti + ((size_t)(h*32 + m))*4096;
    #pragma unroll
    for (int j = 0; j < 16; j++) {
        int v = t + j*256;
        int r = v >> 6, c = v & 63;
        swr[r][c] = pr[v];
        swi[r][c] = pi[v];
    }
    #pragma unroll
    for (int j = 0; j < 16; j++) {
        int v = t + j*256;
        int b = v >> 6, i = v & 63;
        if (j < 8) {
            float vr = xs[((size_t)(2*m)*64 + b)*Dq + h*64 + i];
            if (m == 0) vr += 512.0f * bq[h*64 + i];
            sxr[b][i] = vr;
        } else {
            sxi[b][i] = xs[((size_t)(2*m+1)*64 + b)*Dq + h*64 + i];
        }
    }
    __syncthreads();

    int b = t >> 2;
    int o0 = (t & 3) * 16;
    float orr[16] = {}, oii[16] = {};
    for (int i = 0; i < 64; i++) {
        float xr = sxr[b][i], xi = sxi[b][i];
        float wr4[16], wi4[16];
        #pragma unroll
        for (int j = 0; j < 16; j += 4) {
            *(float4*)&wr4[j] = *(float4*)&swr[i][o0+j];
            *(float4*)&wi4[j] = *(float4*)&swi[i][o0+j];
        }
        #pragma unroll
        for (int j = 0; j < 16; j++) {
            orr[j] = fmaf(xr, wr4[j], orr[j]);
            orr[j] = fmaf(-xi, wi4[j], orr[j]);
            oii[j] = fmaf(xr, wi4[j], oii[j]);
            oii[j] = fmaf(xi, wr4[j], oii[j]);
        }
    }
    #pragma unroll
    for (int j = 0; j < 16; j++) {
        int o = o0 + j;
        __half2 hp;
        hp.x = __float2half_rn(orr[j] * 256.0f);
        hp.y = __float2half_rn(oii[j] * 256.0f);
        size_t base = ((size_t)b*512 + h*64 + o)*64 + 2*m;
        *(__half2*)&osh[base] = hp;
    }
}

// ========== series_decomp: half in; writes EITHER xh (half) OR fx (fp32) =====
__global__ void decomp_kernel(const __half* __restrict__ in, float* __restrict__ out_f,
                              __half* __restrict__ oh) {
    int gid = blockIdx.x*blockDim.x + threadIdx.x;
    int seg = gid >> 14;
    int r = gid & 16383;
    int b = r >> 8, d2 = (r & 255) * 2;
    const __half2* p = (const __half2*)(in + (size_t)b*Lq*Dq + d2);
    size_t obase = (size_t)b*Lq*Dq + d2;
    int lstart = seg * 64;
    float2 ws; ws.x = 0.f; ws.y = 0.f;
    #pragma unroll
    for (int j = -12; j <= 12; j++) {
        int jj = lstart + j;
        jj = jj < 0 ? 0 : jj;
        float2 q = __half22float2(p[(size_t)jj*256]);
        ws.x += q.x; ws.y += q.y;
    }
    int lend = lstart + 64;
    if (oh) {
        for (int l = lstart; l < lend; l++) {
            float2 xl = __half22float2(p[(size_t)l*256]);
            float2 v;
            v.x = xl.x - ws.x*(1.0f/25.0f);
            v.y = xl.y - ws.y*(1.0f/25.0f);
            __half2 hv; hv.x = __float2half_rn(v.x); hv.y = __float2half_rn(v.y);
            *(__half2*)&oh[obase + (size_t)l*Dq] = hv;
            int jn = l+13 > Lq-1 ? Lq-1 : l+13;
            int jo = l-12 < 0 ? 0 : l-12;
            float2 a = __half22float2(p[(size_t)jn*256]);
            float2 bb = __half22float2(p[(size_t)jo*256]);
            ws.x += a.x - bb.x; ws.y += a.y - bb.y;
        }
    } else {
        for (int l = lstart; l < lend; l++) {
            float2 xl = __half22float2(p[(size_t)l*256]);
            float2 v;
            v.x = xl.x - ws.x*(1.0f/25.0f);
            v.y = xl.y - ws.y*(1.0f/25.0f);
            *(float2*)&out_f[obase + (size_t)l*Dq] = v;
            int jn = l+13 > Lq-1 ? Lq-1 : l+13;
            int jo = l-12 < 0 ? 0 : l-12;
            float2 a = __half22float2(p[(size_t)jn*256]);
            float2 bb = __half22float2(p[(size_t)jo*256]);
            ws.x += a.x - bb.x; ws.y += a.y - bb.y;
        }
    }
}

// ================= final layernorm / projection =================
__global__ void ln_rows(const float* __restrict__ x) {
    int row = blockIdx.x;
    int t = threadIdx.x;
    const float* p = x + (size_t)row*Dq;
    float v0 = p[t], v1 = p[t+256];
    __shared__ float sh[8];
    float s = v0 + v1;
    int lane = t & 31, w = t >> 5;
    #pragma unroll
    for (int o = 16; o > 0; o >>= 1) s += __shfl_down_sync(~0u, s, o);
    if (lane == 0) sh[w] = s;
    __syncthreads();
    if (t < 32) {
        float v = (t < 8) ? sh[t] : 0.f;
        #pragma unroll
        for (int o = 4; o > 0; o >>= 1) v += __shfl_down_sync(~0u, v, o);
        if (t == 0) sh[0] = v;
    }
    __syncthreads();
    float mu = sh[0] * (1.0f/512.0f);
    __syncthreads();
    float d0 = v0 - mu, d1 = v1 - mu;
    s = d0*d0 + d1*d1;
    #pragma unroll
    for (int o = 16; o > 0; o >>= 1) s += __shfl_down_sync(~0u, s, o);
    if (lane == 0) sh[w] = s;
    __syncthreads();
    if (t < 32) {
        float v = (t < 8) ? sh[t] : 0.f;
        #pragma unroll
        for (int o = 4; o > 0; o >>= 1) v += __shfl_down_sync(~0u, v, o);
        if (t == 0) {
            float var = v * (1.0f/512.0f);
            g_mu[row] = mu;
            g_rs[row] = rsqrtf(var + 1e-5f);
        }
    }
}

__global__ void ln_cols_part(const float* __restrict__ x, const float* __restrict__ nw,
                             const float* __restrict__ nb) {
    int blk = blockIdx.x;
    int b = blk >> 3, seg = blk & 7;
    int d = threadIdx.x;
    float w = nw[d], bb = nb[d];
    float sum = 0.f;
    int l0 = seg * 64;
    #pragma unroll 4
    for (int l = l0; l < l0 + 64; l++) {
        int row = b*Lq + l;
        sum += (x[(size_t)row*Dq + d] - g_mu[row]) * g_rs[row] * w + bb;
    }
    g_part[(size_t)seg*Bq*Dq + b*Dq + d] = sum;
}

__global__ void ln_cols_fin(const float* __restrict__ x, const float* __restrict__ nw,
                            const float* __restrict__ nb, const float* __restrict__ tv) {
    int b = blockIdx.x;
    int d = threadIdx.x;
    float sum = 0.f;
    #pragma unroll
    for (int seg = 0; seg < 8; seg++)
        sum += g_part[(size_t)seg*Bq*Dq + b*Dq + d];
    int row = b*Lq + (Lq-1);
    float lastv = (x[(size_t)row*Dq + d] - g_mu[row]) * g_rs[row] * nw[d] + nb[d];
    g_cat[b*CATD + d] = lastv - sum*(1.0f/512.0f);
    if (d < 24) g_cat[b*CATD + 512 + d] = tv[((size_t)b*Lq + (Lq-1))*24 + d];
}

__global__ void __launch_bounds__(256) proj_kernel(const float* __restrict__ pw,
                                                   const float* __restrict__ pb,
                                                   float* __restrict__ out) {
    __shared__ float As[8][65];
    __shared__ float Bs[8][65];
    int n0 = blockIdx.x * 64;
    int t = threadIdx.x;
    int tx = t & 15, ty = t >> 4;
    float acc[4][4] = {};
    for (int k0 = 0; k0 < CATD; k0 += 8) {
        int v = t*2;
        int r = v >> 3, c = v & 7;
        As[c][r]   = g_cat[r*CATD + k0 + c];
        As[c+1][r] = g_cat[r*CATD + k0 + c + 1];
        int n = n0 + r;
        float f0 = 0.f, f1 = 0.f;
        if (n < NUM_APP) {
            f0 = pw[(size_t)n*CATD + k0 + c];
            f1 = pw[(size_t)n*CATD + k0 + c + 1];
        }
        Bs[c][r] = f0; Bs[c+1][r] = f1;
        __syncthreads();
        #pragma unroll
        for (int k = 0; k < 8; k++) {
            float a[4], bv[4];
            #pragma unroll
            for (int i = 0; i < 4; i++) { a[i] = As[k][ty*4+i]; bv[i] = Bs[k][tx*4+i]; }
            #pragma unroll
            for (int i = 0; i < 4; i++)
                #pragma unroll
                for (int j = 0; j < 4; j++)
                    acc[i][j] = fmaf(a[i], bv[j], acc[i][j]);
        }
        __syncthreads();
    }
    #pragma unroll
    for (int i = 0; i < 4; i++) {
        int bi = ty*4 + i;
        #pragma unroll
        for (int j = 0; j < 4; j++) {
            int n = n0 + tx*4 + j;
            if (n < NUM_APP) out[(size_t)bi*NUM_APP + n] = acc[i][j] + pb[n];
        }
    }
}

// ================= host orchestration =================
extern "C" void kernel_launch(void* const* d_in, const int* in_sizes, int n_in,
                              void* d_out, int out_size) {
    const int*   x_app     = (const int*)  d_in[0];
    const float* x_time    = (const float*)d_in[1];
    const float* time_vecs = (const float*)d_in[2];
    const float* app_emb_w = (const float*)d_in[4];
    const float* time_w    = (const float*)d_in[5];
    const float* time_b    = (const float*)d_in[6];
    const float* Wq        = (const float*)d_in[7];
    const float* bq        = (const float*)d_in[8];
    const float* Wo        = (const float*)d_in[9];
    const float* bo        = (const float*)d_in[10];
    const float* four_wr   = (const float*)d_in[11];
    const float* four_wi   = (const float*)d_in[12];
    const float* conv1_w   = (const float*)d_in[13];
    const float* conv2_w   = (const float*)d_in[14];
    const float* norm_w    = (const float*)d_in[15];
    const float* norm_b    = (const float*)d_in[16];
    const float* proj_w    = (const float*)d_in[17];
    const float* proj_b    = (const float*)d_in[18];
    float* out = (float*)d_out;

    cudaFuncSetAttribute((const void*)gemm_mma<GF_OUTF32, 2>,                cudaFuncAttributeMaxDynamicSharedMemorySize, SMEM_GEMM);
    cudaFuncSetAttribute((const void*)gemm_mma<GF_BIAS|GF_RES|GF_OUTH16, 2>, cudaFuncAttributeMaxDynamicSharedMemorySize, SMEM_GEMM);
    cudaFuncSetAttribute((const void*)gemm_mma<GF_RELU|GF_OUTH16, 1>,        cudaFuncAttributeMaxDynamicSharedMemorySize, SMEM_GEMM);
    cudaFuncSetAttribute((const void*)gemm_mma<GF_RES|GF_OUTH16, 1>,         cudaFuncAttributeMaxDynamicSharedMemorySize, SMEM_GEMM);

    void *px, *pq, *pth;
    void *pxh, *pXh, *pyh, *posh, *pwth, *pwtl;
    void *pwqh, *pwql, *pc1h, *pc2h, *pwtr, *pwti;
    cudaGetSymbolAddress(&px, g_x);
    cudaGetSymbolAddress(&pq, g_q);
    cudaGetSymbolAddress(&pth, g_th);
    cudaGetSymbolAddress(&pxh, g_xh);
    cudaGetSymbolAddress(&pXh, g_Xh);
    cudaGetSymbolAddress(&pyh, g_yh);
    cudaGetSymbolAddress(&posh, g_osh);
    cudaGetSymbolAddress(&pwth, g_wth); cudaGetSymbolAddress(&pwtl, g_wtl);
    cudaGetSymbolAddress(&pwqh, g_wqh); cudaGetSymbolAddress(&pwql, g_wql);
    cudaGetSymbolAddress(&pc1h, g_c1h);
    cudaGetSymbolAddress(&pc2h, g_c2h);
    cudaGetSymbolAddress(&pwtr, g_wtr); cudaGetSymbolAddress(&pwti, g_wti);
    float* fx = (float*)px;
    float* fq = (float*)pq;
    __half* th = (__half*)pth;
    __half *xh=(__half*)pxh;
    __half *Xh=(__half*)pXh;
    __half *yh=(__half*)pyh;
    __half *osh=(__half*)posh;
    __half *wth=(__half*)pwth, *wtl=(__half*)pwtl;
    __half *wqh=(__half*)pwqh, *wql=(__half*)pwql;
    __half *c1h=(__half*)pc1h;
    __half *c2h=(__half*)pc2h;
    float *wtr=(float*)pwtr, *wti=(float*)pwti;

    prep_kernel<<<PB_TOTAL, 256>>>(Wq, conv1_w, conv2_w, four_wr, four_wi,
                                   x_app, x_time, app_emb_w, time_w, time_b);
    wotab_kernel<<<dim3(128, 2), 128>>>(Wo, wth, wtl);

    const int M = BLq;
    for (int l = 0; l < 2; l++) {
        size_t woff = (size_t)l*Dq*Dq;
        size_t coff1 = (size_t)l*DFF*Dq;
        size_t mixoff = (size_t)l*Hq*MODES*Eq*Eq;

        dftx_kernel<<<512, 128>>>(xh, Xh);
        // xs = X @ Wq^T, 2-term (X single, Wq hi/lo)
        gemm_mma<GF_OUTF32, 2><<<dim3(4, 32), 256, SMEM_GEMM>>>(
            Xh, wqh + woff, wql + woff, nullptr, nullptr,
            fq, nullptr, 4096, Dq, Dq, 1.0f);
        mix2_kernel<<<Hq*MODES, 256>>>(fq, wtr + mixoff, wti + mixoff,
                                       bq + l*Dq, osh);
        // new_x = os @ WoT^T * (1/65536) + bo + x(half), 2-term (os single)
        gemm_mma<GF_BIAS|GF_RES|GF_OUTH16, 2><<<dim3(4, 256), 256, SMEM_GEMM>>>(
            osh, wth + (size_t)l*Dq*64, wtl + (size_t)l*Dq*64, bo + l*Dq, xh,
            nullptr, th, M, Dq, 64, 1.0f/65536.0f);
        decomp_kernel<<<512, 256>>>(th, nullptr, xh);
        gemm_mma<GF_RELU|GF_OUTH16, 1><<<dim3(DFF/128, M/128), 256, SMEM_GEMM>>>(
            xh, c1h + coff1, nullptr, nullptr, nullptr,
            nullptr, yh, M, DFF, Dq, 1.0f);
        gemm_mma<GF_RES|GF_OUTH16, 1><<<dim3(Dq/128, M/128), 256, SMEM_GEMM>>>(
            yh, c2h + coff1, nullptr, nullptr, xh,
            nullptr, th, M, Dq, DFF, 1.0f);
        if (l == 1) decomp_kernel<<<512, 256>>>(th, fx, nullptr);
        else        decomp_kernel<<<512, 256>>>(th, nullptr, xh);
    }

    ln_rows<<<BLq, 256>>>(fx);
    ln_cols_part<<<Bq*8, 512>>>(fx, norm_w, norm_b);
    ln_cols_fin<<<Bq, 512>>>(fx, norm_w, norm_b, time_vecs);
    proj_kernel<<<(NUM_APP + 63)/64, 256>>>(proj_w, proj_b, out);
}

// round 14
// speedup vs baseline: 5.2632x; 1.0017x over previous
#include <cuda_runtime.h>
#include <cuda_fp16.h>
#include <math.h>
#include <stdint.h>

#define Bq 64
#define Lq 512
#define Dq 512
#define Hq 8
#define Eq 64
#define DFF 2048
#define MODES 32
#define VOCAB 10000
#define NUM_APP 10000
#define CATD 536
#define BLq (Bq*Lq)

// ================= helpers =================
__device__ __forceinline__ uint32_t smem_u32(const void* p) {
    uint32_t a;
    asm("{ .reg .u64 t; cvta.to.shared.u64 t, %1; cvt.u32.u64 %0, t; }" : "=r"(a) : "l"(p));
    return a;
}
__device__ __forceinline__ void cp16(uint32_t dst, const void* src) {
    asm volatile("cp.async.cg.shared.global [%0], [%1], 16;" :: "r"(dst), "l"(src) : "memory");
}
#define CP_COMMIT() asm volatile("cp.async.commit_group;" ::: "memory")

#define LDSM_X4(r0,r1,r2,r3, addr) \
    asm volatile("ldmatrix.sync.aligned.m8n8.x4.shared.b16 {%0,%1,%2,%3}, [%4];" \
        : "=r"(r0), "=r"(r1), "=r"(r2), "=r"(r3) : "r"(addr))

#define MMA_F32(d, a, b0, b1) \
    asm volatile("mma.sync.aligned.m16n8k16.row.col.f32.f16.f16.f32 " \
        "{%0,%1,%2,%3},{%4,%5,%6,%7},{%8,%9},{%0,%1,%2,%3};" \
        : "+f"((d)[0]), "+f"((d)[1]), "+f"((d)[2]), "+f"((d)[3]) \
        : "r"((a)[0]), "r"((a)[1]), "r"((a)[2]), "r"((a)[3]), "r"(b0), "r"(b1))

// ================= scratch (device globals) =================
__device__ float g_x[BLq*Dq];                        // only final-layer x (for ln)
__device__ float g_q[BLq*Dq];
__device__ __align__(256) __half g_th[BLq*Dq];       // pre-decomp tensor, fp16
__device__ __align__(256) __half g_xh[BLq*Dq];       // activation x, fp16
__device__ __align__(256) __half g_Xh[4096*Dq];
__device__ __align__(256) __half g_yh[BLq*DFF];
__device__ __align__(256) __half g_osh[BLq*64];
__device__ __align__(256) __half g_wth[2*Dq*64], g_wtl[2*Dq*64];
__device__ __align__(256) __half g_wqh[2*Dq*Dq], g_wql[2*Dq*Dq];
__device__ __align__(256) __half g_c1h[2*DFF*Dq];
__device__ __align__(256) __half g_c2h[2*Dq*DFF];
__device__ float g_wtr[2*Hq*MODES*Eq*Eq];
__device__ float g_wti[2*Hq*MODES*Eq*Eq];
__device__ float g_ct[Lq*MODES], g_st[Lq*MODES];
__device__ float g_mu[BLq], g_rs[BLq];
__device__ float g_part[8*Bq*Dq];
__device__ float g_cat[Bq*CATD];

// ================= merged preamble kernel =================
#define NWQ (2*Dq*Dq)
#define NC1 (2*DFF*Dq)
#define NC2 (2*Dq*DFF)
#define PB_INIT 64
#define PB_CONV ((NWQ + NC1 + NC2 + 255)/256)
#define PB_WTRANS 1024
#define PB_EMBED (BLq*Dq/4/256)
#define PB_TOTAL (PB_INIT + PB_CONV + PB_WTRANS + PB_EMBED)

__global__ void __launch_bounds__(256) prep_kernel(
    const float* __restrict__ Wq, const float* __restrict__ c1, const float* __restrict__ c2,
    const float* __restrict__ wr, const float* __restrict__ wi,
    const int* __restrict__ app, const float* __restrict__ xt,
    const float* __restrict__ emb, const float* __restrict__ tw, const float* __restrict__ tb)
{
    __shared__ float tr[64][33], ti_[64][33];
    int blk = blockIdx.x;
    int t = threadIdx.x;

    if (blk < PB_INIT) {
        // trig tables
        int idx = blk*256 + t;
        int l = idx >> 5, m = idx & 31;
        double a = (double)(m*l) / 256.0;
        double s, c;
        sincospi(a, &s, &c);
        g_ct[idx] = (float)c;
        g_st[idx] = (float)s;
    } else if (blk < PB_INIT + PB_CONV) {
        // weight conversions
        int i = (blk - PB_INIT)*256 + t;
        if (i < NWQ) {
            float v = Wq[i];
            __half hv = __float2half_rn(v);
            g_wqh[i] = hv;
            g_wql[i] = __float2half_rn(v - __half2float(hv));
        } else if (i < NWQ + NC1) {
            int j = i - NWQ;
            g_c1h[j] = __float2half_rn(c1[j]);
        } else if (i < NWQ + NC1 + NC2) {
            int j = i - NWQ - NC1;
            g_c2h[j] = __float2half_rn(c2[j]);
        }
    } else if (blk < PB_INIT + PB_CONV + PB_WTRANS) {
        // transpose four_wr/wi: [l][h][i][o][m] -> [l][h][m][i][o]
        int b2 = blk - PB_INIT - PB_CONV;
        int i  = b2 & 63;
        int lh = b2 >> 6;
        const float* pr = wr + ((size_t)lh*64 + i)*64*32;
        const float* pi = wi + ((size_t)lh*64 + i)*64*32;
        #pragma unroll
        for (int j = 0; j < 8; j++) {
            int v = t + j*256;
            int o = v >> 5, m = v & 31;
            tr[o][m]  = pr[v];
            ti_[o][m] = pi[v];
        }
        __syncthreads();
        #pragma unroll
        for (int j = 0; j < 8; j++) {
            int v = t + j*256;
            int m = v >> 6, o = v & 63;
            size_t dst = ((size_t)(lh*32 + m)*64 + i)*64 + o;
            g_wtr[dst] = tr[o][m];
            g_wti[dst] = ti_[o][m];
        }
    } else {
        // embed -> xh (half)
        int idx = (blk - PB_INIT - PB_CONV - PB_WTRANS)*256 + t;
        int d4 = (idx & 127) * 4;
        size_t bl = (size_t)(idx >> 7);
        int a = app[bl];
        float xtv = xt[bl];
        float4 e = *(const float4*)&emb[(size_t)a*Dq + d4];
        float4 w = *(const float4*)&tw[d4];
        float4 bb = *(const float4*)&tb[d4];
        __half2 h0, h1;
        h0.x = __float2half_rn(fmaf(xtv, w.x, e.x) + bb.x);
        h0.y = __float2half_rn(fmaf(xtv, w.y, e.y) + bb.y);
        h1.x = __float2half_rn(fmaf(xtv, w.z, e.z) + bb.z);
        h1.y = __float2half_rn(fmaf(xtv, w.w, e.w) + bb.w);
        *(__half2*)&g_xh[bl*Dq + d4]     = h0;
        *(__half2*)&g_xh[bl*Dq + d4 + 2] = h1;
    }
}

// ========== Wo frequency table (needs g_ct/g_st) ==========
__global__ void __launch_bounds__(128) wotab_kernel(const float* __restrict__ Wo,
                                                    __half* __restrict__ wth,
                                                    __half* __restrict__ wtl) {
    int layer = blockIdx.y;
    int j0 = blockIdx.x * 4;
    __shared__ float sw[4][512];
    int t = threadIdx.x;
    const float* wo = Wo + (size_t)layer*Dq*Dq + (size_t)j0*Dq;
    #pragma unroll
    for (int j = 0; j < 4; j++) {
        int v = t + j*128;
        int r = v >> 7, c4 = (v & 127) * 4;
        *(float4*)&sw[r][c4] = *(const float4*)&wo[(size_t)r*Dq + c4];
    }
    __syncthreads();
    int tj = t >> 5, tm = t & 31;
    float ac = 0.f, as = 0.f;
    for (int l = 0; l < Lq; l++) {
        float w = sw[tj][l];
        ac = fmaf(w, g_ct[l*32 + tm], ac);
        as = fmaf(w, g_st[l*32 + tm], as);
    }
    float cm = (tm == 0 ? 1.0f : 2.0f) * (256.0f/512.0f);
    float vc = ac*cm, vs = -as*cm;
    size_t base = ((size_t)layer*Dq + j0 + tj)*64 + tm*2;
    __half hc = __float2half_rn(vc);
    __half hs = __float2half_rn(vs);
    wth[base]   = hc;  wtl[base]   = __float2half_rn(vc - __half2float(hc));
    wth[base+1] = hs;  wtl[base+1] = __float2half_rn(vs - __half2float(hs));
}

// ================= mma.sync fp16 GEMM: C = A(MxK) @ B(NxK)^T =============
// TERMS==2: Ah*(Bh+Bl).  TERMS==1: Ah*Bh.   (residual fp16)
#define GF_BIAS 1
#define GF_RES  2
#define GF_RELU 4
#define GF_OUTF32 8
#define GF_OUTH16 16

#define STG 32768
#define SMEM_GEMM (3*STG + 256)

template<int FLAGS, int TERMS>
__global__ void __launch_bounds__(256, 1) gemm_mma(
    const __half* __restrict__ Ah,
    const __half* __restrict__ Bh, const __half* __restrict__ Bl,
    const float* __restrict__ bias, const __half* __restrict__ res,
    float* __restrict__ Cf, __half* __restrict__ Ch,
    int M, int N, int K, float scal)
{
    extern __shared__ char dsm[];
    uint32_t sbase = (smem_u32(dsm) + 127) & ~127u;

    const int t = threadIdx.x;
    const int lane = t & 31;
    const int wid = t >> 5;
    const int wm = wid >> 2;
    const int wn = wid & 3;
    const int bm = blockIdx.y * 128, bn = blockIdx.x * 128;
    const int NC = K >> 5;

    float acc[4][4][4] = {};

    const int lrow = t >> 2;
    const int lcell = t & 3;
    auto load_chunk = [&](int c, int stg) {
        uint32_t sb = sbase + stg*STG;
        size_t k0 = (size_t)c * 32 + lcell*8;
        #pragma unroll
        for (int j = 0; j < 2; j++) {
            int row = lrow + j*64;
            uint32_t soff = row*64 + (((uint32_t)(lcell ^ (row & 3))) << 4);
            size_t ga = (size_t)(bm + row)*K + k0;
            size_t gb = (size_t)(bn + row)*K + k0;
            cp16(sb +         soff, Ah + ga);
            cp16(sb + 16384 + soff, Bh + gb);
            if (TERMS >= 2) cp16(sb + 24576 + soff, Bl + gb);
        }
        CP_COMMIT();
    };

    load_chunk(0, 0);
    if (NC > 1) load_chunk(1, 1);

    const int arow_base = wm*64 + (lane & 15);
    const int brow_base = wn*32 + (lane & 15);
    const int kc_hi = lane >> 4;

    for (int c = 0; c < NC; c++) {
        if (c + 2 < NC) asm volatile("cp.async.wait_group 1;" ::: "memory");
        else            asm volatile("cp.async.wait_group 0;" ::: "memory");
        __syncthreads();
        if (c + 2 < NC) load_chunk(c + 2, (c + 2) % 3);

        uint32_t sb = sbase + (c % 3)*STG;
        #pragma unroll
        for (int s = 0; s < 2; s++) {
            uint32_t ah[4][4], bh[2][4], bl[2][4];
            int chunk = s*2 + kc_hi;
            #pragma unroll
            for (int mt = 0; mt < 4; mt++) {
                int row = arow_base + mt*16;
                uint32_t off = row*64 + (((uint32_t)(chunk ^ (row & 3))) << 4);
                LDSM_X4(ah[mt][0], ah[mt][1], ah[mt][2], ah[mt][3], sb + off);
            }
            #pragma unroll
            for (int g = 0; g < 2; g++) {
                int row = brow_base + g*16;
                uint32_t off = row*64 + (((uint32_t)(chunk ^ (row & 3))) << 4);
                LDSM_X4(bh[g][0], bh[g][1], bh[g][2], bh[g][3], sb + 16384 + off);
                if (TERMS >= 2)
                    LDSM_X4(bl[g][0], bl[g][1], bl[g][2], bl[g][3], sb + 24576 + off);
            }
            #pragma unroll
            for (int mt = 0; mt < 4; mt++) {
                #pragma unroll
                for (int nt = 0; nt < 4; nt++) {
                    int g = nt >> 1, o = nt & 1;
                    MMA_F32(acc[mt][nt], ah[mt], bh[g][o], bh[g][o+2]);
                    if (TERMS >= 2)
                        MMA_F32(acc[mt][nt], ah[mt], bl[g][o], bl[g][o+2]);
                }
            }
        }
    }

    int r0 = bm + wm*64 + (lane >> 2);
    int c0 = bn + wn*32 + (lane & 3)*2;
    #pragma unroll
    for (int mt = 0; mt < 4; mt++) {
        #pragma unroll
        for (int nt = 0; nt < 4; nt++) {
            int col = c0 + nt*8;
            float b0 = 0.f, b1 = 0.f;
            if (FLAGS & GF_BIAS) { b0 = bias[col]; b1 = bias[col+1]; }
            #pragma unroll
            for (int half = 0; half < 2; half++) {
                int row = r0 + mt*16 + half*8;
                float v0 = acc[mt][nt][half*2+0] * scal + b0;
                float v1 = acc[mt][nt][half*2+1] * scal + b1;
                size_t ro = (size_t)row * N + col;
                if (FLAGS & GF_RES) {
                    float2 r2 = __half22float2(*(const __half2*)&res[ro]);
                    v0 += r2.x; v1 += r2.y;
                }
                if (FLAGS & GF_RELU) { v0 = fmaxf(v0, 0.f); v1 = fmaxf(v1, 0.f); }
                if (FLAGS & GF_OUTF32) {
                    float2 o2; o2.x = v0; o2.y = v1;
                    *(float2*)&Cf[ro] = o2;
                }
                if (FLAGS & GF_OUTH16) {
                    __half2 hp; hp.x = __float2half_rn(v0); hp.y = __float2half_rn(v1);
                    *(__half2*)&Ch[ro] = hp;
                }
            }
        }
    }
}

// ========== DFT of x (half input) with l/l+256 symmetry; half output ==========
__global__ void __launch_bounds__(128) dftx_kernel(const __half* __restrict__ x,
                                                   __half* __restrict__ Xh) {
    int blk = blockIdx.x;
    int b = blk >> 3;
    int dchunk = (blk & 7) * 64;
    __shared__ float sqA[32][68];
    __shared__ float sqB[32][68];
    __shared__ float sct[32][32];
    __shared__ float sst[32][32];
    int t = threadIdx.x;
    int td = t & 63;
    int tm = (t >> 6) * 16;

    float ar[16] = {}, ai[16] = {};
    const __half* qbase = x + (size_t)b*Lq*Dq + dchunk;

    for (int l0 = 0; l0 < 256; l0 += 32) {
        #pragma unroll
        for (int j = 0; j < 8; j++) {
            int v = t + j*128;
            int ll = v >> 5;
            int c2 = (v & 31) * 2;
            float2 fa = __half22float2(*(const __half2*)&qbase[(size_t)(l0+ll)*Dq + c2]);
            sqA[ll][c2] = fa.x; sqA[ll][c2+1] = fa.y;
            float2 fb = __half22float2(*(const __half2*)&qbase[(size_t)(l0+256+ll)*Dq + c2]);
            sqB[ll][c2] = fb.x; sqB[ll][c2+1] = fb.y;
        }
        #pragma unroll
        for (int j = 0; j < 2; j++) {
            int v = t + j*128;
            int ll = v >> 3;
            int c4 = (v & 7) * 4;
            *(float4*)&sct[ll][c4] = *(const float4*)&g_ct[(l0+ll)*32 + c4];
            *(float4*)&sst[ll][c4] = *(const float4*)&g_st[(l0+ll)*32 + c4];
        }
        __syncthreads();
        #pragma unroll 2
        for (int ll = 0; ll < 32; ll++) {
            float xa = sqA[ll][td], xb = sqB[ll][td];
            float u = xa + xb;
            float w = xa - xb;
            float c[16], s[16];
            #pragma unroll
            for (int j = 0; j < 16; j += 4) {
                *(float4*)&c[j] = *(float4*)&sct[ll][tm+j];
                *(float4*)&s[j] = *(float4*)&sst[ll][tm+j];
            }
            #pragma unroll
            for (int mm = 0; mm < 16; mm++) {
                float v = (mm & 1) ? w : u;
                ar[mm] = fmaf(v,  c[mm], ar[mm]);
                ai[mm] = fmaf(-v, s[mm], ai[mm]);
            }
        }
        __syncthreads();
    }
    int d0 = dchunk + td;
    #pragma unroll
    for (int mm = 0; mm < 16; mm++) {
        int m = tm + mm;
        size_t rowr = ((size_t)(m*2+0)*64 + b)*Dq + d0;
        size_t rowi = ((size_t)(m*2+1)*64 + b)*Dq + d0;
        Xh[rowr] = __float2half_rn(ar[mm]);
        Xh[rowi] = __float2half_rn(ai[mm]);
    }
}

// ========== complex mode mix (half output, single) ==========
__global__ void __launch_bounds__(256) mix2_kernel(const float* __restrict__ xs,
                                                   const float* __restrict__ wtr,
                                                   const float* __restrict__ wti,
                                                   const float* __restrict__ bq,
                                                   __half* __restrict__ osh) {
    int h = blockIdx.x >> 5, m = blockIdx.x & 31;
    __shared__ float swr[64][64];
    __shared__ float swi[64][64];
    __shared__ float sxr[64][65];
    __shared__ float sxi[64][65];
    int t = threadIdx.x;
    const float* pr = wtr + ((size_t)(h*32 + m))*4096;
    const float* pi = wti + ((size_t)(h*32 + m))*4096;
    #pragma unroll
    for (int j = 0; j < 16; j++) {
        int v = t + j*256;
        int r = v >> 6, c = v & 63;
        swr[r][c] = pr[v];
        swi[r][c] = pi[v];
    }
    #pragma unroll
    for (int j = 0; j < 16; j++) {
        int v = t + j*256;
        int b = v >> 6, i = v & 63;
        if (j < 8) {
            float vr = xs[((size_t)(2*m)*64 + b)*Dq + h*64 + i];
            if (m == 0) vr += 512.0f * bq[h*64 + i];
            sxr[b][i] = vr;
        } else {
            sxi[b][i] = xs[((size_t)(2*m+1)*64 + b)*Dq + h*64 + i];
        }
    }
    __syncthreads();

    int b = t >> 2;
    int o0 = (t & 3) * 16;
    float orr[16] = {}, oii[16] = {};
    for (int i = 0; i < 64; i++) {
        float xr = sxr[b][i], xi = sxi[b][i];
        float wr4[16], wi4[16];
        #pragma unroll
        for (int j = 0; j < 16; j += 4) {
            *(float4*)&wr4[j] = *(float4*)&swr[i][o0+j];
            *(float4*)&wi4[j] = *(float4*)&swi[i][o0+j];
        }
        #pragma unroll
        for (int j = 0; j < 16; j++) {
            orr[j] = fmaf(xr, wr4[j], orr[j]);
            orr[j] = fmaf(-xi, wi4[j], orr[j]);
            oii[j] = fmaf(xr, wi4[j], oii[j]);
            oii[j] = fmaf(xi, wr4[j], oii[j]);
        }
    }
    #pragma unroll
    for (int j = 0; j < 16; j++) {
        int o = o0 + j;
        __half2 hp;
        hp.x = __float2half_rn(orr[j] * 256.0f);
        hp.y = __float2half_rn(oii[j] * 256.0f);
        size_t base = ((size_t)b*512 + h*64 + o)*64 + 2*m;
        *(__half2*)&osh[base] = hp;
    }
}

// ========== series_decomp: half in; writes EITHER xh (half) OR fx (fp32) =====
__global__ void decomp_kernel(const __half* __restrict__ in, float* __restrict__ out_f,
                              __half* __restrict__ oh) {
    int gid = blockIdx.x*blockDim.x + threadIdx.x;
    int seg = gid >> 14;
    int r = gid & 16383;
    int b = r >> 8, d2 = (r & 255) * 2;
    const __half2* p = (const __half2*)(in + (size_t)b*Lq*Dq + d2);
    size_t obase = (size_t)b*Lq*Dq + d2;
    int lstart = seg * 64;
    float2 ws; ws.x = 0.f; ws.y = 0.f;
    #pragma unroll
    for (int j = -12; j <= 12; j++) {
        int jj = lstart + j;
        jj = jj < 0 ? 0 : jj;
        float2 q = __half22float2(p[(size_t)jj*256]);
        ws.x += q.x; ws.y += q.y;
    }
    int lend = lstart + 64;
    if (oh) {
        for (int l = lstart; l < lend; l++) {
            float2 xl = __half22float2(p[(size_t)l*256]);
            float2 v;
            v.x = xl.x - ws.x*(1.0f/25.0f);
            v.y = xl.y - ws.y*(1.0f/25.0f);
            __half2 hv; hv.x = __float2half_rn(v.x); hv.y = __float2half_rn(v.y);
            *(__half2*)&oh[obase + (size_t)l*Dq] = hv;
            int jn = l+13 > Lq-1 ? Lq-1 : l+13;
            int jo = l-12 < 0 ? 0 : l-12;
            float2 a = __half22float2(p[(size_t)jn*256]);
            float2 bb = __half22float2(p[(size_t)jo*256]);
            ws.x += a.x - bb.x; ws.y += a.y - bb.y;
        }
    } else {
        for (int l = lstart; l < lend; l++) {
            float2 xl = __half22float2(p[(size_t)l*256]);
            float2 v;
            v.x = xl.x - ws.x*(1.0f/25.0f);
            v.y = xl.y - ws.y*(1.0f/25.0f);
            *(float2*)&out_f[obase + (size_t)l*Dq] = v;
            int jn = l+13 > Lq-1 ? Lq-1 : l+13;
            int jo = l-12 < 0 ? 0 : l-12;
            float2 a = __half22float2(p[(size_t)jn*256]);
            float2 bb = __half22float2(p[(size_t)jo*256]);
            ws.x += a.x - bb.x; ws.y += a.y - bb.y;
        }
    }
}

// ================= final layernorm / projection =================
__global__ void ln_rows(const float* __restrict__ x) {
    int row = blockIdx.x;
    int t = threadIdx.x;
    const float* p = x + (size_t)row*Dq;
    float v0 = p[t], v1 = p[t+256];
    __shared__ float sh[8];
    float s = v0 + v1;
    int lane = t & 31, w = t >> 5;
    #pragma unroll
    for (int o = 16; o > 0; o >>= 1) s += __shfl_down_sync(~0u, s, o);
    if (lane == 0) sh[w] = s;
    __syncthreads();
    if (t < 32) {
        float v = (t < 8) ? sh[t] : 0.f;
        #pragma unroll
        for (int o = 4; o > 0; o >>= 1) v += __shfl_down_sync(~0u, v, o);
        if (t == 0) sh[0] = v;
    }
    __syncthreads();
    float mu = sh[0] * (1.0f/512.0f);
    __syncthreads();
    float d0 = v0 - mu, d1 = v1 - mu;
    s = d0*d0 + d1*d1;
    #pragma unroll
    for (int o = 16; o > 0; o >>= 1) s += __shfl_down_sync(~0u, s, o);
    if (lane == 0) sh[w] = s;
    __syncthreads();
    if (t < 32) {
        float v = (t < 8) ? sh[t] : 0.f;
        #pragma unroll
        for (int o = 4; o > 0; o >>= 1) v += __shfl_down_sync(~0u, v, o);
        if (t == 0) {
            float var = v * (1.0f/512.0f);
            g_mu[row] = mu;
            g_rs[row] = rsqrtf(var + 1e-5f);
        }
    }
}

__global__ void ln_cols_part(const float* __restrict__ x, const float* __restrict__ nw,
                             const float* __restrict__ nb) {
    int blk = blockIdx.x;
    int b = blk >> 3, seg = blk & 7;
    int d = threadIdx.x;
    float w = nw[d], bb = nb[d];
    float sum = 0.f;
    int l0 = seg * 64;
    #pragma unroll 4
    for (int l = l0; l < l0 + 64; l++) {
        int row = b*Lq + l;
        sum += (x[(size_t)row*Dq + d] - g_mu[row]) * g_rs[row] * w + bb;
    }
    g_part[(size_t)seg*Bq*Dq + b*Dq + d] = sum;
}

__global__ void ln_cols_fin(const float* __restrict__ x, const float* __restrict__ nw,
                            const float* __restrict__ nb, const float* __restrict__ tv) {
    int b = blockIdx.x;
    int d = threadIdx.x;
    float sum = 0.f;
    #pragma unroll
    for (int seg = 0; seg < 8; seg++)
        sum += g_part[(size_t)seg*Bq*Dq + b*Dq + d];
    int row = b*Lq + (Lq-1);
    float lastv = (x[(size_t)row*Dq + d] - g_mu[row]) * g_rs[row] * nw[d] + nb[d];
    g_cat[b*CATD + d] = lastv - sum*(1.0f/512.0f);
    if (d < 24) g_cat[b*CATD + 512 + d] = tv[((size_t)b*Lq + (Lq-1))*24 + d];
}

__global__ void __launch_bounds__(256) proj_kernel(const float* __restrict__ pw,
                                                   const float* __restrict__ pb,
                                                   float* __restrict__ out) {
    __shared__ float As[8][65];
    __shared__ float Bs[8][65];
    int n0 = blockIdx.x * 64;
    int t = threadIdx.x;
    int tx = t & 15, ty = t >> 4;
    float acc[4][4] = {};
    for (int k0 = 0; k0 < CATD; k0 += 8) {
        int v = t*2;
        int r = v >> 3, c = v & 7;
        As[c][r]   = g_cat[r*CATD + k0 + c];
        As[c+1][r] = g_cat[r*CATD + k0 + c + 1];
        int n = n0 + r;
        float f0 = 0.f, f1 = 0.f;
        if (n < NUM_APP) {
            f0 = pw[(size_t)n*CATD + k0 + c];
            f1 = pw[(size_t)n*CATD + k0 + c + 1];
        }
        Bs[c][r] = f0; Bs[c+1][r] = f1;
        __syncthreads();
        #pragma unroll
        for (int k = 0; k < 8; k++) {
            float a[4], bv[4];
            #pragma unroll
            for (int i = 0; i < 4; i++) { a[i] = As[k][ty*4+i]; bv[i] = Bs[k][tx*4+i]; }
            #pragma unroll
            for (int i = 0; i < 4; i++)
                #pragma unroll
                for (int j = 0; j < 4; j++)
                    acc[i][j] = fmaf(a[i], bv[j], acc[i][j]);
        }
        __syncthreads();
    }
    #pragma unroll
    for (int i = 0; i < 4; i++) {
        int bi = ty*4 + i;
        #pragma unroll
        for (int j = 0; j < 4; j++) {
            int n = n0 + tx*4 + j;
            if (n < NUM_APP) out[(size_t)bi*NUM_APP + n] = acc[i][j] + pb[n];
        }
    }
}

// ================= host orchestration =================
extern "C" void kernel_launch(void* const* d_in, const int* in_sizes, int n_in,
                              void* d_out, int out_size) {
    const int*   x_app     = (const int*)  d_in[0];
    const float* x_time    = (const float*)d_in[1];
    const float* time_vecs = (const float*)d_in[2];
    const float* app_emb_w = (const float*)d_in[4];
    const float* time_w    = (const float*)d_in[5];
    const float* time_b    = (const float*)d_in[6];
    const float* Wq        = (const float*)d_in[7];
    const float* bq        = (const float*)d_in[8];
    const float* Wo        = (const float*)d_in[9];
    const float* bo        = (const float*)d_in[10];
    const float* four_wr   = (const float*)d_in[11];
    const float* four_wi   = (const float*)d_in[12];
    const float* conv1_w   = (const float*)d_in[13];
    const float* conv2_w   = (const float*)d_in[14];
    const float* norm_w    = (const float*)d_in[15];
    const float* norm_b    = (const float*)d_in[16];
    const float* proj_w    = (const float*)d_in[17];
    const float* proj_b    = (const float*)d_in[18];
    float* out = (float*)d_out;

    cudaFuncSetAttribute((const void*)gemm_mma<GF_OUTF32, 2>,                cudaFuncAttributeMaxDynamicSharedMemorySize, SMEM_GEMM);
    cudaFuncSetAttribute((const void*)gemm_mma<GF_BIAS|GF_RES|GF_OUTH16, 2>, cudaFuncAttributeMaxDynamicSharedMemorySize, SMEM_GEMM);
    cudaFuncSetAttribute((const void*)gemm_mma<GF_RELU|GF_OUTH16, 1>,        cudaFuncAttributeMaxDynamicSharedMemorySize, SMEM_GEMM);
    cudaFuncSetAttribute((const void*)gemm_mma<GF_RES|GF_OUTH16, 1>,         cudaFuncAttributeMaxDynamicSharedMemorySize, SMEM_GEMM);

    void *px, *pq, *pth;
    void *pxh, *pXh, *pyh, *posh, *pwth, *pwtl;
    void *pwqh, *pwql, *pc1h, *pc2h, *pwtr, *pwti;
    cudaGetSymbolAddress(&px, g_x);
    cudaGetSymbolAddress(&pq, g_q);
    cudaGetSymbolAddress(&pth, g_th);
    cudaGetSymbolAddress(&pxh, g_xh);
    cudaGetSymbolAddress(&pXh, g_Xh);
    cudaGetSymbolAddress(&pyh, g_yh);
    cudaGetSymbolAddress(&posh, g_osh);
    cudaGetSymbolAddress(&pwth, g_wth); cudaGetSymbolAddress(&pwtl, g_wtl);
    cudaGetSymbolAddress(&pwqh, g_wqh); cudaGetSymbolAddress(&pwql, g_wql);
    cudaGetSymbolAddress(&pc1h, g_c1h);
    cudaGetSymbolAddress(&pc2h, g_c2h);
    cudaGetSymbolAddress(&pwtr, g_wtr); cudaGetSymbolAddress(&pwti, g_wti);
    float* fx = (float*)px;
    float* fq = (float*)pq;
    __half* th = (__half*)pth;
    __half *xh=(__half*)pxh;
    __half *Xh=(__half*)pXh;
    __half *yh=(__half*)pyh;
    __half *osh=(__half*)posh;
    __half *wth=(__half*)pwth, *wtl=(__half*)pwtl;
    __half *wqh=(__half*)pwqh, *wql=(__half*)pwql;
    __half *c1h=(__half*)pc1h;
    __half *c2h=(__half*)pc2h;
    float *wtr=(float*)pwtr, *wti=(float*)pwti;

    prep_kernel<<<PB_TOTAL, 256>>>(Wq, conv1_w, conv2_w, four_wr, four_wi,
                                   x_app, x_time, app_emb_w, time_w, time_b);
    wotab_kernel<<<dim3(128, 2), 128>>>(Wo, wth, wtl);

    const int M = BLq;
    for (int l = 0; l < 2; l++) {
        size_t woff = (size_t)l*Dq*Dq;
        size_t coff1 = (size_t)l*DFF*Dq;
        size_t mixoff = (size_t)l*Hq*MODES*Eq*Eq;

        dftx_kernel<<<512, 128>>>(xh, Xh);
        // xs = X @ Wq^T, 2-term (X single, Wq hi/lo)
        gemm_mma<GF_OUTF32, 2><<<dim3(4, 32), 256, SMEM_GEMM>>>(
            Xh, wqh + woff, wql + woff, nullptr, nullptr,
            fq, nullptr, 4096, Dq, Dq, 1.0f);
        mix2_kernel<<<Hq*MODES, 256>>>(fq, wtr + mixoff, wti + mixoff,
                                       bq + l*Dq, osh);
        // new_x = os @ WoT^T * (1/65536) + bo + x(half), 2-term (os single)
        gemm_mma<GF_BIAS|GF_RES|GF_OUTH16, 2><<<dim3(4, 256), 256, SMEM_GEMM>>>(
            osh, wth + (size_t)l*Dq*64, wtl + (size_t)l*Dq*64, bo + l*Dq, xh,
            nullptr, th, M, Dq, 64, 1.0f/65536.0f);
        decomp_kernel<<<512, 256>>>(th, nullptr, xh);
        gemm_mma<GF_RELU|GF_OUTH16, 1><<<dim3(DFF/128, M/128), 256, SMEM_GEMM>>>(
            xh, c1h + coff1, nullptr, nullptr, nullptr,
            nullptr, yh, M, DFF, Dq, 1.0f);
        gemm_mma<GF_RES|GF_OUTH16, 1><<<dim3(Dq/128, M/128), 256, SMEM_GEMM>>>(
            yh, c2h + coff1, nullptr, nullptr, xh,
            nullptr, th, M, Dq, DFF, 1.0f);
        if (l == 1) decomp_kernel<<<512, 256>>>(th, fx, nullptr);
        else        decomp_kernel<<<512, 256>>>(th, nullptr, xh);
    }

    ln_rows<<<BLq, 256>>>(fx);
    ln_cols_part<<<Bq*8, 512>>>(fx, norm_w, norm_b);
    ln_cols_fin<<<Bq, 512>>>(fx, norm_w, norm_b, time_vecs);
    proj_kernel<<<(NUM_APP + 63)/64, 256>>>(proj_w, proj_b, out);
}

// round 16
// speedup vs baseline: 5.2685x; 1.0010x over previous
#include <cuda_runtime.h>
#include <cuda_fp16.h>
#include <math.h>
#include <stdint.h>

#define Bq 64
#define Lq 512
#define Dq 512
#define Hq 8
#define Eq 64
#define DFF 2048
#define MODES 32
#define VOCAB 10000
#define NUM_APP 10000
#define CATD 536
#define BLq (Bq*Lq)

// ================= helpers =================
__device__ __forceinline__ uint32_t smem_u32(const void* p) {
    uint32_t a;
    asm("{ .reg .u64 t; cvta.to.shared.u64 t, %1; cvt.u32.u64 %0, t; }" : "=r"(a) : "l"(p));
    return a;
}
__device__ __forceinline__ void cp16(uint32_t dst, const void* src) {
    asm volatile("cp.async.cg.shared.global [%0], [%1], 16;" :: "r"(dst), "l"(src) : "memory");
}
#define CP_COMMIT() asm volatile("cp.async.commit_group;" ::: "memory")

#define LDSM_X4(r0,r1,r2,r3, addr) \
    asm volatile("ldmatrix.sync.aligned.m8n8.x4.shared.b16 {%0,%1,%2,%3}, [%4];" \
        : "=r"(r0), "=r"(r1), "=r"(r2), "=r"(r3) : "r"(addr))

#define MMA_F32(d, a, b0, b1) \
    asm volatile("mma.sync.aligned.m16n8k16.row.col.f32.f16.f16.f32 " \
        "{%0,%1,%2,%3},{%4,%5,%6,%7},{%8,%9},{%0,%1,%2,%3};" \
        : "+f"((d)[0]), "+f"((d)[1]), "+f"((d)[2]), "+f"((d)[3]) \
        : "r"((a)[0]), "r"((a)[1]), "r"((a)[2]), "r"((a)[3]), "r"(b0), "r"(b1))

// ================= scratch (device globals) =================
__device__ float g_x[BLq*Dq];
__device__ float g_q[BLq*Dq];
__device__ __align__(256) __half g_th[BLq*Dq];
__device__ __align__(256) __half g_xh[BLq*Dq];
__device__ __align__(256) __half g_Xh[4096*Dq];
__device__ __align__(256) __half g_yh[BLq*DFF];
__device__ __align__(256) __half g_osh[BLq*64];
__device__ __align__(256) __half g_wth[2*Dq*64], g_wtl[2*Dq*64];
__device__ __align__(256) __half g_wqh[2*Dq*Dq], g_wql[2*Dq*Dq];
__device__ __align__(256) __half g_c1h[2*DFF*Dq];
__device__ __align__(256) __half g_c2h[2*Dq*DFF];
__device__ float g_wtr[2*Hq*MODES*Eq*Eq];
__device__ float g_wti[2*Hq*MODES*Eq*Eq];
__device__ float g_ct[Lq*MODES], g_st[Lq*MODES];
__device__ float g_mu[BLq], g_rs[BLq];
__device__ float g_part[8*Bq*Dq];
__device__ float g_cat[Bq*CATD];

// ================= merged preamble kernel =================
#define NWQ (2*Dq*Dq)
#define NC1 (2*DFF*Dq)
#define NC2 (2*Dq*DFF)
#define PB_INIT 64
#define PB_CONV ((NWQ + NC1 + NC2 + 255)/256)
#define PB_WTRANS 1024
#define PB_EMBED (BLq*Dq/4/256)
#define PB_TOTAL (PB_INIT + PB_CONV + PB_WTRANS + PB_EMBED)

__global__ void __launch_bounds__(256) prep_kernel(
    const float* __restrict__ Wq, const float* __restrict__ c1, const float* __restrict__ c2,
    const float* __restrict__ wr, const float* __restrict__ wi,
    const int* __restrict__ app, const float* __restrict__ xt,
    const float* __restrict__ emb, const float* __restrict__ tw, const float* __restrict__ tb)
{
    __shared__ float tr[64][33], ti_[64][33];
    int blk = blockIdx.x;
    int t = threadIdx.x;

    if (blk < PB_INIT) {
        int idx = blk*256 + t;
        int l = idx >> 5, m = idx & 31;
        double a = (double)(m*l) / 256.0;
        double s, c;
        sincospi(a, &s, &c);
        g_ct[idx] = (float)c;
        g_st[idx] = (float)s;
    } else if (blk < PB_INIT + PB_CONV) {
        int i = (blk - PB_INIT)*256 + t;
        if (i < NWQ) {
            float v = Wq[i];
            __half hv = __float2half_rn(v);
            g_wqh[i] = hv;
            g_wql[i] = __float2half_rn(v - __half2float(hv));
        } else if (i < NWQ + NC1) {
            int j = i - NWQ;
            g_c1h[j] = __float2half_rn(c1[j]);
        } else if (i < NWQ + NC1 + NC2) {
            int j = i - NWQ - NC1;
            g_c2h[j] = __float2half_rn(c2[j]);
        }
    } else if (blk < PB_INIT + PB_CONV + PB_WTRANS) {
        int b2 = blk - PB_INIT - PB_CONV;
        int i  = b2 & 63;
        int lh = b2 >> 6;
        const float* pr = wr + ((size_t)lh*64 + i)*64*32;
        const float* pi = wi + ((size_t)lh*64 + i)*64*32;
        #pragma unroll
        for (int j = 0; j < 8; j++) {
            int v = t + j*256;
            int o = v >> 5, m = v & 31;
            tr[o][m]  = pr[v];
            ti_[o][m] = pi[v];
        }
        __syncthreads();
        #pragma unroll
        for (int j = 0; j < 8; j++) {
            int v = t + j*256;
            int m = v >> 6, o = v & 63;
            size_t dst = ((size_t)(lh*32 + m)*64 + i)*64 + o;
            g_wtr[dst] = tr[o][m];
            g_wti[dst] = ti_[o][m];
        }
    } else {
        int idx = (blk - PB_INIT - PB_CONV - PB_WTRANS)*256 + t;
        int d4 = (idx & 127) * 4;
        size_t bl = (size_t)(idx >> 7);
        int a = app[bl];
        float xtv = xt[bl];
        float4 e = *(const float4*)&emb[(size_t)a*Dq + d4];
        float4 w = *(const float4*)&tw[d4];
        float4 bb = *(const float4*)&tb[d4];
        __half2 h0, h1;
        h0.x = __float2half_rn(fmaf(xtv, w.x, e.x) + bb.x);
        h0.y = __float2half_rn(fmaf(xtv, w.y, e.y) + bb.y);
        h1.x = __float2half_rn(fmaf(xtv, w.z, e.z) + bb.z);
        h1.y = __float2half_rn(fmaf(xtv, w.w, e.w) + bb.w);
        *(__half2*)&g_xh[bl*Dq + d4]     = h0;
        *(__half2*)&g_xh[bl*Dq + d4 + 2] = h1;
    }
}

// ========== Wo frequency table ==========
__global__ void __launch_bounds__(128) wotab_kernel(const float* __restrict__ Wo,
                                                    __half* __restrict__ wth,
                                                    __half* __restrict__ wtl) {
    int layer = blockIdx.y;
    int j0 = blockIdx.x * 4;
    __shared__ float sw[4][512];
    int t = threadIdx.x;
    const float* wo = Wo + (size_t)layer*Dq*Dq + (size_t)j0*Dq;
    #pragma unroll
    for (int j = 0; j < 4; j++) {
        int v = t + j*128;
        int r = v >> 7, c4 = (v & 127) * 4;
        *(float4*)&sw[r][c4] = *(const float4*)&wo[(size_t)r*Dq + c4];
    }
    __syncthreads();
    int tj = t >> 5, tm = t & 31;
    float ac = 0.f, as = 0.f;
    for (int l = 0; l < Lq; l++) {
        float w = sw[tj][l];
        ac = fmaf(w, g_ct[l*32 + tm], ac);
        as = fmaf(w, g_st[l*32 + tm], as);
    }
    float cm = (tm == 0 ? 1.0f : 2.0f) * (256.0f/512.0f);
    float vc = ac*cm, vs = -as*cm;
    size_t base = ((size_t)layer*Dq + j0 + tj)*64 + tm*2;
    __half hc = __float2half_rn(vc);
    __half hs = __float2half_rn(vs);
    wth[base]   = hc;  wtl[base]   = __float2half_rn(vc - __half2float(hc));
    wth[base+1] = hs;  wtl[base+1] = __float2half_rn(vs - __half2float(hs));
}

// ================= mma.sync fp16 GEMM: C = A(MxK) @ B(NxK)^T =============
// TERMS==2: Ah*(Bh+Bl), 1 CTA/SM.  TERMS==1: Ah*Bh, compact smem, 2 CTA/SM.
#define GF_BIAS 1
#define GF_RES  2
#define GF_RELU 4
#define GF_OUTF32 8
#define GF_OUTH16 16

template<int TERMS> struct GCfg;
template<> struct GCfg<1> { static const int STG = 16384, BOFF = 8192,  OCC = 2; };
template<> struct GCfg<2> { static const int STG = 32768, BOFF = 16384, OCC = 1; };

#define SMEM_G(TERMS) (3*GCfg<TERMS>::STG + 256)

template<int FLAGS, int TERMS>
__global__ void __launch_bounds__(256, GCfg<TERMS>::OCC) gemm_mma(
    const __half* __restrict__ Ah,
    const __half* __restrict__ Bh, const __half* __restrict__ Bl,
    const float* __restrict__ bias, const __half* __restrict__ res,
    float* __restrict__ Cf, __half* __restrict__ Ch,
    int M, int N, int K, float scal)
{
    extern __shared__ char dsm[];
    const int STG_ = GCfg<TERMS>::STG;
    const int BOFF_ = GCfg<TERMS>::BOFF;
    uint32_t sbase = (smem_u32(dsm) + 127) & ~127u;

    const int t = threadIdx.x;
    const int lane = t & 31;
    const int wid = t >> 5;
    const int wm = wid >> 2;
    const int wn = wid & 3;
    const int bm = blockIdx.y * 128, bn = blockIdx.x * 128;
    const int NC = K >> 5;

    float acc[4][4][4] = {};

    const int lrow = t >> 2;
    const int lcell = t & 3;
    auto load_chunk = [&](int c, int stg) {
        uint32_t sb = sbase + stg*STG_;
        size_t k0 = (size_t)c * 32 + lcell*8;
        #pragma unroll
        for (int j = 0; j < 2; j++) {
            int row = lrow + j*64;
            uint32_t soff = row*64 + (((uint32_t)(lcell ^ (row & 3))) << 4);
            size_t ga = (size_t)(bm + row)*K + k0;
            size_t gb = (size_t)(bn + row)*K + k0;
            cp16(sb +        soff, Ah + ga);
            cp16(sb + BOFF_ + soff, Bh + gb);
            if (TERMS >= 2) cp16(sb + 24576 + soff, Bl + gb);
        }
        CP_COMMIT();
    };

    load_chunk(0, 0);
    if (NC > 1) load_chunk(1, 1);

    const int arow_base = wm*64 + (lane & 15);
    const int brow_base = wn*32 + (lane & 15);
    const int kc_hi = lane >> 4;

    for (int c = 0; c < NC; c++) {
        if (c + 2 < NC) asm volatile("cp.async.wait_group 1;" ::: "memory");
        else            asm volatile("cp.async.wait_group 0;" ::: "memory");
        __syncthreads();
        if (c + 2 < NC) load_chunk(c + 2, (c + 2) % 3);

        uint32_t sb = sbase + (c % 3)*STG_;
        #pragma unroll
        for (int s = 0; s < 2; s++) {
            uint32_t ah[4][4], bh[2][4], bl[2][4];
            int chunk = s*2 + kc_hi;
            #pragma unroll
            for (int mt = 0; mt < 4; mt++) {
                int row = arow_base + mt*16;
                uint32_t off = row*64 + (((uint32_t)(chunk ^ (row & 3))) << 4);
                LDSM_X4(ah[mt][0], ah[mt][1], ah[mt][2], ah[mt][3], sb + off);
            }
            #pragma unroll
            for (int g = 0; g < 2; g++) {
                int row = brow_base + g*16;
                uint32_t off = row*64 + (((uint32_t)(chunk ^ (row & 3))) << 4);
                LDSM_X4(bh[g][0], bh[g][1], bh[g][2], bh[g][3], sb + BOFF_ + off);
                if (TERMS >= 2)
                    LDSM_X4(bl[g][0], bl[g][1], bl[g][2], bl[g][3], sb + 24576 + off);
            }
            #pragma unroll
            for (int mt = 0; mt < 4; mt++) {
                #pragma unroll
                for (int nt = 0; nt < 4; nt++) {
                    int g = nt >> 1, o = nt & 1;
                    MMA_F32(acc[mt][nt], ah[mt], bh[g][o], bh[g][o+2]);
                    if (TERMS >= 2)
                        MMA_F32(acc[mt][nt], ah[mt], bl[g][o], bl[g][o+2]);
                }
            }
        }
    }

    int r0 = bm + wm*64 + (lane >> 2);
    int c0 = bn + wn*32 + (lane & 3)*2;
    #pragma unroll
    for (int mt = 0; mt < 4; mt++) {
        #pragma unroll
        for (int nt = 0; nt < 4; nt++) {
            int col = c0 + nt*8;
            float b0 = 0.f, b1 = 0.f;
            if (FLAGS & GF_BIAS) { b0 = bias[col]; b1 = bias[col+1]; }
            #pragma unroll
            for (int half = 0; half < 2; half++) {
                int row = r0 + mt*16 + half*8;
                float v0 = acc[mt][nt][half*2+0] * scal + b0;
                float v1 = acc[mt][nt][half*2+1] * scal + b1;
                size_t ro = (size_t)row * N + col;
                if (FLAGS & GF_RES) {
                    float2 r2 = __half22float2(*(const __half2*)&res[ro]);
                    v0 += r2.x; v1 += r2.y;
                }
                if (FLAGS & GF_RELU) { v0 = fmaxf(v0, 0.f); v1 = fmaxf(v1, 0.f); }
                if (FLAGS & GF_OUTF32) {
                    float2 o2; o2.x = v0; o2.y = v1;
                    *(float2*)&Cf[ro] = o2;
                }
                if (FLAGS & GF_OUTH16) {
                    __half2 hp; hp.x = __float2half_rn(v0); hp.y = __float2half_rn(v1);
                    *(__half2*)&Ch[ro] = hp;
                }
            }
        }
    }
}

// ========== DFT of x (half input) with l/l+256 symmetry; half output ==========
__global__ void __launch_bounds__(128) dftx_kernel(const __half* __restrict__ x,
                                                   __half* __restrict__ Xh) {
    int blk = blockIdx.x;
    int b = blk >> 3;
    int dchunk = (blk & 7) * 64;
    __shared__ float sqA[32][68];
    __shared__ float sqB[32][68];
    __shared__ float sct[32][32];
    __shared__ float sst[32][32];
    int t = threadIdx.x;
    int td = t & 63;
    int tm = (t >> 6) * 16;

    float ar[16] = {}, ai[16] = {};
    const __half* qbase = x + (size_t)b*Lq*Dq + dchunk;

    for (int l0 = 0; l0 < 256; l0 += 32) {
        #pragma unroll
        for (int j = 0; j < 8; j++) {
            int v = t + j*128;
            int ll = v >> 5;
            int c2 = (v & 31) * 2;
            float2 fa = __half22float2(*(const __half2*)&qbase[(size_t)(l0+ll)*Dq + c2]);
            sqA[ll][c2] = fa.x; sqA[ll][c2+1] = fa.y;
            float2 fb = __half22float2(*(const __half2*)&qbase[(size_t)(l0+256+ll)*Dq + c2]);
            sqB[ll][c2] = fb.x; sqB[ll][c2+1] = fb.y;
        }
        #pragma unroll
        for (int j = 0; j < 2; j++) {
            int v = t + j*128;
            int ll = v >> 3;
            int c4 = (v & 7) * 4;
            *(float4*)&sct[ll][c4] = *(const float4*)&g_ct[(l0+ll)*32 + c4];
            *(float4*)&sst[ll][c4] = *(const float4*)&g_st[(l0+ll)*32 + c4];
        }
        __syncthreads();
        #pragma unroll 2
        for (int ll = 0; ll < 32; ll++) {
            float xa = sqA[ll][td], xb = sqB[ll][td];
            float u = xa + xb;
            float w = xa - xb;
            float c[16], s[16];
            #pragma unroll
            for (int j = 0; j < 16; j += 4) {
                *(float4*)&c[j] = *(float4*)&sct[ll][tm+j];
                *(float4*)&s[j] = *(float4*)&sst[ll][tm+j];
            }
            #pragma unroll
            for (int mm = 0; mm < 16; mm++) {
                float v = (mm & 1) ? w : u;
                ar[mm] = fmaf(v,  c[mm], ar[mm]);
                ai[mm] = fmaf(-v, s[mm], ai[mm]);
            }
        }
        __syncthreads();
    }
    int d0 = dchunk + td;
    #pragma unroll
    for (int mm = 0; mm < 16; mm++) {
        int m = tm + mm;
        size_t rowr = ((size_t)(m*2+0)*64 + b)*Dq + d0;
        size_t rowi = ((size_t)(m*2+1)*64 + b)*Dq + d0;
        Xh[rowr] = __float2half_rn(ar[mm]);
        Xh[rowi] = __float2half_rn(ai[mm]);
    }
}

// ========== complex mode mix ==========
__global__ void __launch_bounds__(256) mix2_kernel(const float* __restrict__ xs,
                                                   const float* __restrict__ wtr,
                                                   const float* __restrict__ wti,
                                                   const float* __restrict__ bq,
                                                   __half* __restrict__ osh) {
    int h = blockIdx.x >> 5, m = blockIdx.x & 31;
    __shared__ float swr[64][64];
    __shared__ float swi[64][64];
    __shared__ float sxr[64][65];
    __shared__ float sxi[64][65];
    int t = threadIdx.x;
    const float* pr = wtr + ((size_t)(h*32 + m))*4096;
    const float* pi = wti + ((size_t)(h*32 + m))*4096;
    #pragma unroll
    for (int j = 0; j < 16; j++) {
        int v = t + j*256;
        int r = v >> 6, c = v & 63;
        swr[r][c] = pr[v];
        swi[r][c] = pi[v];
    }
    #pragma unroll
    for (int j = 0; j < 16; j++) {
        int v = t + j*256;
        int b = v >> 6, i = v & 63;
        if (j < 8) {
            float vr = xs[((size_t)(2*m)*64 + b)*Dq + h*64 + i];
            if (m == 0) vr += 512.0f * bq[h*64 + i];
            sxr[b][i] = vr;
        } else {
            sxi[b][i] = xs[((size_t)(2*m+1)*64 + b)*Dq + h*64 + i];
        }
    }
    __syncthreads();

    int b = t >> 2;
    int o0 = (t & 3) * 16;
    float orr[16] = {}, oii[16] = {};
    for (int i = 0; i < 64; i++) {
        float xr = sxr[b][i], xi = sxi[b][i];
        float wr4[16], wi4[16];
        #pragma unroll
        for (int j = 0; j < 16; j += 4) {
            *(float4*)&wr4[j] = *(float4*)&swr[i][o0+j];
            *(float4*)&wi4[j] = *(float4*)&swi[i][o0+j];
        }
        #pragma unroll
        for (int j = 0; j < 16; j++) {
            orr[j] = fmaf(xr, wr4[j], orr[j]);
            orr[j] = fmaf(-xi, wi4[j], orr[j]);
            oii[j] = fmaf(xr, wi4[j], oii[j]);
            oii[j] = fmaf(xi, wr4[j], oii[j]);
        }
    }
    #pragma unroll
    for (int j = 0; j < 16; j++) {
        int o = o0 + j;
        __half2 hp;
        hp.x = __float2half_rn(orr[j] * 256.0f);
        hp.y = __float2half_rn(oii[j] * 256.0f);
        size_t base = ((size_t)b*512 + h*64 + o)*64 + 2*m;
        *(__half2*)&osh[base] = hp;
    }
}

// ========== series_decomp ==========
__global__ void decomp_kernel(const __half* __restrict__ in, float* __restrict__ out_f,
                              __half* __restrict__ oh) {
    int gid = blockIdx.x*blockDim.x + threadIdx.x;
    int seg = gid >> 14;
    int r = gid & 16383;
    int b = r >> 8, d2 = (r & 255) * 2;
    const __half2* p = (const __half2*)(in + (size_t)b*Lq*Dq + d2);
    size_t obase = (size_t)b*Lq*Dq + d2;
    int lstart = seg * 64;
    float2 ws; ws.x = 0.f; ws.y = 0.f;
    #pragma unroll
    for (int j = -12; j <= 12; j++) {
        int jj = lstart + j;
        jj = jj < 0 ? 0 : jj;
        float2 q = __half22float2(p[(size_t)jj*256]);
        ws.x += q.x; ws.y += q.y;
    }
    int lend = lstart + 64;
    if (oh) {
        for (int l = lstart; l < lend; l++) {
            float2 xl = __half22float2(p[(size_t)l*256]);
            float2 v;
            v.x = xl.x - ws.x*(1.0f/25.0f);
            v.y = xl.y - ws.y*(1.0f/25.0f);
            __half2 hv; hv.x = __float2half_rn(v.x); hv.y = __float2half_rn(v.y);
            *(__half2*)&oh[obase + (size_t)l*Dq] = hv;
            int jn = l+13 > Lq-1 ? Lq-1 : l+13;
            int jo = l-12 < 0 ? 0 : l-12;
            float2 a = __half22float2(p[(size_t)jn*256]);
            float2 bb = __half22float2(p[(size_t)jo*256]);
            ws.x += a.x - bb.x; ws.y += a.y - bb.y;
        }
    } else {
        for (int l = lstart; l < lend; l++) {
            float2 xl = __half22float2(p[(size_t)l*256]);
            float2 v;
            v.x = xl.x - ws.x*(1.0f/25.0f);
            v.y = xl.y - ws.y*(1.0f/25.0f);
            *(float2*)&out_f[obase + (size_t)l*Dq] = v;
            int jn = l+13 > Lq-1 ? Lq-1 : l+13;
            int jo = l-12 < 0 ? 0 : l-12;
            float2 a = __half22float2(p[(size_t)jn*256]);
            float2 bb = __half22float2(p[(size_t)jo*256]);
            ws.x += a.x - bb.x; ws.y += a.y - bb.y;
        }
    }
}

// ================= final layernorm / projection =================
__global__ void ln_rows(const float* __restrict__ x) {
    int row = blockIdx.x;
    int t = threadIdx.x;
    const float* p = x + (size_t)row*Dq;
    float v0 = p[t], v1 = p[t+256];
    __shared__ float sh[8];
    float s = v0 + v1;
    int lane = t & 31, w = t >> 5;
    #pragma unroll
    for (int o = 16; o > 0; o >>= 1) s += __shfl_down_sync(~0u, s, o);
    if (lane == 0) sh[w] = s;
    __syncthreads();
    if (t < 32) {
        float v = (t < 8) ? sh[t] : 0.f;
        #pragma unroll
        for (int o = 4; o > 0; o >>= 1) v += __shfl_down_sync(~0u, v, o);
        if (t == 0) sh[0] = v;
    }
    __syncthreads();
    float mu = sh[0] * (1.0f/512.0f);
    __syncthreads();
    float d0 = v0 - mu, d1 = v1 - mu;
    s = d0*d0 + d1*d1;
    #pragma unroll
    for (int o = 16; o > 0; o >>= 1) s += __shfl_down_sync(~0u, s, o);
    if (lane == 0) sh[w] = s;
    __syncthreads();
    if (t < 32) {
        float v = (t < 8) ? sh[t] : 0.f;
        #pragma unroll
        for (int o = 4; o > 0; o >>= 1) v += __shfl_down_sync(~0u, v, o);
        if (t == 0) {
            float var = v * (1.0f/512.0f);
            g_mu[row] = mu;
            g_rs[row] = rsqrtf(var + 1e-5f);
        }
    }
}

__global__ void ln_cols_part(const float* __restrict__ x, const float* __restrict__ nw,
                             const float* __restrict__ nb) {
    int blk = blockIdx.x;
    int b = blk >> 3, seg = blk & 7;
    int d = threadIdx.x;
    float w = nw[d], bb = nb[d];
    float sum = 0.f;
    int l0 = seg * 64;
    #pragma unroll 4
    for (int l = l0; l < l0 + 64; l++) {
        int row = b*Lq + l;
        sum += (x[(size_t)row*Dq + d] - g_mu[row]) * g_rs[row] * w + bb;
    }
    g_part[(size_t)seg*Bq*Dq + b*Dq + d] = sum;
}

__global__ void ln_cols_fin(const float* __restrict__ x, const float* __restrict__ nw,
                            const float* __restrict__ nb, const float* __restrict__ tv) {
    int b = blockIdx.x;
    int d = threadIdx.x;
    float sum = 0.f;
    #pragma unroll
    for (int seg = 0; seg < 8; seg++)
        sum += g_part[(size_t)seg*Bq*Dq + b*Dq + d];
    int row = b*Lq + (Lq-1);
    float lastv = (x[(size_t)row*Dq + d] - g_mu[row]) * g_rs[row] * nw[d] + nb[d];
    g_cat[b*CATD + d] = lastv - sum*(1.0f/512.0f);
    if (d < 24) g_cat[b*CATD + 512 + d] = tv[((size_t)b*Lq + (Lq-1))*24 + d];
}

__global__ void __launch_bounds__(256) proj_kernel(const float* __restrict__ pw,
                                                   const float* __restrict__ pb,
                                                   float* __restrict__ out) {
    __shared__ float As[8][65];
    __shared__ float Bs[8][65];
    int n0 = blockIdx.x * 64;
    int t = threadIdx.x;
    int tx = t & 15, ty = t >> 4;
    float acc[4][4] = {};
    for (int k0 = 0; k0 < CATD; k0 += 8) {
        int v = t*2;
        int r = v >> 3, c = v & 7;
        As[c][r]   = g_cat[r*CATD + k0 + c];
        As[c+1][r] = g_cat[r*CATD + k0 + c + 1];
        int n = n0 + r;
        float f0 = 0.f, f1 = 0.f;
        if (n < NUM_APP) {
            f0 = pw[(size_t)n*CATD + k0 + c];
            f1 = pw[(size_t)n*CATD + k0 + c + 1];
        }
        Bs[c][r] = f0; Bs[c+1][r] = f1;
        __syncthreads();
        #pragma unroll
        for (int k = 0; k < 8; k++) {
            float a[4], bv[4];
            #pragma unroll
            for (int i = 0; i < 4; i++) { a[i] = As[k][ty*4+i]; bv[i] = Bs[k][tx*4+i]; }
            #pragma unroll
            for (int i = 0; i < 4; i++)
                #pragma unroll
                for (int j = 0; j < 4; j++)
                    acc[i][j] = fmaf(a[i], bv[j], acc[i][j]);
        }
        __syncthreads();
    }
    #pragma unroll
    for (int i = 0; i < 4; i++) {
        int bi = ty*4 + i;
        #pragma unroll
        for (int j = 0; j < 4; j++) {
            int n = n0 + tx*4 + j;
            if (n < NUM_APP) out[(size_t)bi*NUM_APP + n] = acc[i][j] + pb[n];
        }
    }
}

// ================= host orchestration =================
extern "C" void kernel_launch(void* const* d_in, const int* in_sizes, int n_in,
                              void* d_out, int out_size) {
    const int*   x_app     = (const int*)  d_in[0];
    const float* x_time    = (const float*)d_in[1];
    const float* time_vecs = (const float*)d_in[2];
    const float* app_emb_w = (const float*)d_in[4];
    const float* time_w    = (const float*)d_in[5];
    const float* time_b    = (const float*)d_in[6];
    const float* Wq        = (const float*)d_in[7];
    const float* bq        = (const float*)d_in[8];
    const float* Wo        = (const float*)d_in[9];
    const float* bo        = (const float*)d_in[10];
    const float* four_wr   = (const float*)d_in[11];
    const float* four_wi   = (const float*)d_in[12];
    const float* conv1_w   = (const float*)d_in[13];
    const float* conv2_w   = (const float*)d_in[14];
    const float* norm_w    = (const float*)d_in[15];
    const float* norm_b    = (const float*)d_in[16];
    const float* proj_w    = (const float*)d_in[17];
    const float* proj_b    = (const float*)d_in[18];
    float* out = (float*)d_out;

    cudaFuncSetAttribute((const void*)gemm_mma<GF_OUTF32, 2>,                cudaFuncAttributeMaxDynamicSharedMemorySize, SMEM_G(2));
    cudaFuncSetAttribute((const void*)gemm_mma<GF_BIAS|GF_RES|GF_OUTH16, 2>, cudaFuncAttributeMaxDynamicSharedMemorySize, SMEM_G(2));
    cudaFuncSetAttribute((const void*)gemm_mma<GF_RELU|GF_OUTH16, 1>,        cudaFuncAttributeMaxDynamicSharedMemorySize, SMEM_G(1));
    cudaFuncSetAttribute((const void*)gemm_mma<GF_RES|GF_OUTH16, 1>,         cudaFuncAttributeMaxDynamicSharedMemorySize, SMEM_G(1));

    void *px, *pq, *pth;
    void *pxh, *pXh, *pyh, *posh, *pwth, *pwtl;
    void *pwqh, *pwql, *pc1h, *pc2h, *pwtr, *pwti;
    cudaGetSymbolAddress(&px, g_x);
    cudaGetSymbolAddress(&pq, g_q);
    cudaGetSymbolAddress(&pth, g_th);
    cudaGetSymbolAddress(&pxh, g_xh);
    cudaGetSymbolAddress(&pXh, g_Xh);
    cudaGetSymbolAddress(&pyh, g_yh);
    cudaGetSymbolAddress(&posh, g_osh);
    cudaGetSymbolAddress(&pwth, g_wth); cudaGetSymbolAddress(&pwtl, g_wtl);
    cudaGetSymbolAddress(&pwqh, g_wqh); cudaGetSymbolAddress(&pwql, g_wql);
    cudaGetSymbolAddress(&pc1h, g_c1h);
    cudaGetSymbolAddress(&pc2h, g_c2h);
    cudaGetSymbolAddress(&pwtr, g_wtr); cudaGetSymbolAddress(&pwti, g_wti);
    float* fx = (float*)px;
    float* fq = (float*)pq;
    __half* th = (__half*)pth;
    __half *xh=(__half*)pxh;
    __half *Xh=(__half*)pXh;
    __half *yh=(__half*)pyh;
    __half *osh=(__half*)posh;
    __half *wth=(__half*)pwth, *wtl=(__half*)pwtl;
    __half *wqh=(__half*)pwqh, *wql=(__half*)pwql;
    __half *c1h=(__half*)pc1h;
    __half *c2h=(__half*)pc2h;
    float *wtr=(float*)pwtr, *wti=(float*)pwti;

    prep_kernel<<<PB_TOTAL, 256>>>(Wq, conv1_w, conv2_w, four_wr, four_wi,
                                   x_app, x_time, app_emb_w, time_w, time_b);
    wotab_kernel<<<dim3(128, 2), 128>>>(Wo, wth, wtl);

    const int M = BLq;
    for (int l = 0; l < 2; l++) {
        size_t woff = (size_t)l*Dq*Dq;
        size_t coff1 = (size_t)l*DFF*Dq;
        size_t mixoff = (size_t)l*Hq*MODES*Eq*Eq;

        dftx_kernel<<<512, 128>>>(xh, Xh);
        gemm_mma<GF_OUTF32, 2><<<dim3(4, 32), 256, SMEM_G(2)>>>(
            Xh, wqh + woff, wql + woff, nullptr, nullptr,
            fq, nullptr, 4096, Dq, Dq, 1.0f);
        mix2_kernel<<<Hq*MODES, 256>>>(fq, wtr + mixoff, wti + mixoff,
                                       bq + l*Dq, osh);
        gemm_mma<GF_BIAS|GF_RES|GF_OUTH16, 2><<<dim3(4, 256), 256, SMEM_G(2)>>>(
            osh, wth + (size_t)l*Dq*64, wtl + (size_t)l*Dq*64, bo + l*Dq, xh,
            nullptr, th, M, Dq, 64, 1.0f/65536.0f);
        decomp_kernel<<<512, 256>>>(th, nullptr, xh);
        gemm_mma<GF_RELU|GF_OUTH16, 1><<<dim3(DFF/128, M/128), 256, SMEM_G(1)>>>(
            xh, c1h + coff1, nullptr, nullptr, nullptr,
            nullptr, yh, M, DFF, Dq, 1.0f);
        gemm_mma<GF_RES|GF_OUTH16, 1><<<dim3(Dq/128, M/128), 256, SMEM_G(1)>>>(
            yh, c2h + coff1, nullptr, nullptr, xh,
            nullptr, th, M, Dq, DFF, 1.0f);
        if (l == 1) decomp_kernel<<<512, 256>>>(th, fx, nullptr);
        else        decomp_kernel<<<512, 256>>>(th, nullptr, xh);
    }

    ln_rows<<<BLq, 256>>>(fx);
    ln_cols_part<<<Bq*8, 512>>>(fx, norm_w, norm_b);
    ln_cols_fin<<<Bq, 512>>>(fx, norm_w, norm_b, time_vecs);
    proj_kernel<<<(NUM_APP + 63)/64, 256>>>(proj_w, proj_b, out);
}